// round 1
// baseline (speedup 1.0000x reference)
#include <cuda_runtime.h>
#include <math.h>

#define Hh 96
#define Ww 96
#define HW 9216
#define Fch 96
#define CIN 8
#define Lk 5
#define Sg 10
#define Bg 4
#define FH3 288          // 3*F
#define K1 480           // L*F
#define STEP_ELEMS (Bg*Fch*HW)   // 3,538,944

// ---- scratch (no allocs allowed; device globals) ----
__device__ float g_i2h[(size_t)Sg*Bg*FH3*HW];   // 425 MB, precomputed once
__device__ float g_f[Bg*32*HW];
__device__ float g_flows[Bg*10*HW];
__device__ float g_warped[(size_t)Bg*K1*HW];
__device__ float g_h2h[(size_t)Bg*FH3*HW];

__device__ __forceinline__ float leaky(float v){ return v > 0.f ? v : 0.2f*v; }
__device__ __forceinline__ float sigm(float v){ return 1.f/(1.f + expf(-v)); }

// ============================================================
// i2h: 3x3 conv pad1, 8->288, over all S*B images (runs once)
// grid (S*B, H, 9 oc-groups of 32), block 96 (x)
// ============================================================
__global__ void k_i2h(const float* __restrict__ x,
                      const float* __restrict__ w,
                      const float* __restrict__ bias){
    int img = blockIdx.x, y = blockIdx.y, ocg = blockIdx.z;
    int tx = threadIdx.x;
    __shared__ float ws[32*72];
    for (int i = tx; i < 32*72; i += 96) ws[i] = w[ocg*32*72 + i];
    __syncthreads();
    const float* xb = x + (size_t)img*CIN*HW;
    float acc[32];
    #pragma unroll
    for (int o = 0; o < 32; o++) acc[o] = 0.f;
    for (int ic = 0; ic < CIN; ic++){
        const float* xc = xb + (size_t)ic*HW;
        #pragma unroll
        for (int dy = 0; dy < 3; dy++){
            int yy = y + dy - 1;
            if (yy < 0 || yy >= Hh) continue;
            #pragma unroll
            for (int dx = 0; dx < 3; dx++){
                int xx = tx + dx - 1;
                float v = (xx >= 0 && xx < Ww) ? xc[yy*Ww + xx] : 0.f;
                int base = ic*9 + dy*3 + dx;
                #pragma unroll
                for (int o = 0; o < 32; o++) acc[o] += v * ws[o*72 + base];
            }
        }
    }
    float* outp = g_i2h + (size_t)img*FH3*HW + (size_t)(ocg*32)*HW + y*Ww + tx;
    #pragma unroll
    for (int o = 0; o < 32; o++) outp[(size_t)o*HW] = acc[o] + bias[ocg*32 + o];
}

// ============================================================
// f = leaky( conv5x5(x_t, 8->32) + conv5x5(h, 96->32) )
// grid (B, H), block 96 (x). 13 ic-groups of 8 staged in smem.
// ============================================================
__global__ void k_fconv(const float* __restrict__ x_t,
                        const float* __restrict__ h,
                        const float* __restrict__ w_i2f,
                        const float* __restrict__ b_i2f,
                        const float* __restrict__ w_h2f,
                        const float* __restrict__ b_h2f){
    int b = blockIdx.x, y = blockIdx.y, tx = threadIdx.x;
    __shared__ float ws[32*8*25];   // 25.6 KB
    float acc[32];
    #pragma unroll
    for (int o = 0; o < 32; o++) acc[o] = b_i2f[o] + b_h2f[o];

    for (int g = 0; g < 13; g++){
        __syncthreads();
        // stage weights for this 8-ic group: ws[oc*200 + icl*25 + tap]
        for (int j = tx; j < 6400; j += 96){
            int oc = j / 200, rem = j % 200;
            int icl = rem / 25, tap = rem % 25;
            ws[j] = (g == 0) ? w_i2f[(oc*8 + icl)*25 + tap]
                             : w_h2f[((size_t)oc*96 + (g-1)*8 + icl)*25 + tap];
        }
        __syncthreads();
        const float* src = (g == 0) ? x_t + (size_t)b*CIN*HW
                                    : h   + (size_t)b*Fch*HW + (size_t)(g-1)*8*HW;
        for (int icl = 0; icl < 8; icl++){
            const float* sc = src + (size_t)icl*HW;
            #pragma unroll
            for (int dy = 0; dy < 5; dy++){
                int yy = y + dy - 2;
                if (yy < 0 || yy >= Hh) continue;
                #pragma unroll
                for (int dx = 0; dx < 5; dx++){
                    int xx = tx + dx - 2;
                    float v = (xx >= 0 && xx < Ww) ? sc[yy*Ww + xx] : 0.f;
                    int base = icl*25 + dy*5 + dx;
                    #pragma unroll
                    for (int o = 0; o < 32; o++) acc[o] += v * ws[o*200 + base];
                }
            }
        }
    }
    float* outp = g_f + (size_t)b*32*HW + y*Ww + tx;
    #pragma unroll
    for (int o = 0; o < 32; o++) outp[(size_t)o*HW] = leaky(acc[o]);
}

// ============================================================
// flows = conv5x5(f, 32->10) + bias ; grid (B, H), block 96
// ============================================================
__global__ void k_flows(const float* __restrict__ w_fl,
                        const float* __restrict__ b_fl){
    int b = blockIdx.x, y = blockIdx.y, tx = threadIdx.x;
    __shared__ float ws[10*32*25];  // 32 KB
    for (int j = tx; j < 8000; j += 96) ws[j] = w_fl[j];
    __syncthreads();
    float acc[10];
    #pragma unroll
    for (int o = 0; o < 10; o++) acc[o] = b_fl[o];
    const float* src = g_f + (size_t)b*32*HW;
    for (int ic = 0; ic < 32; ic++){
        const float* sc = src + (size_t)ic*HW;
        #pragma unroll
        for (int dy = 0; dy < 5; dy++){
            int yy = y + dy - 2;
            if (yy < 0 || yy >= Hh) continue;
            #pragma unroll
            for (int dx = 0; dx < 5; dx++){
                int xx = tx + dx - 2;
                float v = (xx >= 0 && xx < Ww) ? sc[yy*Ww + xx] : 0.f;
                int tap = ic*25 + dy*5 + dx;
                #pragma unroll
                for (int o = 0; o < 10; o++) acc[o] += v * ws[o*800 + tap];
            }
        }
    }
    float* outp = g_flows + (size_t)b*10*HW + y*Ww + tx;
    #pragma unroll
    for (int o = 0; o < 10; o++) outp[(size_t)o*HW] = acc[o];
}

// ============================================================
// warp: warped[b, l*96+c, y, x] = bilinear(h[b,c], x - fx, y - fy)
// zeros padding, align_corners=False semantics. grid (B*L, H), block 96
// ============================================================
__global__ void k_warp(const float* __restrict__ h){
    int bl = blockIdx.x, y = blockIdx.y, tx = threadIdx.x;
    int b = bl / Lk, l = bl % Lk;
    const float* fl = g_flows + (size_t)b*10*HW + y*Ww + tx;
    float fx = fl[(size_t)(2*l)*HW];
    float fy = fl[(size_t)(2*l+1)*HW];
    float vx = (float)tx - fx;
    float vy = (float)y  - fy;
    const float sc = 96.0f/95.0f;
    float ix = vx*sc - 0.5f;
    float iy = vy*sc - 0.5f;
    float fx0 = floorf(ix), fy0 = floorf(iy);
    int ix0 = (int)fx0, iy0 = (int)fy0;
    int ix1 = ix0 + 1, iy1 = iy0 + 1;
    float wx1 = ix - fx0, wy1 = iy - fy0;
    float wx0 = 1.f - wx1, wy0 = 1.f - wy1;
    float mx0 = (ix0 >= 0 && ix0 < Ww) ? 1.f : 0.f;
    float mx1 = (ix1 >= 0 && ix1 < Ww) ? 1.f : 0.f;
    float my0 = (iy0 >= 0 && iy0 < Hh) ? 1.f : 0.f;
    float my1 = (iy1 >= 0 && iy1 < Hh) ? 1.f : 0.f;
    int cx0 = min(max(ix0, 0), Ww-1), cx1 = min(max(ix1, 0), Ww-1);
    int cy0 = min(max(iy0, 0), Hh-1), cy1 = min(max(iy1, 0), Hh-1);
    int o00 = cy0*Ww + cx0, o01 = cy0*Ww + cx1;
    int o10 = cy1*Ww + cx0, o11 = cy1*Ww + cx1;
    float w00 = wy0*wx0*my0*mx0, w01 = wy0*wx1*my0*mx1;
    float w10 = wy1*wx0*my1*mx0, w11 = wy1*wx1*my1*mx1;
    const float* hb = h + (size_t)b*Fch*HW;
    float* op = g_warped + ((size_t)b*K1 + l*Fch)*HW + y*Ww + tx;
    for (int c = 0; c < Fch; c++){
        const float* p = hb + (size_t)c*HW;
        op[(size_t)c*HW] = w00*p[o00] + w01*p[o01] + w10*p[o10] + w11*p[o11];
    }
}

// ============================================================
// h2h[b] (288 x 9216) = w_ret(288 x 480) @ warped[b](480 x 9216) + b_ret
// tiled SGEMM: BM=BN=64, BK=16, 256 thr, 4x4 per thread
// grid (144, 5, B)
// ============================================================
__global__ void k_gemm(const float* __restrict__ A,
                       const float* __restrict__ bias){
    __shared__ float As[16][68];
    __shared__ float Bs[16][68];
    int tid = threadIdx.x;
    int txq = tid % 16, tyq = tid / 16;
    int n0 = blockIdx.x * 64, m0 = blockIdx.y * 64;
    const float* Bp = g_warped + (size_t)blockIdx.z*K1*HW;
    float* Cp = g_h2h + (size_t)blockIdx.z*FH3*HW;
    float acc[4][4];
    #pragma unroll
    for (int i = 0; i < 4; i++)
        #pragma unroll
        for (int j = 0; j < 4; j++) acc[i][j] = 0.f;

    for (int kk = 0; kk < K1; kk += 16){
        #pragma unroll
        for (int i = tid; i < 1024; i += 256){
            int m = i / 16, k = i % 16;
            As[k][m] = (m0 + m < FH3) ? A[(size_t)(m0+m)*K1 + kk + k] : 0.f;
        }
        #pragma unroll
        for (int i = tid; i < 1024; i += 256){
            int k = i / 64, n = i % 64;
            Bs[k][n] = Bp[(size_t)(kk+k)*HW + n0 + n];
        }
        __syncthreads();
        #pragma unroll
        for (int k = 0; k < 16; k++){
            float a[4], bb[4];
            #pragma unroll
            for (int i = 0; i < 4; i++) a[i] = As[k][tyq*4 + i];
            #pragma unroll
            for (int j = 0; j < 4; j++) bb[j] = Bs[k][txq*4 + j];
            #pragma unroll
            for (int i = 0; i < 4; i++)
                #pragma unroll
                for (int j = 0; j < 4; j++) acc[i][j] += a[i]*bb[j];
        }
        __syncthreads();
    }
    #pragma unroll
    for (int i = 0; i < 4; i++){
        int m = m0 + tyq*4 + i;
        if (m >= FH3) continue;
        float bv = bias[m];
        #pragma unroll
        for (int j = 0; j < 4; j++)
            Cp[(size_t)m*HW + n0 + txq*4 + j] = acc[i][j] + bv;
    }
}

// ============================================================
// gates: elementwise GRU update -> next_h (written to d_out slice)
// ============================================================
__global__ void k_gates(int t, const float* __restrict__ hprev,
                        float* __restrict__ hnext){
    int idx = blockIdx.x * blockDim.x + threadIdx.x;
    if (idx >= STEP_ELEMS) return;
    int p  = idx % HW;
    int fc = (idx / HW) % Fch;
    int b  = idx / (HW * Fch);
    const float* i2h = g_i2h + (size_t)(t*Bg + b)*FH3*HW + p;
    const float* h2h = g_h2h + (size_t)b*FH3*HW + p;
    float ir = i2h[(size_t)fc*HW];
    float iu = i2h[(size_t)(Fch + fc)*HW];
    float im = i2h[(size_t)(2*Fch + fc)*HW];
    float hr = h2h[(size_t)fc*HW];
    float hu = h2h[(size_t)(Fch + fc)*HW];
    float hm = h2h[(size_t)(2*Fch + fc)*HW];
    float hp = hprev[(size_t)b*Fch*HW + (size_t)fc*HW + p];
    float reset  = sigm(ir + hr);
    float update = sigm(iu + hu);
    float newmem = leaky(im + reset*hm);
    hnext[idx] = update*hp + (1.f - update)*newmem;
}

// ============================================================
extern "C" void kernel_launch(void* const* d_in, const int* in_sizes, int n_in,
                              void* d_out, int out_size){
    const float* inputs = (const float*)d_in[0];
    const float* h0     = (const float*)d_in[1];
    const float* w_i2h  = (const float*)d_in[2];
    const float* b_i2h  = (const float*)d_in[3];
    const float* w_i2f  = (const float*)d_in[4];
    const float* b_i2f  = (const float*)d_in[5];
    const float* w_h2f  = (const float*)d_in[6];
    const float* b_h2f  = (const float*)d_in[7];
    const float* w_fl   = (const float*)d_in[8];
    const float* b_fl   = (const float*)d_in[9];
    const float* w_ret  = (const float*)d_in[10];
    const float* b_ret  = (const float*)d_in[11];
    float* out = (float*)d_out;

    // i2h for all timesteps at once (non-recurrent)
    k_i2h<<<dim3(Sg*Bg, Hh, 9), 96>>>(inputs, w_i2h, b_i2h);

    for (int t = 0; t < Sg; t++){
        const float* x_t = inputs + (size_t)t*Bg*CIN*HW;
        const float* h   = (t == 0) ? h0 : out + (size_t)(t-1)*STEP_ELEMS;
        float* hn = out + (size_t)t*STEP_ELEMS;

        k_fconv<<<dim3(Bg, Hh), 96>>>(x_t, h, w_i2f, b_i2f, w_h2f, b_h2f);
        k_flows<<<dim3(Bg, Hh), 96>>>(w_fl, b_fl);
        k_warp <<<dim3(Bg*Lk, Hh), 96>>>(h);
        k_gemm <<<dim3(HW/64, (FH3+63)/64, Bg), 256>>>(w_ret, b_ret);
        k_gates<<<(STEP_ELEMS + 255)/256, 256>>>(t, h, hn);
    }

    // final_h == last step's output; append if the flattened output includes it
    const size_t OUT_SEQ = (size_t)Sg*STEP_ELEMS;
    if ((size_t)out_size >= OUT_SEQ + STEP_ELEMS){
        cudaMemcpyAsync(out + OUT_SEQ, out + (size_t)(Sg-1)*STEP_ELEMS,
                        (size_t)STEP_ELEMS*sizeof(float),
                        cudaMemcpyDeviceToDevice);
    }
}

// round 3
// speedup vs baseline: 1.3700x; 1.3700x over previous
#include <cuda_runtime.h>
#include <cuda_bf16.h>
#include <cstdint>
#include <math.h>

#define Hh 96
#define Ww 96
#define HW 9216
#define Fch 96
#define CIN 8
#define Lk 5
#define Sg 10
#define Bg 4
#define FH3 288          // 3*F
#define K1 480           // L*F
#define KPAD 512
#define MPAD 384
#define STEP_ELEMS (Bg*Fch*HW)   // 3,538,944

// ---- scratch (device globals) ----
__device__ float g_i2h[(size_t)Sg*Bg*FH3*HW];                 // 425 MB (once)
__device__ float g_f[Bg*32*HW];
__device__ float g_flows[Bg*10*HW];
__device__ __align__(16) __nv_bfloat16 g_whi[(size_t)Bg*HW*KPAD];  // warped^T hi  [b][p][k]
__device__ __align__(16) __nv_bfloat16 g_wlo[(size_t)Bg*HW*KPAD];  // warped^T lo
__device__ __align__(16) __nv_bfloat16 g_Ahi[(size_t)MPAD*KPAD];   // w_ret hi [m][k]
__device__ __align__(16) __nv_bfloat16 g_Alo[(size_t)MPAD*KPAD];
__device__ float g_h2h[(size_t)Bg*FH3*HW];

__device__ __forceinline__ float leaky(float v){ return v > 0.f ? v : 0.2f*v; }
__device__ __forceinline__ float sigm(float v){ return 1.f/(1.f + expf(-v)); }

__device__ __forceinline__ uint32_t smem_u32(const void* p){
    uint32_t a;
    asm("{ .reg .u64 t; cvta.to.shared.u64 t, %1; cvt.u32.u64 %0, t; }" : "=r"(a) : "l"(p));
    return a;
}
__device__ __forceinline__ void ldm_x4(uint32_t* r, uint32_t addr){
    asm volatile("ldmatrix.sync.aligned.m8n8.x4.shared.b16 {%0,%1,%2,%3}, [%4];"
        : "=r"(r[0]), "=r"(r[1]), "=r"(r[2]), "=r"(r[3]) : "r"(addr));
}
#define MMA_BF16(c, a, b) \
    asm volatile("mma.sync.aligned.m16n8k16.row.col.f32.bf16.bf16.f32 " \
        "{%0,%1,%2,%3}, {%4,%5,%6,%7}, {%8,%9}, {%0,%1,%2,%3};" \
        : "+f"((c)[0]), "+f"((c)[1]), "+f"((c)[2]), "+f"((c)[3]) \
        : "r"((a)[0]), "r"((a)[1]), "r"((a)[2]), "r"((a)[3]), \
          "r"((b)[0]), "r"((b)[1]))

// ============================================================
// i2h: 3x3 conv pad1, 8->288, over all S*B images (runs once)
// ============================================================
__global__ void k_i2h(const float* __restrict__ x,
                      const float* __restrict__ w,
                      const float* __restrict__ bias){
    int img = blockIdx.x, y = blockIdx.y, ocg = blockIdx.z;
    int tx = threadIdx.x;
    __shared__ float ws[32*72];
    for (int i = tx; i < 32*72; i += 96) ws[i] = w[ocg*32*72 + i];
    __syncthreads();
    const float* xb = x + (size_t)img*CIN*HW;
    float acc[32];
    #pragma unroll
    for (int o = 0; o < 32; o++) acc[o] = 0.f;
    for (int ic = 0; ic < CIN; ic++){
        const float* xc = xb + (size_t)ic*HW;
        #pragma unroll
        for (int dy = 0; dy < 3; dy++){
            int yy = y + dy - 1;
            if (yy < 0 || yy >= Hh) continue;
            #pragma unroll
            for (int dx = 0; dx < 3; dx++){
                int xx = tx + dx - 1;
                float v = (xx >= 0 && xx < Ww) ? xc[yy*Ww + xx] : 0.f;
                int base = ic*9 + dy*3 + dx;
                #pragma unroll
                for (int o = 0; o < 32; o++) acc[o] += v * ws[o*72 + base];
            }
        }
    }
    float* outp = g_i2h + (size_t)img*FH3*HW + (size_t)(ocg*32)*HW + y*Ww + tx;
    #pragma unroll
    for (int o = 0; o < 32; o++) outp[(size_t)o*HW] = acc[o] + bias[ocg*32 + o];
}

// ============================================================
// f = leaky( conv5x5(x_t, 8->32) + conv5x5(h, 96->32) )
// grid (B, H, 4 oc-groups of 8), block 96
// ============================================================
__global__ void k_fconv(const float* __restrict__ x_t,
                        const float* __restrict__ h,
                        const float* __restrict__ w_i2f,
                        const float* __restrict__ b_i2f,
                        const float* __restrict__ w_h2f,
                        const float* __restrict__ b_h2f){
    int b = blockIdx.x, y = blockIdx.y, ocg = blockIdx.z;
    int tx = threadIdx.x;
    __shared__ float ws[8*8*25];
    float acc[8];
    #pragma unroll
    for (int o = 0; o < 8; o++) acc[o] = b_i2f[ocg*8+o] + b_h2f[ocg*8+o];

    for (int g = 0; g < 13; g++){
        __syncthreads();
        for (int j = tx; j < 1600; j += 96){
            int ol = j / 200, rem = j % 200;
            int oc = ocg*8 + ol;
            int icl = rem / 25, tap = rem % 25;
            ws[j] = (g == 0) ? w_i2f[(oc*8 + icl)*25 + tap]
                             : w_h2f[((size_t)oc*96 + (g-1)*8 + icl)*25 + tap];
        }
        __syncthreads();
        const float* src = (g == 0) ? x_t + (size_t)b*CIN*HW
                                    : h   + (size_t)b*Fch*HW + (size_t)(g-1)*8*HW;
        for (int icl = 0; icl < 8; icl++){
            const float* sc = src + (size_t)icl*HW;
            #pragma unroll
            for (int dy = 0; dy < 5; dy++){
                int yy = y + dy - 2;
                if (yy < 0 || yy >= Hh) continue;
                #pragma unroll
                for (int dx = 0; dx < 5; dx++){
                    int xx = tx + dx - 2;
                    float v = (xx >= 0 && xx < Ww) ? sc[yy*Ww + xx] : 0.f;
                    int base = icl*25 + dy*5 + dx;
                    #pragma unroll
                    for (int o = 0; o < 8; o++) acc[o] += v * ws[o*200 + base];
                }
            }
        }
    }
    float* outp = g_f + (size_t)b*32*HW + (size_t)(ocg*8)*HW + y*Ww + tx;
    #pragma unroll
    for (int o = 0; o < 8; o++) outp[(size_t)o*HW] = leaky(acc[o]);
}

// ============================================================
// flows = conv5x5(f, 32->10) + bias ; grid (B, H, 2 groups of 5)
// ============================================================
__global__ void k_flows(const float* __restrict__ w_fl,
                        const float* __restrict__ b_fl){
    int b = blockIdx.x, y = blockIdx.y, ocg = blockIdx.z;
    int tx = threadIdx.x;
    __shared__ float ws[5*32*25];
    for (int j = tx; j < 4000; j += 96) ws[j] = w_fl[ocg*4000 + j];
    __syncthreads();
    float acc[5];
    #pragma unroll
    for (int o = 0; o < 5; o++) acc[o] = b_fl[ocg*5 + o];
    const float* src = g_f + (size_t)b*32*HW;
    for (int ic = 0; ic < 32; ic++){
        const float* sc = src + (size_t)ic*HW;
        #pragma unroll
        for (int dy = 0; dy < 5; dy++){
            int yy = y + dy - 2;
            if (yy < 0 || yy >= Hh) continue;
            #pragma unroll
            for (int dx = 0; dx < 5; dx++){
                int xx = tx + dx - 2;
                float v = (xx >= 0 && xx < Ww) ? sc[yy*Ww + xx] : 0.f;
                int tap = ic*25 + dy*5 + dx;
                #pragma unroll
                for (int o = 0; o < 5; o++) acc[o] += v * ws[o*800 + tap];
            }
        }
    }
    float* outp = g_flows + (size_t)b*10*HW + (size_t)(ocg*5)*HW + y*Ww + tx;
    #pragma unroll
    for (int o = 0; o < 5; o++) outp[(size_t)o*HW] = acc[o];
}

// ============================================================
// warp: bilinear-warp h, emit transposed bf16 hi/lo [b][p][k]
// grid (B*L, H), block 96
// ============================================================
__global__ void k_warp(const float* __restrict__ h){
    int bl = blockIdx.x, y = blockIdx.y, tx = threadIdx.x;
    int b = bl / Lk, l = bl % Lk;
    const float* fl = g_flows + (size_t)b*10*HW + y*Ww + tx;
    float fx = fl[(size_t)(2*l)*HW];
    float fy = fl[(size_t)(2*l+1)*HW];
    float vx = (float)tx - fx;
    float vy = (float)y  - fy;
    const float sc = 96.0f/95.0f;
    float ix = vx*sc - 0.5f;
    float iy = vy*sc - 0.5f;
    float fx0 = floorf(ix), fy0 = floorf(iy);
    int ix0 = (int)fx0, iy0 = (int)fy0;
    int ix1 = ix0 + 1, iy1 = iy0 + 1;
    float wx1 = ix - fx0, wy1 = iy - fy0;
    float wx0 = 1.f - wx1, wy0 = 1.f - wy1;
    float mx0 = (ix0 >= 0 && ix0 < Ww) ? 1.f : 0.f;
    float mx1 = (ix1 >= 0 && ix1 < Ww) ? 1.f : 0.f;
    float my0 = (iy0 >= 0 && iy0 < Hh) ? 1.f : 0.f;
    float my1 = (iy1 >= 0 && iy1 < Hh) ? 1.f : 0.f;
    int cx0 = min(max(ix0, 0), Ww-1), cx1 = min(max(ix1, 0), Ww-1);
    int cy0 = min(max(iy0, 0), Hh-1), cy1 = min(max(iy1, 0), Hh-1);
    int o00 = cy0*Ww + cx0, o01 = cy0*Ww + cx1;
    int o10 = cy1*Ww + cx0, o11 = cy1*Ww + cx1;
    float w00 = wy0*wx0*my0*mx0, w01 = wy0*wx1*my0*mx1;
    float w10 = wy1*wx0*my1*mx0, w11 = wy1*wx1*my1*mx1;
    const float* hb = h + (size_t)b*Fch*HW;
    int p = y*Ww + tx;
    size_t obase = ((size_t)b*HW + p)*KPAD + l*Fch;

    #pragma unroll 1
    for (int c0 = 0; c0 < Fch; c0 += 8){
        uint32_t hibuf[4], lobuf[4];
        #pragma unroll
        for (int j = 0; j < 4; j++){
            const float* p0 = hb + (size_t)(c0 + 2*j)*HW;
            const float* p1 = p0 + HW;
            float v0 = w00*p0[o00] + w01*p0[o01] + w10*p0[o10] + w11*p0[o11];
            float v1 = w00*p1[o00] + w01*p1[o01] + w10*p1[o10] + w11*p1[o11];
            __nv_bfloat16 h0 = __float2bfloat16(v0);
            __nv_bfloat16 h1 = __float2bfloat16(v1);
            __nv_bfloat16 l0 = __float2bfloat16(v0 - __bfloat162float(h0));
            __nv_bfloat16 l1 = __float2bfloat16(v1 - __bfloat162float(h1));
            __nv_bfloat162 hp; hp.x = h0; hp.y = h1;
            __nv_bfloat162 lp; lp.x = l0; lp.y = l1;
            hibuf[j] = *reinterpret_cast<uint32_t*>(&hp);
            lobuf[j] = *reinterpret_cast<uint32_t*>(&lp);
        }
        *reinterpret_cast<uint4*>(g_whi + obase + c0) = *reinterpret_cast<uint4*>(hibuf);
        *reinterpret_cast<uint4*>(g_wlo + obase + c0) = *reinterpret_cast<uint4*>(lobuf);
    }
}

// ============================================================
// prep: split w_ret into bf16 hi/lo with zero padding (per launch)
// ============================================================
__global__ void k_prepA(const float* __restrict__ w_ret){
    int idx = blockIdx.x*blockDim.x + threadIdx.x;
    if (idx >= MPAD*KPAD) return;
    int m = idx / KPAD, k = idx % KPAD;
    float v = (m < FH3 && k < K1) ? w_ret[m*K1 + k] : 0.f;
    __nv_bfloat16 hi = __float2bfloat16(v);
    __nv_bfloat16 lo = __float2bfloat16(v - __bfloat162float(hi));
    g_Ahi[idx] = hi;
    g_Alo[idx] = lo;
}
// zero the K-padding columns [480,512) of g_whi/g_wlo
__global__ void k_padB(){
    int idx = blockIdx.x*blockDim.x + threadIdx.x;
    if (idx >= Bg*HW*4) return;
    int u = idx & 3;
    size_t row = (size_t)(idx >> 2);
    size_t off = row*KPAD + 480 + u*8;
    uint4 z = make_uint4(0,0,0,0);
    *reinterpret_cast<uint4*>(g_whi + off) = z;
    *reinterpret_cast<uint4*>(g_wlo + off) = z;
}

// ============================================================
// h2h GEMM via mma.sync bf16 hi/lo (3-term, fp32 accum):
// C[b](288x9216) = w_ret(288x480) @ warped[b]^T + bias
// CTA 128x128, BK=32, 8 warps (2x4), warp tile 64x32.
// grid (72, 3, B), 256 threads. smem stride 40 elems (conflict-free ldmatrix)
// ============================================================
#define TS 40

__global__ void __launch_bounds__(256, 1) k_h2h(const float* __restrict__ bias){
    __shared__ __nv_bfloat16 sAh[128*TS], sAl[128*TS], sBh[128*TS], sBl[128*TS];
    int tid = threadIdx.x, lane = tid & 31, wid = tid >> 5;
    int wm = wid & 1, wn = wid >> 1;
    int n0 = blockIdx.x*128, m0 = blockIdx.y*128, bz = blockIdx.z;

    const __nv_bfloat16* Ah = g_Ahi + (size_t)m0*KPAD;
    const __nv_bfloat16* Al = g_Alo + (size_t)m0*KPAD;
    const __nv_bfloat16* Bh = g_whi + ((size_t)bz*HW + n0)*KPAD;
    const __nv_bfloat16* Bl = g_wlo + ((size_t)bz*HW + n0)*KPAD;

    uint32_t aSh = smem_u32(sAh), aSl = smem_u32(sAl);
    uint32_t aBh = smem_u32(sBh), aBl = smem_u32(sBl);

    // ldmatrix lane addressing (element offsets; col part added per k-step)
    int arow = wm*64 + (lane & 15);          // + mi*16
    int acol = (lane >> 4) * 8;
    int brow = wn*32 + (lane & 7) + ((lane >> 4) & 1)*8;   // + jp*16
    int bcol = ((lane >> 3) & 1) * 8;

    float c[4][4][4];
    #pragma unroll
    for (int i = 0; i < 4; i++)
        #pragma unroll
        for (int j = 0; j < 4; j++)
            #pragma unroll
            for (int q = 0; q < 4; q++) c[i][j][q] = 0.f;

    for (int chunk = 0; chunk < 16; chunk++){
        // stage 128x32 tiles (x4 matrices); 2 uint4 per thread per matrix
        #pragma unroll
        for (int i = 0; i < 2; i++){
            int idx = i*256 + tid;
            int r = idx >> 2, u = idx & 3;
            size_t goff = (size_t)r*KPAD + chunk*32 + u*8;
            int soff = r*TS + u*8;
            *reinterpret_cast<uint4*>(&sAh[soff]) = *reinterpret_cast<const uint4*>(Ah + goff);
            *reinterpret_cast<uint4*>(&sAl[soff]) = *reinterpret_cast<const uint4*>(Al + goff);
            *reinterpret_cast<uint4*>(&sBh[soff]) = *reinterpret_cast<const uint4*>(Bh + goff);
            *reinterpret_cast<uint4*>(&sBl[soff]) = *reinterpret_cast<const uint4*>(Bl + goff);
        }
        __syncthreads();

        #pragma unroll
        for (int ks = 0; ks < 2; ks++){
            int kc = ks*16;
            uint32_t ah[4][4], al[4][4], bh[2][4], bl[2][4];
            #pragma unroll
            for (int mi = 0; mi < 4; mi++){
                uint32_t off = 2u*((arow + mi*16)*TS + kc + acol);
                ldm_x4(ah[mi], aSh + off);
                ldm_x4(al[mi], aSl + off);
            }
            #pragma unroll
            for (int jp = 0; jp < 2; jp++){
                uint32_t off = 2u*((brow + jp*16)*TS + kc + bcol);
                ldm_x4(bh[jp], aBh + off);
                ldm_x4(bl[jp], aBl + off);
            }
            #pragma unroll
            for (int mi = 0; mi < 4; mi++){
                #pragma unroll
                for (int j = 0; j < 4; j++){
                    uint32_t* fh = &bh[j >> 1][(j & 1)*2];
                    uint32_t* fl2 = &bl[j >> 1][(j & 1)*2];
                    MMA_BF16(c[mi][j], ah[mi], fh);
                    MMA_BF16(c[mi][j], ah[mi], fl2);
                    MMA_BF16(c[mi][j], al[mi], fh);
                }
            }
        }
        __syncthreads();
    }

    // epilogue
    float* Cb = g_h2h + (size_t)bz*FH3*HW;
    int mbase = m0 + wm*64 + (lane >> 2);
    int nbase = n0 + wn*32 + (lane & 3)*2;
    #pragma unroll
    for (int mi = 0; mi < 4; mi++){
        int r0 = mbase + mi*16;
        #pragma unroll
        for (int j = 0; j < 4; j++){
            int col = nbase + j*8;
            if (r0 < FH3){
                float bv = bias[r0];
                float2 v; v.x = c[mi][j][0] + bv; v.y = c[mi][j][1] + bv;
                *reinterpret_cast<float2*>(Cb + (size_t)r0*HW + col) = v;
            }
            if (r0 + 8 < FH3){
                float bv = bias[r0 + 8];
                float2 v; v.x = c[mi][j][2] + bv; v.y = c[mi][j][3] + bv;
                *reinterpret_cast<float2*>(Cb + (size_t)(r0+8)*HW + col) = v;
            }
        }
    }
}

// ============================================================
// gates: elementwise GRU update -> next_h
// ============================================================
__global__ void k_gates(int t, const float* __restrict__ hprev,
                        float* __restrict__ hnext){
    int idx = blockIdx.x * blockDim.x + threadIdx.x;
    if (idx >= STEP_ELEMS) return;
    int p  = idx % HW;
    int fc = (idx / HW) % Fch;
    int b  = idx / (HW * Fch);
    const float* i2h = g_i2h + (size_t)(t*Bg + b)*FH3*HW + p;
    const float* h2h = g_h2h + (size_t)b*FH3*HW + p;
    float ir = i2h[(size_t)fc*HW];
    float iu = i2h[(size_t)(Fch + fc)*HW];
    float im = i2h[(size_t)(2*Fch + fc)*HW];
    float hr = h2h[(size_t)fc*HW];
    float hu = h2h[(size_t)(Fch + fc)*HW];
    float hm = h2h[(size_t)(2*Fch + fc)*HW];
    float hp = hprev[(size_t)b*Fch*HW + (size_t)fc*HW + p];
    float reset  = sigm(ir + hr);
    float update = sigm(iu + hu);
    float newmem = leaky(im + reset*hm);
    hnext[idx] = update*hp + (1.f - update)*newmem;
}

// ============================================================
extern "C" void kernel_launch(void* const* d_in, const int* in_sizes, int n_in,
                              void* d_out, int out_size){
    const float* inputs = (const float*)d_in[0];
    const float* h0     = (const float*)d_in[1];
    const float* w_i2h  = (const float*)d_in[2];
    const float* b_i2h  = (const float*)d_in[3];
    const float* w_i2f  = (const float*)d_in[4];
    const float* b_i2f  = (const float*)d_in[5];
    const float* w_h2f  = (const float*)d_in[6];
    const float* b_h2f  = (const float*)d_in[7];
    const float* w_fl   = (const float*)d_in[8];
    const float* b_fl   = (const float*)d_in[9];
    const float* w_ret  = (const float*)d_in[10];
    const float* b_ret  = (const float*)d_in[11];
    float* out = (float*)d_out;

    // once per launch: i2h over all timesteps; A split; B pad columns
    k_i2h  <<<dim3(Sg*Bg, Hh, 9), 96>>>(inputs, w_i2h, b_i2h);
    k_prepA<<<(MPAD*KPAD + 255)/256, 256>>>(w_ret);
    k_padB <<<(Bg*HW*4 + 255)/256, 256>>>();

    for (int t = 0; t < Sg; t++){
        const float* x_t = inputs + (size_t)t*Bg*CIN*HW;
        const float* h   = (t == 0) ? h0 : out + (size_t)(t-1)*STEP_ELEMS;
        float* hn = out + (size_t)t*STEP_ELEMS;

        k_fconv<<<dim3(Bg, Hh, 4), 96>>>(x_t, h, w_i2f, b_i2f, w_h2f, b_h2f);
        k_flows<<<dim3(Bg, Hh, 2), 96>>>(w_fl, b_fl);
        k_warp <<<dim3(Bg*Lk, Hh), 96>>>(h);
        k_h2h  <<<dim3(HW/128, 3, Bg), 256>>>(b_ret);
        k_gates<<<(STEP_ELEMS + 255)/256, 256>>>(t, h, hn);
    }

    const size_t OUT_SEQ = (size_t)Sg*STEP_ELEMS;
    if ((size_t)out_size >= OUT_SEQ + STEP_ELEMS){
        cudaMemcpyAsync(out + OUT_SEQ, out + (size_t)(Sg-1)*STEP_ELEMS,
                        (size_t)STEP_ELEMS*sizeof(float),
                        cudaMemcpyDeviceToDevice);
    }
}

// round 4
// speedup vs baseline: 1.6189x; 1.1817x over previous
#include <cuda_runtime.h>
#include <cuda_bf16.h>
#include <cstdint>
#include <math.h>

#define Hh 96
#define Ww 96
#define HW 9216
#define Fch 96
#define CIN 8
#define Lk 5
#define Sg 10
#define Bg 4
#define FH3 288          // 3*F
#define K1 480           // L*F
#define KPAD 512
#define MPAD 384
#define CH 112           // packed input channels: 8 x | 96 h | 8 zero
#define STEP_ELEMS (Bg*Fch*HW)   // 3,538,944

// ---- scratch (device globals) ----
__device__ float g_i2h[(size_t)Sg*Bg*FH3*HW];                 // 425 MB (once)
__device__ float g_f[Bg*32*HW];
__device__ float g_flows[Bg*10*HW];
__device__ __align__(16) __nv_bfloat16 g_whi[(size_t)Bg*HW*KPAD];  // warped^T hi [b][p][k]
__device__ __align__(16) __nv_bfloat16 g_wlo[(size_t)Bg*HW*KPAD];
__device__ __align__(16) __nv_bfloat16 g_Ahi[(size_t)MPAD*KPAD];   // w_ret hi [m][k]
__device__ __align__(16) __nv_bfloat16 g_Alo[(size_t)MPAD*KPAD];
__device__ float g_h2h[(size_t)Bg*FH3*HW];
// fconv operands
__device__ __align__(16) __nv_bfloat16 g_inhi[(size_t)Bg*HW*CH];   // [b][p][ch]
__device__ __align__(16) __nv_bfloat16 g_inlo[(size_t)Bg*HW*CH];
__device__ __align__(16) __nv_bfloat16 g_wfhi[7*25*32*16];         // [chunk][tap][oc][16]
__device__ __align__(16) __nv_bfloat16 g_wflo[7*25*32*16];

__device__ __forceinline__ float leaky(float v){ return v > 0.f ? v : 0.2f*v; }
__device__ __forceinline__ float sigm(float v){ return 1.f/(1.f + expf(-v)); }

__device__ __forceinline__ uint32_t smem_u32(const void* p){
    uint32_t a;
    asm("{ .reg .u64 t; cvta.to.shared.u64 t, %1; cvt.u32.u64 %0, t; }" : "=r"(a) : "l"(p));
    return a;
}
__device__ __forceinline__ void ldm_x4(uint32_t* r, uint32_t addr){
    asm volatile("ldmatrix.sync.aligned.m8n8.x4.shared.b16 {%0,%1,%2,%3}, [%4];"
        : "=r"(r[0]), "=r"(r[1]), "=r"(r[2]), "=r"(r[3]) : "r"(addr));
}
#define MMA_BF16(c, a, b) \
    asm volatile("mma.sync.aligned.m16n8k16.row.col.f32.bf16.bf16.f32 " \
        "{%0,%1,%2,%3}, {%4,%5,%6,%7}, {%8,%9}, {%0,%1,%2,%3};" \
        : "+f"((c)[0]), "+f"((c)[1]), "+f"((c)[2]), "+f"((c)[3]) \
        : "r"((a)[0]), "r"((a)[1]), "r"((a)[2]), "r"((a)[3]), \
          "r"((b)[0]), "r"((b)[1]))

// ============================================================
// i2h: 3x3 conv pad1, 8->288, over all S*B images (runs once)
// ============================================================
__global__ void k_i2h(const float* __restrict__ x,
                      const float* __restrict__ w,
                      const float* __restrict__ bias){
    int img = blockIdx.x, y = blockIdx.y, ocg = blockIdx.z;
    int tx = threadIdx.x;
    __shared__ float ws[32*72];
    for (int i = tx; i < 32*72; i += 96) ws[i] = w[ocg*32*72 + i];
    __syncthreads();
    const float* xb = x + (size_t)img*CIN*HW;
    float acc[32];
    #pragma unroll
    for (int o = 0; o < 32; o++) acc[o] = 0.f;
    for (int ic = 0; ic < CIN; ic++){
        const float* xc = xb + (size_t)ic*HW;
        #pragma unroll
        for (int dy = 0; dy < 3; dy++){
            int yy = y + dy - 1;
            if (yy < 0 || yy >= Hh) continue;
            #pragma unroll
            for (int dx = 0; dx < 3; dx++){
                int xx = tx + dx - 1;
                float v = (xx >= 0 && xx < Ww) ? xc[yy*Ww + xx] : 0.f;
                int base = ic*9 + dy*3 + dx;
                #pragma unroll
                for (int o = 0; o < 32; o++) acc[o] += v * ws[o*72 + base];
            }
        }
    }
    float* outp = g_i2h + (size_t)img*FH3*HW + (size_t)(ocg*32)*HW + y*Ww + tx;
    #pragma unroll
    for (int o = 0; o < 32; o++) outp[(size_t)o*HW] = acc[o] + bias[ocg*32 + o];
}

// ============================================================
// k_pack: pack x_t(8ch)+h(96ch) -> [b][p][112] bf16 hi/lo
// grid (144, B), block 256
// ============================================================
__global__ void k_pack(const float* __restrict__ x_t, const float* __restrict__ h){
    __shared__ float s[CH*65];
    int b = blockIdx.y, p0 = blockIdx.x*64, tid = threadIdx.x;
    for (int i = tid; i < CH*64; i += 256){
        int c = i >> 6, px = i & 63;
        float v = 0.f;
        if (c < 8)        v = x_t[((size_t)b*CIN + c)*HW + p0 + px];
        else if (c < 104) v = h  [((size_t)b*Fch + (c-8))*HW + p0 + px];
        s[c*65 + px] = v;
    }
    __syncthreads();
    for (int i = tid; i < 64*14; i += 256){
        int px = i/14, oct = i%14;
        uint32_t hw[4], lw[4];
        #pragma unroll
        for (int q = 0; q < 4; q++){
            float v0 = s[(oct*8 + 2*q    )*65 + px];
            float v1 = s[(oct*8 + 2*q + 1)*65 + px];
            __nv_bfloat16 h0 = __float2bfloat16(v0), h1 = __float2bfloat16(v1);
            __nv_bfloat16 l0 = __float2bfloat16(v0 - __bfloat162float(h0));
            __nv_bfloat16 l1 = __float2bfloat16(v1 - __bfloat162float(h1));
            __nv_bfloat162 hp; hp.x = h0; hp.y = h1; hw[q] = *reinterpret_cast<uint32_t*>(&hp);
            __nv_bfloat162 lp; lp.x = l0; lp.y = l1; lw[q] = *reinterpret_cast<uint32_t*>(&lp);
        }
        size_t off = ((size_t)b*HW + p0 + px)*CH + oct*8;
        *reinterpret_cast<uint4*>(g_inhi + off) = *reinterpret_cast<uint4*>(hw);
        *reinterpret_cast<uint4*>(g_inlo + off) = *reinterpret_cast<uint4*>(lw);
    }
}

// ============================================================
// k_prepW: weights -> [chunk7][tap25][oc32][16] bf16 hi/lo (once)
// ============================================================
__global__ void k_prepW(const float* __restrict__ w_i2f, const float* __restrict__ w_h2f){
    int idx = blockIdx.x*blockDim.x + threadIdx.x;
    if (idx >= 7*25*32*16) return;
    int kc = idx & 15, oc = (idx >> 4) & 31, tap = (idx >> 9) % 25, chunk = idx / 12800;
    int ch = chunk*16 + kc;
    float v = 0.f;
    if (ch < 8)        v = w_i2f[(oc*8 + ch)*25 + tap];
    else if (ch < 104) v = w_h2f[((size_t)oc*Fch + (ch-8))*25 + tap];
    __nv_bfloat16 hi = __float2bfloat16(v);
    __nv_bfloat16 lo = __float2bfloat16(v - __bfloat162float(hi));
    g_wfhi[idx] = hi;
    g_wflo[idx] = lo;
}

// ============================================================
// fconv as implicit GEMM on tensor cores (bf16 hi/lo 3-term):
// f[p][oc] = leaky( sum_{tap,chunk} in[p_shift][16] @ W[16][oc] + bias )
// CTA = 2 rows x 96 px (M=192), N=32; 8 warps (4M x 2N), warp 3x(m16) x 2x(n8)
// grid (48, B), 256 thr, dyn smem 108.8 KB
// ============================================================
#define FSM_ELEMS 54400
#define FSM_BYTES (FSM_ELEMS*2)

__global__ void __launch_bounds__(256, 2) k_fconv(const float* __restrict__ b_i2f,
                                                  const float* __restrict__ b_h2f){
    extern __shared__ __nv_bfloat16 sm[];
    __nv_bfloat16* sInH = sm;             // 600 entries * 24 elems
    __nv_bfloat16* sInL = sm + 14400;
    __nv_bfloat16* sWH  = sm + 28800;     // [tap25][oc32][16]
    __nv_bfloat16* sWL  = sm + 41600;
    uint32_t aInH = smem_u32(sInH), aInL = smem_u32(sInL);
    uint32_t aWH  = smem_u32(sWH),  aWL  = smem_u32(sWL);

    int tid = threadIdx.x, lane = tid & 31, wid = tid >> 5;
    int wm = wid & 3, wn = wid >> 2;
    int y0 = blockIdx.x*2, b = blockIdx.y;

    float c[3][2][4];
    #pragma unroll
    for (int i = 0; i < 3; i++)
        #pragma unroll
        for (int j = 0; j < 2; j++)
            #pragma unroll
            for (int q = 0; q < 4; q++) c[i][j][q] = 0.f;

    for (int chunk = 0; chunk < 7; chunk++){
        __syncthreads();
        // stage input tile: 6 rows x 100 cols x 16ch (hi/lo), 48B pixel stride
        for (int e = tid; e < 1200; e += 256){
            int ent = e >> 1, half = e & 1;
            int row = ent/100, cc = ent%100;
            int y = y0 + row - 2, x = cc - 2;
            uint4 vh = make_uint4(0,0,0,0), vl = make_uint4(0,0,0,0);
            if ((unsigned)y < 96u && (unsigned)x < 96u){
                size_t off = ((size_t)b*HW + y*Ww + x)*CH + chunk*16 + half*8;
                vh = *reinterpret_cast<const uint4*>(g_inhi + off);
                vl = *reinterpret_cast<const uint4*>(g_inlo + off);
            }
            int so = ent*24 + half*8;
            *reinterpret_cast<uint4*>(sInH + so) = vh;
            *reinterpret_cast<uint4*>(sInL + so) = vl;
        }
        // stage weights for this chunk: 12800 elems each
        for (int e = tid; e < 1600; e += 256){
            reinterpret_cast<uint4*>(sWH)[e] = reinterpret_cast<const uint4*>(g_wfhi + chunk*12800)[e];
            reinterpret_cast<uint4*>(sWL)[e] = reinterpret_cast<const uint4*>(g_wflo + chunk*12800)[e];
        }
        __syncthreads();

        #pragma unroll 1
        for (int tap = 0; tap < 25; tap++){
            int dy = tap/5, dx = tap%5;
            uint32_t bh[4], bl[4];
            uint32_t boff = 2u*(uint32_t)((tap*32 + wn*16 + (lane&7) + ((lane>>4)&1)*8)*16
                                          + ((lane>>3)&1)*8);
            ldm_x4(bh, aWH + boff);
            ldm_x4(bl, aWL + boff);
            uint32_t ah[3][4], al[3][4];
            #pragma unroll
            for (int mi = 0; mi < 3; mi++){
                int tmi = wm*3 + mi;
                int r = tmi/6, xb = (tmi%6)*16;
                uint32_t aoff = 2u*(uint32_t)(((r+dy)*100 + xb + (lane&15) + dx)*24
                                              + (lane>>4)*8);
                ldm_x4(ah[mi], aInH + aoff);
                ldm_x4(al[mi], aInL + aoff);
            }
            #pragma unroll
            for (int mi = 0; mi < 3; mi++){
                #pragma unroll
                for (int j = 0; j < 2; j++){
                    MMA_BF16(c[mi][j], ah[mi], &bh[j*2]);
                    MMA_BF16(c[mi][j], ah[mi], &bl[j*2]);
                    MMA_BF16(c[mi][j], al[mi], &bh[j*2]);
                }
            }
        }
    }

    // epilogue: bias + leaky -> planar g_f[b][oc][p]
    #pragma unroll
    for (int mi = 0; mi < 3; mi++){
        int tmi = wm*3 + mi;
        int r = tmi/6, xb = (tmi%6)*16;
        int gp = (y0 + r)*Ww + xb + (lane>>2);
        #pragma unroll
        for (int j = 0; j < 2; j++){
            int oc = wn*16 + j*8 + (lane&3)*2;
            float bb0 = b_i2f[oc]   + b_h2f[oc];
            float bb1 = b_i2f[oc+1] + b_h2f[oc+1];
            float* f0 = g_f + ((size_t)b*32 + oc)*HW;
            f0[gp]        = leaky(c[mi][j][0] + bb0);
            f0[HW + gp]   = leaky(c[mi][j][1] + bb1);
            f0[gp + 8]    = leaky(c[mi][j][2] + bb0);
            f0[HW + gp+8] = leaky(c[mi][j][3] + bb1);
        }
    }
}

// ============================================================
// flows = conv5x5(f, 32->10) + bias ; grid (B, H, 2 groups of 5)
// ============================================================
__global__ void k_flows(const float* __restrict__ w_fl,
                        const float* __restrict__ b_fl){
    int b = blockIdx.x, y = blockIdx.y, ocg = blockIdx.z;
    int tx = threadIdx.x;
    __shared__ float ws[5*32*25];
    for (int j = tx; j < 4000; j += 96) ws[j] = w_fl[ocg*4000 + j];
    __syncthreads();
    float acc[5];
    #pragma unroll
    for (int o = 0; o < 5; o++) acc[o] = b_fl[ocg*5 + o];
    const float* src = g_f + (size_t)b*32*HW;
    for (int ic = 0; ic < 32; ic++){
        const float* sc = src + (size_t)ic*HW;
        #pragma unroll
        for (int dy = 0; dy < 5; dy++){
            int yy = y + dy - 2;
            if (yy < 0 || yy >= Hh) continue;
            #pragma unroll
            for (int dx = 0; dx < 5; dx++){
                int xx = tx + dx - 2;
                float v = (xx >= 0 && xx < Ww) ? sc[yy*Ww + xx] : 0.f;
                int tap = ic*25 + dy*5 + dx;
                #pragma unroll
                for (int o = 0; o < 5; o++) acc[o] += v * ws[o*800 + tap];
            }
        }
    }
    float* outp = g_flows + (size_t)b*10*HW + (size_t)(ocg*5)*HW + y*Ww + tx;
    #pragma unroll
    for (int o = 0; o < 5; o++) outp[(size_t)o*HW] = acc[o];
}

// ============================================================
// warp: bilinear-warp h, emit transposed bf16 hi/lo [b][p][k]
// grid (B*L, H), block 96
// ============================================================
__global__ void k_warp(const float* __restrict__ h){
    int bl = blockIdx.x, y = blockIdx.y, tx = threadIdx.x;
    int b = bl / Lk, l = bl % Lk;
    const float* fl = g_flows + (size_t)b*10*HW + y*Ww + tx;
    float fx = fl[(size_t)(2*l)*HW];
    float fy = fl[(size_t)(2*l+1)*HW];
    float vx = (float)tx - fx;
    float vy = (float)y  - fy;
    const float sc = 96.0f/95.0f;
    float ix = vx*sc - 0.5f;
    float iy = vy*sc - 0.5f;
    float fx0 = floorf(ix), fy0 = floorf(iy);
    int ix0 = (int)fx0, iy0 = (int)fy0;
    int ix1 = ix0 + 1, iy1 = iy0 + 1;
    float wx1 = ix - fx0, wy1 = iy - fy0;
    float wx0 = 1.f - wx1, wy0 = 1.f - wy1;
    float mx0 = (ix0 >= 0 && ix0 < Ww) ? 1.f : 0.f;
    float mx1 = (ix1 >= 0 && ix1 < Ww) ? 1.f : 0.f;
    float my0 = (iy0 >= 0 && iy0 < Hh) ? 1.f : 0.f;
    float my1 = (iy1 >= 0 && iy1 < Hh) ? 1.f : 0.f;
    int cx0 = min(max(ix0, 0), Ww-1), cx1 = min(max(ix1, 0), Ww-1);
    int cy0 = min(max(iy0, 0), Hh-1), cy1 = min(max(iy1, 0), Hh-1);
    int o00 = cy0*Ww + cx0, o01 = cy0*Ww + cx1;
    int o10 = cy1*Ww + cx0, o11 = cy1*Ww + cx1;
    float w00 = wy0*wx0*my0*mx0, w01 = wy0*wx1*my0*mx1;
    float w10 = wy1*wx0*my1*mx0, w11 = wy1*wx1*my1*mx1;
    const float* hb = h + (size_t)b*Fch*HW;
    int p = y*Ww + tx;
    size_t obase = ((size_t)b*HW + p)*KPAD + l*Fch;

    #pragma unroll 1
    for (int c0 = 0; c0 < Fch; c0 += 8){
        uint32_t hibuf[4], lobuf[4];
        #pragma unroll
        for (int j = 0; j < 4; j++){
            const float* p0 = hb + (size_t)(c0 + 2*j)*HW;
            const float* p1 = p0 + HW;
            float v0 = w00*p0[o00] + w01*p0[o01] + w10*p0[o10] + w11*p0[o11];
            float v1 = w00*p1[o00] + w01*p1[o01] + w10*p1[o10] + w11*p1[o11];
            __nv_bfloat16 h0 = __float2bfloat16(v0);
            __nv_bfloat16 h1 = __float2bfloat16(v1);
            __nv_bfloat16 l0 = __float2bfloat16(v0 - __bfloat162float(h0));
            __nv_bfloat16 l1 = __float2bfloat16(v1 - __bfloat162float(h1));
            __nv_bfloat162 hp; hp.x = h0; hp.y = h1;
            __nv_bfloat162 lp; lp.x = l0; lp.y = l1;
            hibuf[j] = *reinterpret_cast<uint32_t*>(&hp);
            lobuf[j] = *reinterpret_cast<uint32_t*>(&lp);
        }
        *reinterpret_cast<uint4*>(g_whi + obase + c0) = *reinterpret_cast<uint4*>(hibuf);
        *reinterpret_cast<uint4*>(g_wlo + obase + c0) = *reinterpret_cast<uint4*>(lobuf);
    }
}

// ============================================================
// prep: split w_ret into bf16 hi/lo with zero padding (per launch)
// ============================================================
__global__ void k_prepA(const float* __restrict__ w_ret){
    int idx = blockIdx.x*blockDim.x + threadIdx.x;
    if (idx >= MPAD*KPAD) return;
    int m = idx / KPAD, k = idx % KPAD;
    float v = (m < FH3 && k < K1) ? w_ret[m*K1 + k] : 0.f;
    __nv_bfloat16 hi = __float2bfloat16(v);
    __nv_bfloat16 lo = __float2bfloat16(v - __bfloat162float(hi));
    g_Ahi[idx] = hi;
    g_Alo[idx] = lo;
}
__global__ void k_padB(){
    int idx = blockIdx.x*blockDim.x + threadIdx.x;
    if (idx >= Bg*HW*4) return;
    int u = idx & 3;
    size_t row = (size_t)(idx >> 2);
    size_t off = row*KPAD + 480 + u*8;
    uint4 z = make_uint4(0,0,0,0);
    *reinterpret_cast<uint4*>(g_whi + off) = z;
    *reinterpret_cast<uint4*>(g_wlo + off) = z;
}

// ============================================================
// h2h GEMM via mma.sync bf16 hi/lo (3-term, fp32 accum)
// ============================================================
#define TS 40

__global__ void __launch_bounds__(256, 1) k_h2h(const float* __restrict__ bias){
    __shared__ __nv_bfloat16 sAh[128*TS], sAl[128*TS], sBh[128*TS], sBl[128*TS];
    int tid = threadIdx.x, lane = tid & 31, wid = tid >> 5;
    int wm = wid & 1, wn = wid >> 1;
    int n0 = blockIdx.x*128, m0 = blockIdx.y*128, bz = blockIdx.z;

    const __nv_bfloat16* Ah = g_Ahi + (size_t)m0*KPAD;
    const __nv_bfloat16* Al = g_Alo + (size_t)m0*KPAD;
    const __nv_bfloat16* Bh = g_whi + ((size_t)bz*HW + n0)*KPAD;
    const __nv_bfloat16* Bl = g_wlo + ((size_t)bz*HW + n0)*KPAD;

    uint32_t aSh = smem_u32(sAh), aSl = smem_u32(sAl);
    uint32_t aBh = smem_u32(sBh), aBl = smem_u32(sBl);

    int arow = wm*64 + (lane & 15);
    int acol = (lane >> 4) * 8;
    int brow = wn*32 + (lane & 7) + ((lane >> 4) & 1)*8;
    int bcol = ((lane >> 3) & 1) * 8;

    float c[4][4][4];
    #pragma unroll
    for (int i = 0; i < 4; i++)
        #pragma unroll
        for (int j = 0; j < 4; j++)
            #pragma unroll
            for (int q = 0; q < 4; q++) c[i][j][q] = 0.f;

    for (int chunk = 0; chunk < 16; chunk++){
        #pragma unroll
        for (int i = 0; i < 2; i++){
            int idx = i*256 + tid;
            int r = idx >> 2, u = idx & 3;
            size_t goff = (size_t)r*KPAD + chunk*32 + u*8;
            int soff = r*TS + u*8;
            *reinterpret_cast<uint4*>(&sAh[soff]) = *reinterpret_cast<const uint4*>(Ah + goff);
            *reinterpret_cast<uint4*>(&sAl[soff]) = *reinterpret_cast<const uint4*>(Al + goff);
            *reinterpret_cast<uint4*>(&sBh[soff]) = *reinterpret_cast<const uint4*>(Bh + goff);
            *reinterpret_cast<uint4*>(&sBl[soff]) = *reinterpret_cast<const uint4*>(Bl + goff);
        }
        __syncthreads();

        #pragma unroll
        for (int ks = 0; ks < 2; ks++){
            int kc = ks*16;
            uint32_t ah[4][4], al[4][4], bh[2][4], bl[2][4];
            #pragma unroll
            for (int mi = 0; mi < 4; mi++){
                uint32_t off = 2u*((arow + mi*16)*TS + kc + acol);
                ldm_x4(ah[mi], aSh + off);
                ldm_x4(al[mi], aSl + off);
            }
            #pragma unroll
            for (int jp = 0; jp < 2; jp++){
                uint32_t off = 2u*((brow + jp*16)*TS + kc + bcol);
                ldm_x4(bh[jp], aBh + off);
                ldm_x4(bl[jp], aBl + off);
            }
            #pragma unroll
            for (int mi = 0; mi < 4; mi++){
                #pragma unroll
                for (int j = 0; j < 4; j++){
                    uint32_t* fh = &bh[j >> 1][(j & 1)*2];
                    uint32_t* fl2 = &bl[j >> 1][(j & 1)*2];
                    MMA_BF16(c[mi][j], ah[mi], fh);
                    MMA_BF16(c[mi][j], ah[mi], fl2);
                    MMA_BF16(c[mi][j], al[mi], fh);
                }
            }
        }
        __syncthreads();
    }

    float* Cb = g_h2h + (size_t)bz*FH3*HW;
    int mbase = m0 + wm*64 + (lane >> 2);
    int nbase = n0 + wn*32 + (lane & 3)*2;
    #pragma unroll
    for (int mi = 0; mi < 4; mi++){
        int r0 = mbase + mi*16;
        #pragma unroll
        for (int j = 0; j < 4; j++){
            int col = nbase + j*8;
            if (r0 < FH3){
                float bv = bias[r0];
                float2 v; v.x = c[mi][j][0] + bv; v.y = c[mi][j][1] + bv;
                *reinterpret_cast<float2*>(Cb + (size_t)r0*HW + col) = v;
            }
            if (r0 + 8 < FH3){
                float bv = bias[r0 + 8];
                float2 v; v.x = c[mi][j][2] + bv; v.y = c[mi][j][3] + bv;
                *reinterpret_cast<float2*>(Cb + (size_t)(r0+8)*HW + col) = v;
            }
        }
    }
}

// ============================================================
// gates: elementwise GRU update -> next_h
// ============================================================
__global__ void k_gates(int t, const float* __restrict__ hprev,
                        float* __restrict__ hnext){
    int idx = blockIdx.x * blockDim.x + threadIdx.x;
    if (idx >= STEP_ELEMS) return;
    int p  = idx % HW;
    int fc = (idx / HW) % Fch;
    int b  = idx / (HW * Fch);
    const float* i2h = g_i2h + (size_t)(t*Bg + b)*FH3*HW + p;
    const float* h2h = g_h2h + (size_t)b*FH3*HW + p;
    float ir = i2h[(size_t)fc*HW];
    float iu = i2h[(size_t)(Fch + fc)*HW];
    float im = i2h[(size_t)(2*Fch + fc)*HW];
    float hr = h2h[(size_t)fc*HW];
    float hu = h2h[(size_t)(Fch + fc)*HW];
    float hm = h2h[(size_t)(2*Fch + fc)*HW];
    float hp = hprev[(size_t)b*Fch*HW + (size_t)fc*HW + p];
    float reset  = sigm(ir + hr);
    float update = sigm(iu + hu);
    float newmem = leaky(im + reset*hm);
    hnext[idx] = update*hp + (1.f - update)*newmem;
}

// ============================================================
extern "C" void kernel_launch(void* const* d_in, const int* in_sizes, int n_in,
                              void* d_out, int out_size){
    const float* inputs = (const float*)d_in[0];
    const float* h0     = (const float*)d_in[1];
    const float* w_i2h  = (const float*)d_in[2];
    const float* b_i2h  = (const float*)d_in[3];
    const float* w_i2f  = (const float*)d_in[4];
    const float* b_i2f  = (const float*)d_in[5];
    const float* w_h2f  = (const float*)d_in[6];
    const float* b_h2f  = (const float*)d_in[7];
    const float* w_fl   = (const float*)d_in[8];
    const float* b_fl   = (const float*)d_in[9];
    const float* w_ret  = (const float*)d_in[10];
    const float* b_ret  = (const float*)d_in[11];
    float* out = (float*)d_out;

    cudaFuncSetAttribute(k_fconv, cudaFuncAttributeMaxDynamicSharedMemorySize, FSM_BYTES);

    // once per launch
    k_i2h  <<<dim3(Sg*Bg, Hh, 9), 96>>>(inputs, w_i2h, b_i2h);
    k_prepA<<<(MPAD*KPAD + 255)/256, 256>>>(w_ret);
    k_padB <<<(Bg*HW*4 + 255)/256, 256>>>();
    k_prepW<<<(7*25*32*16 + 255)/256, 256>>>(w_i2f, w_h2f);

    for (int t = 0; t < Sg; t++){
        const float* x_t = inputs + (size_t)t*Bg*CIN*HW;
        const float* h   = (t == 0) ? h0 : out + (size_t)(t-1)*STEP_ELEMS;
        float* hn = out + (size_t)t*STEP_ELEMS;

        k_pack <<<dim3(HW/64, Bg), 256>>>(x_t, h);
        k_fconv<<<dim3(48, Bg), 256, FSM_BYTES>>>(b_i2f, b_h2f);
        k_flows<<<dim3(Bg, Hh, 2), 96>>>(w_fl, b_fl);
        k_warp <<<dim3(Bg*Lk, Hh), 96>>>(h);
        k_h2h  <<<dim3(HW/128, 3, Bg), 256>>>(b_ret);
        k_gates<<<(STEP_ELEMS + 255)/256, 256>>>(t, h, hn);
    }

    const size_t OUT_SEQ = (size_t)Sg*STEP_ELEMS;
    if ((size_t)out_size >= OUT_SEQ + STEP_ELEMS){
        cudaMemcpyAsync(out + OUT_SEQ, out + (size_t)(Sg-1)*STEP_ELEMS,
                        (size_t)STEP_ELEMS*sizeof(float),
                        cudaMemcpyDeviceToDevice);
    }
}

// round 5
// speedup vs baseline: 2.6814x; 1.6563x over previous
#include <cuda_runtime.h>
#include <cuda_bf16.h>
#include <cstdint>
#include <math.h>

#define Hh 96
#define Ww 96
#define HW 9216
#define Fch 96
#define CIN 8
#define Lk 5
#define Sg 10
#define Bg 4
#define FH3 288          // 3*F
#define K1 480           // L*F
#define KPAD 512
#define MPAD 384
#define CH 112           // packed input channels: 8 x | 96 h | 8 zero
#define STEP_ELEMS (Bg*Fch*HW)   // 3,538,944

// ---- scratch (device globals) ----
__device__ float g_i2h[(size_t)Sg*Bg*FH3*HW];                 // 425 MB (once)
__device__ float g_flows[Bg*10*HW];
__device__ __align__(16) __nv_bfloat16 g_whi[(size_t)Bg*HW*KPAD];  // warped^T hi [b][p][k]
__device__ __align__(16) __nv_bfloat16 g_wlo[(size_t)Bg*HW*KPAD];
__device__ __align__(16) __nv_bfloat16 g_Ahi[(size_t)MPAD*KPAD];   // w_ret hi [m][k]
__device__ __align__(16) __nv_bfloat16 g_Alo[(size_t)MPAD*KPAD];
__device__ float g_h2h[(size_t)Bg*FH3*HW];
// fconv inputs: per-step slots [Sg][Bg][p][112]
__device__ __align__(16) __nv_bfloat16 g_inhi[(size_t)Sg*Bg*HW*CH];
__device__ __align__(16) __nv_bfloat16 g_inlo[(size_t)Sg*Bg*HW*CH];
__device__ __align__(16) __nv_bfloat16 g_wfhi[7*25*32*16];         // [chunk][tap][oc][16]
__device__ __align__(16) __nv_bfloat16 g_wflo[7*25*32*16];
// f as bf16 hi/lo [b][p][32]
__device__ __align__(16) __nv_bfloat16 g_fhi[(size_t)Bg*HW*32];
__device__ __align__(16) __nv_bfloat16 g_flo[(size_t)Bg*HW*32];
// flows weights [chunk2][tap25][oc32][16] (oc>=10 zero)
__device__ __align__(16) __nv_bfloat16 g_w2hi[2*25*32*16];
__device__ __align__(16) __nv_bfloat16 g_w2lo[2*25*32*16];

__device__ __forceinline__ float leaky(float v){ return v > 0.f ? v : 0.2f*v; }
__device__ __forceinline__ float sigm(float v){ return 1.f/(1.f + expf(-v)); }

__device__ __forceinline__ uint32_t smem_u32(const void* p){
    uint32_t a;
    asm("{ .reg .u64 t; cvta.to.shared.u64 t, %1; cvt.u32.u64 %0, t; }" : "=r"(a) : "l"(p));
    return a;
}
__device__ __forceinline__ void ldm_x4(uint32_t* r, uint32_t addr){
    asm volatile("ldmatrix.sync.aligned.m8n8.x4.shared.b16 {%0,%1,%2,%3}, [%4];"
        : "=r"(r[0]), "=r"(r[1]), "=r"(r[2]), "=r"(r[3]) : "r"(addr));
}
#define MMA_BF16(c, a, b) \
    asm volatile("mma.sync.aligned.m16n8k16.row.col.f32.bf16.bf16.f32 " \
        "{%0,%1,%2,%3}, {%4,%5,%6,%7}, {%8,%9}, {%0,%1,%2,%3};" \
        : "+f"((c)[0]), "+f"((c)[1]), "+f"((c)[2]), "+f"((c)[3]) \
        : "r"((a)[0]), "r"((a)[1]), "r"((a)[2]), "r"((a)[3]), \
          "r"((b)[0]), "r"((b)[1]))
#define CPA16(sm, gp) asm volatile("cp.async.ca.shared.global [%0], [%1], 16;" :: "r"(sm), "l"(gp))
#define CPA_COMMIT()  asm volatile("cp.async.commit_group;" ::: "memory")

__device__ __forceinline__ void split2(float v0, float v1, uint32_t& hw, uint32_t& lw){
    __nv_bfloat16 h0 = __float2bfloat16(v0), h1 = __float2bfloat16(v1);
    __nv_bfloat16 l0 = __float2bfloat16(v0 - __bfloat162float(h0));
    __nv_bfloat16 l1 = __float2bfloat16(v1 - __bfloat162float(h1));
    __nv_bfloat162 hp; hp.x = h0; hp.y = h1;
    __nv_bfloat162 lp; lp.x = l0; lp.y = l1;
    hw = *reinterpret_cast<uint32_t*>(&hp);
    lw = *reinterpret_cast<uint32_t*>(&lp);
}

// ============================================================
// i2h: 3x3 conv pad1, 8->288, all S*B images (runs once)
// ============================================================
__global__ void k_i2h(const float* __restrict__ x,
                      const float* __restrict__ w,
                      const float* __restrict__ bias){
    int img = blockIdx.x, y = blockIdx.y, ocg = blockIdx.z;
    int tx = threadIdx.x;
    __shared__ float ws[32*72];
    for (int i = tx; i < 32*72; i += 96) ws[i] = w[ocg*32*72 + i];
    __syncthreads();
    const float* xb = x + (size_t)img*CIN*HW;
    float acc[32];
    #pragma unroll
    for (int o = 0; o < 32; o++) acc[o] = 0.f;
    for (int ic = 0; ic < CIN; ic++){
        const float* xc = xb + (size_t)ic*HW;
        #pragma unroll
        for (int dy = 0; dy < 3; dy++){
            int yy = y + dy - 1;
            if (yy < 0 || yy >= Hh) continue;
            #pragma unroll
            for (int dx = 0; dx < 3; dx++){
                int xx = tx + dx - 1;
                float v = (xx >= 0 && xx < Ww) ? xc[yy*Ww + xx] : 0.f;
                int base = ic*9 + dy*3 + dx;
                #pragma unroll
                for (int o = 0; o < 32; o++) acc[o] += v * ws[o*72 + base];
            }
        }
    }
    float* outp = g_i2h + (size_t)img*FH3*HW + (size_t)(ocg*32)*HW + y*Ww + tx;
    #pragma unroll
    for (int o = 0; o < 32; o++) outp[(size_t)o*HW] = acc[o] + bias[ocg*32 + o];
}

// ============================================================
// k_prepX (once): pack x channels for ALL step slots, zero pad ch,
// and slot-0 h channels from h0.
// thread per (t,b,p)
// ============================================================
__global__ void k_prepX(const float* __restrict__ inputs, const float* __restrict__ h0){
    int idx = blockIdx.x*blockDim.x + threadIdx.x;
    if (idx >= Sg*Bg*HW) return;
    int p = idx % HW, b = (idx/HW) % Bg, t = idx/(HW*Bg);
    size_t base = ((size_t)(t*Bg + b)*HW + p)*CH;
    const float* xp = inputs + ((size_t)(t*Bg + b)*CIN)*HW + p;
    uint32_t hw[4], lw[4];
    #pragma unroll
    for (int q = 0; q < 4; q++)
        split2(xp[(size_t)(2*q)*HW], xp[(size_t)(2*q+1)*HW], hw[q], lw[q]);
    *reinterpret_cast<uint4*>(g_inhi + base) = *reinterpret_cast<uint4*>(hw);
    *reinterpret_cast<uint4*>(g_inlo + base) = *reinterpret_cast<uint4*>(lw);
    uint4 z = make_uint4(0,0,0,0);
    *reinterpret_cast<uint4*>(g_inhi + base + 104) = z;
    *reinterpret_cast<uint4*>(g_inlo + base + 104) = z;
    if (t == 0){
        const float* hp = h0 + (size_t)b*Fch*HW + p;
        for (int g = 0; g < 12; g++){
            #pragma unroll
            for (int q = 0; q < 4; q++)
                split2(hp[(size_t)(g*8 + 2*q)*HW], hp[(size_t)(g*8 + 2*q+1)*HW], hw[q], lw[q]);
            *reinterpret_cast<uint4*>(g_inhi + base + 8 + g*8) = *reinterpret_cast<uint4*>(hw);
            *reinterpret_cast<uint4*>(g_inlo + base + 8 + g*8) = *reinterpret_cast<uint4*>(lw);
        }
    }
}

// ============================================================
// k_prepW (once): fconv weights -> [chunk7][tap25][oc32][16]
// ============================================================
__global__ void k_prepW(const float* __restrict__ w_i2f, const float* __restrict__ w_h2f){
    int idx = blockIdx.x*blockDim.x + threadIdx.x;
    if (idx >= 7*25*32*16) return;
    int kc = idx & 15, oc = (idx >> 4) & 31, tap = (idx >> 9) % 25, chunk = idx / 12800;
    int ch = chunk*16 + kc;
    float v = 0.f;
    if (ch < 8)        v = w_i2f[(oc*8 + ch)*25 + tap];
    else if (ch < 104) v = w_h2f[((size_t)oc*Fch + (ch-8))*25 + tap];
    __nv_bfloat16 hi = __float2bfloat16(v);
    __nv_bfloat16 lo = __float2bfloat16(v - __bfloat162float(hi));
    g_wfhi[idx] = hi; g_wflo[idx] = lo;
}
// flows weights -> [chunk2][tap25][oc32][16], oc>=10 zero (once)
__global__ void k_prepW2(const float* __restrict__ w_fl){
    int idx = blockIdx.x*blockDim.x + threadIdx.x;
    if (idx >= 2*25*32*16) return;
    int kc = idx & 15, oc = (idx >> 4) & 31, tap = (idx >> 9) % 25, chunk = idx / 12800;
    int ch = chunk*16 + kc;
    float v = (oc < 10) ? w_fl[((size_t)oc*32 + ch)*25 + tap] : 0.f;
    __nv_bfloat16 hi = __float2bfloat16(v);
    __nv_bfloat16 lo = __float2bfloat16(v - __bfloat162float(hi));
    g_w2hi[idx] = hi; g_w2lo[idx] = lo;
}

// ============================================================
// fconv implicit GEMM (bf16 hi/lo 3-term). CTA = 2 rows x 96 px,
// N=32, 8 warps (4M x 2N). Epilogue -> f bf16 hi/lo [b][p][32].
// grid (48, B), 256 thr, dyn smem 108.8 KB
// ============================================================
#define FSM_ELEMS 54400
#define FSM_BYTES (FSM_ELEMS*2)

__global__ void __launch_bounds__(256, 2) k_fconv(int t,
                                                  const float* __restrict__ b_i2f,
                                                  const float* __restrict__ b_h2f){
    extern __shared__ __nv_bfloat16 sm[];
    __nv_bfloat16* sInH = sm;
    __nv_bfloat16* sInL = sm + 14400;
    __nv_bfloat16* sWH  = sm + 28800;
    __nv_bfloat16* sWL  = sm + 41600;
    uint32_t aInH = smem_u32(sInH), aInL = smem_u32(sInL);
    uint32_t aWH  = smem_u32(sWH),  aWL  = smem_u32(sWL);

    int tid = threadIdx.x, lane = tid & 31, wid = tid >> 5;
    int wm = wid & 3, wn = wid >> 2;
    int y0 = blockIdx.x*2, b = blockIdx.y;
    size_t slot = (size_t)(t*Bg + b)*HW;

    float c[3][2][4];
    #pragma unroll
    for (int i = 0; i < 3; i++)
        #pragma unroll
        for (int j = 0; j < 2; j++)
            #pragma unroll
            for (int q = 0; q < 4; q++) c[i][j][q] = 0.f;

    for (int chunk = 0; chunk < 7; chunk++){
        __syncthreads();
        for (int e = tid; e < 1200; e += 256){
            int ent = e >> 1, half = e & 1;
            int row = ent/100, cc = ent%100;
            int y = y0 + row - 2, x = cc - 2;
            uint4 vh = make_uint4(0,0,0,0), vl = make_uint4(0,0,0,0);
            if ((unsigned)y < 96u && (unsigned)x < 96u){
                size_t off = (slot + y*Ww + x)*CH + chunk*16 + half*8;
                vh = *reinterpret_cast<const uint4*>(g_inhi + off);
                vl = *reinterpret_cast<const uint4*>(g_inlo + off);
            }
            int so = ent*24 + half*8;
            *reinterpret_cast<uint4*>(sInH + so) = vh;
            *reinterpret_cast<uint4*>(sInL + so) = vl;
        }
        for (int e = tid; e < 1600; e += 256){
            reinterpret_cast<uint4*>(sWH)[e] = reinterpret_cast<const uint4*>(g_wfhi + chunk*12800)[e];
            reinterpret_cast<uint4*>(sWL)[e] = reinterpret_cast<const uint4*>(g_wflo + chunk*12800)[e];
        }
        __syncthreads();

        #pragma unroll 1
        for (int tap = 0; tap < 25; tap++){
            int dy = tap/5, dx = tap%5;
            uint32_t bh[4], bl[4];
            uint32_t boff = 2u*(uint32_t)((tap*32 + wn*16 + (lane&7) + ((lane>>4)&1)*8)*16
                                          + ((lane>>3)&1)*8);
            ldm_x4(bh, aWH + boff);
            ldm_x4(bl, aWL + boff);
            uint32_t ah[3][4], al[3][4];
            #pragma unroll
            for (int mi = 0; mi < 3; mi++){
                int tmi = wm*3 + mi;
                int r = tmi/6, xb = (tmi%6)*16;
                uint32_t aoff = 2u*(uint32_t)(((r+dy)*100 + xb + (lane&15) + dx)*24
                                              + (lane>>4)*8);
                ldm_x4(ah[mi], aInH + aoff);
                ldm_x4(al[mi], aInL + aoff);
            }
            #pragma unroll
            for (int mi = 0; mi < 3; mi++){
                #pragma unroll
                for (int j = 0; j < 2; j++){
                    MMA_BF16(c[mi][j], ah[mi], &bh[j*2]);
                    MMA_BF16(c[mi][j], ah[mi], &bl[j*2]);
                    MMA_BF16(c[mi][j], al[mi], &bh[j*2]);
                }
            }
        }
    }

    // epilogue: bias + leaky -> f bf16 hi/lo [b][p][32]
    #pragma unroll
    for (int mi = 0; mi < 3; mi++){
        int tmi = wm*3 + mi;
        int r = tmi/6, xb = (tmi%6)*16;
        int gp = (y0 + r)*Ww + xb + (lane>>2);
        #pragma unroll
        for (int j = 0; j < 2; j++){
            int oc = wn*16 + j*8 + (lane&3)*2;
            float bb0 = b_i2f[oc]   + b_h2f[oc];
            float bb1 = b_i2f[oc+1] + b_h2f[oc+1];
            uint32_t hw, lw;
            split2(leaky(c[mi][j][0] + bb0), leaky(c[mi][j][1] + bb1), hw, lw);
            size_t o0 = ((size_t)b*HW + gp)*32 + oc;
            *reinterpret_cast<uint32_t*>(g_fhi + o0) = hw;
            *reinterpret_cast<uint32_t*>(g_flo + o0) = lw;
            split2(leaky(c[mi][j][2] + bb0), leaky(c[mi][j][3] + bb1), hw, lw);
            size_t o1 = ((size_t)b*HW + gp + 8)*32 + oc;
            *reinterpret_cast<uint32_t*>(g_fhi + o1) = hw;
            *reinterpret_cast<uint32_t*>(g_flo + o1) = lw;
        }
    }
}

// ============================================================
// flows implicit GEMM (same structure, 2 chunks, oc padded to 32)
// epilogue -> g_flows fp32 planar [b][10][HW]
// ============================================================
__global__ void __launch_bounds__(256, 2) k_flowsT(const float* __restrict__ b_fl){
    extern __shared__ __nv_bfloat16 sm[];
    __nv_bfloat16* sInH = sm;
    __nv_bfloat16* sInL = sm + 14400;
    __nv_bfloat16* sWH  = sm + 28800;
    __nv_bfloat16* sWL  = sm + 41600;
    uint32_t aInH = smem_u32(sInH), aInL = smem_u32(sInL);
    uint32_t aWH  = smem_u32(sWH),  aWL  = smem_u32(sWL);

    int tid = threadIdx.x, lane = tid & 31, wid = tid >> 5;
    int wm = wid & 3, wn = wid >> 2;
    int y0 = blockIdx.x*2, b = blockIdx.y;

    float c[3][2][4];
    #pragma unroll
    for (int i = 0; i < 3; i++)
        #pragma unroll
        for (int j = 0; j < 2; j++)
            #pragma unroll
            for (int q = 0; q < 4; q++) c[i][j][q] = 0.f;

    for (int chunk = 0; chunk < 2; chunk++){
        __syncthreads();
        for (int e = tid; e < 1200; e += 256){
            int ent = e >> 1, half = e & 1;
            int row = ent/100, cc = ent%100;
            int y = y0 + row - 2, x = cc - 2;
            uint4 vh = make_uint4(0,0,0,0), vl = make_uint4(0,0,0,0);
            if ((unsigned)y < 96u && (unsigned)x < 96u){
                size_t off = ((size_t)b*HW + y*Ww + x)*32 + chunk*16 + half*8;
                vh = *reinterpret_cast<const uint4*>(g_fhi + off);
                vl = *reinterpret_cast<const uint4*>(g_flo + off);
            }
            int so = ent*24 + half*8;
            *reinterpret_cast<uint4*>(sInH + so) = vh;
            *reinterpret_cast<uint4*>(sInL + so) = vl;
        }
        for (int e = tid; e < 1600; e += 256){
            reinterpret_cast<uint4*>(sWH)[e] = reinterpret_cast<const uint4*>(g_w2hi + chunk*12800)[e];
            reinterpret_cast<uint4*>(sWL)[e] = reinterpret_cast<const uint4*>(g_w2lo + chunk*12800)[e];
        }
        __syncthreads();

        #pragma unroll 1
        for (int tap = 0; tap < 25; tap++){
            int dy = tap/5, dx = tap%5;
            uint32_t bh[4], bl[4];
            uint32_t boff = 2u*(uint32_t)((tap*32 + wn*16 + (lane&7) + ((lane>>4)&1)*8)*16
                                          + ((lane>>3)&1)*8);
            ldm_x4(bh, aWH + boff);
            ldm_x4(bl, aWL + boff);
            uint32_t ah[3][4], al[3][4];
            #pragma unroll
            for (int mi = 0; mi < 3; mi++){
                int tmi = wm*3 + mi;
                int r = tmi/6, xb = (tmi%6)*16;
                uint32_t aoff = 2u*(uint32_t)(((r+dy)*100 + xb + (lane&15) + dx)*24
                                              + (lane>>4)*8);
                ldm_x4(ah[mi], aInH + aoff);
                ldm_x4(al[mi], aInL + aoff);
            }
            #pragma unroll
            for (int mi = 0; mi < 3; mi++){
                #pragma unroll
                for (int j = 0; j < 2; j++){
                    MMA_BF16(c[mi][j], ah[mi], &bh[j*2]);
                    MMA_BF16(c[mi][j], ah[mi], &bl[j*2]);
                    MMA_BF16(c[mi][j], al[mi], &bh[j*2]);
                }
            }
        }
    }

    #pragma unroll
    for (int mi = 0; mi < 3; mi++){
        int tmi = wm*3 + mi;
        int r = tmi/6, xb = (tmi%6)*16;
        int gp = (y0 + r)*Ww + xb + (lane>>2);
        #pragma unroll
        for (int j = 0; j < 2; j++){
            int oc = wn*16 + j*8 + (lane&3)*2;
            if (oc < 10){
                float bv0 = b_fl[oc], bv1 = b_fl[oc+1];
                float* f0 = g_flows + ((size_t)b*10 + oc)*HW;
                float* f1 = g_flows + ((size_t)b*10 + oc + 1)*HW;
                f0[gp]     = c[mi][j][0] + bv0;
                f1[gp]     = c[mi][j][1] + bv1;
                f0[gp + 8] = c[mi][j][2] + bv0;
                f1[gp + 8] = c[mi][j][3] + bv1;
            }
        }
    }
}

// ============================================================
// warp: bilinear-warp h, emit transposed bf16 hi/lo [b][p][k]
// ============================================================
__global__ void k_warp(const float* __restrict__ h){
    int bl = blockIdx.x, y = blockIdx.y, tx = threadIdx.x;
    int b = bl / Lk, l = bl % Lk;
    const float* fl = g_flows + (size_t)b*10*HW + y*Ww + tx;
    float fx = fl[(size_t)(2*l)*HW];
    float fy = fl[(size_t)(2*l+1)*HW];
    float vx = (float)tx - fx;
    float vy = (float)y  - fy;
    const float sc = 96.0f/95.0f;
    float ix = vx*sc - 0.5f;
    float iy = vy*sc - 0.5f;
    float fx0 = floorf(ix), fy0 = floorf(iy);
    int ix0 = (int)fx0, iy0 = (int)fy0;
    int ix1 = ix0 + 1, iy1 = iy0 + 1;
    float wx1 = ix - fx0, wy1 = iy - fy0;
    float wx0 = 1.f - wx1, wy0 = 1.f - wy1;
    float mx0 = (ix0 >= 0 && ix0 < Ww) ? 1.f : 0.f;
    float mx1 = (ix1 >= 0 && ix1 < Ww) ? 1.f : 0.f;
    float my0 = (iy0 >= 0 && iy0 < Hh) ? 1.f : 0.f;
    float my1 = (iy1 >= 0 && iy1 < Hh) ? 1.f : 0.f;
    int cx0 = min(max(ix0, 0), Ww-1), cx1 = min(max(ix1, 0), Ww-1);
    int cy0 = min(max(iy0, 0), Hh-1), cy1 = min(max(iy1, 0), Hh-1);
    int o00 = cy0*Ww + cx0, o01 = cy0*Ww + cx1;
    int o10 = cy1*Ww + cx0, o11 = cy1*Ww + cx1;
    float w00 = wy0*wx0*my0*mx0, w01 = wy0*wx1*my0*mx1;
    float w10 = wy1*wx0*my1*mx0, w11 = wy1*wx1*my1*mx1;
    const float* hb = h + (size_t)b*Fch*HW;
    int p = y*Ww + tx;
    size_t obase = ((size_t)b*HW + p)*KPAD + l*Fch;

    #pragma unroll 1
    for (int c0 = 0; c0 < Fch; c0 += 8){
        uint32_t hibuf[4], lobuf[4];
        #pragma unroll
        for (int j = 0; j < 4; j++){
            const float* p0 = hb + (size_t)(c0 + 2*j)*HW;
            const float* p1 = p0 + HW;
            float v0 = w00*p0[o00] + w01*p0[o01] + w10*p0[o10] + w11*p0[o11];
            float v1 = w00*p1[o00] + w01*p1[o01] + w10*p1[o10] + w11*p1[o11];
            split2(v0, v1, hibuf[j], lobuf[j]);
        }
        *reinterpret_cast<uint4*>(g_whi + obase + c0) = *reinterpret_cast<uint4*>(hibuf);
        *reinterpret_cast<uint4*>(g_wlo + obase + c0) = *reinterpret_cast<uint4*>(lobuf);
    }
}

// ============================================================
// prep: split w_ret into bf16 hi/lo; zero K-pad cols of g_w*
// ============================================================
__global__ void k_prepA(const float* __restrict__ w_ret){
    int idx = blockIdx.x*blockDim.x + threadIdx.x;
    if (idx >= MPAD*KPAD) return;
    int m = idx / KPAD, k = idx % KPAD;
    float v = (m < FH3 && k < K1) ? w_ret[m*K1 + k] : 0.f;
    __nv_bfloat16 hi = __float2bfloat16(v);
    __nv_bfloat16 lo = __float2bfloat16(v - __bfloat162float(hi));
    g_Ahi[idx] = hi; g_Alo[idx] = lo;
}
__global__ void k_padB(){
    int idx = blockIdx.x*blockDim.x + threadIdx.x;
    if (idx >= Bg*HW*4) return;
    int u = idx & 3;
    size_t row = (size_t)(idx >> 2);
    size_t off = row*KPAD + 480 + u*8;
    uint4 z = make_uint4(0,0,0,0);
    *reinterpret_cast<uint4*>(g_whi + off) = z;
    *reinterpret_cast<uint4*>(g_wlo + off) = z;
}

// ============================================================
// h2h GEMM: mma.sync bf16 hi/lo, cp.async double-buffered.
// CTA 128x128, BK=32, 8 warps (2x4), warp 64x32. grid (72,3,B)
// ============================================================
#define TS 40
#define BUFB (128*TS*2)   // bytes per matrix per buffer

__global__ void __launch_bounds__(256, 1) k_h2h(const float* __restrict__ bias){
    __shared__ __nv_bfloat16 sAh[2*128*TS], sAl[2*128*TS], sBh[2*128*TS], sBl[2*128*TS];
    int tid = threadIdx.x, lane = tid & 31, wid = tid >> 5;
    int wm = wid & 1, wn = wid >> 1;
    int n0 = blockIdx.x*128, m0 = blockIdx.y*128, bz = blockIdx.z;

    const __nv_bfloat16* Ah = g_Ahi + (size_t)m0*KPAD;
    const __nv_bfloat16* Al = g_Alo + (size_t)m0*KPAD;
    const __nv_bfloat16* Bh = g_whi + ((size_t)bz*HW + n0)*KPAD;
    const __nv_bfloat16* Bl = g_wlo + ((size_t)bz*HW + n0)*KPAD;

    uint32_t aSh = smem_u32(sAh), aSl = smem_u32(sAl);
    uint32_t aBh = smem_u32(sBh), aBl = smem_u32(sBl);

    int arow = wm*64 + (lane & 15);
    int acol = (lane >> 4) * 8;
    int brow = wn*32 + (lane & 7) + ((lane >> 4) & 1)*8;
    int bcol = ((lane >> 3) & 1) * 8;

    float c[4][4][4];
    #pragma unroll
    for (int i = 0; i < 4; i++)
        #pragma unroll
        for (int j = 0; j < 4; j++)
            #pragma unroll
            for (int q = 0; q < 4; q++) c[i][j][q] = 0.f;

    // staging lambda-ish macro: one chunk -> buffer buf
    int sr = tid >> 2, su = tid & 3;          // 2 rows per thread pass
    #define H2H_STAGE(chunk, buf) do { \
        uint32_t sb = (uint32_t)(buf)*BUFB; \
        _Pragma("unroll") \
        for (int i2 = 0; i2 < 2; i2++){ \
            int r = sr + i2*64; \
            size_t goff = (size_t)r*KPAD + (chunk)*32 + su*8; \
            uint32_t soff = sb + (uint32_t)(r*TS + su*8)*2u; \
            CPA16(aSh + soff, Ah + goff); \
            CPA16(aSl + soff, Al + goff); \
            CPA16(aBh + soff, Bh + goff); \
            CPA16(aBl + soff, Bl + goff); \
        } \
        CPA_COMMIT(); \
    } while(0)

    H2H_STAGE(0, 0);
    for (int chunk = 0; chunk < 16; chunk++){
        if (chunk + 1 < 16){
            H2H_STAGE(chunk + 1, (chunk + 1) & 1);
            asm volatile("cp.async.wait_group 1;" ::: "memory");
        } else {
            asm volatile("cp.async.wait_group 0;" ::: "memory");
        }
        __syncthreads();

        uint32_t sb = (uint32_t)(chunk & 1)*BUFB;
        #pragma unroll
        for (int ks = 0; ks < 2; ks++){
            int kc = ks*16;
            uint32_t ah[4][4], al[4][4], bh[2][4], bl[2][4];
            #pragma unroll
            for (int mi = 0; mi < 4; mi++){
                uint32_t off = sb + 2u*((arow + mi*16)*TS + kc + acol);
                ldm_x4(ah[mi], aSh + off);
                ldm_x4(al[mi], aSl + off);
            }
            #pragma unroll
            for (int jp = 0; jp < 2; jp++){
                uint32_t off = sb + 2u*((brow + jp*16)*TS + kc + bcol);
                ldm_x4(bh[jp], aBh + off);
                ldm_x4(bl[jp], aBl + off);
            }
            #pragma unroll
            for (int mi = 0; mi < 4; mi++){
                #pragma unroll
                for (int j = 0; j < 4; j++){
                    uint32_t* fh = &bh[j >> 1][(j & 1)*2];
                    uint32_t* fl2 = &bl[j >> 1][(j & 1)*2];
                    MMA_BF16(c[mi][j], ah[mi], fh);
                    MMA_BF16(c[mi][j], ah[mi], fl2);
                    MMA_BF16(c[mi][j], al[mi], fh);
                }
            }
        }
        __syncthreads();
    }

    float* Cb = g_h2h + (size_t)bz*FH3*HW;
    int mbase = m0 + wm*64 + (lane >> 2);
    int nbase = n0 + wn*32 + (lane & 3)*2;
    #pragma unroll
    for (int mi = 0; mi < 4; mi++){
        int r0 = mbase + mi*16;
        #pragma unroll
        for (int j = 0; j < 4; j++){
            int col = nbase + j*8;
            if (r0 < FH3){
                float bv = bias[r0];
                float2 v; v.x = c[mi][j][0] + bv; v.y = c[mi][j][1] + bv;
                *reinterpret_cast<float2*>(Cb + (size_t)r0*HW + col) = v;
            }
            if (r0 + 8 < FH3){
                float bv = bias[r0 + 8];
                float2 v; v.x = c[mi][j][2] + bv; v.y = c[mi][j][3] + bv;
                *reinterpret_cast<float2*>(Cb + (size_t)(r0+8)*HW + col) = v;
            }
        }
    }
}

// ============================================================
// gates: GRU update -> next_h, fused packing into next input slot
// thread per (b, fc-group of 8, p)
// ============================================================
__global__ void k_gates(int t, const float* __restrict__ hprev,
                        float* __restrict__ hnext, int pack){
    int idx = blockIdx.x * blockDim.x + threadIdx.x;
    if (idx >= Bg*12*HW) return;
    int p = idx % HW, fcg = (idx/HW) % 12, b = idx/(HW*12);
    const float* i2h = g_i2h + (size_t)(t*Bg + b)*FH3*HW + p;
    const float* h2h = g_h2h + (size_t)b*FH3*HW + p;
    const float* hp_ = hprev + (size_t)b*Fch*HW + p;
    float* hn_ = hnext + (size_t)b*Fch*HW + p;
    uint32_t hw[4], lw[4];
    #pragma unroll
    for (int q = 0; q < 4; q++){
        float nv[2];
        #pragma unroll
        for (int s = 0; s < 2; s++){
            int fc = fcg*8 + 2*q + s;
            float ir = i2h[(size_t)fc*HW];
            float iu = i2h[(size_t)(Fch + fc)*HW];
            float im = i2h[(size_t)(2*Fch + fc)*HW];
            float hr = h2h[(size_t)fc*HW];
            float hu = h2h[(size_t)(Fch + fc)*HW];
            float hm = h2h[(size_t)(2*Fch + fc)*HW];
            float hp = hp_[(size_t)fc*HW];
            float reset  = sigm(ir + hr);
            float update = sigm(iu + hu);
            float newmem = leaky(im + reset*hm);
            nv[s] = update*hp + (1.f - update)*newmem;
            hn_[(size_t)fc*HW] = nv[s];
        }
        split2(nv[0], nv[1], hw[q], lw[q]);
    }
    if (pack){
        size_t off = ((size_t)((t+1)*Bg + b)*HW + p)*CH + 8 + fcg*8;
        *reinterpret_cast<uint4*>(g_inhi + off) = *reinterpret_cast<uint4*>(hw);
        *reinterpret_cast<uint4*>(g_inlo + off) = *reinterpret_cast<uint4*>(lw);
    }
}

// ============================================================
extern "C" void kernel_launch(void* const* d_in, const int* in_sizes, int n_in,
                              void* d_out, int out_size){
    const float* inputs = (const float*)d_in[0];
    const float* h0     = (const float*)d_in[1];
    const float* w_i2h  = (const float*)d_in[2];
    const float* b_i2h  = (const float*)d_in[3];
    const float* w_i2f  = (const float*)d_in[4];
    const float* b_i2f  = (const float*)d_in[5];
    const float* w_h2f  = (const float*)d_in[6];
    const float* b_h2f  = (const float*)d_in[7];
    const float* w_fl   = (const float*)d_in[8];
    const float* b_fl   = (const float*)d_in[9];
    const float* w_ret  = (const float*)d_in[10];
    const float* b_ret  = (const float*)d_in[11];
    float* out = (float*)d_out;

    cudaFuncSetAttribute(k_fconv,  cudaFuncAttributeMaxDynamicSharedMemorySize, FSM_BYTES);
    cudaFuncSetAttribute(k_flowsT, cudaFuncAttributeMaxDynamicSharedMemorySize, FSM_BYTES);

    // once per launch
    k_i2h   <<<dim3(Sg*Bg, Hh, 9), 96>>>(inputs, w_i2h, b_i2h);
    k_prepA <<<(MPAD*KPAD + 255)/256, 256>>>(w_ret);
    k_padB  <<<(Bg*HW*4 + 255)/256, 256>>>();
    k_prepW <<<(7*25*32*16 + 255)/256, 256>>>(w_i2f, w_h2f);
    k_prepW2<<<(2*25*32*16 + 255)/256, 256>>>(w_fl);
    k_prepX <<<(Sg*Bg*HW + 255)/256, 256>>>(inputs, h0);

    for (int t = 0; t < Sg; t++){
        const float* h = (t == 0) ? h0 : out + (size_t)(t-1)*STEP_ELEMS;
        float* hn = out + (size_t)t*STEP_ELEMS;

        k_fconv <<<dim3(48, Bg), 256, FSM_BYTES>>>(t, b_i2f, b_h2f);
        k_flowsT<<<dim3(48, Bg), 256, FSM_BYTES>>>(b_fl);
        k_warp  <<<dim3(Bg*Lk, Hh), 96>>>(h);
        k_h2h   <<<dim3(HW/128, 3, Bg), 256>>>(b_ret);
        k_gates <<<(Bg*12*HW + 255)/256, 256>>>(t, h, hn, (t < Sg-1) ? 1 : 0);
    }

    const size_t OUT_SEQ = (size_t)Sg*STEP_ELEMS;
    if ((size_t)out_size >= OUT_SEQ + STEP_ELEMS){
        cudaMemcpyAsync(out + OUT_SEQ, out + (size_t)(Sg-1)*STEP_ELEMS,
                        (size_t)STEP_ELEMS*sizeof(float),
                        cudaMemcpyDeviceToDevice);
    }
}

// round 6
// speedup vs baseline: 3.1866x; 1.1884x over previous
#include <cuda_runtime.h>
#include <cuda_bf16.h>
#include <cstdint>
#include <math.h>

#define Hh 96
#define Ww 96
#define HW 9216
#define Fch 96
#define CIN 8
#define Lk 5
#define Sg 10
#define Bg 4
#define FH3 288          // 3*F
#define K1 480           // L*F
#define KPAD 512
#define MPAD 384
#define CH 112           // packed input channels: 8 x | 96 h | 8 zero
#define STEP_ELEMS (Bg*Fch*HW)   // 3,538,944

// ---- scratch (device globals) ----
__device__ float g_i2h[(size_t)Sg*Bg*FH3*HW];                 // 425 MB (once)
__device__ float g_flows[Bg*10*HW];
__device__ __align__(16) __nv_bfloat16 g_whi[(size_t)Bg*HW*KPAD];  // warped^T hi [b][p][k]
__device__ __align__(16) __nv_bfloat16 g_wlo[(size_t)Bg*HW*KPAD];
__device__ __align__(16) __nv_bfloat16 g_Ahi[(size_t)MPAD*KPAD];   // w_ret hi [m][k]
__device__ __align__(16) __nv_bfloat16 g_Alo[(size_t)MPAD*KPAD];
__device__ float g_h2h[(size_t)Bg*FH3*HW];
// fconv inputs: per-step slots [Sg][Bg][p][112]
__device__ __align__(16) __nv_bfloat16 g_inhi[(size_t)Sg*Bg*HW*CH];
__device__ __align__(16) __nv_bfloat16 g_inlo[(size_t)Sg*Bg*HW*CH];
__device__ __align__(16) __nv_bfloat16 g_wfhi[7*25*32*16];         // [chunk][tap][oc][16]
__device__ __align__(16) __nv_bfloat16 g_wflo[7*25*32*16];
// f as bf16 hi/lo [b][p][32]
__device__ __align__(16) __nv_bfloat16 g_fhi[(size_t)Bg*HW*32];
__device__ __align__(16) __nv_bfloat16 g_flo[(size_t)Bg*HW*32];
// flows weights [chunk2][tap25][oc32][16] (oc>=10 zero)
__device__ __align__(16) __nv_bfloat16 g_w2hi[2*25*32*16];
__device__ __align__(16) __nv_bfloat16 g_w2lo[2*25*32*16];
// i2h weights [ocg3][tap9][oc96][8] hi/lo
__device__ __align__(16) __nv_bfloat16 g_w3hi[3*9*96*8];
__device__ __align__(16) __nv_bfloat16 g_w3lo[3*9*96*8];

__device__ __forceinline__ float leaky(float v){ return v > 0.f ? v : 0.2f*v; }
__device__ __forceinline__ float sigm(float v){ return 1.f/(1.f + expf(-v)); }

__device__ __forceinline__ uint32_t smem_u32(const void* p){
    uint32_t a;
    asm("{ .reg .u64 t; cvta.to.shared.u64 t, %1; cvt.u32.u64 %0, t; }" : "=r"(a) : "l"(p));
    return a;
}
__device__ __forceinline__ void ldm_x4(uint32_t* r, uint32_t addr){
    asm volatile("ldmatrix.sync.aligned.m8n8.x4.shared.b16 {%0,%1,%2,%3}, [%4];"
        : "=r"(r[0]), "=r"(r[1]), "=r"(r[2]), "=r"(r[3]) : "r"(addr));
}
__device__ __forceinline__ void ldm_x2(uint32_t* r, uint32_t addr){
    asm volatile("ldmatrix.sync.aligned.m8n8.x2.shared.b16 {%0,%1}, [%2];"
        : "=r"(r[0]), "=r"(r[1]) : "r"(addr));
}
#define MMA_BF16(c, a, b) \
    asm volatile("mma.sync.aligned.m16n8k16.row.col.f32.bf16.bf16.f32 " \
        "{%0,%1,%2,%3}, {%4,%5,%6,%7}, {%8,%9}, {%0,%1,%2,%3};" \
        : "+f"((c)[0]), "+f"((c)[1]), "+f"((c)[2]), "+f"((c)[3]) \
        : "r"((a)[0]), "r"((a)[1]), "r"((a)[2]), "r"((a)[3]), \
          "r"((b)[0]), "r"((b)[1]))
#define MMA_BF16_K8(c, a, b) \
    asm volatile("mma.sync.aligned.m16n8k8.row.col.f32.bf16.bf16.f32 " \
        "{%0,%1,%2,%3}, {%4,%5}, {%6}, {%0,%1,%2,%3};" \
        : "+f"((c)[0]), "+f"((c)[1]), "+f"((c)[2]), "+f"((c)[3]) \
        : "r"((a)[0]), "r"((a)[1]), "r"(b))
#define CPA16(sm, gp) asm volatile("cp.async.ca.shared.global [%0], [%1], 16;" :: "r"(sm), "l"(gp))
#define CPA_COMMIT()  asm volatile("cp.async.commit_group;" ::: "memory")

__device__ __forceinline__ void split2(float v0, float v1, uint32_t& hw, uint32_t& lw){
    __nv_bfloat16 h0 = __float2bfloat16(v0), h1 = __float2bfloat16(v1);
    __nv_bfloat16 l0 = __float2bfloat16(v0 - __bfloat162float(h0));
    __nv_bfloat16 l1 = __float2bfloat16(v1 - __bfloat162float(h1));
    __nv_bfloat162 hp; hp.x = h0; hp.y = h1;
    __nv_bfloat162 lp; lp.x = l0; lp.y = l1;
    hw = *reinterpret_cast<uint32_t*>(&hp);
    lw = *reinterpret_cast<uint32_t*>(&lp);
}

// ============================================================
// k_prepX (once): pack x channels for ALL step slots, zero pad ch,
// and slot-0 h channels from h0.
// ============================================================
__global__ void k_prepX(const float* __restrict__ inputs, const float* __restrict__ h0){
    int idx = blockIdx.x*blockDim.x + threadIdx.x;
    if (idx >= Sg*Bg*HW) return;
    int p = idx % HW, b = (idx/HW) % Bg, t = idx/(HW*Bg);
    size_t base = ((size_t)(t*Bg + b)*HW + p)*CH;
    const float* xp = inputs + ((size_t)(t*Bg + b)*CIN)*HW + p;
    uint32_t hw[4], lw[4];
    #pragma unroll
    for (int q = 0; q < 4; q++)
        split2(xp[(size_t)(2*q)*HW], xp[(size_t)(2*q+1)*HW], hw[q], lw[q]);
    *reinterpret_cast<uint4*>(g_inhi + base) = *reinterpret_cast<uint4*>(hw);
    *reinterpret_cast<uint4*>(g_inlo + base) = *reinterpret_cast<uint4*>(lw);
    uint4 z = make_uint4(0,0,0,0);
    *reinterpret_cast<uint4*>(g_inhi + base + 104) = z;
    *reinterpret_cast<uint4*>(g_inlo + base + 104) = z;
    if (t == 0){
        const float* hp = h0 + (size_t)b*Fch*HW + p;
        for (int g = 0; g < 12; g++){
            #pragma unroll
            for (int q = 0; q < 4; q++)
                split2(hp[(size_t)(g*8 + 2*q)*HW], hp[(size_t)(g*8 + 2*q+1)*HW], hw[q], lw[q]);
            *reinterpret_cast<uint4*>(g_inhi + base + 8 + g*8) = *reinterpret_cast<uint4*>(hw);
            *reinterpret_cast<uint4*>(g_inlo + base + 8 + g*8) = *reinterpret_cast<uint4*>(lw);
        }
    }
}

// ============================================================
// weight preps (once)
// ============================================================
__global__ void k_prepW(const float* __restrict__ w_i2f, const float* __restrict__ w_h2f){
    int idx = blockIdx.x*blockDim.x + threadIdx.x;
    if (idx >= 7*25*32*16) return;
    int kc = idx & 15, oc = (idx >> 4) & 31, tap = (idx >> 9) % 25, chunk = idx / 12800;
    int ch = chunk*16 + kc;
    float v = 0.f;
    if (ch < 8)        v = w_i2f[(oc*8 + ch)*25 + tap];
    else if (ch < 104) v = w_h2f[((size_t)oc*Fch + (ch-8))*25 + tap];
    __nv_bfloat16 hi = __float2bfloat16(v);
    __nv_bfloat16 lo = __float2bfloat16(v - __bfloat162float(hi));
    g_wfhi[idx] = hi; g_wflo[idx] = lo;
}
__global__ void k_prepW2(const float* __restrict__ w_fl){
    int idx = blockIdx.x*blockDim.x + threadIdx.x;
    if (idx >= 2*25*32*16) return;
    int kc = idx & 15, oc = (idx >> 4) & 31, tap = (idx >> 9) % 25, chunk = idx / 12800;
    int ch = chunk*16 + kc;
    float v = (oc < 10) ? w_fl[((size_t)oc*32 + ch)*25 + tap] : 0.f;
    __nv_bfloat16 hi = __float2bfloat16(v);
    __nv_bfloat16 lo = __float2bfloat16(v - __bfloat162float(hi));
    g_w2hi[idx] = hi; g_w2lo[idx] = lo;
}
// i2h weights: w_i2h [288][8][3][3] -> [ocg][tap][oc96][8]
__global__ void k_prepW3(const float* __restrict__ w_i2h){
    int idx = blockIdx.x*blockDim.x + threadIdx.x;
    if (idx >= 3*9*96*8) return;
    int ch = idx & 7, oc = (idx >> 3) % 96, tap = (idx/(96*8)) % 9, ocg = idx/(9*96*8);
    int ocG = ocg*96 + oc;
    float v = w_i2h[((size_t)ocG*CIN + ch)*9 + tap];
    __nv_bfloat16 hi = __float2bfloat16(v);
    __nv_bfloat16 lo = __float2bfloat16(v - __bfloat162float(hi));
    g_w3hi[idx] = hi; g_w3lo[idx] = lo;
}

// ============================================================
// i2h as implicit GEMM (m16n8k8, bf16 hi/lo 3-term), runs once:
// out[img][oc][p] = conv3x3(x)[oc][p] + bias[oc]
// CTA = 2 rows x 96 px (M=192), N=96 oc; 8 warps (4M x 2N), warp 3xm16 x 6xn8
// grid (48, 40 img, 3 ocg), 256 thr
// ============================================================
__global__ void __launch_bounds__(256, 2) k_i2hT(const float* __restrict__ bias){
    __shared__ __nv_bfloat16 sInH[400*8], sInL[400*8];
    __shared__ __nv_bfloat16 sWH[9*96*8], sWL[9*96*8];
    uint32_t aInH = smem_u32(sInH), aInL = smem_u32(sInL);
    uint32_t aWH  = smem_u32(sWH),  aWL  = smem_u32(sWL);

    int tid = threadIdx.x, lane = tid & 31, wid = tid >> 5;
    int wm = wid & 3, wn = wid >> 2;
    int y0 = blockIdx.x*2, img = blockIdx.y, ocg = blockIdx.z;

    // stage input halo tile: 4 rows x 100 cols x 8ch
    for (int e = tid; e < 400; e += 256){
        int row = e/100, cc = e%100;
        int y = y0 + row - 1, x = cc - 1;
        uint4 vh = make_uint4(0,0,0,0), vl = make_uint4(0,0,0,0);
        if ((unsigned)y < 96u && (unsigned)x < 96u){
            size_t off = ((size_t)img*HW + y*Ww + x)*CH;
            vh = *reinterpret_cast<const uint4*>(g_inhi + off);
            vl = *reinterpret_cast<const uint4*>(g_inlo + off);
        }
        *reinterpret_cast<uint4*>(sInH + e*8) = vh;
        *reinterpret_cast<uint4*>(sInL + e*8) = vl;
    }
    // stage weights for this ocg: 6912 elems = 864 uint4
    for (int e = tid; e < 864; e += 256){
        reinterpret_cast<uint4*>(sWH)[e] = reinterpret_cast<const uint4*>(g_w3hi + (size_t)ocg*9*96*8)[e];
        reinterpret_cast<uint4*>(sWL)[e] = reinterpret_cast<const uint4*>(g_w3lo + (size_t)ocg*9*96*8)[e];
    }
    __syncthreads();

    float c[3][6][4];
    #pragma unroll
    for (int i = 0; i < 3; i++)
        #pragma unroll
        for (int j = 0; j < 6; j++)
            #pragma unroll
            for (int q = 0; q < 4; q++) c[i][j][q] = 0.f;

    #pragma unroll 1
    for (int tap = 0; tap < 9; tap++){
        int dy = tap/3, dx = tap%3;
        uint32_t bh[6], bl[6];
        {
            uint32_t a4 = aWH + 2u*(uint32_t)((tap*96 + wn*48 + lane)*8);
            ldm_x4(bh, a4);
            ldm_x4(bl, aWL + 2u*(uint32_t)((tap*96 + wn*48 + lane)*8));
            uint32_t a2 = 2u*(uint32_t)((tap*96 + wn*48 + 32 + (lane & 15))*8);
            ldm_x2(bh + 4, aWH + a2);
            ldm_x2(bl + 4, aWL + a2);
        }
        uint32_t ah[3][2], al[3][2];
        #pragma unroll
        for (int mi = 0; mi < 3; mi++){
            int tmi = wm*3 + mi;
            int r = tmi/6, xb = (tmi%6)*16;
            uint32_t aoff = 2u*(uint32_t)(((r+dy)*100 + xb + (lane&15) + dx)*8);
            ldm_x2(ah[mi], aInH + aoff);
            ldm_x2(al[mi], aInL + aoff);
        }
        #pragma unroll
        for (int mi = 0; mi < 3; mi++){
            #pragma unroll
            for (int j = 0; j < 6; j++){
                MMA_BF16_K8(c[mi][j], ah[mi], bh[j]);
                MMA_BF16_K8(c[mi][j], ah[mi], bl[j]);
                MMA_BF16_K8(c[mi][j], al[mi], bh[j]);
            }
        }
    }

    // epilogue: + bias -> g_i2h[img][oc][p] fp32 planar
    float* Ob = g_i2h + (size_t)img*FH3*HW;
    #pragma unroll
    for (int mi = 0; mi < 3; mi++){
        int tmi = wm*3 + mi;
        int r = tmi/6, xb = (tmi%6)*16;
        int p = (y0 + r)*Ww + xb + (lane>>2);
        #pragma unroll
        for (int j = 0; j < 6; j++){
            int oc = ocg*96 + wn*48 + j*8 + (lane&3)*2;
            float bv0 = bias[oc], bv1 = bias[oc+1];
            Ob[(size_t)oc*HW + p]           = c[mi][j][0] + bv0;
            Ob[(size_t)(oc+1)*HW + p]       = c[mi][j][1] + bv1;
            Ob[(size_t)oc*HW + p + 8]       = c[mi][j][2] + bv0;
            Ob[(size_t)(oc+1)*HW + p + 8]   = c[mi][j][3] + bv1;
        }
    }
}

// ============================================================
// fconv implicit GEMM (bf16 hi/lo 3-term). CTA = 2 rows x 96 px,
// N=32, 8 warps (4M x 2N). Epilogue -> f bf16 hi/lo [b][p][32].
// ============================================================
#define FSM_ELEMS 54400
#define FSM_BYTES (FSM_ELEMS*2)

__global__ void __launch_bounds__(256, 2) k_fconv(int t,
                                                  const float* __restrict__ b_i2f,
                                                  const float* __restrict__ b_h2f){
    extern __shared__ __nv_bfloat16 sm[];
    __nv_bfloat16* sInH = sm;
    __nv_bfloat16* sInL = sm + 14400;
    __nv_bfloat16* sWH  = sm + 28800;
    __nv_bfloat16* sWL  = sm + 41600;
    uint32_t aInH = smem_u32(sInH), aInL = smem_u32(sInL);
    uint32_t aWH  = smem_u32(sWH),  aWL  = smem_u32(sWL);

    int tid = threadIdx.x, lane = tid & 31, wid = tid >> 5;
    int wm = wid & 3, wn = wid >> 2;
    int y0 = blockIdx.x*2, b = blockIdx.y;
    size_t slot = (size_t)(t*Bg + b)*HW;

    float c[3][2][4];
    #pragma unroll
    for (int i = 0; i < 3; i++)
        #pragma unroll
        for (int j = 0; j < 2; j++)
            #pragma unroll
            for (int q = 0; q < 4; q++) c[i][j][q] = 0.f;

    for (int chunk = 0; chunk < 7; chunk++){
        __syncthreads();
        for (int e = tid; e < 1200; e += 256){
            int ent = e >> 1, half = e & 1;
            int row = ent/100, cc = ent%100;
            int y = y0 + row - 2, x = cc - 2;
            uint4 vh = make_uint4(0,0,0,0), vl = make_uint4(0,0,0,0);
            if ((unsigned)y < 96u && (unsigned)x < 96u){
                size_t off = (slot + y*Ww + x)*CH + chunk*16 + half*8;
                vh = *reinterpret_cast<const uint4*>(g_inhi + off);
                vl = *reinterpret_cast<const uint4*>(g_inlo + off);
            }
            int so = ent*24 + half*8;
            *reinterpret_cast<uint4*>(sInH + so) = vh;
            *reinterpret_cast<uint4*>(sInL + so) = vl;
        }
        for (int e = tid; e < 1600; e += 256){
            reinterpret_cast<uint4*>(sWH)[e] = reinterpret_cast<const uint4*>(g_wfhi + chunk*12800)[e];
            reinterpret_cast<uint4*>(sWL)[e] = reinterpret_cast<const uint4*>(g_wflo + chunk*12800)[e];
        }
        __syncthreads();

        #pragma unroll 1
        for (int tap = 0; tap < 25; tap++){
            int dy = tap/5, dx = tap%5;
            uint32_t bh[4], bl[4];
            uint32_t boff = 2u*(uint32_t)((tap*32 + wn*16 + (lane&7) + ((lane>>4)&1)*8)*16
                                          + ((lane>>3)&1)*8);
            ldm_x4(bh, aWH + boff);
            ldm_x4(bl, aWL + boff);
            uint32_t ah[3][4], al[3][4];
            #pragma unroll
            for (int mi = 0; mi < 3; mi++){
                int tmi = wm*3 + mi;
                int r = tmi/6, xb = (tmi%6)*16;
                uint32_t aoff = 2u*(uint32_t)(((r+dy)*100 + xb + (lane&15) + dx)*24
                                              + (lane>>4)*8);
                ldm_x4(ah[mi], aInH + aoff);
                ldm_x4(al[mi], aInL + aoff);
            }
            #pragma unroll
            for (int mi = 0; mi < 3; mi++){
                #pragma unroll
                for (int j = 0; j < 2; j++){
                    MMA_BF16(c[mi][j], ah[mi], &bh[j*2]);
                    MMA_BF16(c[mi][j], ah[mi], &bl[j*2]);
                    MMA_BF16(c[mi][j], al[mi], &bh[j*2]);
                }
            }
        }
    }

    #pragma unroll
    for (int mi = 0; mi < 3; mi++){
        int tmi = wm*3 + mi;
        int r = tmi/6, xb = (tmi%6)*16;
        int gp = (y0 + r)*Ww + xb + (lane>>2);
        #pragma unroll
        for (int j = 0; j < 2; j++){
            int oc = wn*16 + j*8 + (lane&3)*2;
            float bb0 = b_i2f[oc]   + b_h2f[oc];
            float bb1 = b_i2f[oc+1] + b_h2f[oc+1];
            uint32_t hw, lw;
            split2(leaky(c[mi][j][0] + bb0), leaky(c[mi][j][1] + bb1), hw, lw);
            size_t o0 = ((size_t)b*HW + gp)*32 + oc;
            *reinterpret_cast<uint32_t*>(g_fhi + o0) = hw;
            *reinterpret_cast<uint32_t*>(g_flo + o0) = lw;
            split2(leaky(c[mi][j][2] + bb0), leaky(c[mi][j][3] + bb1), hw, lw);
            size_t o1 = ((size_t)b*HW + gp + 8)*32 + oc;
            *reinterpret_cast<uint32_t*>(g_fhi + o1) = hw;
            *reinterpret_cast<uint32_t*>(g_flo + o1) = lw;
        }
    }
}

// ============================================================
// flows implicit GEMM (2 chunks, oc padded to 32)
// ============================================================
__global__ void __launch_bounds__(256, 2) k_flowsT(const float* __restrict__ b_fl){
    extern __shared__ __nv_bfloat16 sm[];
    __nv_bfloat16* sInH = sm;
    __nv_bfloat16* sInL = sm + 14400;
    __nv_bfloat16* sWH  = sm + 28800;
    __nv_bfloat16* sWL  = sm + 41600;
    uint32_t aInH = smem_u32(sInH), aInL = smem_u32(sInL);
    uint32_t aWH  = smem_u32(sWH),  aWL  = smem_u32(sWL);

    int tid = threadIdx.x, lane = tid & 31, wid = tid >> 5;
    int wm = wid & 3, wn = wid >> 2;
    int y0 = blockIdx.x*2, b = blockIdx.y;

    float c[3][2][4];
    #pragma unroll
    for (int i = 0; i < 3; i++)
        #pragma unroll
        for (int j = 0; j < 2; j++)
            #pragma unroll
            for (int q = 0; q < 4; q++) c[i][j][q] = 0.f;

    for (int chunk = 0; chunk < 2; chunk++){
        __syncthreads();
        for (int e = tid; e < 1200; e += 256){
            int ent = e >> 1, half = e & 1;
            int row = ent/100, cc = ent%100;
            int y = y0 + row - 2, x = cc - 2;
            uint4 vh = make_uint4(0,0,0,0), vl = make_uint4(0,0,0,0);
            if ((unsigned)y < 96u && (unsigned)x < 96u){
                size_t off = ((size_t)b*HW + y*Ww + x)*32 + chunk*16 + half*8;
                vh = *reinterpret_cast<const uint4*>(g_fhi + off);
                vl = *reinterpret_cast<const uint4*>(g_flo + off);
            }
            int so = ent*24 + half*8;
            *reinterpret_cast<uint4*>(sInH + so) = vh;
            *reinterpret_cast<uint4*>(sInL + so) = vl;
        }
        for (int e = tid; e < 1600; e += 256){
            reinterpret_cast<uint4*>(sWH)[e] = reinterpret_cast<const uint4*>(g_w2hi + chunk*12800)[e];
            reinterpret_cast<uint4*>(sWL)[e] = reinterpret_cast<const uint4*>(g_w2lo + chunk*12800)[e];
        }
        __syncthreads();

        #pragma unroll 1
        for (int tap = 0; tap < 25; tap++){
            int dy = tap/5, dx = tap%5;
            uint32_t bh[4], bl[4];
            uint32_t boff = 2u*(uint32_t)((tap*32 + wn*16 + (lane&7) + ((lane>>4)&1)*8)*16
                                          + ((lane>>3)&1)*8);
            ldm_x4(bh, aWH + boff);
            ldm_x4(bl, aWL + boff);
            uint32_t ah[3][4], al[3][4];
            #pragma unroll
            for (int mi = 0; mi < 3; mi++){
                int tmi = wm*3 + mi;
                int r = tmi/6, xb = (tmi%6)*16;
                uint32_t aoff = 2u*(uint32_t)(((r+dy)*100 + xb + (lane&15) + dx)*24
                                              + (lane>>4)*8);
                ldm_x4(ah[mi], aInH + aoff);
                ldm_x4(al[mi], aInL + aoff);
            }
            #pragma unroll
            for (int mi = 0; mi < 3; mi++){
                #pragma unroll
                for (int j = 0; j < 2; j++){
                    MMA_BF16(c[mi][j], ah[mi], &bh[j*2]);
                    MMA_BF16(c[mi][j], ah[mi], &bl[j*2]);
                    MMA_BF16(c[mi][j], al[mi], &bh[j*2]);
                }
            }
        }
    }

    #pragma unroll
    for (int mi = 0; mi < 3; mi++){
        int tmi = wm*3 + mi;
        int r = tmi/6, xb = (tmi%6)*16;
        int gp = (y0 + r)*Ww + xb + (lane>>2);
        #pragma unroll
        for (int j = 0; j < 2; j++){
            int oc = wn*16 + j*8 + (lane&3)*2;
            if (oc < 10){
                float bv0 = b_fl[oc], bv1 = b_fl[oc+1];
                float* f0 = g_flows + ((size_t)b*10 + oc)*HW;
                float* f1 = g_flows + ((size_t)b*10 + oc + 1)*HW;
                f0[gp]     = c[mi][j][0] + bv0;
                f1[gp]     = c[mi][j][1] + bv1;
                f0[gp + 8] = c[mi][j][2] + bv0;
                f1[gp + 8] = c[mi][j][3] + bv1;
            }
        }
    }
}

// ============================================================
// warp: bilinear-warp h, emit transposed bf16 hi/lo [b][p][k]
// ============================================================
__global__ void k_warp(const float* __restrict__ h){
    int bl = blockIdx.x, y = blockIdx.y, tx = threadIdx.x;
    int b = bl / Lk, l = bl % Lk;
    const float* fl = g_flows + (size_t)b*10*HW + y*Ww + tx;
    float fx = fl[(size_t)(2*l)*HW];
    float fy = fl[(size_t)(2*l+1)*HW];
    float vx = (float)tx - fx;
    float vy = (float)y  - fy;
    const float sc = 96.0f/95.0f;
    float ix = vx*sc - 0.5f;
    float iy = vy*sc - 0.5f;
    float fx0 = floorf(ix), fy0 = floorf(iy);
    int ix0 = (int)fx0, iy0 = (int)fy0;
    int ix1 = ix0 + 1, iy1 = iy0 + 1;
    float wx1 = ix - fx0, wy1 = iy - fy0;
    float wx0 = 1.f - wx1, wy0 = 1.f - wy1;
    float mx0 = (ix0 >= 0 && ix0 < Ww) ? 1.f : 0.f;
    float mx1 = (ix1 >= 0 && ix1 < Ww) ? 1.f : 0.f;
    float my0 = (iy0 >= 0 && iy0 < Hh) ? 1.f : 0.f;
    float my1 = (iy1 >= 0 && iy1 < Hh) ? 1.f : 0.f;
    int cx0 = min(max(ix0, 0), Ww-1), cx1 = min(max(ix1, 0), Ww-1);
    int cy0 = min(max(iy0, 0), Hh-1), cy1 = min(max(iy1, 0), Hh-1);
    int o00 = cy0*Ww + cx0, o01 = cy0*Ww + cx1;
    int o10 = cy1*Ww + cx0, o11 = cy1*Ww + cx1;
    float w00 = wy0*wx0*my0*mx0, w01 = wy0*wx1*my0*mx1;
    float w10 = wy1*wx0*my1*mx0, w11 = wy1*wx1*my1*mx1;
    const float* hb = h + (size_t)b*Fch*HW;
    int p = y*Ww + tx;
    size_t obase = ((size_t)b*HW + p)*KPAD + l*Fch;

    #pragma unroll 1
    for (int c0 = 0; c0 < Fch; c0 += 8){
        uint32_t hibuf[4], lobuf[4];
        #pragma unroll
        for (int j = 0; j < 4; j++){
            const float* p0 = hb + (size_t)(c0 + 2*j)*HW;
            const float* p1 = p0 + HW;
            float v0 = w00*p0[o00] + w01*p0[o01] + w10*p0[o10] + w11*p0[o11];
            float v1 = w00*p1[o00] + w01*p1[o01] + w10*p1[o10] + w11*p1[o11];
            split2(v0, v1, hibuf[j], lobuf[j]);
        }
        *reinterpret_cast<uint4*>(g_whi + obase + c0) = *reinterpret_cast<uint4*>(hibuf);
        *reinterpret_cast<uint4*>(g_wlo + obase + c0) = *reinterpret_cast<uint4*>(lobuf);
    }
}

// ============================================================
// prep: split w_ret; zero K-pad cols of g_w*
// ============================================================
__global__ void k_prepA(const float* __restrict__ w_ret){
    int idx = blockIdx.x*blockDim.x + threadIdx.x;
    if (idx >= MPAD*KPAD) return;
    int m = idx / KPAD, k = idx % KPAD;
    float v = (m < FH3 && k < K1) ? w_ret[m*K1 + k] : 0.f;
    __nv_bfloat16 hi = __float2bfloat16(v);
    __nv_bfloat16 lo = __float2bfloat16(v - __bfloat162float(hi));
    g_Ahi[idx] = hi; g_Alo[idx] = lo;
}
__global__ void k_padB(){
    int idx = blockIdx.x*blockDim.x + threadIdx.x;
    if (idx >= Bg*HW*4) return;
    int u = idx & 3;
    size_t row = (size_t)(idx >> 2);
    size_t off = row*KPAD + 480 + u*8;
    uint4 z = make_uint4(0,0,0,0);
    *reinterpret_cast<uint4*>(g_whi + off) = z;
    *reinterpret_cast<uint4*>(g_wlo + off) = z;
}

// ============================================================
// h2h GEMM: mma.sync bf16 hi/lo, cp.async double-buffered.
// ============================================================
#define TS 40
#define BUFB (128*TS*2)

__global__ void __launch_bounds__(256, 1) k_h2h(const float* __restrict__ bias){
    __shared__ __nv_bfloat16 sAh[2*128*TS], sAl[2*128*TS], sBh[2*128*TS], sBl[2*128*TS];
    int tid = threadIdx.x, lane = tid & 31, wid = tid >> 5;
    int wm = wid & 1, wn = wid >> 1;
    int n0 = blockIdx.x*128, m0 = blockIdx.y*128, bz = blockIdx.z;

    const __nv_bfloat16* Ah = g_Ahi + (size_t)m0*KPAD;
    const __nv_bfloat16* Al = g_Alo + (size_t)m0*KPAD;
    const __nv_bfloat16* Bh = g_whi + ((size_t)bz*HW + n0)*KPAD;
    const __nv_bfloat16* Bl = g_wlo + ((size_t)bz*HW + n0)*KPAD;

    uint32_t aSh = smem_u32(sAh), aSl = smem_u32(sAl);
    uint32_t aBh = smem_u32(sBh), aBl = smem_u32(sBl);

    int arow = wm*64 + (lane & 15);
    int acol = (lane >> 4) * 8;
    int brow = wn*32 + (lane & 7) + ((lane >> 4) & 1)*8;
    int bcol = ((lane >> 3) & 1) * 8;

    float c[4][4][4];
    #pragma unroll
    for (int i = 0; i < 4; i++)
        #pragma unroll
        for (int j = 0; j < 4; j++)
            #pragma unroll
            for (int q = 0; q < 4; q++) c[i][j][q] = 0.f;

    int sr = tid >> 2, su = tid & 3;
    #define H2H_STAGE(chunk, buf) do { \
        uint32_t sb = (uint32_t)(buf)*BUFB; \
        _Pragma("unroll") \
        for (int i2 = 0; i2 < 2; i2++){ \
            int r = sr + i2*64; \
            size_t goff = (size_t)r*KPAD + (chunk)*32 + su*8; \
            uint32_t soff = sb + (uint32_t)(r*TS + su*8)*2u; \
            CPA16(aSh + soff, Ah + goff); \
            CPA16(aSl + soff, Al + goff); \
            CPA16(aBh + soff, Bh + goff); \
            CPA16(aBl + soff, Bl + goff); \
        } \
        CPA_COMMIT(); \
    } while(0)

    H2H_STAGE(0, 0);
    for (int chunk = 0; chunk < 16; chunk++){
        if (chunk + 1 < 16){
            H2H_STAGE(chunk + 1, (chunk + 1) & 1);
            asm volatile("cp.async.wait_group 1;" ::: "memory");
        } else {
            asm volatile("cp.async.wait_group 0;" ::: "memory");
        }
        __syncthreads();

        uint32_t sb = (uint32_t)(chunk & 1)*BUFB;
        #pragma unroll
        for (int ks = 0; ks < 2; ks++){
            int kc = ks*16;
            uint32_t ah[4][4], al[4][4], bh[2][4], bl[2][4];
            #pragma unroll
            for (int mi = 0; mi < 4; mi++){
                uint32_t off = sb + 2u*((arow + mi*16)*TS + kc + acol);
                ldm_x4(ah[mi], aSh + off);
                ldm_x4(al[mi], aSl + off);
            }
            #pragma unroll
            for (int jp = 0; jp < 2; jp++){
                uint32_t off = sb + 2u*((brow + jp*16)*TS + kc + bcol);
                ldm_x4(bh[jp], aBh + off);
                ldm_x4(bl[jp], aBl + off);
            }
            #pragma unroll
            for (int mi = 0; mi < 4; mi++){
                #pragma unroll
                for (int j = 0; j < 4; j++){
                    uint32_t* fh = &bh[j >> 1][(j & 1)*2];
                    uint32_t* fl2 = &bl[j >> 1][(j & 1)*2];
                    MMA_BF16(c[mi][j], ah[mi], fh);
                    MMA_BF16(c[mi][j], ah[mi], fl2);
                    MMA_BF16(c[mi][j], al[mi], fh);
                }
            }
        }
        __syncthreads();
    }

    float* Cb = g_h2h + (size_t)bz*FH3*HW;
    int mbase = m0 + wm*64 + (lane >> 2);
    int nbase = n0 + wn*32 + (lane & 3)*2;
    #pragma unroll
    for (int mi = 0; mi < 4; mi++){
        int r0 = mbase + mi*16;
        #pragma unroll
        for (int j = 0; j < 4; j++){
            int col = nbase + j*8;
            if (r0 < FH3){
                float bv = bias[r0];
                float2 v; v.x = c[mi][j][0] + bv; v.y = c[mi][j][1] + bv;
                *reinterpret_cast<float2*>(Cb + (size_t)r0*HW + col) = v;
            }
            if (r0 + 8 < FH3){
                float bv = bias[r0 + 8];
                float2 v; v.x = c[mi][j][2] + bv; v.y = c[mi][j][3] + bv;
                *reinterpret_cast<float2*>(Cb + (size_t)(r0+8)*HW + col) = v;
            }
        }
    }
}

// ============================================================
// gates: GRU update -> next_h, fused packing into next input slot
// ============================================================
__global__ void k_gates(int t, const float* __restrict__ hprev,
                        float* __restrict__ hnext, int pack){
    int idx = blockIdx.x * blockDim.x + threadIdx.x;
    if (idx >= Bg*12*HW) return;
    int p = idx % HW, fcg = (idx/HW) % 12, b = idx/(HW*12);
    const float* i2h = g_i2h + (size_t)(t*Bg + b)*FH3*HW + p;
    const float* h2h = g_h2h + (size_t)b*FH3*HW + p;
    const float* hp_ = hprev + (size_t)b*Fch*HW + p;
    float* hn_ = hnext + (size_t)b*Fch*HW + p;
    uint32_t hw[4], lw[4];
    #pragma unroll
    for (int q = 0; q < 4; q++){
        float nv[2];
        #pragma unroll
        for (int s = 0; s < 2; s++){
            int fc = fcg*8 + 2*q + s;
            float ir = i2h[(size_t)fc*HW];
            float iu = i2h[(size_t)(Fch + fc)*HW];
            float im = i2h[(size_t)(2*Fch + fc)*HW];
            float hr = h2h[(size_t)fc*HW];
            float hu = h2h[(size_t)(Fch + fc)*HW];
            float hm = h2h[(size_t)(2*Fch + fc)*HW];
            float hp = hp_[(size_t)fc*HW];
            float reset  = sigm(ir + hr);
            float update = sigm(iu + hu);
            float newmem = leaky(im + reset*hm);
            nv[s] = update*hp + (1.f - update)*newmem;
            hn_[(size_t)fc*HW] = nv[s];
        }
        split2(nv[0], nv[1], hw[q], lw[q]);
    }
    if (pack){
        size_t off = ((size_t)((t+1)*Bg + b)*HW + p)*CH + 8 + fcg*8;
        *reinterpret_cast<uint4*>(g_inhi + off) = *reinterpret_cast<uint4*>(hw);
        *reinterpret_cast<uint4*>(g_inlo + off) = *reinterpret_cast<uint4*>(lw);
    }
}

// ============================================================
extern "C" void kernel_launch(void* const* d_in, const int* in_sizes, int n_in,
                              void* d_out, int out_size){
    const float* inputs = (const float*)d_in[0];
    const float* h0     = (const float*)d_in[1];
    const float* w_i2h  = (const float*)d_in[2];
    const float* b_i2h  = (const float*)d_in[3];
    const float* w_i2f  = (const float*)d_in[4];
    const float* b_i2f  = (const float*)d_in[5];
    const float* w_h2f  = (const float*)d_in[6];
    const float* b_h2f  = (const float*)d_in[7];
    const float* w_fl   = (const float*)d_in[8];
    const float* b_fl   = (const float*)d_in[9];
    const float* w_ret  = (const float*)d_in[10];
    const float* b_ret  = (const float*)d_in[11];
    float* out = (float*)d_out;

    cudaFuncSetAttribute(k_fconv,  cudaFuncAttributeMaxDynamicSharedMemorySize, FSM_BYTES);
    cudaFuncSetAttribute(k_flowsT, cudaFuncAttributeMaxDynamicSharedMemorySize, FSM_BYTES);

    // once per launch
    k_prepX <<<(Sg*Bg*HW + 255)/256, 256>>>(inputs, h0);
    k_prepW3<<<(3*9*96*8 + 255)/256, 256>>>(w_i2h);
    k_i2hT  <<<dim3(48, Sg*Bg, 3), 256>>>(b_i2h);
    k_prepA <<<(MPAD*KPAD + 255)/256, 256>>>(w_ret);
    k_padB  <<<(Bg*HW*4 + 255)/256, 256>>>();
    k_prepW <<<(7*25*32*16 + 255)/256, 256>>>(w_i2f, w_h2f);
    k_prepW2<<<(2*25*32*16 + 255)/256, 256>>>(w_fl);

    for (int t = 0; t < Sg; t++){
        const float* h = (t == 0) ? h0 : out + (size_t)(t-1)*STEP_ELEMS;
        float* hn = out + (size_t)t*STEP_ELEMS;

        k_fconv <<<dim3(48, Bg), 256, FSM_BYTES>>>(t, b_i2f, b_h2f);
        k_flowsT<<<dim3(48, Bg), 256, FSM_BYTES>>>(b_fl);
        k_warp  <<<dim3(Bg*Lk, Hh), 96>>>(h);
        k_h2h   <<<dim3(HW/128, 3, Bg), 256>>>(b_ret);
        k_gates <<<(Bg*12*HW + 255)/256, 256>>>(t, h, hn, (t < Sg-1) ? 1 : 0);
    }

    const size_t OUT_SEQ = (size_t)Sg*STEP_ELEMS;
    if ((size_t)out_size >= OUT_SEQ + STEP_ELEMS){
        cudaMemcpyAsync(out + OUT_SEQ, out + (size_t)(Sg-1)*STEP_ELEMS,
                        (size_t)STEP_ELEMS*sizeof(float),
                        cudaMemcpyDeviceToDevice);
    }
}

// round 7
// speedup vs baseline: 3.6067x; 1.1318x over previous
#include <cuda_runtime.h>
#include <cuda_bf16.h>
#include <cstdint>
#include <math.h>

#define Hh 96
#define Ww 96
#define HW 9216
#define Fch 96
#define CIN 8
#define Lk 5
#define Sg 10
#define Bg 4
#define FH3 288          // 3*F
#define K1 480           // L*F
#define KPAD 512         // row STRIDE of k-major operands (pad cols never read)
#define CH 112           // packed input channels: 8 x | 96 h | 8 zero
#define STEP_ELEMS (Bg*Fch*HW)   // 3,538,944

// ---- scratch (device globals) ----
__device__ float g_i2h[(size_t)Sg*Bg*FH3*HW];                 // 425 MB (once)
__device__ float g_flows[Bg*10*HW];
__device__ __align__(16) __nv_bfloat16 g_whi[(size_t)Bg*HW*KPAD];  // warped^T hi [b][p][k]
__device__ __align__(16) __nv_bfloat16 g_wlo[(size_t)Bg*HW*KPAD];
__device__ __align__(16) __nv_bfloat16 g_Ahi[(size_t)FH3*KPAD];    // w_ret hi [m][k]
__device__ __align__(16) __nv_bfloat16 g_Alo[(size_t)FH3*KPAD];
__device__ float g_h2h[(size_t)Bg*FH3*HW];
// fconv inputs: per-step slots [Sg][Bg][p][112]
__device__ __align__(16) __nv_bfloat16 g_inhi[(size_t)Sg*Bg*HW*CH];
__device__ __align__(16) __nv_bfloat16 g_inlo[(size_t)Sg*Bg*HW*CH];
__device__ __align__(16) __nv_bfloat16 g_wfhi[7*25*32*16];         // [chunk][tap][oc][16]
__device__ __align__(16) __nv_bfloat16 g_wflo[7*25*32*16];
// f as bf16 hi/lo [b][p][32]
__device__ __align__(16) __nv_bfloat16 g_fhi[(size_t)Bg*HW*32];
__device__ __align__(16) __nv_bfloat16 g_flo[(size_t)Bg*HW*32];
// flows weights [chunk2][tap25][oc32][16] (oc>=10 zero)
__device__ __align__(16) __nv_bfloat16 g_w2hi[2*25*32*16];
__device__ __align__(16) __nv_bfloat16 g_w2lo[2*25*32*16];
// i2h weights [ocg3][tap9][oc96][8] hi/lo
__device__ __align__(16) __nv_bfloat16 g_w3hi[3*9*96*8];
__device__ __align__(16) __nv_bfloat16 g_w3lo[3*9*96*8];

__device__ __forceinline__ float leaky(float v){ return v > 0.f ? v : 0.2f*v; }
__device__ __forceinline__ float sigm(float v){ return 1.f/(1.f + expf(-v)); }

__device__ __forceinline__ uint32_t smem_u32(const void* p){
    uint32_t a;
    asm("{ .reg .u64 t; cvta.to.shared.u64 t, %1; cvt.u32.u64 %0, t; }" : "=r"(a) : "l"(p));
    return a;
}
__device__ __forceinline__ void ldm_x4(uint32_t* r, uint32_t addr){
    asm volatile("ldmatrix.sync.aligned.m8n8.x4.shared.b16 {%0,%1,%2,%3}, [%4];"
        : "=r"(r[0]), "=r"(r[1]), "=r"(r[2]), "=r"(r[3]) : "r"(addr));
}
__device__ __forceinline__ void ldm_x2(uint32_t* r, uint32_t addr){
    asm volatile("ldmatrix.sync.aligned.m8n8.x2.shared.b16 {%0,%1}, [%2];"
        : "=r"(r[0]), "=r"(r[1]) : "r"(addr));
}
#define MMA_BF16(c, a, b) \
    asm volatile("mma.sync.aligned.m16n8k16.row.col.f32.bf16.bf16.f32 " \
        "{%0,%1,%2,%3}, {%4,%5,%6,%7}, {%8,%9}, {%0,%1,%2,%3};" \
        : "+f"((c)[0]), "+f"((c)[1]), "+f"((c)[2]), "+f"((c)[3]) \
        : "r"((a)[0]), "r"((a)[1]), "r"((a)[2]), "r"((a)[3]), \
          "r"((b)[0]), "r"((b)[1]))
#define MMA_BF16_K8(c, a, b) \
    asm volatile("mma.sync.aligned.m16n8k8.row.col.f32.bf16.bf16.f32 " \
        "{%0,%1,%2,%3}, {%4,%5}, {%6}, {%0,%1,%2,%3};" \
        : "+f"((c)[0]), "+f"((c)[1]), "+f"((c)[2]), "+f"((c)[3]) \
        : "r"((a)[0]), "r"((a)[1]), "r"(b))
#define CPA16(sm, gp) asm volatile("cp.async.ca.shared.global [%0], [%1], 16;" :: "r"(sm), "l"(gp))
#define CPA_COMMIT()  asm volatile("cp.async.commit_group;" ::: "memory")

__device__ __forceinline__ void split2(float v0, float v1, uint32_t& hw, uint32_t& lw){
    __nv_bfloat16 h0 = __float2bfloat16(v0), h1 = __float2bfloat16(v1);
    __nv_bfloat16 l0 = __float2bfloat16(v0 - __bfloat162float(h0));
    __nv_bfloat16 l1 = __float2bfloat16(v1 - __bfloat162float(h1));
    __nv_bfloat162 hp; hp.x = h0; hp.y = h1;
    __nv_bfloat162 lp; lp.x = l0; lp.y = l1;
    hw = *reinterpret_cast<uint32_t*>(&hp);
    lw = *reinterpret_cast<uint32_t*>(&lp);
}

// ============================================================
// k_prepX (once): pack x channels for ALL step slots, zero pad ch,
// and slot-0 h channels from h0.
// ============================================================
__global__ void k_prepX(const float* __restrict__ inputs, const float* __restrict__ h0){
    int idx = blockIdx.x*blockDim.x + threadIdx.x;
    if (idx >= Sg*Bg*HW) return;
    int p = idx % HW, b = (idx/HW) % Bg, t = idx/(HW*Bg);
    size_t base = ((size_t)(t*Bg + b)*HW + p)*CH;
    const float* xp = inputs + ((size_t)(t*Bg + b)*CIN)*HW + p;
    uint32_t hw[4], lw[4];
    #pragma unroll
    for (int q = 0; q < 4; q++)
        split2(xp[(size_t)(2*q)*HW], xp[(size_t)(2*q+1)*HW], hw[q], lw[q]);
    *reinterpret_cast<uint4*>(g_inhi + base) = *reinterpret_cast<uint4*>(hw);
    *reinterpret_cast<uint4*>(g_inlo + base) = *reinterpret_cast<uint4*>(lw);
    uint4 z = make_uint4(0,0,0,0);
    *reinterpret_cast<uint4*>(g_inhi + base + 104) = z;
    *reinterpret_cast<uint4*>(g_inlo + base + 104) = z;
    if (t == 0){
        const float* hp = h0 + (size_t)b*Fch*HW + p;
        for (int g = 0; g < 12; g++){
            #pragma unroll
            for (int q = 0; q < 4; q++)
                split2(hp[(size_t)(g*8 + 2*q)*HW], hp[(size_t)(g*8 + 2*q+1)*HW], hw[q], lw[q]);
            *reinterpret_cast<uint4*>(g_inhi + base + 8 + g*8) = *reinterpret_cast<uint4*>(hw);
            *reinterpret_cast<uint4*>(g_inlo + base + 8 + g*8) = *reinterpret_cast<uint4*>(lw);
        }
    }
}

// ============================================================
// k_prepWall (once): all three conv-weight repacks in one launch
//   range0: fconv [chunk7][tap25][oc32][16]   (89600)
//   range1: flows [chunk2][tap25][oc32][16]   (25600)
//   range2: i2h   [ocg3][tap9][oc96][8]       (20736)
// ============================================================
__global__ void k_prepWall(const float* __restrict__ w_i2f, const float* __restrict__ w_h2f,
                           const float* __restrict__ w_fl,  const float* __restrict__ w_i2h){
    int idx = blockIdx.x*blockDim.x + threadIdx.x;
    float v; __nv_bfloat16* dh; __nv_bfloat16* dl; int o;
    if (idx < 89600){
        o = idx;
        int kc = o & 15, oc = (o >> 4) & 31, tap = (o >> 9) % 25, chunk = o / 12800;
        int ch = chunk*16 + kc;
        v = 0.f;
        if (ch < 8)        v = w_i2f[(oc*8 + ch)*25 + tap];
        else if (ch < 104) v = w_h2f[((size_t)oc*Fch + (ch-8))*25 + tap];
        dh = g_wfhi; dl = g_wflo;
    } else if (idx < 89600 + 25600){
        o = idx - 89600;
        int kc = o & 15, oc = (o >> 4) & 31, tap = (o >> 9) % 25, chunk = o / 12800;
        int ch = chunk*16 + kc;
        v = (oc < 10) ? w_fl[((size_t)oc*32 + ch)*25 + tap] : 0.f;
        dh = g_w2hi; dl = g_w2lo;
    } else if (idx < 89600 + 25600 + 20736){
        o = idx - 89600 - 25600;
        int ch = o & 7, oc = (o >> 3) % 96, tap = (o/(96*8)) % 9, ocg = o/(9*96*8);
        v = w_i2h[((size_t)(ocg*96 + oc)*CIN + ch)*9 + tap];
        dh = g_w3hi; dl = g_w3lo;
    } else return;
    __nv_bfloat16 hi = __float2bfloat16(v);
    dh[o] = hi;
    dl[o] = __float2bfloat16(v - __bfloat162float(hi));
}

// ============================================================
// i2h as implicit GEMM (m16n8k8, bf16 hi/lo 3-term), runs once
// ============================================================
__global__ void __launch_bounds__(256, 2) k_i2hT(const float* __restrict__ bias){
    __shared__ __nv_bfloat16 sInH[400*8], sInL[400*8];
    __shared__ __nv_bfloat16 sWH[9*96*8], sWL[9*96*8];
    uint32_t aInH = smem_u32(sInH), aInL = smem_u32(sInL);
    uint32_t aWH  = smem_u32(sWH),  aWL  = smem_u32(sWL);

    int tid = threadIdx.x, lane = tid & 31, wid = tid >> 5;
    int wm = wid & 3, wn = wid >> 2;
    int y0 = blockIdx.x*2, img = blockIdx.y, ocg = blockIdx.z;

    for (int e = tid; e < 400; e += 256){
        int row = e/100, cc = e%100;
        int y = y0 + row - 1, x = cc - 1;
        uint4 vh = make_uint4(0,0,0,0), vl = make_uint4(0,0,0,0);
        if ((unsigned)y < 96u && (unsigned)x < 96u){
            size_t off = ((size_t)img*HW + y*Ww + x)*CH;
            vh = *reinterpret_cast<const uint4*>(g_inhi + off);
            vl = *reinterpret_cast<const uint4*>(g_inlo + off);
        }
        *reinterpret_cast<uint4*>(sInH + e*8) = vh;
        *reinterpret_cast<uint4*>(sInL + e*8) = vl;
    }
    for (int e = tid; e < 864; e += 256){
        reinterpret_cast<uint4*>(sWH)[e] = reinterpret_cast<const uint4*>(g_w3hi + (size_t)ocg*9*96*8)[e];
        reinterpret_cast<uint4*>(sWL)[e] = reinterpret_cast<const uint4*>(g_w3lo + (size_t)ocg*9*96*8)[e];
    }
    __syncthreads();

    float c[3][6][4];
    #pragma unroll
    for (int i = 0; i < 3; i++)
        #pragma unroll
        for (int j = 0; j < 6; j++)
            #pragma unroll
            for (int q = 0; q < 4; q++) c[i][j][q] = 0.f;

    #pragma unroll 1
    for (int tap = 0; tap < 9; tap++){
        int dy = tap/3, dx = tap%3;
        uint32_t bh[6], bl[6];
        {
            ldm_x4(bh, aWH + 2u*(uint32_t)((tap*96 + wn*48 + lane)*8));
            ldm_x4(bl, aWL + 2u*(uint32_t)((tap*96 + wn*48 + lane)*8));
            uint32_t a2 = 2u*(uint32_t)((tap*96 + wn*48 + 32 + (lane & 15))*8);
            ldm_x2(bh + 4, aWH + a2);
            ldm_x2(bl + 4, aWL + a2);
        }
        uint32_t ah[3][2], al[3][2];
        #pragma unroll
        for (int mi = 0; mi < 3; mi++){
            int tmi = wm*3 + mi;
            int r = tmi/6, xb = (tmi%6)*16;
            uint32_t aoff = 2u*(uint32_t)(((r+dy)*100 + xb + (lane&15) + dx)*8);
            ldm_x2(ah[mi], aInH + aoff);
            ldm_x2(al[mi], aInL + aoff);
        }
        #pragma unroll
        for (int mi = 0; mi < 3; mi++){
            #pragma unroll
            for (int j = 0; j < 6; j++){
                MMA_BF16_K8(c[mi][j], ah[mi], bh[j]);
                MMA_BF16_K8(c[mi][j], ah[mi], bl[j]);
                MMA_BF16_K8(c[mi][j], al[mi], bh[j]);
            }
        }
    }

    float* Ob = g_i2h + (size_t)img*FH3*HW;
    #pragma unroll
    for (int mi = 0; mi < 3; mi++){
        int tmi = wm*3 + mi;
        int r = tmi/6, xb = (tmi%6)*16;
        int p = (y0 + r)*Ww + xb + (lane>>2);
        #pragma unroll
        for (int j = 0; j < 6; j++){
            int oc = ocg*96 + wn*48 + j*8 + (lane&3)*2;
            float bv0 = bias[oc], bv1 = bias[oc+1];
            Ob[(size_t)oc*HW + p]           = c[mi][j][0] + bv0;
            Ob[(size_t)(oc+1)*HW + p]       = c[mi][j][1] + bv1;
            Ob[(size_t)oc*HW + p + 8]       = c[mi][j][2] + bv0;
            Ob[(size_t)(oc+1)*HW + p + 8]   = c[mi][j][3] + bv1;
        }
    }
}

// ============================================================
// fconv implicit GEMM
// ============================================================
#define FSM_ELEMS 54400
#define FSM_BYTES (FSM_ELEMS*2)

__global__ void __launch_bounds__(256, 2) k_fconv(int t,
                                                  const float* __restrict__ b_i2f,
                                                  const float* __restrict__ b_h2f){
    extern __shared__ __nv_bfloat16 sm[];
    __nv_bfloat16* sInH = sm;
    __nv_bfloat16* sInL = sm + 14400;
    __nv_bfloat16* sWH  = sm + 28800;
    __nv_bfloat16* sWL  = sm + 41600;
    uint32_t aInH = smem_u32(sInH), aInL = smem_u32(sInL);
    uint32_t aWH  = smem_u32(sWH),  aWL  = smem_u32(sWL);

    int tid = threadIdx.x, lane = tid & 31, wid = tid >> 5;
    int wm = wid & 3, wn = wid >> 2;
    int y0 = blockIdx.x*2, b = blockIdx.y;
    size_t slot = (size_t)(t*Bg + b)*HW;

    float c[3][2][4];
    #pragma unroll
    for (int i = 0; i < 3; i++)
        #pragma unroll
        for (int j = 0; j < 2; j++)
            #pragma unroll
            for (int q = 0; q < 4; q++) c[i][j][q] = 0.f;

    for (int chunk = 0; chunk < 7; chunk++){
        __syncthreads();
        for (int e = tid; e < 1200; e += 256){
            int ent = e >> 1, half = e & 1;
            int row = ent/100, cc = ent%100;
            int y = y0 + row - 2, x = cc - 2;
            uint4 vh = make_uint4(0,0,0,0), vl = make_uint4(0,0,0,0);
            if ((unsigned)y < 96u && (unsigned)x < 96u){
                size_t off = (slot + y*Ww + x)*CH + chunk*16 + half*8;
                vh = *reinterpret_cast<const uint4*>(g_inhi + off);
                vl = *reinterpret_cast<const uint4*>(g_inlo + off);
            }
            int so = ent*24 + half*8;
            *reinterpret_cast<uint4*>(sInH + so) = vh;
            *reinterpret_cast<uint4*>(sInL + so) = vl;
        }
        for (int e = tid; e < 1600; e += 256){
            reinterpret_cast<uint4*>(sWH)[e] = reinterpret_cast<const uint4*>(g_wfhi + chunk*12800)[e];
            reinterpret_cast<uint4*>(sWL)[e] = reinterpret_cast<const uint4*>(g_wflo + chunk*12800)[e];
        }
        __syncthreads();

        #pragma unroll 1
        for (int tap = 0; tap < 25; tap++){
            int dy = tap/5, dx = tap%5;
            uint32_t bh[4], bl[4];
            uint32_t boff = 2u*(uint32_t)((tap*32 + wn*16 + (lane&7) + ((lane>>4)&1)*8)*16
                                          + ((lane>>3)&1)*8);
            ldm_x4(bh, aWH + boff);
            ldm_x4(bl, aWL + boff);
            uint32_t ah[3][4], al[3][4];
            #pragma unroll
            for (int mi = 0; mi < 3; mi++){
                int tmi = wm*3 + mi;
                int r = tmi/6, xb = (tmi%6)*16;
                uint32_t aoff = 2u*(uint32_t)(((r+dy)*100 + xb + (lane&15) + dx)*24
                                              + (lane>>4)*8);
                ldm_x4(ah[mi], aInH + aoff);
                ldm_x4(al[mi], aInL + aoff);
            }
            #pragma unroll
            for (int mi = 0; mi < 3; mi++){
                #pragma unroll
                for (int j = 0; j < 2; j++){
                    MMA_BF16(c[mi][j], ah[mi], &bh[j*2]);
                    MMA_BF16(c[mi][j], ah[mi], &bl[j*2]);
                    MMA_BF16(c[mi][j], al[mi], &bh[j*2]);
                }
            }
        }
    }

    #pragma unroll
    for (int mi = 0; mi < 3; mi++){
        int tmi = wm*3 + mi;
        int r = tmi/6, xb = (tmi%6)*16;
        int gp = (y0 + r)*Ww + xb + (lane>>2);
        #pragma unroll
        for (int j = 0; j < 2; j++){
            int oc = wn*16 + j*8 + (lane&3)*2;
            float bb0 = b_i2f[oc]   + b_h2f[oc];
            float bb1 = b_i2f[oc+1] + b_h2f[oc+1];
            uint32_t hw, lw;
            split2(leaky(c[mi][j][0] + bb0), leaky(c[mi][j][1] + bb1), hw, lw);
            size_t o0 = ((size_t)b*HW + gp)*32 + oc;
            *reinterpret_cast<uint32_t*>(g_fhi + o0) = hw;
            *reinterpret_cast<uint32_t*>(g_flo + o0) = lw;
            split2(leaky(c[mi][j][2] + bb0), leaky(c[mi][j][3] + bb1), hw, lw);
            size_t o1 = ((size_t)b*HW + gp + 8)*32 + oc;
            *reinterpret_cast<uint32_t*>(g_fhi + o1) = hw;
            *reinterpret_cast<uint32_t*>(g_flo + o1) = lw;
        }
    }
}

// ============================================================
// flows implicit GEMM (2 chunks, oc padded to 32)
// ============================================================
__global__ void __launch_bounds__(256, 2) k_flowsT(const float* __restrict__ b_fl){
    extern __shared__ __nv_bfloat16 sm[];
    __nv_bfloat16* sInH = sm;
    __nv_bfloat16* sInL = sm + 14400;
    __nv_bfloat16* sWH  = sm + 28800;
    __nv_bfloat16* sWL  = sm + 41600;
    uint32_t aInH = smem_u32(sInH), aInL = smem_u32(sInL);
    uint32_t aWH  = smem_u32(sWH),  aWL  = smem_u32(sWL);

    int tid = threadIdx.x, lane = tid & 31, wid = tid >> 5;
    int wm = wid & 3, wn = wid >> 2;
    int y0 = blockIdx.x*2, b = blockIdx.y;

    float c[3][2][4];
    #pragma unroll
    for (int i = 0; i < 3; i++)
        #pragma unroll
        for (int j = 0; j < 2; j++)
            #pragma unroll
            for (int q = 0; q < 4; q++) c[i][j][q] = 0.f;

    for (int chunk = 0; chunk < 2; chunk++){
        __syncthreads();
        for (int e = tid; e < 1200; e += 256){
            int ent = e >> 1, half = e & 1;
            int row = ent/100, cc = ent%100;
            int y = y0 + row - 2, x = cc - 2;
            uint4 vh = make_uint4(0,0,0,0), vl = make_uint4(0,0,0,0);
            if ((unsigned)y < 96u && (unsigned)x < 96u){
                size_t off = ((size_t)b*HW + y*Ww + x)*32 + chunk*16 + half*8;
                vh = *reinterpret_cast<const uint4*>(g_fhi + off);
                vl = *reinterpret_cast<const uint4*>(g_flo + off);
            }
            int so = ent*24 + half*8;
            *reinterpret_cast<uint4*>(sInH + so) = vh;
            *reinterpret_cast<uint4*>(sInL + so) = vl;
        }
        for (int e = tid; e < 1600; e += 256){
            reinterpret_cast<uint4*>(sWH)[e] = reinterpret_cast<const uint4*>(g_w2hi + chunk*12800)[e];
            reinterpret_cast<uint4*>(sWL)[e] = reinterpret_cast<const uint4*>(g_w2lo + chunk*12800)[e];
        }
        __syncthreads();

        #pragma unroll 1
        for (int tap = 0; tap < 25; tap++){
            int dy = tap/5, dx = tap%5;
            uint32_t bh[4], bl[4];
            uint32_t boff = 2u*(uint32_t)((tap*32 + wn*16 + (lane&7) + ((lane>>4)&1)*8)*16
                                          + ((lane>>3)&1)*8);
            ldm_x4(bh, aWH + boff);
            ldm_x4(bl, aWL + boff);
            uint32_t ah[3][4], al[3][4];
            #pragma unroll
            for (int mi = 0; mi < 3; mi++){
                int tmi = wm*3 + mi;
                int r = tmi/6, xb = (tmi%6)*16;
                uint32_t aoff = 2u*(uint32_t)(((r+dy)*100 + xb + (lane&15) + dx)*24
                                              + (lane>>4)*8);
                ldm_x4(ah[mi], aInH + aoff);
                ldm_x4(al[mi], aInL + aoff);
            }
            #pragma unroll
            for (int mi = 0; mi < 3; mi++){
                #pragma unroll
                for (int j = 0; j < 2; j++){
                    MMA_BF16(c[mi][j], ah[mi], &bh[j*2]);
                    MMA_BF16(c[mi][j], ah[mi], &bl[j*2]);
                    MMA_BF16(c[mi][j], al[mi], &bh[j*2]);
                }
            }
        }
    }

    #pragma unroll
    for (int mi = 0; mi < 3; mi++){
        int tmi = wm*3 + mi;
        int r = tmi/6, xb = (tmi%6)*16;
        int gp = (y0 + r)*Ww + xb + (lane>>2);
        #pragma unroll
        for (int j = 0; j < 2; j++){
            int oc = wn*16 + j*8 + (lane&3)*2;
            if (oc < 10){
                float bv0 = b_fl[oc], bv1 = b_fl[oc+1];
                float* f0 = g_flows + ((size_t)b*10 + oc)*HW;
                float* f1 = g_flows + ((size_t)b*10 + oc + 1)*HW;
                f0[gp]     = c[mi][j][0] + bv0;
                f1[gp]     = c[mi][j][1] + bv1;
                f0[gp + 8] = c[mi][j][2] + bv0;
                f1[gp + 8] = c[mi][j][3] + bv1;
            }
        }
    }
}

// ============================================================
// warp: bilinear-warp h, emit transposed bf16 hi/lo [b][p][k]
// ============================================================
__global__ void k_warp(const float* __restrict__ h){
    int bl = blockIdx.x, y = blockIdx.y, tx = threadIdx.x;
    int b = bl / Lk, l = bl % Lk;
    const float* fl = g_flows + (size_t)b*10*HW + y*Ww + tx;
    float fx = fl[(size_t)(2*l)*HW];
    float fy = fl[(size_t)(2*l+1)*HW];
    float vx = (float)tx - fx;
    float vy = (float)y  - fy;
    const float sc = 96.0f/95.0f;
    float ix = vx*sc - 0.5f;
    float iy = vy*sc - 0.5f;
    float fx0 = floorf(ix), fy0 = floorf(iy);
    int ix0 = (int)fx0, iy0 = (int)fy0;
    int ix1 = ix0 + 1, iy1 = iy0 + 1;
    float wx1 = ix - fx0, wy1 = iy - fy0;
    float wx0 = 1.f - wx1, wy0 = 1.f - wy1;
    float mx0 = (ix0 >= 0 && ix0 < Ww) ? 1.f : 0.f;
    float mx1 = (ix1 >= 0 && ix1 < Ww) ? 1.f : 0.f;
    float my0 = (iy0 >= 0 && iy0 < Hh) ? 1.f : 0.f;
    float my1 = (iy1 >= 0 && iy1 < Hh) ? 1.f : 0.f;
    int cx0 = min(max(ix0, 0), Ww-1), cx1 = min(max(ix1, 0), Ww-1);
    int cy0 = min(max(iy0, 0), Hh-1), cy1 = min(max(iy1, 0), Hh-1);
    int o00 = cy0*Ww + cx0, o01 = cy0*Ww + cx1;
    int o10 = cy1*Ww + cx0, o11 = cy1*Ww + cx1;
    float w00 = wy0*wx0*my0*mx0, w01 = wy0*wx1*my0*mx1;
    float w10 = wy1*wx0*my1*mx0, w11 = wy1*wx1*my1*mx1;
    const float* hb = h + (size_t)b*Fch*HW;
    int p = y*Ww + tx;
    size_t obase = ((size_t)b*HW + p)*KPAD + l*Fch;

    #pragma unroll 1
    for (int c0 = 0; c0 < Fch; c0 += 8){
        uint32_t hibuf[4], lobuf[4];
        #pragma unroll
        for (int j = 0; j < 4; j++){
            const float* p0 = hb + (size_t)(c0 + 2*j)*HW;
            const float* p1 = p0 + HW;
            float v0 = w00*p0[o00] + w01*p0[o01] + w10*p0[o10] + w11*p0[o11];
            float v1 = w00*p1[o00] + w01*p1[o01] + w10*p1[o10] + w11*p1[o11];
            split2(v0, v1, hibuf[j], lobuf[j]);
        }
        *reinterpret_cast<uint4*>(g_whi + obase + c0) = *reinterpret_cast<uint4*>(hibuf);
        *reinterpret_cast<uint4*>(g_wlo + obase + c0) = *reinterpret_cast<uint4*>(lobuf);
    }
}

// ============================================================
// prep: split w_ret (288 x 480, stride KPAD)
// ============================================================
__global__ void k_prepA(const float* __restrict__ w_ret){
    int idx = blockIdx.x*blockDim.x + threadIdx.x;
    if (idx >= FH3*KPAD) return;
    int m = idx / KPAD, k = idx % KPAD;
    float v = (k < K1) ? w_ret[m*K1 + k] : 0.f;
    __nv_bfloat16 hi = __float2bfloat16(v);
    __nv_bfloat16 lo = __float2bfloat16(v - __bfloat162float(hi));
    g_Ahi[idx] = hi; g_Alo[idx] = lo;
}

// ============================================================
// h2h GEMM: BM=96 (no M pad), 15 chunks (no K pad), cp.async
// double-buffered. 8 warps (2M x 4N), warp 48x32. grid (72,3,B)
// ============================================================
#define TS 40
#define ABUF (96*TS)
#define BBUF (128*TS)

__global__ void __launch_bounds__(256, 2) k_h2h(const float* __restrict__ bias){
    __shared__ __nv_bfloat16 sAh[2*ABUF], sAl[2*ABUF], sBh[2*BBUF], sBl[2*BBUF];
    int tid = threadIdx.x, lane = tid & 31, wid = tid >> 5;
    int wm = wid & 1, wn = wid >> 1;
    int n0 = blockIdx.x*128, m0 = blockIdx.y*96, bz = blockIdx.z;

    const __nv_bfloat16* Ah = g_Ahi + (size_t)m0*KPAD;
    const __nv_bfloat16* Al = g_Alo + (size_t)m0*KPAD;
    const __nv_bfloat16* Bh = g_whi + ((size_t)bz*HW + n0)*KPAD;
    const __nv_bfloat16* Bl = g_wlo + ((size_t)bz*HW + n0)*KPAD;

    uint32_t aSh = smem_u32(sAh), aSl = smem_u32(sAl);
    uint32_t aBh = smem_u32(sBh), aBl = smem_u32(sBl);

    int arow = wm*48 + (lane & 15);
    int acol = (lane >> 4) * 8;
    int brow = wn*32 + (lane & 7) + ((lane >> 4) & 1)*8;
    int bcol = ((lane >> 3) & 1) * 8;

    float c[3][4][4];
    #pragma unroll
    for (int i = 0; i < 3; i++)
        #pragma unroll
        for (int j = 0; j < 4; j++)
            #pragma unroll
            for (int q = 0; q < 4; q++) c[i][j][q] = 0.f;

    #define H2H_STAGE(chunk, buf) do { \
        uint32_t sbA = (uint32_t)(buf)*(ABUF*2); \
        uint32_t sbB = (uint32_t)(buf)*(BBUF*2); \
        for (int e = tid; e < 384; e += 256){ \
            int r = e >> 2, u = e & 3; \
            size_t goff = (size_t)r*KPAD + (chunk)*32 + u*8; \
            uint32_t soff = sbA + (uint32_t)(r*TS + u*8)*2u; \
            CPA16(aSh + soff, Ah + goff); \
            CPA16(aSl + soff, Al + goff); \
        } \
        for (int e = tid; e < 512; e += 256){ \
            int r = e >> 2, u = e & 3; \
            size_t goff = (size_t)r*KPAD + (chunk)*32 + u*8; \
            uint32_t soff = sbB + (uint32_t)(r*TS + u*8)*2u; \
            CPA16(aBh + soff, Bh + goff); \
            CPA16(aBl + soff, Bl + goff); \
        } \
        CPA_COMMIT(); \
    } while(0)

    H2H_STAGE(0, 0);
    for (int chunk = 0; chunk < 15; chunk++){
        if (chunk + 1 < 15){
            H2H_STAGE(chunk + 1, (chunk + 1) & 1);
            asm volatile("cp.async.wait_group 1;" ::: "memory");
        } else {
            asm volatile("cp.async.wait_group 0;" ::: "memory");
        }
        __syncthreads();

        uint32_t sbA = (uint32_t)(chunk & 1)*(ABUF*2);
        uint32_t sbB = (uint32_t)(chunk & 1)*(BBUF*2);
        #pragma unroll
        for (int ks = 0; ks < 2; ks++){
            int kc = ks*16;
            uint32_t ah[3][4], al[3][4], bh[2][4], bl[2][4];
            #pragma unroll
            for (int mi = 0; mi < 3; mi++){
                uint32_t off = sbA + 2u*((arow + mi*16)*TS + kc + acol);
                ldm_x4(ah[mi], aSh + off);
                ldm_x4(al[mi], aSl + off);
            }
            #pragma unroll
            for (int jp = 0; jp < 2; jp++){
                uint32_t off = sbB + 2u*((brow + jp*16)*TS + kc + bcol);
                ldm_x4(bh[jp], aBh + off);
                ldm_x4(bl[jp], aBl + off);
            }
            #pragma unroll
            for (int mi = 0; mi < 3; mi++){
                #pragma unroll
                for (int j = 0; j < 4; j++){
                    uint32_t* fh = &bh[j >> 1][(j & 1)*2];
                    uint32_t* fl2 = &bl[j >> 1][(j & 1)*2];
                    MMA_BF16(c[mi][j], ah[mi], fh);
                    MMA_BF16(c[mi][j], ah[mi], fl2);
                    MMA_BF16(c[mi][j], al[mi], fh);
                }
            }
        }
        __syncthreads();
    }

    float* Cb = g_h2h + (size_t)bz*FH3*HW;
    int mbase = m0 + wm*48 + (lane >> 2);
    int nbase = n0 + wn*32 + (lane & 3)*2;
    #pragma unroll
    for (int mi = 0; mi < 3; mi++){
        int r0 = mbase + mi*16;
        float bv0 = bias[r0], bv1 = bias[r0 + 8];
        #pragma unroll
        for (int j = 0; j < 4; j++){
            int col = nbase + j*8;
            float2 v0; v0.x = c[mi][j][0] + bv0; v0.y = c[mi][j][1] + bv0;
            *reinterpret_cast<float2*>(Cb + (size_t)r0*HW + col) = v0;
            float2 v1; v1.x = c[mi][j][2] + bv1; v1.y = c[mi][j][3] + bv1;
            *reinterpret_cast<float2*>(Cb + (size_t)(r0+8)*HW + col) = v1;
        }
    }
}

// ============================================================
// gates: GRU update -> next_h, fused packing into next input slot
// ============================================================
__global__ void k_gates(int t, const float* __restrict__ hprev,
                        float* __restrict__ hnext, int pack){
    int idx = blockIdx.x * blockDim.x + threadIdx.x;
    if (idx >= Bg*12*HW) return;
    int p = idx % HW, fcg = (idx/HW) % 12, b = idx/(HW*12);
    const float* i2h = g_i2h + (size_t)(t*Bg + b)*FH3*HW + p;
    const float* h2h = g_h2h + (size_t)b*FH3*HW + p;
    const float* hp_ = hprev + (size_t)b*Fch*HW + p;
    float* hn_ = hnext + (size_t)b*Fch*HW + p;
    uint32_t hw[4], lw[4];
    #pragma unroll
    for (int q = 0; q < 4; q++){
        float nv[2];
        #pragma unroll
        for (int s = 0; s < 2; s++){
            int fc = fcg*8 + 2*q + s;
            float ir = i2h[(size_t)fc*HW];
            float iu = i2h[(size_t)(Fch + fc)*HW];
            float im = i2h[(size_t)(2*Fch + fc)*HW];
            float hr = h2h[(size_t)fc*HW];
            float hu = h2h[(size_t)(Fch + fc)*HW];
            float hm = h2h[(size_t)(2*Fch + fc)*HW];
            float hp = hp_[(size_t)fc*HW];
            float reset  = sigm(ir + hr);
            float update = sigm(iu + hu);
            float newmem = leaky(im + reset*hm);
            nv[s] = update*hp + (1.f - update)*newmem;
            hn_[(size_t)fc*HW] = nv[s];
        }
        split2(nv[0], nv[1], hw[q], lw[q]);
    }
    if (pack){
        size_t off = ((size_t)((t+1)*Bg + b)*HW + p)*CH + 8 + fcg*8;
        *reinterpret_cast<uint4*>(g_inhi + off) = *reinterpret_cast<uint4*>(hw);
        *reinterpret_cast<uint4*>(g_inlo + off) = *reinterpret_cast<uint4*>(lw);
    }
}

// ============================================================
extern "C" void kernel_launch(void* const* d_in, const int* in_sizes, int n_in,
                              void* d_out, int out_size){
    const float* inputs = (const float*)d_in[0];
    const float* h0     = (const float*)d_in[1];
    const float* w_i2h  = (const float*)d_in[2];
    const float* b_i2h  = (const float*)d_in[3];
    const float* w_i2f  = (const float*)d_in[4];
    const float* b_i2f  = (const float*)d_in[5];
    const float* w_h2f  = (const float*)d_in[6];
    const float* b_h2f  = (const float*)d_in[7];
    const float* w_fl   = (const float*)d_in[8];
    const float* b_fl   = (const float*)d_in[9];
    const float* w_ret  = (const float*)d_in[10];
    const float* b_ret  = (const float*)d_in[11];
    float* out = (float*)d_out;

    cudaFuncSetAttribute(k_fconv,  cudaFuncAttributeMaxDynamicSharedMemorySize, FSM_BYTES);
    cudaFuncSetAttribute(k_flowsT, cudaFuncAttributeMaxDynamicSharedMemorySize, FSM_BYTES);

    // once per launch
    k_prepX   <<<(Sg*Bg*HW + 255)/256, 256>>>(inputs, h0);
    k_prepWall<<<(89600 + 25600 + 20736 + 255)/256, 256>>>(w_i2f, w_h2f, w_fl, w_i2h);
    k_prepA   <<<(FH3*KPAD + 255)/256, 256>>>(w_ret);
    k_i2hT    <<<dim3(48, Sg*Bg, 3), 256>>>(b_i2h);

    for (int t = 0; t < Sg; t++){
        const float* h = (t == 0) ? h0 : out + (size_t)(t-1)*STEP_ELEMS;
        float* hn = out + (size_t)t*STEP_ELEMS;

        k_fconv <<<dim3(48, Bg), 256, FSM_BYTES>>>(t, b_i2f, b_h2f);
        k_flowsT<<<dim3(48, Bg), 256, FSM_BYTES>>>(b_fl);
        k_warp  <<<dim3(Bg*Lk, Hh), 96>>>(h);
        k_h2h   <<<dim3(HW/128, 3, Bg), 256>>>(b_ret);
        k_gates <<<(Bg*12*HW + 255)/256, 256>>>(t, h, hn, (t < Sg-1) ? 1 : 0);
    }

    const size_t OUT_SEQ = (size_t)Sg*STEP_ELEMS;
    if ((size_t)out_size >= OUT_SEQ + STEP_ELEMS){
        cudaMemcpyAsync(out + OUT_SEQ, out + (size_t)(Sg-1)*STEP_ELEMS,
                        (size_t)STEP_ELEMS*sizeof(float),
                        cudaMemcpyDeviceToDevice);
    }
}

// round 8
// speedup vs baseline: 3.7112x; 1.0290x over previous
#include <cuda_runtime.h>
#include <cuda_bf16.h>
#include <cstdint>
#include <math.h>

#define Hh 96
#define Ww 96
#define HW 9216
#define Fch 96
#define CIN 8
#define Lk 5
#define Sg 10
#define Bg 4
#define FH3 288          // 3*F
#define K1 480           // L*F
#define KPAD 512         // row STRIDE of k-major operands (pad cols never read)
#define CH 112           // packed input channels: 8 x | 96 h | 8 zero
#define STEP_ELEMS (Bg*Fch*HW)   // 3,538,944

// ---- scratch (device globals) ----
__device__ float g_i2h[(size_t)Sg*Bg*FH3*HW];                 // 425 MB (once)
__device__ float g_flows[Bg*10*HW];
__device__ __align__(16) __nv_bfloat16 g_whi[(size_t)Bg*HW*KPAD];  // warped^T hi [b][p][k]
__device__ __align__(16) __nv_bfloat16 g_wlo[(size_t)Bg*HW*KPAD];
__device__ __align__(16) __nv_bfloat16 g_Ahi[(size_t)FH3*KPAD];    // w_ret hi [m][k]
__device__ __align__(16) __nv_bfloat16 g_Alo[(size_t)FH3*KPAD];
// fconv inputs: per-step slots [Sg][Bg][p][112]
__device__ __align__(16) __nv_bfloat16 g_inhi[(size_t)Sg*Bg*HW*CH];
__device__ __align__(16) __nv_bfloat16 g_inlo[(size_t)Sg*Bg*HW*CH];
__device__ __align__(16) __nv_bfloat16 g_wfhi[7*25*32*16];         // [chunk][tap][oc][16]
__device__ __align__(16) __nv_bfloat16 g_wflo[7*25*32*16];
// f as bf16 hi/lo [b][p][32]
__device__ __align__(16) __nv_bfloat16 g_fhi[(size_t)Bg*HW*32];
__device__ __align__(16) __nv_bfloat16 g_flo[(size_t)Bg*HW*32];
// flows weights [chunk2][tap25][oc32][16] (oc>=10 zero)
__device__ __align__(16) __nv_bfloat16 g_w2hi[2*25*32*16];
__device__ __align__(16) __nv_bfloat16 g_w2lo[2*25*32*16];
// i2h weights [ocg3][tap9][oc96][8] hi/lo
__device__ __align__(16) __nv_bfloat16 g_w3hi[3*9*96*8];
__device__ __align__(16) __nv_bfloat16 g_w3lo[3*9*96*8];

__device__ __forceinline__ float leaky(float v){ return v > 0.f ? v : 0.2f*v; }
__device__ __forceinline__ float sigm(float v){ return 1.f/(1.f + expf(-v)); }

__device__ __forceinline__ uint32_t smem_u32(const void* p){
    uint32_t a;
    asm("{ .reg .u64 t; cvta.to.shared.u64 t, %1; cvt.u32.u64 %0, t; }" : "=r"(a) : "l"(p));
    return a;
}
__device__ __forceinline__ void ldm_x4(uint32_t* r, uint32_t addr){
    asm volatile("ldmatrix.sync.aligned.m8n8.x4.shared.b16 {%0,%1,%2,%3}, [%4];"
        : "=r"(r[0]), "=r"(r[1]), "=r"(r[2]), "=r"(r[3]) : "r"(addr));
}
__device__ __forceinline__ void ldm_x2(uint32_t* r, uint32_t addr){
    asm volatile("ldmatrix.sync.aligned.m8n8.x2.shared.b16 {%0,%1}, [%2];"
        : "=r"(r[0]), "=r"(r[1]) : "r"(addr));
}
#define MMA_BF16(c, a, b) \
    asm volatile("mma.sync.aligned.m16n8k16.row.col.f32.bf16.bf16.f32 " \
        "{%0,%1,%2,%3}, {%4,%5,%6,%7}, {%8,%9}, {%0,%1,%2,%3};" \
        : "+f"((c)[0]), "+f"((c)[1]), "+f"((c)[2]), "+f"((c)[3]) \
        : "r"((a)[0]), "r"((a)[1]), "r"((a)[2]), "r"((a)[3]), \
          "r"((b)[0]), "r"((b)[1]))
#define MMA_BF16_K8(c, a, b) \
    asm volatile("mma.sync.aligned.m16n8k8.row.col.f32.bf16.bf16.f32 " \
        "{%0,%1,%2,%3}, {%4,%5}, {%6}, {%0,%1,%2,%3};" \
        : "+f"((c)[0]), "+f"((c)[1]), "+f"((c)[2]), "+f"((c)[3]) \
        : "r"((a)[0]), "r"((a)[1]), "r"(b))
#define CPA16(sm, gp) asm volatile("cp.async.ca.shared.global [%0], [%1], 16;" :: "r"(sm), "l"(gp))
#define CPA_COMMIT()  asm volatile("cp.async.commit_group;" ::: "memory")

__device__ __forceinline__ void split2(float v0, float v1, uint32_t& hw, uint32_t& lw){
    __nv_bfloat16 h0 = __float2bfloat16(v0), h1 = __float2bfloat16(v1);
    __nv_bfloat16 l0 = __float2bfloat16(v0 - __bfloat162float(h0));
    __nv_bfloat16 l1 = __float2bfloat16(v1 - __bfloat162float(h1));
    __nv_bfloat162 hp; hp.x = h0; hp.y = h1;
    __nv_bfloat162 lp; lp.x = l0; lp.y = l1;
    hw = *reinterpret_cast<uint32_t*>(&hp);
    lw = *reinterpret_cast<uint32_t*>(&lp);
}

// ============================================================
// k_prepX (once): pack x channels for ALL step slots, zero pad ch,
// and slot-0 h channels from h0.
// ============================================================
__global__ void k_prepX(const float* __restrict__ inputs, const float* __restrict__ h0){
    int idx = blockIdx.x*blockDim.x + threadIdx.x;
    if (idx >= Sg*Bg*HW) return;
    int p = idx % HW, b = (idx/HW) % Bg, t = idx/(HW*Bg);
    size_t base = ((size_t)(t*Bg + b)*HW + p)*CH;
    const float* xp = inputs + ((size_t)(t*Bg + b)*CIN)*HW + p;
    uint32_t hw[4], lw[4];
    #pragma unroll
    for (int q = 0; q < 4; q++)
        split2(xp[(size_t)(2*q)*HW], xp[(size_t)(2*q+1)*HW], hw[q], lw[q]);
    *reinterpret_cast<uint4*>(g_inhi + base) = *reinterpret_cast<uint4*>(hw);
    *reinterpret_cast<uint4*>(g_inlo + base) = *reinterpret_cast<uint4*>(lw);
    uint4 z = make_uint4(0,0,0,0);
    *reinterpret_cast<uint4*>(g_inhi + base + 104) = z;
    *reinterpret_cast<uint4*>(g_inlo + base + 104) = z;
    if (t == 0){
        const float* hp = h0 + (size_t)b*Fch*HW + p;
        for (int g = 0; g < 12; g++){
            #pragma unroll
            for (int q = 0; q < 4; q++)
                split2(hp[(size_t)(g*8 + 2*q)*HW], hp[(size_t)(g*8 + 2*q+1)*HW], hw[q], lw[q]);
            *reinterpret_cast<uint4*>(g_inhi + base + 8 + g*8) = *reinterpret_cast<uint4*>(hw);
            *reinterpret_cast<uint4*>(g_inlo + base + 8 + g*8) = *reinterpret_cast<uint4*>(lw);
        }
    }
}

// ============================================================
// k_prepWall (once): all three conv-weight repacks in one launch
// ============================================================
__global__ void k_prepWall(const float* __restrict__ w_i2f, const float* __restrict__ w_h2f,
                           const float* __restrict__ w_fl,  const float* __restrict__ w_i2h){
    int idx = blockIdx.x*blockDim.x + threadIdx.x;
    float v; __nv_bfloat16* dh; __nv_bfloat16* dl; int o;
    if (idx < 89600){
        o = idx;
        int kc = o & 15, oc = (o >> 4) & 31, tap = (o >> 9) % 25, chunk = o / 12800;
        int ch = chunk*16 + kc;
        v = 0.f;
        if (ch < 8)        v = w_i2f[(oc*8 + ch)*25 + tap];
        else if (ch < 104) v = w_h2f[((size_t)oc*Fch + (ch-8))*25 + tap];
        dh = g_wfhi; dl = g_wflo;
    } else if (idx < 89600 + 25600){
        o = idx - 89600;
        int kc = o & 15, oc = (o >> 4) & 31, tap = (o >> 9) % 25, chunk = o / 12800;
        int ch = chunk*16 + kc;
        v = (oc < 10) ? w_fl[((size_t)oc*32 + ch)*25 + tap] : 0.f;
        dh = g_w2hi; dl = g_w2lo;
    } else if (idx < 89600 + 25600 + 20736){
        o = idx - 89600 - 25600;
        int ch = o & 7, oc = (o >> 3) % 96, tap = (o/(96*8)) % 9, ocg = o/(9*96*8);
        v = w_i2h[((size_t)(ocg*96 + oc)*CIN + ch)*9 + tap];
        dh = g_w3hi; dl = g_w3lo;
    } else return;
    __nv_bfloat16 hi = __float2bfloat16(v);
    dh[o] = hi;
    dl[o] = __float2bfloat16(v - __bfloat162float(hi));
}

// ============================================================
// i2h as implicit GEMM (m16n8k8, bf16 hi/lo 3-term), runs once
// ============================================================
__global__ void __launch_bounds__(256, 2) k_i2hT(const float* __restrict__ bias){
    __shared__ __nv_bfloat16 sInH[400*8], sInL[400*8];
    __shared__ __nv_bfloat16 sWH[9*96*8], sWL[9*96*8];
    uint32_t aInH = smem_u32(sInH), aInL = smem_u32(sInL);
    uint32_t aWH  = smem_u32(sWH),  aWL  = smem_u32(sWL);

    int tid = threadIdx.x, lane = tid & 31, wid = tid >> 5;
    int wm = wid & 3, wn = wid >> 2;
    int y0 = blockIdx.x*2, img = blockIdx.y, ocg = blockIdx.z;

    for (int e = tid; e < 400; e += 256){
        int row = e/100, cc = e%100;
        int y = y0 + row - 1, x = cc - 1;
        uint4 vh = make_uint4(0,0,0,0), vl = make_uint4(0,0,0,0);
        if ((unsigned)y < 96u && (unsigned)x < 96u){
            size_t off = ((size_t)img*HW + y*Ww + x)*CH;
            vh = *reinterpret_cast<const uint4*>(g_inhi + off);
            vl = *reinterpret_cast<const uint4*>(g_inlo + off);
        }
        *reinterpret_cast<uint4*>(sInH + e*8) = vh;
        *reinterpret_cast<uint4*>(sInL + e*8) = vl;
    }
    for (int e = tid; e < 864; e += 256){
        reinterpret_cast<uint4*>(sWH)[e] = reinterpret_cast<const uint4*>(g_w3hi + (size_t)ocg*9*96*8)[e];
        reinterpret_cast<uint4*>(sWL)[e] = reinterpret_cast<const uint4*>(g_w3lo + (size_t)ocg*9*96*8)[e];
    }
    __syncthreads();

    float c[3][6][4];
    #pragma unroll
    for (int i = 0; i < 3; i++)
        #pragma unroll
        for (int j = 0; j < 6; j++)
            #pragma unroll
            for (int q = 0; q < 4; q++) c[i][j][q] = 0.f;

    #pragma unroll 1
    for (int tap = 0; tap < 9; tap++){
        int dy = tap/3, dx = tap%3;
        uint32_t bh[6], bl[6];
        {
            ldm_x4(bh, aWH + 2u*(uint32_t)((tap*96 + wn*48 + lane)*8));
            ldm_x4(bl, aWL + 2u*(uint32_t)((tap*96 + wn*48 + lane)*8));
            uint32_t a2 = 2u*(uint32_t)((tap*96 + wn*48 + 32 + (lane & 15))*8);
            ldm_x2(bh + 4, aWH + a2);
            ldm_x2(bl + 4, aWL + a2);
        }
        uint32_t ah[3][2], al[3][2];
        #pragma unroll
        for (int mi = 0; mi < 3; mi++){
            int tmi = wm*3 + mi;
            int r = tmi/6, xb = (tmi%6)*16;
            uint32_t aoff = 2u*(uint32_t)(((r+dy)*100 + xb + (lane&15) + dx)*8);
            ldm_x2(ah[mi], aInH + aoff);
            ldm_x2(al[mi], aInL + aoff);
        }
        #pragma unroll
        for (int mi = 0; mi < 3; mi++){
            #pragma unroll
            for (int j = 0; j < 6; j++){
                MMA_BF16_K8(c[mi][j], ah[mi], bh[j]);
                MMA_BF16_K8(c[mi][j], ah[mi], bl[j]);
                MMA_BF16_K8(c[mi][j], al[mi], bh[j]);
            }
        }
    }

    float* Ob = g_i2h + (size_t)img*FH3*HW;
    #pragma unroll
    for (int mi = 0; mi < 3; mi++){
        int tmi = wm*3 + mi;
        int r = tmi/6, xb = (tmi%6)*16;
        int p = (y0 + r)*Ww + xb + (lane>>2);
        #pragma unroll
        for (int j = 0; j < 6; j++){
            int oc = ocg*96 + wn*48 + j*8 + (lane&3)*2;
            float bv0 = bias[oc], bv1 = bias[oc+1];
            Ob[(size_t)oc*HW + p]           = c[mi][j][0] + bv0;
            Ob[(size_t)(oc+1)*HW + p]       = c[mi][j][1] + bv1;
            Ob[(size_t)oc*HW + p + 8]       = c[mi][j][2] + bv0;
            Ob[(size_t)(oc+1)*HW + p + 8]   = c[mi][j][3] + bv1;
        }
    }
}

// ============================================================
// fconv implicit GEMM
// ============================================================
#define FSM_ELEMS 54400
#define FSM_BYTES (FSM_ELEMS*2)

__global__ void __launch_bounds__(256, 2) k_fconv(int t,
                                                  const float* __restrict__ b_i2f,
                                                  const float* __restrict__ b_h2f){
    extern __shared__ __nv_bfloat16 sm[];
    __nv_bfloat16* sInH = sm;
    __nv_bfloat16* sInL = sm + 14400;
    __nv_bfloat16* sWH  = sm + 28800;
    __nv_bfloat16* sWL  = sm + 41600;
    uint32_t aInH = smem_u32(sInH), aInL = smem_u32(sInL);
    uint32_t aWH  = smem_u32(sWH),  aWL  = smem_u32(sWL);

    int tid = threadIdx.x, lane = tid & 31, wid = tid >> 5;
    int wm = wid & 3, wn = wid >> 2;
    int y0 = blockIdx.x*2, b = blockIdx.y;
    size_t slot = (size_t)(t*Bg + b)*HW;

    float c[3][2][4];
    #pragma unroll
    for (int i = 0; i < 3; i++)
        #pragma unroll
        for (int j = 0; j < 2; j++)
            #pragma unroll
            for (int q = 0; q < 4; q++) c[i][j][q] = 0.f;

    for (int chunk = 0; chunk < 7; chunk++){
        __syncthreads();
        for (int e = tid; e < 1200; e += 256){
            int ent = e >> 1, half = e & 1;
            int row = ent/100, cc = ent%100;
            int y = y0 + row - 2, x = cc - 2;
            uint4 vh = make_uint4(0,0,0,0), vl = make_uint4(0,0,0,0);
            if ((unsigned)y < 96u && (unsigned)x < 96u){
                size_t off = (slot + y*Ww + x)*CH + chunk*16 + half*8;
                vh = *reinterpret_cast<const uint4*>(g_inhi + off);
                vl = *reinterpret_cast<const uint4*>(g_inlo + off);
            }
            int so = ent*24 + half*8;
            *reinterpret_cast<uint4*>(sInH + so) = vh;
            *reinterpret_cast<uint4*>(sInL + so) = vl;
        }
        for (int e = tid; e < 1600; e += 256){
            reinterpret_cast<uint4*>(sWH)[e] = reinterpret_cast<const uint4*>(g_wfhi + chunk*12800)[e];
            reinterpret_cast<uint4*>(sWL)[e] = reinterpret_cast<const uint4*>(g_wflo + chunk*12800)[e];
        }
        __syncthreads();

        #pragma unroll 1
        for (int tap = 0; tap < 25; tap++){
            int dy = tap/5, dx = tap%5;
            uint32_t bh[4], bl[4];
            uint32_t boff = 2u*(uint32_t)((tap*32 + wn*16 + (lane&7) + ((lane>>4)&1)*8)*16
                                          + ((lane>>3)&1)*8);
            ldm_x4(bh, aWH + boff);
            ldm_x4(bl, aWL + boff);
            uint32_t ah[3][4], al[3][4];
            #pragma unroll
            for (int mi = 0; mi < 3; mi++){
                int tmi = wm*3 + mi;
                int r = tmi/6, xb = (tmi%6)*16;
                uint32_t aoff = 2u*(uint32_t)(((r+dy)*100 + xb + (lane&15) + dx)*24
                                              + (lane>>4)*8);
                ldm_x4(ah[mi], aInH + aoff);
                ldm_x4(al[mi], aInL + aoff);
            }
            #pragma unroll
            for (int mi = 0; mi < 3; mi++){
                #pragma unroll
                for (int j = 0; j < 2; j++){
                    MMA_BF16(c[mi][j], ah[mi], &bh[j*2]);
                    MMA_BF16(c[mi][j], ah[mi], &bl[j*2]);
                    MMA_BF16(c[mi][j], al[mi], &bh[j*2]);
                }
            }
        }
    }

    #pragma unroll
    for (int mi = 0; mi < 3; mi++){
        int tmi = wm*3 + mi;
        int r = tmi/6, xb = (tmi%6)*16;
        int gp = (y0 + r)*Ww + xb + (lane>>2);
        #pragma unroll
        for (int j = 0; j < 2; j++){
            int oc = wn*16 + j*8 + (lane&3)*2;
            float bb0 = b_i2f[oc]   + b_h2f[oc];
            float bb1 = b_i2f[oc+1] + b_h2f[oc+1];
            uint32_t hw, lw;
            split2(leaky(c[mi][j][0] + bb0), leaky(c[mi][j][1] + bb1), hw, lw);
            size_t o0 = ((size_t)b*HW + gp)*32 + oc;
            *reinterpret_cast<uint32_t*>(g_fhi + o0) = hw;
            *reinterpret_cast<uint32_t*>(g_flo + o0) = lw;
            split2(leaky(c[mi][j][2] + bb0), leaky(c[mi][j][3] + bb1), hw, lw);
            size_t o1 = ((size_t)b*HW + gp + 8)*32 + oc;
            *reinterpret_cast<uint32_t*>(g_fhi + o1) = hw;
            *reinterpret_cast<uint32_t*>(g_flo + o1) = lw;
        }
    }
}

// ============================================================
// flows implicit GEMM (2 chunks, oc padded to 32)
// ============================================================
__global__ void __launch_bounds__(256, 2) k_flowsT(const float* __restrict__ b_fl){
    extern __shared__ __nv_bfloat16 sm[];
    __nv_bfloat16* sInH = sm;
    __nv_bfloat16* sInL = sm + 14400;
    __nv_bfloat16* sWH  = sm + 28800;
    __nv_bfloat16* sWL  = sm + 41600;
    uint32_t aInH = smem_u32(sInH), aInL = smem_u32(sInL);
    uint32_t aWH  = smem_u32(sWH),  aWL  = smem_u32(sWL);

    int tid = threadIdx.x, lane = tid & 31, wid = tid >> 5;
    int wm = wid & 3, wn = wid >> 2;
    int y0 = blockIdx.x*2, b = blockIdx.y;

    float c[3][2][4];
    #pragma unroll
    for (int i = 0; i < 3; i++)
        #pragma unroll
        for (int j = 0; j < 2; j++)
            #pragma unroll
            for (int q = 0; q < 4; q++) c[i][j][q] = 0.f;

    for (int chunk = 0; chunk < 2; chunk++){
        __syncthreads();
        for (int e = tid; e < 1200; e += 256){
            int ent = e >> 1, half = e & 1;
            int row = ent/100, cc = ent%100;
            int y = y0 + row - 2, x = cc - 2;
            uint4 vh = make_uint4(0,0,0,0), vl = make_uint4(0,0,0,0);
            if ((unsigned)y < 96u && (unsigned)x < 96u){
                size_t off = ((size_t)b*HW + y*Ww + x)*32 + chunk*16 + half*8;
                vh = *reinterpret_cast<const uint4*>(g_fhi + off);
                vl = *reinterpret_cast<const uint4*>(g_flo + off);
            }
            int so = ent*24 + half*8;
            *reinterpret_cast<uint4*>(sInH + so) = vh;
            *reinterpret_cast<uint4*>(sInL + so) = vl;
        }
        for (int e = tid; e < 1600; e += 256){
            reinterpret_cast<uint4*>(sWH)[e] = reinterpret_cast<const uint4*>(g_w2hi + chunk*12800)[e];
            reinterpret_cast<uint4*>(sWL)[e] = reinterpret_cast<const uint4*>(g_w2lo + chunk*12800)[e];
        }
        __syncthreads();

        #pragma unroll 1
        for (int tap = 0; tap < 25; tap++){
            int dy = tap/5, dx = tap%5;
            uint32_t bh[4], bl[4];
            uint32_t boff = 2u*(uint32_t)((tap*32 + wn*16 + (lane&7) + ((lane>>4)&1)*8)*16
                                          + ((lane>>3)&1)*8);
            ldm_x4(bh, aWH + boff);
            ldm_x4(bl, aWL + boff);
            uint32_t ah[3][4], al[3][4];
            #pragma unroll
            for (int mi = 0; mi < 3; mi++){
                int tmi = wm*3 + mi;
                int r = tmi/6, xb = (tmi%6)*16;
                uint32_t aoff = 2u*(uint32_t)(((r+dy)*100 + xb + (lane&15) + dx)*24
                                              + (lane>>4)*8);
                ldm_x4(ah[mi], aInH + aoff);
                ldm_x4(al[mi], aInL + aoff);
            }
            #pragma unroll
            for (int mi = 0; mi < 3; mi++){
                #pragma unroll
                for (int j = 0; j < 2; j++){
                    MMA_BF16(c[mi][j], ah[mi], &bh[j*2]);
                    MMA_BF16(c[mi][j], ah[mi], &bl[j*2]);
                    MMA_BF16(c[mi][j], al[mi], &bh[j*2]);
                }
            }
        }
    }

    #pragma unroll
    for (int mi = 0; mi < 3; mi++){
        int tmi = wm*3 + mi;
        int r = tmi/6, xb = (tmi%6)*16;
        int gp = (y0 + r)*Ww + xb + (lane>>2);
        #pragma unroll
        for (int j = 0; j < 2; j++){
            int oc = wn*16 + j*8 + (lane&3)*2;
            if (oc < 10){
                float bv0 = b_fl[oc], bv1 = b_fl[oc+1];
                float* f0 = g_flows + ((size_t)b*10 + oc)*HW;
                float* f1 = g_flows + ((size_t)b*10 + oc + 1)*HW;
                f0[gp]     = c[mi][j][0] + bv0;
                f1[gp]     = c[mi][j][1] + bv1;
                f0[gp + 8] = c[mi][j][2] + bv0;
                f1[gp + 8] = c[mi][j][3] + bv1;
            }
        }
    }
}

// ============================================================
// warp: bilinear-warp h -> bf16 hi/lo [b][p][k], smem-staged
// coalesced writes (192B runs per pixel). grid (B*L, H), block 96
// ============================================================
__global__ void k_warp(const float* __restrict__ h){
    __shared__ uint32_t sHi[96*49], sLo[96*49];
    int bl = blockIdx.x, y = blockIdx.y, tx = threadIdx.x;
    int b = bl / Lk, l = bl % Lk;
    const float* fl = g_flows + (size_t)b*10*HW + y*Ww + tx;
    float fx = fl[(size_t)(2*l)*HW];
    float fy = fl[(size_t)(2*l+1)*HW];
    float vx = (float)tx - fx;
    float vy = (float)y  - fy;
    const float sc = 96.0f/95.0f;
    float ix = vx*sc - 0.5f;
    float iy = vy*sc - 0.5f;
    float fx0 = floorf(ix), fy0 = floorf(iy);
    int ix0 = (int)fx0, iy0 = (int)fy0;
    int ix1 = ix0 + 1, iy1 = iy0 + 1;
    float wx1 = ix - fx0, wy1 = iy - fy0;
    float wx0 = 1.f - wx1, wy0 = 1.f - wy1;
    float mx0 = (ix0 >= 0 && ix0 < Ww) ? 1.f : 0.f;
    float mx1 = (ix1 >= 0 && ix1 < Ww) ? 1.f : 0.f;
    float my0 = (iy0 >= 0 && iy0 < Hh) ? 1.f : 0.f;
    float my1 = (iy1 >= 0 && iy1 < Hh) ? 1.f : 0.f;
    int cx0 = min(max(ix0, 0), Ww-1), cx1 = min(max(ix1, 0), Ww-1);
    int cy0 = min(max(iy0, 0), Hh-1), cy1 = min(max(iy1, 0), Hh-1);
    int o00 = cy0*Ww + cx0, o01 = cy0*Ww + cx1;
    int o10 = cy1*Ww + cx0, o11 = cy1*Ww + cx1;
    float w00 = wy0*wx0*my0*mx0, w01 = wy0*wx1*my0*mx1;
    float w10 = wy1*wx0*my1*mx0, w11 = wy1*wx1*my1*mx1;
    const float* hb = h + (size_t)b*Fch*HW;

    #pragma unroll 1
    for (int c0 = 0; c0 < Fch; c0 += 8){
        #pragma unroll
        for (int j = 0; j < 4; j++){
            const float* p0 = hb + (size_t)(c0 + 2*j)*HW;
            const float* p1 = p0 + HW;
            float v0 = w00*p0[o00] + w01*p0[o01] + w10*p0[o10] + w11*p0[o11];
            float v1 = w00*p1[o00] + w01*p1[o01] + w10*p1[o10] + w11*p1[o11];
            uint32_t hw, lw;
            split2(v0, v1, hw, lw);
            sHi[tx*49 + (c0>>1) + j] = hw;
            sLo[tx*49 + (c0>>1) + j] = lw;
        }
    }
    __syncthreads();
    size_t rowbase = ((size_t)b*HW + y*Ww)*KPAD + (size_t)l*Fch;
    for (int e = tx; e < 96*12; e += 96){
        int pl = e/12, u = e%12;
        uint4 vh, vl;
        vh.x = sHi[pl*49 + u*4 + 0]; vh.y = sHi[pl*49 + u*4 + 1];
        vh.z = sHi[pl*49 + u*4 + 2]; vh.w = sHi[pl*49 + u*4 + 3];
        vl.x = sLo[pl*49 + u*4 + 0]; vl.y = sLo[pl*49 + u*4 + 1];
        vl.z = sLo[pl*49 + u*4 + 2]; vl.w = sLo[pl*49 + u*4 + 3];
        *reinterpret_cast<uint4*>(g_whi + rowbase + (size_t)pl*KPAD + u*8) = vh;
        *reinterpret_cast<uint4*>(g_wlo + rowbase + (size_t)pl*KPAD + u*8) = vl;
    }
}

// ============================================================
// prep: split w_ret (288 x 480, stride KPAD)
// ============================================================
__global__ void k_prepA(const float* __restrict__ w_ret){
    int idx = blockIdx.x*blockDim.x + threadIdx.x;
    if (idx >= FH3*KPAD) return;
    int m = idx / KPAD, k = idx % KPAD;
    float v = (k < K1) ? w_ret[m*K1 + k] : 0.f;
    __nv_bfloat16 hi = __float2bfloat16(v);
    __nv_bfloat16 lo = __float2bfloat16(v - __bfloat162float(hi));
    g_Ahi[idx] = hi; g_Alo[idx] = lo;
}

// ============================================================
// FUSED h2h GEMM + GRU gates:
// One CTA = ALL 288 m-rows x 128 pixels. B staged once per chunk
// (shared by the 3 m-tiles), cp.async double-buffered. Epilogue
// computes gates inline, writes hnext fp32 + packs bf16 hi/lo into
// the next step's fconv input slot via an smem transpose stage.
// grid (72, B), 256 thr, dyn smem 133.1 KB
// ============================================================
#define TS 40
#define H2_ABUF (288*TS)            // elems per A matrix per buffer
#define H2_BBUF (128*TS)
#define H2_SMEM ((2*H2_ABUF*2 + 2*H2_BBUF*2)*2)   // bytes = 133120

__global__ void __launch_bounds__(256, 1) k_h2hg(int t,
                                                 const float* __restrict__ bias,
                                                 const float* __restrict__ hprev,
                                                 float* __restrict__ hnext,
                                                 int pack){
    extern __shared__ __nv_bfloat16 sm[];
    __nv_bfloat16* sAh = sm;                       // 2*H2_ABUF
    __nv_bfloat16* sAl = sm + 2*H2_ABUF;
    __nv_bfloat16* sBh = sm + 4*H2_ABUF;           // 2*H2_BBUF
    __nv_bfloat16* sBl = sm + 4*H2_ABUF + 2*H2_BBUF;
    uint32_t aSh = smem_u32(sAh), aSl = smem_u32(sAl);
    uint32_t aBh = smem_u32(sBh), aBl = smem_u32(sBl);

    int tid = threadIdx.x, lane = tid & 31, wid = tid >> 5;
    int wm = wid & 1, wn = wid >> 1;
    int n0 = blockIdx.x*128, b = blockIdx.y;

    const __nv_bfloat16* Bh = g_whi + ((size_t)b*HW + n0)*KPAD;
    const __nv_bfloat16* Bl = g_wlo + ((size_t)b*HW + n0)*KPAD;

    int arow = wm*48 + (lane & 15);
    int acol = (lane >> 4) * 8;
    int brow = wn*32 + (lane & 7) + ((lane >> 4) & 1)*8;
    int bcol = ((lane >> 3) & 1) * 8;

    float c[3][3][4][4];
    #pragma unroll
    for (int mt = 0; mt < 3; mt++)
        #pragma unroll
        for (int i = 0; i < 3; i++)
            #pragma unroll
            for (int j = 0; j < 4; j++)
                #pragma unroll
                for (int q = 0; q < 4; q++) c[mt][i][j][q] = 0.f;

    #define H2G_STAGE(chunk, buf) do { \
        uint32_t sbA = (uint32_t)(buf)*(H2_ABUF*2); \
        uint32_t sbB = (uint32_t)(buf)*(H2_BBUF*2); \
        for (int e = tid; e < 1152; e += 256){ \
            int r = e >> 2, u = e & 3; \
            size_t goff = (size_t)r*KPAD + (chunk)*32 + u*8; \
            uint32_t soff = sbA + (uint32_t)(r*TS + u*8)*2u; \
            CPA16(aSh + soff, g_Ahi + goff); \
            CPA16(aSl + soff, g_Alo + goff); \
        } \
        for (int e = tid; e < 512; e += 256){ \
            int r = e >> 2, u = e & 3; \
            size_t goff = (size_t)r*KPAD + (chunk)*32 + u*8; \
            uint32_t soff = sbB + (uint32_t)(r*TS + u*8)*2u; \
            CPA16(aBh + soff, Bh + goff); \
            CPA16(aBl + soff, Bl + goff); \
        } \
        CPA_COMMIT(); \
    } while(0)

    H2G_STAGE(0, 0);
    for (int chunk = 0; chunk < 15; chunk++){
        if (chunk + 1 < 15){
            H2G_STAGE(chunk + 1, (chunk + 1) & 1);
            asm volatile("cp.async.wait_group 1;" ::: "memory");
        } else {
            asm volatile("cp.async.wait_group 0;" ::: "memory");
        }
        __syncthreads();

        uint32_t sbA = (uint32_t)(chunk & 1)*(H2_ABUF*2);
        uint32_t sbB = (uint32_t)(chunk & 1)*(H2_BBUF*2);
        #pragma unroll
        for (int ks = 0; ks < 2; ks++){
            int kc = ks*16;
            uint32_t bh[2][4], bl[2][4];
            #pragma unroll
            for (int jp = 0; jp < 2; jp++){
                uint32_t off = sbB + 2u*((brow + jp*16)*TS + kc + bcol);
                ldm_x4(bh[jp], aBh + off);
                ldm_x4(bl[jp], aBl + off);
            }
            #pragma unroll
            for (int mt = 0; mt < 3; mt++){
                uint32_t ah[3][4], al[3][4];
                #pragma unroll
                for (int mi = 0; mi < 3; mi++){
                    uint32_t off = sbA + 2u*((mt*96 + arow + mi*16)*TS + kc + acol);
                    ldm_x4(ah[mi], aSh + off);
                    ldm_x4(al[mi], aSl + off);
                }
                #pragma unroll
                for (int mi = 0; mi < 3; mi++){
                    #pragma unroll
                    for (int j = 0; j < 4; j++){
                        uint32_t* fh = &bh[j >> 1][(j & 1)*2];
                        uint32_t* fl2 = &bl[j >> 1][(j & 1)*2];
                        MMA_BF16(c[mt][mi][j], ah[mi], fh);
                        MMA_BF16(c[mt][mi][j], ah[mi], fl2);
                        MMA_BF16(c[mt][mi][j], al[mi], fh);
                    }
                }
            }
        }
        __syncthreads();
    }

    // ---- fused GRU gate epilogue ----
    __syncthreads();                    // smem reuse barrier
    float* sF = reinterpret_cast<float*>(sm);   // [128 px][stride 100] fp32

    const float* i2hb = g_i2h + (size_t)(t*Bg + b)*FH3*HW;
    const float* hpb  = hprev + (size_t)b*Fch*HW;
    float* hnb        = hnext + (size_t)b*Fch*HW;

    #pragma unroll
    for (int mi = 0; mi < 3; mi++){
        int fc0 = wm*48 + mi*16 + (lane >> 2);
        #pragma unroll
        for (int j = 0; j < 4; j++){
            int pl = wn*32 + (lane & 3)*2 + j*8;
            int p = n0 + pl;
            #pragma unroll
            for (int half = 0; half < 2; half++){
                int fc = fc0 + half*8;
                int q0 = half*2;
                float rb = bias[fc], ub = bias[96 + fc], mb = bias[192 + fc];
                float2 i2r = *reinterpret_cast<const float2*>(i2hb + (size_t)fc*HW + p);
                float2 i2u = *reinterpret_cast<const float2*>(i2hb + (size_t)(96+fc)*HW + p);
                float2 i2m = *reinterpret_cast<const float2*>(i2hb + (size_t)(192+fc)*HW + p);
                float2 hpv = *reinterpret_cast<const float2*>(hpb + (size_t)fc*HW + p);
                float nh[2];
                #pragma unroll
                for (int s = 0; s < 2; s++){
                    float hr = c[0][mi][j][q0+s] + rb;
                    float hu = c[1][mi][j][q0+s] + ub;
                    float hm = c[2][mi][j][q0+s] + mb;
                    float ir = s ? i2r.y : i2r.x;
                    float iu = s ? i2u.y : i2u.x;
                    float im = s ? i2m.y : i2m.x;
                    float hp = s ? hpv.y : hpv.x;
                    float reset  = sigm(ir + hr);
                    float update = sigm(iu + hu);
                    float newmem = leaky(im + reset*hm);
                    nh[s] = update*hp + (1.f - update)*newmem;
                }
                float2 wv; wv.x = nh[0]; wv.y = nh[1];
                *reinterpret_cast<float2*>(hnb + (size_t)fc*HW + p) = wv;
                sF[pl*100 + fc]     = nh[0];
                sF[(pl+1)*100 + fc] = nh[1];
            }
        }
    }
    __syncthreads();
    if (pack){
        size_t slotn = (size_t)((t+1)*Bg + b)*HW;
        for (int e = tid; e < 128*12; e += 256){
            int pl = e/12, u = e%12;
            const float* src = sF + pl*100 + u*8;
            uint32_t hw[4], lw[4];
            #pragma unroll
            for (int q = 0; q < 4; q++)
                split2(src[2*q], src[2*q+1], hw[q], lw[q]);
            size_t off = (slotn + n0 + pl)*CH + 8 + u*8;
            *reinterpret_cast<uint4*>(g_inhi + off) = *reinterpret_cast<uint4*>(hw);
            *reinterpret_cast<uint4*>(g_inlo + off) = *reinterpret_cast<uint4*>(lw);
        }
    }
}

// ============================================================
extern "C" void kernel_launch(void* const* d_in, const int* in_sizes, int n_in,
                              void* d_out, int out_size){
    const float* inputs = (const float*)d_in[0];
    const float* h0     = (const float*)d_in[1];
    const float* w_i2h  = (const float*)d_in[2];
    const float* b_i2h  = (const float*)d_in[3];
    const float* w_i2f  = (const float*)d_in[4];
    const float* b_i2f  = (const float*)d_in[5];
    const float* w_h2f  = (const float*)d_in[6];
    const float* b_h2f  = (const float*)d_in[7];
    const float* w_fl   = (const float*)d_in[8];
    const float* b_fl   = (const float*)d_in[9];
    const float* w_ret  = (const float*)d_in[10];
    const float* b_ret  = (const float*)d_in[11];
    float* out = (float*)d_out;

    cudaFuncSetAttribute(k_fconv,  cudaFuncAttributeMaxDynamicSharedMemorySize, FSM_BYTES);
    cudaFuncSetAttribute(k_flowsT, cudaFuncAttributeMaxDynamicSharedMemorySize, FSM_BYTES);
    cudaFuncSetAttribute(k_h2hg,   cudaFuncAttributeMaxDynamicSharedMemorySize, H2_SMEM);

    // once per launch
    k_prepX   <<<(Sg*Bg*HW + 255)/256, 256>>>(inputs, h0);
    k_prepWall<<<(89600 + 25600 + 20736 + 255)/256, 256>>>(w_i2f, w_h2f, w_fl, w_i2h);
    k_prepA   <<<(FH3*KPAD + 255)/256, 256>>>(w_ret);
    k_i2hT    <<<dim3(48, Sg*Bg, 3), 256>>>(b_i2h);

    for (int t = 0; t < Sg; t++){
        const float* h = (t == 0) ? h0 : out + (size_t)(t-1)*STEP_ELEMS;
        float* hn = out + (size_t)t*STEP_ELEMS;

        k_fconv <<<dim3(48, Bg), 256, FSM_BYTES>>>(t, b_i2f, b_h2f);
        k_flowsT<<<dim3(48, Bg), 256, FSM_BYTES>>>(b_fl);
        k_warp  <<<dim3(Bg*Lk, Hh), 96>>>(h);
        k_h2hg  <<<dim3(HW/128, Bg), 256, H2_SMEM>>>(t, b_ret, h, hn, (t < Sg-1) ? 1 : 0);
    }

    const size_t OUT_SEQ = (size_t)Sg*STEP_ELEMS;
    if ((size_t)out_size >= OUT_SEQ + STEP_ELEMS){
        cudaMemcpyAsync(out + OUT_SEQ, out + (size_t)(Sg-1)*STEP_ELEMS,
                        (size_t)STEP_ELEMS*sizeof(float),
                        cudaMemcpyDeviceToDevice);
    }
}

// round 9
// speedup vs baseline: 4.4071x; 1.1875x over previous
#include <cuda_runtime.h>
#include <cuda_bf16.h>
#include <cstdint>
#include <math.h>

#define Hh 96
#define Ww 96
#define HW 9216
#define Fch 96
#define CIN 8
#define Lk 5
#define Sg 10
#define Bg 4
#define FH3 288          // 3*F
#define K1 480           // L*F
#define KPAD 512         // row STRIDE of k-major operands (pad cols never read)
#define CH 112           // packed input channels: 8 x | 96 h | 8 zero
#define STEP_ELEMS (Bg*Fch*HW)   // 3,538,944

// ---- scratch (device globals) ----
__device__ float g_i2h[(size_t)Sg*Bg*FH3*HW];                 // 425 MB (once)
__device__ float g_flows[Bg*10*HW];
__device__ __align__(16) __nv_bfloat16 g_whi[(size_t)Bg*HW*KPAD];  // warped^T hi [b][p][k]
__device__ __align__(16) __nv_bfloat16 g_wlo[(size_t)Bg*HW*KPAD];
__device__ __align__(16) __nv_bfloat16 g_Ahi[(size_t)FH3*KPAD];    // w_ret hi [m][k]
__device__ __align__(16) __nv_bfloat16 g_Alo[(size_t)FH3*KPAD];
// fconv inputs: per-step slots [Sg][Bg][p][112]
// hi: all channels. lo: only x-channels (0..7) + slot-0 h channels are live.
__device__ __align__(16) __nv_bfloat16 g_inhi[(size_t)Sg*Bg*HW*CH];
__device__ __align__(16) __nv_bfloat16 g_inlo[(size_t)Sg*Bg*HW*CH];
__device__ __align__(16) __nv_bfloat16 g_wfhi[7*25*32*16];         // [chunk][tap][oc][16]
// f as bf16 (1-term) [b][p][32]
__device__ __align__(16) __nv_bfloat16 g_fhi[(size_t)Bg*HW*32];
// flows weights [chunk2][tap25][oc32][16] (oc>=10 zero)
__device__ __align__(16) __nv_bfloat16 g_w2hi[2*25*32*16];
// i2h weights [ocg3][tap9][oc96][8] hi/lo
__device__ __align__(16) __nv_bfloat16 g_w3hi[3*9*96*8];
__device__ __align__(16) __nv_bfloat16 g_w3lo[3*9*96*8];

__device__ __forceinline__ float leaky(float v){ return v > 0.f ? v : 0.2f*v; }
__device__ __forceinline__ float sigm(float v){ return 1.f/(1.f + expf(-v)); }

__device__ __forceinline__ uint32_t smem_u32(const void* p){
    uint32_t a;
    asm("{ .reg .u64 t; cvta.to.shared.u64 t, %1; cvt.u32.u64 %0, t; }" : "=r"(a) : "l"(p));
    return a;
}
__device__ __forceinline__ void ldm_x4(uint32_t* r, uint32_t addr){
    asm volatile("ldmatrix.sync.aligned.m8n8.x4.shared.b16 {%0,%1,%2,%3}, [%4];"
        : "=r"(r[0]), "=r"(r[1]), "=r"(r[2]), "=r"(r[3]) : "r"(addr));
}
__device__ __forceinline__ void ldm_x2(uint32_t* r, uint32_t addr){
    asm volatile("ldmatrix.sync.aligned.m8n8.x2.shared.b16 {%0,%1}, [%2];"
        : "=r"(r[0]), "=r"(r[1]) : "r"(addr));
}
#define MMA_BF16(c, a, b) \
    asm volatile("mma.sync.aligned.m16n8k16.row.col.f32.bf16.bf16.f32 " \
        "{%0,%1,%2,%3}, {%4,%5,%6,%7}, {%8,%9}, {%0,%1,%2,%3};" \
        : "+f"((c)[0]), "+f"((c)[1]), "+f"((c)[2]), "+f"((c)[3]) \
        : "r"((a)[0]), "r"((a)[1]), "r"((a)[2]), "r"((a)[3]), \
          "r"((b)[0]), "r"((b)[1]))
#define MMA_BF16_K8(c, a, b) \
    asm volatile("mma.sync.aligned.m16n8k8.row.col.f32.bf16.bf16.f32 " \
        "{%0,%1,%2,%3}, {%4,%5}, {%6}, {%0,%1,%2,%3};" \
        : "+f"((c)[0]), "+f"((c)[1]), "+f"((c)[2]), "+f"((c)[3]) \
        : "r"((a)[0]), "r"((a)[1]), "r"(b))
#define CPA16(sm, gp) asm volatile("cp.async.ca.shared.global [%0], [%1], 16;" :: "r"(sm), "l"(gp))
#define CPA_COMMIT()  asm volatile("cp.async.commit_group;" ::: "memory")

__device__ __forceinline__ void split2(float v0, float v1, uint32_t& hw, uint32_t& lw){
    __nv_bfloat16 h0 = __float2bfloat16(v0), h1 = __float2bfloat16(v1);
    __nv_bfloat16 l0 = __float2bfloat16(v0 - __bfloat162float(h0));
    __nv_bfloat16 l1 = __float2bfloat16(v1 - __bfloat162float(h1));
    __nv_bfloat162 hp; hp.x = h0; hp.y = h1;
    __nv_bfloat162 lp; lp.x = l0; lp.y = l1;
    hw = *reinterpret_cast<uint32_t*>(&hp);
    lw = *reinterpret_cast<uint32_t*>(&lp);
}
__device__ __forceinline__ uint32_t pack2(float v0, float v1){
    __nv_bfloat162 hp; hp.x = __float2bfloat16(v0); hp.y = __float2bfloat16(v1);
    return *reinterpret_cast<uint32_t*>(&hp);
}

// ============================================================
// k_prepX (once): pack x channels for ALL step slots, zero pad ch,
// and slot-0 h channels from h0.
// ============================================================
__global__ void k_prepX(const float* __restrict__ inputs, const float* __restrict__ h0){
    int idx = blockIdx.x*blockDim.x + threadIdx.x;
    if (idx >= Sg*Bg*HW) return;
    int p = idx % HW, b = (idx/HW) % Bg, t = idx/(HW*Bg);
    size_t base = ((size_t)(t*Bg + b)*HW + p)*CH;
    const float* xp = inputs + ((size_t)(t*Bg + b)*CIN)*HW + p;
    uint32_t hw[4], lw[4];
    #pragma unroll
    for (int q = 0; q < 4; q++)
        split2(xp[(size_t)(2*q)*HW], xp[(size_t)(2*q+1)*HW], hw[q], lw[q]);
    *reinterpret_cast<uint4*>(g_inhi + base) = *reinterpret_cast<uint4*>(hw);
    *reinterpret_cast<uint4*>(g_inlo + base) = *reinterpret_cast<uint4*>(lw);
    uint4 z = make_uint4(0,0,0,0);
    *reinterpret_cast<uint4*>(g_inhi + base + 104) = z;
    if (t == 0){
        const float* hp = h0 + (size_t)b*Fch*HW + p;
        for (int g = 0; g < 12; g++){
            #pragma unroll
            for (int q = 0; q < 4; q++)
                split2(hp[(size_t)(g*8 + 2*q)*HW], hp[(size_t)(g*8 + 2*q+1)*HW], hw[q], lw[q]);
            *reinterpret_cast<uint4*>(g_inhi + base + 8 + g*8) = *reinterpret_cast<uint4*>(hw);
            *reinterpret_cast<uint4*>(g_inlo + base + 8 + g*8) = *reinterpret_cast<uint4*>(lw);
        }
    }
}

// ============================================================
// k_prepWall (once): conv-weight repacks
//   range0: fconv hi [chunk7][tap25][oc32][16]   (89600)
//   range1: flows hi [chunk2][tap25][oc32][16]   (25600)
//   range2: i2h hi/lo [ocg3][tap9][oc96][8]      (20736)
// ============================================================
__global__ void k_prepWall(const float* __restrict__ w_i2f, const float* __restrict__ w_h2f,
                           const float* __restrict__ w_fl,  const float* __restrict__ w_i2h){
    int idx = blockIdx.x*blockDim.x + threadIdx.x;
    if (idx < 89600){
        int o = idx;
        int kc = o & 15, oc = (o >> 4) & 31, tap = (o >> 9) % 25, chunk = o / 12800;
        int ch = chunk*16 + kc;
        float v = 0.f;
        if (ch < 8)        v = w_i2f[(oc*8 + ch)*25 + tap];
        else if (ch < 104) v = w_h2f[((size_t)oc*Fch + (ch-8))*25 + tap];
        g_wfhi[o] = __float2bfloat16(v);
    } else if (idx < 89600 + 25600){
        int o = idx - 89600;
        int kc = o & 15, oc = (o >> 4) & 31, tap = (o >> 9) % 25, chunk = o / 12800;
        int ch = chunk*16 + kc;
        float v = (oc < 10) ? w_fl[((size_t)oc*32 + ch)*25 + tap] : 0.f;
        g_w2hi[o] = __float2bfloat16(v);
    } else if (idx < 89600 + 25600 + 20736){
        int o = idx - 89600 - 25600;
        int ch = o & 7, oc = (o >> 3) % 96, tap = (o/(96*8)) % 9, ocg = o/(9*96*8);
        float v = w_i2h[((size_t)(ocg*96 + oc)*CIN + ch)*9 + tap];
        __nv_bfloat16 hi = __float2bfloat16(v);
        g_w3hi[o] = hi;
        g_w3lo[o] = __float2bfloat16(v - __bfloat162float(hi));
    }
}

// ============================================================
// i2h as implicit GEMM (m16n8k8, bf16 hi/lo 3-term), runs once
// ============================================================
__global__ void __launch_bounds__(256, 2) k_i2hT(const float* __restrict__ bias){
    __shared__ __nv_bfloat16 sInH[400*8], sInL[400*8];
    __shared__ __nv_bfloat16 sWH[9*96*8], sWL[9*96*8];
    uint32_t aInH = smem_u32(sInH), aInL = smem_u32(sInL);
    uint32_t aWH  = smem_u32(sWH),  aWL  = smem_u32(sWL);

    int tid = threadIdx.x, lane = tid & 31, wid = tid >> 5;
    int wm = wid & 3, wn = wid >> 2;
    int y0 = blockIdx.x*2, img = blockIdx.y, ocg = blockIdx.z;

    for (int e = tid; e < 400; e += 256){
        int row = e/100, cc = e%100;
        int y = y0 + row - 1, x = cc - 1;
        uint4 vh = make_uint4(0,0,0,0), vl = make_uint4(0,0,0,0);
        if ((unsigned)y < 96u && (unsigned)x < 96u){
            size_t off = ((size_t)img*HW + y*Ww + x)*CH;
            vh = *reinterpret_cast<const uint4*>(g_inhi + off);
            vl = *reinterpret_cast<const uint4*>(g_inlo + off);
        }
        *reinterpret_cast<uint4*>(sInH + e*8) = vh;
        *reinterpret_cast<uint4*>(sInL + e*8) = vl;
    }
    for (int e = tid; e < 864; e += 256){
        reinterpret_cast<uint4*>(sWH)[e] = reinterpret_cast<const uint4*>(g_w3hi + (size_t)ocg*9*96*8)[e];
        reinterpret_cast<uint4*>(sWL)[e] = reinterpret_cast<const uint4*>(g_w3lo + (size_t)ocg*9*96*8)[e];
    }
    __syncthreads();

    float c[3][6][4];
    #pragma unroll
    for (int i = 0; i < 3; i++)
        #pragma unroll
        for (int j = 0; j < 6; j++)
            #pragma unroll
            for (int q = 0; q < 4; q++) c[i][j][q] = 0.f;

    #pragma unroll 1
    for (int tap = 0; tap < 9; tap++){
        int dy = tap/3, dx = tap%3;
        uint32_t bh[6], bl[6];
        {
            ldm_x4(bh, aWH + 2u*(uint32_t)((tap*96 + wn*48 + lane)*8));
            ldm_x4(bl, aWL + 2u*(uint32_t)((tap*96 + wn*48 + lane)*8));
            uint32_t a2 = 2u*(uint32_t)((tap*96 + wn*48 + 32 + (lane & 15))*8);
            ldm_x2(bh + 4, aWH + a2);
            ldm_x2(bl + 4, aWL + a2);
        }
        uint32_t ah[3][2], al[3][2];
        #pragma unroll
        for (int mi = 0; mi < 3; mi++){
            int tmi = wm*3 + mi;
            int r = tmi/6, xb = (tmi%6)*16;
            uint32_t aoff = 2u*(uint32_t)(((r+dy)*100 + xb + (lane&15) + dx)*8);
            ldm_x2(ah[mi], aInH + aoff);
            ldm_x2(al[mi], aInL + aoff);
        }
        #pragma unroll
        for (int mi = 0; mi < 3; mi++){
            #pragma unroll
            for (int j = 0; j < 6; j++){
                MMA_BF16_K8(c[mi][j], ah[mi], bh[j]);
                MMA_BF16_K8(c[mi][j], ah[mi], bl[j]);
                MMA_BF16_K8(c[mi][j], al[mi], bh[j]);
            }
        }
    }

    float* Ob = g_i2h + (size_t)img*FH3*HW;
    #pragma unroll
    for (int mi = 0; mi < 3; mi++){
        int tmi = wm*3 + mi;
        int r = tmi/6, xb = (tmi%6)*16;
        int p = (y0 + r)*Ww + xb + (lane>>2);
        #pragma unroll
        for (int j = 0; j < 6; j++){
            int oc = ocg*96 + wn*48 + j*8 + (lane&3)*2;
            float bv0 = bias[oc], bv1 = bias[oc+1];
            Ob[(size_t)oc*HW + p]           = c[mi][j][0] + bv0;
            Ob[(size_t)(oc+1)*HW + p]       = c[mi][j][1] + bv1;
            Ob[(size_t)oc*HW + p + 8]       = c[mi][j][2] + bv0;
            Ob[(size_t)(oc+1)*HW + p + 8]   = c[mi][j][3] + bv1;
        }
    }
}

// ============================================================
// fconv implicit GEMM — 1-term bf16 (hi only). CTA = 2 rows x 96 px,
// N=32, 8 warps (4M x 2N). Epilogue -> f bf16 [b][p][32].
// dyn smem = (14400 + 12800)*2 = 54.4 KB
// ============================================================
#define FSM_BYTES ((14400 + 12800)*2)

__global__ void __launch_bounds__(256, 2) k_fconv(int t,
                                                  const float* __restrict__ b_i2f,
                                                  const float* __restrict__ b_h2f){
    extern __shared__ __nv_bfloat16 sm[];
    __nv_bfloat16* sInH = sm;             // 600 entries * 24
    __nv_bfloat16* sWH  = sm + 14400;     // 12800
    uint32_t aInH = smem_u32(sInH), aWH = smem_u32(sWH);

    int tid = threadIdx.x, lane = tid & 31, wid = tid >> 5;
    int wm = wid & 3, wn = wid >> 2;
    int y0 = blockIdx.x*2, b = blockIdx.y;
    size_t slot = (size_t)(t*Bg + b)*HW;

    float c[3][2][4];
    #pragma unroll
    for (int i = 0; i < 3; i++)
        #pragma unroll
        for (int j = 0; j < 2; j++)
            #pragma unroll
            for (int q = 0; q < 4; q++) c[i][j][q] = 0.f;

    for (int chunk = 0; chunk < 7; chunk++){
        __syncthreads();
        for (int e = tid; e < 1200; e += 256){
            int ent = e >> 1, half = e & 1;
            int row = ent/100, cc = ent%100;
            int y = y0 + row - 2, x = cc - 2;
            uint4 vh = make_uint4(0,0,0,0);
            if ((unsigned)y < 96u && (unsigned)x < 96u){
                size_t off = (slot + y*Ww + x)*CH + chunk*16 + half*8;
                vh = *reinterpret_cast<const uint4*>(g_inhi + off);
            }
            *reinterpret_cast<uint4*>(sInH + ent*24 + half*8) = vh;
        }
        for (int e = tid; e < 1600; e += 256){
            reinterpret_cast<uint4*>(sWH)[e] = reinterpret_cast<const uint4*>(g_wfhi + chunk*12800)[e];
        }
        __syncthreads();

        #pragma unroll 1
        for (int tap = 0; tap < 25; tap++){
            int dy = tap/5, dx = tap%5;
            uint32_t bh[4];
            uint32_t boff = 2u*(uint32_t)((tap*32 + wn*16 + (lane&7) + ((lane>>4)&1)*8)*16
                                          + ((lane>>3)&1)*8);
            ldm_x4(bh, aWH + boff);
            uint32_t ah[3][4];
            #pragma unroll
            for (int mi = 0; mi < 3; mi++){
                int tmi = wm*3 + mi;
                int r = tmi/6, xb = (tmi%6)*16;
                uint32_t aoff = 2u*(uint32_t)(((r+dy)*100 + xb + (lane&15) + dx)*24
                                              + (lane>>4)*8);
                ldm_x4(ah[mi], aInH + aoff);
            }
            #pragma unroll
            for (int mi = 0; mi < 3; mi++){
                #pragma unroll
                for (int j = 0; j < 2; j++){
                    MMA_BF16(c[mi][j], ah[mi], &bh[j*2]);
                }
            }
        }
    }

    #pragma unroll
    for (int mi = 0; mi < 3; mi++){
        int tmi = wm*3 + mi;
        int r = tmi/6, xb = (tmi%6)*16;
        int gp = (y0 + r)*Ww + xb + (lane>>2);
        #pragma unroll
        for (int j = 0; j < 2; j++){
            int oc = wn*16 + j*8 + (lane&3)*2;
            float bb0 = b_i2f[oc]   + b_h2f[oc];
            float bb1 = b_i2f[oc+1] + b_h2f[oc+1];
            *reinterpret_cast<uint32_t*>(g_fhi + ((size_t)b*HW + gp)*32 + oc)
                = pack2(leaky(c[mi][j][0] + bb0), leaky(c[mi][j][1] + bb1));
            *reinterpret_cast<uint32_t*>(g_fhi + ((size_t)b*HW + gp + 8)*32 + oc)
                = pack2(leaky(c[mi][j][2] + bb0), leaky(c[mi][j][3] + bb1));
        }
    }
}

// ============================================================
// flows implicit GEMM — 1-term bf16 (2 chunks, oc padded to 32)
// ============================================================
__global__ void __launch_bounds__(256, 2) k_flowsT(const float* __restrict__ b_fl){
    extern __shared__ __nv_bfloat16 sm[];
    __nv_bfloat16* sInH = sm;
    __nv_bfloat16* sWH  = sm + 14400;
    uint32_t aInH = smem_u32(sInH), aWH = smem_u32(sWH);

    int tid = threadIdx.x, lane = tid & 31, wid = tid >> 5;
    int wm = wid & 3, wn = wid >> 2;
    int y0 = blockIdx.x*2, b = blockIdx.y;

    float c[3][2][4];
    #pragma unroll
    for (int i = 0; i < 3; i++)
        #pragma unroll
        for (int j = 0; j < 2; j++)
            #pragma unroll
            for (int q = 0; q < 4; q++) c[i][j][q] = 0.f;

    for (int chunk = 0; chunk < 2; chunk++){
        __syncthreads();
        for (int e = tid; e < 1200; e += 256){
            int ent = e >> 1, half = e & 1;
            int row = ent/100, cc = ent%100;
            int y = y0 + row - 2, x = cc - 2;
            uint4 vh = make_uint4(0,0,0,0);
            if ((unsigned)y < 96u && (unsigned)x < 96u){
                size_t off = ((size_t)b*HW + y*Ww + x)*32 + chunk*16 + half*8;
                vh = *reinterpret_cast<const uint4*>(g_fhi + off);
            }
            *reinterpret_cast<uint4*>(sInH + ent*24 + half*8) = vh;
        }
        for (int e = tid; e < 1600; e += 256){
            reinterpret_cast<uint4*>(sWH)[e] = reinterpret_cast<const uint4*>(g_w2hi + chunk*12800)[e];
        }
        __syncthreads();

        #pragma unroll 1
        for (int tap = 0; tap < 25; tap++){
            int dy = tap/5, dx = tap%5;
            uint32_t bh[4];
            uint32_t boff = 2u*(uint32_t)((tap*32 + wn*16 + (lane&7) + ((lane>>4)&1)*8)*16
                                          + ((lane>>3)&1)*8);
            ldm_x4(bh, aWH + boff);
            uint32_t ah[3][4];
            #pragma unroll
            for (int mi = 0; mi < 3; mi++){
                int tmi = wm*3 + mi;
                int r = tmi/6, xb = (tmi%6)*16;
                uint32_t aoff = 2u*(uint32_t)(((r+dy)*100 + xb + (lane&15) + dx)*24
                                              + (lane>>4)*8);
                ldm_x4(ah[mi], aInH + aoff);
            }
            #pragma unroll
            for (int mi = 0; mi < 3; mi++){
                #pragma unroll
                for (int j = 0; j < 2; j++){
                    MMA_BF16(c[mi][j], ah[mi], &bh[j*2]);
                }
            }
        }
    }

    #pragma unroll
    for (int mi = 0; mi < 3; mi++){
        int tmi = wm*3 + mi;
        int r = tmi/6, xb = (tmi%6)*16;
        int gp = (y0 + r)*Ww + xb + (lane>>2);
        #pragma unroll
        for (int j = 0; j < 2; j++){
            int oc = wn*16 + j*8 + (lane&3)*2;
            if (oc < 10){
                float bv0 = b_fl[oc], bv1 = b_fl[oc+1];
                float* f0 = g_flows + ((size_t)b*10 + oc)*HW;
                float* f1 = g_flows + ((size_t)b*10 + oc + 1)*HW;
                f0[gp]     = c[mi][j][0] + bv0;
                f1[gp]     = c[mi][j][1] + bv1;
                f0[gp + 8] = c[mi][j][2] + bv0;
                f1[gp + 8] = c[mi][j][3] + bv1;
            }
        }
    }
}

// ============================================================
// warp: bilinear-warp h -> bf16 hi/lo [b][p][k], smem-staged
// coalesced writes. grid (B*L, H), block 96
// ============================================================
__global__ void k_warp(const float* __restrict__ h){
    __shared__ uint32_t sHi[96*49], sLo[96*49];
    int bl = blockIdx.x, y = blockIdx.y, tx = threadIdx.x;
    int b = bl / Lk, l = bl % Lk;
    const float* fl = g_flows + (size_t)b*10*HW + y*Ww + tx;
    float fx = fl[(size_t)(2*l)*HW];
    float fy = fl[(size_t)(2*l+1)*HW];
    float vx = (float)tx - fx;
    float vy = (float)y  - fy;
    const float sc = 96.0f/95.0f;
    float ix = vx*sc - 0.5f;
    float iy = vy*sc - 0.5f;
    float fx0 = floorf(ix), fy0 = floorf(iy);
    int ix0 = (int)fx0, iy0 = (int)fy0;
    int ix1 = ix0 + 1, iy1 = iy0 + 1;
    float wx1 = ix - fx0, wy1 = iy - fy0;
    float wx0 = 1.f - wx1, wy0 = 1.f - wy1;
    float mx0 = (ix0 >= 0 && ix0 < Ww) ? 1.f : 0.f;
    float mx1 = (ix1 >= 0 && ix1 < Ww) ? 1.f : 0.f;
    float my0 = (iy0 >= 0 && iy0 < Hh) ? 1.f : 0.f;
    float my1 = (iy1 >= 0 && iy1 < Hh) ? 1.f : 0.f;
    int cx0 = min(max(ix0, 0), Ww-1), cx1 = min(max(ix1, 0), Ww-1);
    int cy0 = min(max(iy0, 0), Hh-1), cy1 = min(max(iy1, 0), Hh-1);
    int o00 = cy0*Ww + cx0, o01 = cy0*Ww + cx1;
    int o10 = cy1*Ww + cx0, o11 = cy1*Ww + cx1;
    float w00 = wy0*wx0*my0*mx0, w01 = wy0*wx1*my0*mx1;
    float w10 = wy1*wx0*my1*mx0, w11 = wy1*wx1*my1*mx1;
    const float* hb = h + (size_t)b*Fch*HW;

    #pragma unroll 1
    for (int c0 = 0; c0 < Fch; c0 += 8){
        #pragma unroll
        for (int j = 0; j < 4; j++){
            const float* p0 = hb + (size_t)(c0 + 2*j)*HW;
            const float* p1 = p0 + HW;
            float v0 = w00*p0[o00] + w01*p0[o01] + w10*p0[o10] + w11*p0[o11];
            float v1 = w00*p1[o00] + w01*p1[o01] + w10*p1[o10] + w11*p1[o11];
            uint32_t hw, lw;
            split2(v0, v1, hw, lw);
            sHi[tx*49 + (c0>>1) + j] = hw;
            sLo[tx*49 + (c0>>1) + j] = lw;
        }
    }
    __syncthreads();
    size_t rowbase = ((size_t)b*HW + y*Ww)*KPAD + (size_t)l*Fch;
    for (int e = tx; e < 96*12; e += 96){
        int pl = e/12, u = e%12;
        uint4 vh, vl;
        vh.x = sHi[pl*49 + u*4 + 0]; vh.y = sHi[pl*49 + u*4 + 1];
        vh.z = sHi[pl*49 + u*4 + 2]; vh.w = sHi[pl*49 + u*4 + 3];
        vl.x = sLo[pl*49 + u*4 + 0]; vl.y = sLo[pl*49 + u*4 + 1];
        vl.z = sLo[pl*49 + u*4 + 2]; vl.w = sLo[pl*49 + u*4 + 3];
        *reinterpret_cast<uint4*>(g_whi + rowbase + (size_t)pl*KPAD + u*8) = vh;
        *reinterpret_cast<uint4*>(g_wlo + rowbase + (size_t)pl*KPAD + u*8) = vl;
    }
}

// ============================================================
// prep: split w_ret (288 x 480, stride KPAD)
// ============================================================
__global__ void k_prepA(const float* __restrict__ w_ret){
    int idx = blockIdx.x*blockDim.x + threadIdx.x;
    if (idx >= FH3*KPAD) return;
    int m = idx / KPAD, k = idx % KPAD;
    float v = (k < K1) ? w_ret[m*K1 + k] : 0.f;
    __nv_bfloat16 hi = __float2bfloat16(v);
    __nv_bfloat16 lo = __float2bfloat16(v - __bfloat162float(hi));
    g_Ahi[idx] = hi; g_Alo[idx] = lo;
}

// ============================================================
// FUSED h2h GEMM (3-term) + GRU gates.
// ============================================================
#define TS 40
#define H2_ABUF (288*TS)
#define H2_BBUF (128*TS)
#define H2_SMEM ((2*H2_ABUF*2 + 2*H2_BBUF*2)*2)   // 133120 B

__global__ void __launch_bounds__(256, 1) k_h2hg(int t,
                                                 const float* __restrict__ bias,
                                                 const float* __restrict__ hprev,
                                                 float* __restrict__ hnext,
                                                 int pack){
    extern __shared__ __nv_bfloat16 sm[];
    __nv_bfloat16* sAh = sm;
    __nv_bfloat16* sAl = sm + 2*H2_ABUF;
    __nv_bfloat16* sBh = sm + 4*H2_ABUF;
    __nv_bfloat16* sBl = sm + 4*H2_ABUF + 2*H2_BBUF;
    uint32_t aSh = smem_u32(sAh), aSl = smem_u32(sAl);
    uint32_t aBh = smem_u32(sBh), aBl = smem_u32(sBl);

    int tid = threadIdx.x, lane = tid & 31, wid = tid >> 5;
    int wm = wid & 1, wn = wid >> 1;
    int n0 = blockIdx.x*128, b = blockIdx.y;

    const __nv_bfloat16* Bh = g_whi + ((size_t)b*HW + n0)*KPAD;
    const __nv_bfloat16* Bl = g_wlo + ((size_t)b*HW + n0)*KPAD;

    int arow = wm*48 + (lane & 15);
    int acol = (lane >> 4) * 8;
    int brow = wn*32 + (lane & 7) + ((lane >> 4) & 1)*8;
    int bcol = ((lane >> 3) & 1) * 8;

    float c[3][3][4][4];
    #pragma unroll
    for (int mt = 0; mt < 3; mt++)
        #pragma unroll
        for (int i = 0; i < 3; i++)
            #pragma unroll
            for (int j = 0; j < 4; j++)
                #pragma unroll
                for (int q = 0; q < 4; q++) c[mt][i][j][q] = 0.f;

    #define H2G_STAGE(chunk, buf) do { \
        uint32_t sbA = (uint32_t)(buf)*(H2_ABUF*2); \
        uint32_t sbB = (uint32_t)(buf)*(H2_BBUF*2); \
        for (int e = tid; e < 1152; e += 256){ \
            int r = e >> 2, u = e & 3; \
            size_t goff = (size_t)r*KPAD + (chunk)*32 + u*8; \
            uint32_t soff = sbA + (uint32_t)(r*TS + u*8)*2u; \
            CPA16(aSh + soff, g_Ahi + goff); \
            CPA16(aSl + soff, g_Alo + goff); \
        } \
        for (int e = tid; e < 512; e += 256){ \
            int r = e >> 2, u = e & 3; \
            size_t goff = (size_t)r*KPAD + (chunk)*32 + u*8; \
            uint32_t soff = sbB + (uint32_t)(r*TS + u*8)*2u; \
            CPA16(aBh + soff, Bh + goff); \
            CPA16(aBl + soff, Bl + goff); \
        } \
        CPA_COMMIT(); \
    } while(0)

    H2G_STAGE(0, 0);
    for (int chunk = 0; chunk < 15; chunk++){
        if (chunk + 1 < 15){
            H2G_STAGE(chunk + 1, (chunk + 1) & 1);
            asm volatile("cp.async.wait_group 1;" ::: "memory");
        } else {
            asm volatile("cp.async.wait_group 0;" ::: "memory");
        }
        __syncthreads();

        uint32_t sbA = (uint32_t)(chunk & 1)*(H2_ABUF*2);
        uint32_t sbB = (uint32_t)(chunk & 1)*(H2_BBUF*2);
        #pragma unroll
        for (int ks = 0; ks < 2; ks++){
            int kc = ks*16;
            uint32_t bh[2][4], bl[2][4];
            #pragma unroll
            for (int jp = 0; jp < 2; jp++){
                uint32_t off = sbB + 2u*((brow + jp*16)*TS + kc + bcol);
                ldm_x4(bh[jp], aBh + off);
                ldm_x4(bl[jp], aBl + off);
            }
            #pragma unroll
            for (int mt = 0; mt < 3; mt++){
                uint32_t ah[3][4], al[3][4];
                #pragma unroll
                for (int mi = 0; mi < 3; mi++){
                    uint32_t off = sbA + 2u*((mt*96 + arow + mi*16)*TS + kc + acol);
                    ldm_x4(ah[mi], aSh + off);
                    ldm_x4(al[mi], aSl + off);
                }
                #pragma unroll
                for (int mi = 0; mi < 3; mi++){
                    #pragma unroll
                    for (int j = 0; j < 4; j++){
                        uint32_t* fh = &bh[j >> 1][(j & 1)*2];
                        uint32_t* fl2 = &bl[j >> 1][(j & 1)*2];
                        MMA_BF16(c[mt][mi][j], ah[mi], fh);
                        MMA_BF16(c[mt][mi][j], ah[mi], fl2);
                        MMA_BF16(c[mt][mi][j], al[mi], fh);
                    }
                }
            }
        }
        __syncthreads();
    }

    // ---- fused GRU gate epilogue ----
    __syncthreads();
    float* sF = reinterpret_cast<float*>(sm);   // [128 px][stride 100]

    const float* i2hb = g_i2h + (size_t)(t*Bg + b)*FH3*HW;
    const float* hpb  = hprev + (size_t)b*Fch*HW;
    float* hnb        = hnext + (size_t)b*Fch*HW;

    #pragma unroll
    for (int mi = 0; mi < 3; mi++){
        int fc0 = wm*48 + mi*16 + (lane >> 2);
        #pragma unroll
        for (int j = 0; j < 4; j++){
            int pl = wn*32 + (lane & 3)*2 + j*8;
            int p = n0 + pl;
            #pragma unroll
            for (int half = 0; half < 2; half++){
                int fc = fc0 + half*8;
                int q0 = half*2;
                float rb = bias[fc], ub = bias[96 + fc], mb = bias[192 + fc];
                float2 i2r = *reinterpret_cast<const float2*>(i2hb + (size_t)fc*HW + p);
                float2 i2u = *reinterpret_cast<const float2*>(i2hb + (size_t)(96+fc)*HW + p);
                float2 i2m = *reinterpret_cast<const float2*>(i2hb + (size_t)(192+fc)*HW + p);
                float2 hpv = *reinterpret_cast<const float2*>(hpb + (size_t)fc*HW + p);
                float nh[2];
                #pragma unroll
                for (int s = 0; s < 2; s++){
                    float hr = c[0][mi][j][q0+s] + rb;
                    float hu = c[1][mi][j][q0+s] + ub;
                    float hm = c[2][mi][j][q0+s] + mb;
                    float ir = s ? i2r.y : i2r.x;
                    float iu = s ? i2u.y : i2u.x;
                    float im = s ? i2m.y : i2m.x;
                    float hp = s ? hpv.y : hpv.x;
                    float reset  = sigm(ir + hr);
                    float update = sigm(iu + hu);
                    float newmem = leaky(im + reset*hm);
                    nh[s] = update*hp + (1.f - update)*newmem;
                }
                float2 wv; wv.x = nh[0]; wv.y = nh[1];
                *reinterpret_cast<float2*>(hnb + (size_t)fc*HW + p) = wv;
                sF[pl*100 + fc]     = nh[0];
                sF[(pl+1)*100 + fc] = nh[1];
            }
        }
    }
    __syncthreads();
    if (pack){
        size_t slotn = (size_t)((t+1)*Bg + b)*HW;
        for (int e = tid; e < 128*12; e += 256){
            int pl = e/12, u = e%12;
            const float* src = sF + pl*100 + u*8;
            uint32_t hw[4];
            #pragma unroll
            for (int q = 0; q < 4; q++)
                hw[q] = pack2(src[2*q], src[2*q+1]);
            size_t off = (slotn + n0 + pl)*CH + 8 + u*8;
            *reinterpret_cast<uint4*>(g_inhi + off) = *reinterpret_cast<uint4*>(hw);
        }
    }
}

// ============================================================
extern "C" void kernel_launch(void* const* d_in, const int* in_sizes, int n_in,
                              void* d_out, int out_size){
    const float* inputs = (const float*)d_in[0];
    const float* h0     = (const float*)d_in[1];
    const float* w_i2h  = (const float*)d_in[2];
    const float* b_i2h  = (const float*)d_in[3];
    const float* w_i2f  = (const float*)d_in[4];
    const float* b_i2f  = (const float*)d_in[5];
    const float* w_h2f  = (const float*)d_in[6];
    const float* b_h2f  = (const float*)d_in[7];
    const float* w_fl   = (const float*)d_in[8];
    const float* b_fl   = (const float*)d_in[9];
    const float* w_ret  = (const float*)d_in[10];
    const float* b_ret  = (const float*)d_in[11];
    float* out = (float*)d_out;

    cudaFuncSetAttribute(k_fconv,  cudaFuncAttributeMaxDynamicSharedMemorySize, FSM_BYTES);
    cudaFuncSetAttribute(k_flowsT, cudaFuncAttributeMaxDynamicSharedMemorySize, FSM_BYTES);
    cudaFuncSetAttribute(k_h2hg,   cudaFuncAttributeMaxDynamicSharedMemorySize, H2_SMEM);

    // once per launch
    k_prepX   <<<(Sg*Bg*HW + 255)/256, 256>>>(inputs, h0);
    k_prepWall<<<(89600 + 25600 + 20736 + 255)/256, 256>>>(w_i2f, w_h2f, w_fl, w_i2h);
    k_prepA   <<<(FH3*KPAD + 255)/256, 256>>>(w_ret);
    k_i2hT    <<<dim3(48, Sg*Bg, 3), 256>>>(b_i2h);

    for (int t = 0; t < Sg; t++){
        const float* h = (t == 0) ? h0 : out + (size_t)(t-1)*STEP_ELEMS;
        float* hn = out + (size_t)t*STEP_ELEMS;

        k_fconv <<<dim3(48, Bg), 256, FSM_BYTES>>>(t, b_i2f, b_h2f);
        k_flowsT<<<dim3(48, Bg), 256, FSM_BYTES>>>(b_fl);
        k_warp  <<<dim3(Bg*Lk, Hh), 96>>>(h);
        k_h2hg  <<<dim3(HW/128, Bg), 256, H2_SMEM>>>(t, b_ret, h, hn, (t < Sg-1) ? 1 : 0);
    }

    const size_t OUT_SEQ = (size_t)Sg*STEP_ELEMS;
    if ((size_t)out_size >= OUT_SEQ + STEP_ELEMS){
        cudaMemcpyAsync(out + OUT_SEQ, out + (size_t)(Sg-1)*STEP_ELEMS,
                        (size_t)STEP_ELEMS*sizeof(float),
                        cudaMemcpyDeviceToDevice);
    }
}

// round 10
// speedup vs baseline: 4.8033x; 1.0899x over previous
#include <cuda_runtime.h>
#include <cuda_fp16.h>
#include <cstdint>
#include <math.h>

#define Hh 96
#define Ww 96
#define HW 9216
#define Fch 96
#define CIN 8
#define Lk 5
#define Sg 10
#define Bg 4
#define FH3 288          // 3*F
#define K1 480           // L*F
#define KPAD 512         // row STRIDE of k-major operands (pad cols never read)
#define CH 112           // packed input channels: 8 x | 96 h | 8 zero
#define STEP_ELEMS (Bg*Fch*HW)   // 3,538,944

// ---- scratch (device globals) ----
__device__ float g_i2h[(size_t)Sg*Bg*FH3*HW];                 // 425 MB (once)
__device__ float g_flows[Bg*10*HW];
__device__ __align__(16) __half g_whi[(size_t)Bg*HW*KPAD];    // warped^T hi [b][p][k]
__device__ __align__(16) __half g_Ahi[(size_t)FH3*KPAD];      // w_ret hi [m][k]
__device__ __align__(16) __half g_Alo[(size_t)FH3*KPAD];
// fconv inputs: per-step slots [Sg][Bg][p][112]
// hi: all channels. lo: x-channels + slot-0 h channels (for 3-term i2h).
__device__ __align__(16) __half g_inhi[(size_t)Sg*Bg*HW*CH];
__device__ __align__(16) __half g_inlo[(size_t)Sg*Bg*HW*CH];
__device__ __align__(16) __half g_wfhi[7*25*32*16];           // [chunk][tap][oc][16]
// f (1-term) [b][p][32]
__device__ __align__(16) __half g_fhi[(size_t)Bg*HW*32];
// flows weights [chunk2][tap25][oc32][16] (oc>=10 zero)
__device__ __align__(16) __half g_w2hi[2*25*32*16];
// i2h weights [ocg3][tap9][oc96][8] hi/lo
__device__ __align__(16) __half g_w3hi[3*9*96*8];
__device__ __align__(16) __half g_w3lo[3*9*96*8];

__device__ __forceinline__ float leaky(float v){ return v > 0.f ? v : 0.2f*v; }
__device__ __forceinline__ float sigm(float v){ return 1.f/(1.f + expf(-v)); }

__device__ __forceinline__ uint32_t smem_u32(const void* p){
    uint32_t a;
    asm("{ .reg .u64 t; cvta.to.shared.u64 t, %1; cvt.u32.u64 %0, t; }" : "=r"(a) : "l"(p));
    return a;
}
__device__ __forceinline__ void ldm_x4(uint32_t* r, uint32_t addr){
    asm volatile("ldmatrix.sync.aligned.m8n8.x4.shared.b16 {%0,%1,%2,%3}, [%4];"
        : "=r"(r[0]), "=r"(r[1]), "=r"(r[2]), "=r"(r[3]) : "r"(addr));
}
__device__ __forceinline__ void ldm_x2(uint32_t* r, uint32_t addr){
    asm volatile("ldmatrix.sync.aligned.m8n8.x2.shared.b16 {%0,%1}, [%2];"
        : "=r"(r[0]), "=r"(r[1]) : "r"(addr));
}
#define MMA_F16(c, a, b) \
    asm volatile("mma.sync.aligned.m16n8k16.row.col.f32.f16.f16.f32 " \
        "{%0,%1,%2,%3}, {%4,%5,%6,%7}, {%8,%9}, {%0,%1,%2,%3};" \
        : "+f"((c)[0]), "+f"((c)[1]), "+f"((c)[2]), "+f"((c)[3]) \
        : "r"((a)[0]), "r"((a)[1]), "r"((a)[2]), "r"((a)[3]), \
          "r"((b)[0]), "r"((b)[1]))
#define MMA_F16_K8(c, a, b) \
    asm volatile("mma.sync.aligned.m16n8k8.row.col.f32.f16.f16.f32 " \
        "{%0,%1,%2,%3}, {%4,%5}, {%6}, {%0,%1,%2,%3};" \
        : "+f"((c)[0]), "+f"((c)[1]), "+f"((c)[2]), "+f"((c)[3]) \
        : "r"((a)[0]), "r"((a)[1]), "r"(b))
#define CPA16(sm, gp) asm volatile("cp.async.ca.shared.global [%0], [%1], 16;" :: "r"(sm), "l"(gp))
#define CPA_COMMIT()  asm volatile("cp.async.commit_group;" ::: "memory")

__device__ __forceinline__ void split2(float v0, float v1, uint32_t& hw, uint32_t& lw){
    __half h0 = __float2half(v0), h1 = __float2half(v1);
    __half l0 = __float2half(v0 - __half2float(h0));
    __half l1 = __float2half(v1 - __half2float(h1));
    __half2 hp = __halves2half2(h0, h1);
    __half2 lp = __halves2half2(l0, l1);
    hw = *reinterpret_cast<uint32_t*>(&hp);
    lw = *reinterpret_cast<uint32_t*>(&lp);
}
__device__ __forceinline__ uint32_t pack2(float v0, float v1){
    __half2 hp = __halves2half2(__float2half(v0), __float2half(v1));
    return *reinterpret_cast<uint32_t*>(&hp);
}

// ============================================================
// k_prepX (once): pack x channels for ALL step slots, zero pad ch,
// and slot-0 h channels from h0.
// ============================================================
__global__ void k_prepX(const float* __restrict__ inputs, const float* __restrict__ h0){
    int idx = blockIdx.x*blockDim.x + threadIdx.x;
    if (idx >= Sg*Bg*HW) return;
    int p = idx % HW, b = (idx/HW) % Bg, t = idx/(HW*Bg);
    size_t base = ((size_t)(t*Bg + b)*HW + p)*CH;
    const float* xp = inputs + ((size_t)(t*Bg + b)*CIN)*HW + p;
    uint32_t hw[4], lw[4];
    #pragma unroll
    for (int q = 0; q < 4; q++)
        split2(xp[(size_t)(2*q)*HW], xp[(size_t)(2*q+1)*HW], hw[q], lw[q]);
    *reinterpret_cast<uint4*>(g_inhi + base) = *reinterpret_cast<uint4*>(hw);
    *reinterpret_cast<uint4*>(g_inlo + base) = *reinterpret_cast<uint4*>(lw);
    uint4 z = make_uint4(0,0,0,0);
    *reinterpret_cast<uint4*>(g_inhi + base + 104) = z;
    if (t == 0){
        const float* hp = h0 + (size_t)b*Fch*HW + p;
        for (int g = 0; g < 12; g++){
            #pragma unroll
            for (int q = 0; q < 4; q++)
                split2(hp[(size_t)(g*8 + 2*q)*HW], hp[(size_t)(g*8 + 2*q+1)*HW], hw[q], lw[q]);
            *reinterpret_cast<uint4*>(g_inhi + base + 8 + g*8) = *reinterpret_cast<uint4*>(hw);
            *reinterpret_cast<uint4*>(g_inlo + base + 8 + g*8) = *reinterpret_cast<uint4*>(lw);
        }
    }
}

// ============================================================
// k_prepWall (once): conv-weight repacks (fp16)
// ============================================================
__global__ void k_prepWall(const float* __restrict__ w_i2f, const float* __restrict__ w_h2f,
                           const float* __restrict__ w_fl,  const float* __restrict__ w_i2h){
    int idx = blockIdx.x*blockDim.x + threadIdx.x;
    if (idx < 89600){
        int o = idx;
        int kc = o & 15, oc = (o >> 4) & 31, tap = (o >> 9) % 25, chunk = o / 12800;
        int ch = chunk*16 + kc;
        float v = 0.f;
        if (ch < 8)        v = w_i2f[(oc*8 + ch)*25 + tap];
        else if (ch < 104) v = w_h2f[((size_t)oc*Fch + (ch-8))*25 + tap];
        g_wfhi[o] = __float2half(v);
    } else if (idx < 89600 + 25600){
        int o = idx - 89600;
        int kc = o & 15, oc = (o >> 4) & 31, tap = (o >> 9) % 25, chunk = o / 12800;
        int ch = chunk*16 + kc;
        float v = (oc < 10) ? w_fl[((size_t)oc*32 + ch)*25 + tap] : 0.f;
        g_w2hi[o] = __float2half(v);
    } else if (idx < 89600 + 25600 + 20736){
        int o = idx - 89600 - 25600;
        int ch = o & 7, oc = (o >> 3) % 96, tap = (o/(96*8)) % 9, ocg = o/(9*96*8);
        float v = w_i2h[((size_t)(ocg*96 + oc)*CIN + ch)*9 + tap];
        __half hi = __float2half(v);
        g_w3hi[o] = hi;
        g_w3lo[o] = __float2half(v - __half2float(hi));
    }
}

// ============================================================
// i2h as implicit GEMM (m16n8k8, fp16 hi/lo 3-term), runs once
// ============================================================
__global__ void __launch_bounds__(256, 2) k_i2hT(const float* __restrict__ bias){
    __shared__ __half sInH[400*8], sInL[400*8];
    __shared__ __half sWH[9*96*8], sWL[9*96*8];
    uint32_t aInH = smem_u32(sInH), aInL = smem_u32(sInL);
    uint32_t aWH  = smem_u32(sWH),  aWL  = smem_u32(sWL);

    int tid = threadIdx.x, lane = tid & 31, wid = tid >> 5;
    int wm = wid & 3, wn = wid >> 2;
    int y0 = blockIdx.x*2, img = blockIdx.y, ocg = blockIdx.z;

    for (int e = tid; e < 400; e += 256){
        int row = e/100, cc = e%100;
        int y = y0 + row - 1, x = cc - 1;
        uint4 vh = make_uint4(0,0,0,0), vl = make_uint4(0,0,0,0);
        if ((unsigned)y < 96u && (unsigned)x < 96u){
            size_t off = ((size_t)img*HW + y*Ww + x)*CH;
            vh = *reinterpret_cast<const uint4*>(g_inhi + off);
            vl = *reinterpret_cast<const uint4*>(g_inlo + off);
        }
        *reinterpret_cast<uint4*>(sInH + e*8) = vh;
        *reinterpret_cast<uint4*>(sInL + e*8) = vl;
    }
    for (int e = tid; e < 864; e += 256){
        reinterpret_cast<uint4*>(sWH)[e] = reinterpret_cast<const uint4*>(g_w3hi + (size_t)ocg*9*96*8)[e];
        reinterpret_cast<uint4*>(sWL)[e] = reinterpret_cast<const uint4*>(g_w3lo + (size_t)ocg*9*96*8)[e];
    }
    __syncthreads();

    float c[3][6][4];
    #pragma unroll
    for (int i = 0; i < 3; i++)
        #pragma unroll
        for (int j = 0; j < 6; j++)
            #pragma unroll
            for (int q = 0; q < 4; q++) c[i][j][q] = 0.f;

    #pragma unroll 1
    for (int tap = 0; tap < 9; tap++){
        int dy = tap/3, dx = tap%3;
        uint32_t bh[6], bl[6];
        {
            ldm_x4(bh, aWH + 2u*(uint32_t)((tap*96 + wn*48 + lane)*8));
            ldm_x4(bl, aWL + 2u*(uint32_t)((tap*96 + wn*48 + lane)*8));
            uint32_t a2 = 2u*(uint32_t)((tap*96 + wn*48 + 32 + (lane & 15))*8);
            ldm_x2(bh + 4, aWH + a2);
            ldm_x2(bl + 4, aWL + a2);
        }
        uint32_t ah[3][2], al[3][2];
        #pragma unroll
        for (int mi = 0; mi < 3; mi++){
            int tmi = wm*3 + mi;
            int r = tmi/6, xb = (tmi%6)*16;
            uint32_t aoff = 2u*(uint32_t)(((r+dy)*100 + xb + (lane&15) + dx)*8);
            ldm_x2(ah[mi], aInH + aoff);
            ldm_x2(al[mi], aInL + aoff);
        }
        #pragma unroll
        for (int mi = 0; mi < 3; mi++){
            #pragma unroll
            for (int j = 0; j < 6; j++){
                MMA_F16_K8(c[mi][j], ah[mi], bh[j]);
                MMA_F16_K8(c[mi][j], ah[mi], bl[j]);
                MMA_F16_K8(c[mi][j], al[mi], bh[j]);
            }
        }
    }

    float* Ob = g_i2h + (size_t)img*FH3*HW;
    #pragma unroll
    for (int mi = 0; mi < 3; mi++){
        int tmi = wm*3 + mi;
        int r = tmi/6, xb = (tmi%6)*16;
        int p = (y0 + r)*Ww + xb + (lane>>2);
        #pragma unroll
        for (int j = 0; j < 6; j++){
            int oc = ocg*96 + wn*48 + j*8 + (lane&3)*2;
            float bv0 = bias[oc], bv1 = bias[oc+1];
            Ob[(size_t)oc*HW + p]           = c[mi][j][0] + bv0;
            Ob[(size_t)(oc+1)*HW + p]       = c[mi][j][1] + bv1;
            Ob[(size_t)oc*HW + p + 8]       = c[mi][j][2] + bv0;
            Ob[(size_t)(oc+1)*HW + p + 8]   = c[mi][j][3] + bv1;
        }
    }
}

// ============================================================
// fconv implicit GEMM — 1-term fp16. CTA = 2 rows x 96 px, N=32.
// ============================================================
#define FSM_BYTES ((14400 + 12800)*2)

__global__ void __launch_bounds__(256, 2) k_fconv(int t,
                                                  const float* __restrict__ b_i2f,
                                                  const float* __restrict__ b_h2f){
    extern __shared__ __half sm[];
    __half* sInH = sm;
    __half* sWH  = sm + 14400;
    uint32_t aInH = smem_u32(sInH), aWH = smem_u32(sWH);

    int tid = threadIdx.x, lane = tid & 31, wid = tid >> 5;
    int wm = wid & 3, wn = wid >> 2;
    int y0 = blockIdx.x*2, b = blockIdx.y;
    size_t slot = (size_t)(t*Bg + b)*HW;

    float c[3][2][4];
    #pragma unroll
    for (int i = 0; i < 3; i++)
        #pragma unroll
        for (int j = 0; j < 2; j++)
            #pragma unroll
            for (int q = 0; q < 4; q++) c[i][j][q] = 0.f;

    for (int chunk = 0; chunk < 7; chunk++){
        __syncthreads();
        for (int e = tid; e < 1200; e += 256){
            int ent = e >> 1, half_ = e & 1;
            int row = ent/100, cc = ent%100;
            int y = y0 + row - 2, x = cc - 2;
            uint4 vh = make_uint4(0,0,0,0);
            if ((unsigned)y < 96u && (unsigned)x < 96u){
                size_t off = (slot + y*Ww + x)*CH + chunk*16 + half_*8;
                vh = *reinterpret_cast<const uint4*>(g_inhi + off);
            }
            *reinterpret_cast<uint4*>(sInH + ent*24 + half_*8) = vh;
        }
        for (int e = tid; e < 1600; e += 256){
            reinterpret_cast<uint4*>(sWH)[e] = reinterpret_cast<const uint4*>(g_wfhi + chunk*12800)[e];
        }
        __syncthreads();

        #pragma unroll 1
        for (int tap = 0; tap < 25; tap++){
            int dy = tap/5, dx = tap%5;
            uint32_t bh[4];
            uint32_t boff = 2u*(uint32_t)((tap*32 + wn*16 + (lane&7) + ((lane>>4)&1)*8)*16
                                          + ((lane>>3)&1)*8);
            ldm_x4(bh, aWH + boff);
            uint32_t ah[3][4];
            #pragma unroll
            for (int mi = 0; mi < 3; mi++){
                int tmi = wm*3 + mi;
                int r = tmi/6, xb = (tmi%6)*16;
                uint32_t aoff = 2u*(uint32_t)(((r+dy)*100 + xb + (lane&15) + dx)*24
                                              + (lane>>4)*8);
                ldm_x4(ah[mi], aInH + aoff);
            }
            #pragma unroll
            for (int mi = 0; mi < 3; mi++){
                #pragma unroll
                for (int j = 0; j < 2; j++){
                    MMA_F16(c[mi][j], ah[mi], &bh[j*2]);
                }
            }
        }
    }

    #pragma unroll
    for (int mi = 0; mi < 3; mi++){
        int tmi = wm*3 + mi;
        int r = tmi/6, xb = (tmi%6)*16;
        int gp = (y0 + r)*Ww + xb + (lane>>2);
        #pragma unroll
        for (int j = 0; j < 2; j++){
            int oc = wn*16 + j*8 + (lane&3)*2;
            float bb0 = b_i2f[oc]   + b_h2f[oc];
            float bb1 = b_i2f[oc+1] + b_h2f[oc+1];
            *reinterpret_cast<uint32_t*>(g_fhi + ((size_t)b*HW + gp)*32 + oc)
                = pack2(leaky(c[mi][j][0] + bb0), leaky(c[mi][j][1] + bb1));
            *reinterpret_cast<uint32_t*>(g_fhi + ((size_t)b*HW + gp + 8)*32 + oc)
                = pack2(leaky(c[mi][j][2] + bb0), leaky(c[mi][j][3] + bb1));
        }
    }
}

// ============================================================
// flows implicit GEMM — 1-term fp16 (2 chunks, oc padded to 32)
// ============================================================
__global__ void __launch_bounds__(256, 2) k_flowsT(const float* __restrict__ b_fl){
    extern __shared__ __half sm[];
    __half* sInH = sm;
    __half* sWH  = sm + 14400;
    uint32_t aInH = smem_u32(sInH), aWH = smem_u32(sWH);

    int tid = threadIdx.x, lane = tid & 31, wid = tid >> 5;
    int wm = wid & 3, wn = wid >> 2;
    int y0 = blockIdx.x*2, b = blockIdx.y;

    float c[3][2][4];
    #pragma unroll
    for (int i = 0; i < 3; i++)
        #pragma unroll
        for (int j = 0; j < 2; j++)
            #pragma unroll
            for (int q = 0; q < 4; q++) c[i][j][q] = 0.f;

    for (int chunk = 0; chunk < 2; chunk++){
        __syncthreads();
        for (int e = tid; e < 1200; e += 256){
            int ent = e >> 1, half_ = e & 1;
            int row = ent/100, cc = ent%100;
            int y = y0 + row - 2, x = cc - 2;
            uint4 vh = make_uint4(0,0,0,0);
            if ((unsigned)y < 96u && (unsigned)x < 96u){
                size_t off = ((size_t)b*HW + y*Ww + x)*32 + chunk*16 + half_*8;
                vh = *reinterpret_cast<const uint4*>(g_fhi + off);
            }
            *reinterpret_cast<uint4*>(sInH + ent*24 + half_*8) = vh;
        }
        for (int e = tid; e < 1600; e += 256){
            reinterpret_cast<uint4*>(sWH)[e] = reinterpret_cast<const uint4*>(g_w2hi + chunk*12800)[e];
        }
        __syncthreads();

        #pragma unroll 1
        for (int tap = 0; tap < 25; tap++){
            int dy = tap/5, dx = tap%5;
            uint32_t bh[4];
            uint32_t boff = 2u*(uint32_t)((tap*32 + wn*16 + (lane&7) + ((lane>>4)&1)*8)*16
                                          + ((lane>>3)&1)*8);
            ldm_x4(bh, aWH + boff);
            uint32_t ah[3][4];
            #pragma unroll
            for (int mi = 0; mi < 3; mi++){
                int tmi = wm*3 + mi;
                int r = tmi/6, xb = (tmi%6)*16;
                uint32_t aoff = 2u*(uint32_t)(((r+dy)*100 + xb + (lane&15) + dx)*24
                                              + (lane>>4)*8);
                ldm_x4(ah[mi], aInH + aoff);
            }
            #pragma unroll
            for (int mi = 0; mi < 3; mi++){
                #pragma unroll
                for (int j = 0; j < 2; j++){
                    MMA_F16(c[mi][j], ah[mi], &bh[j*2]);
                }
            }
        }
    }

    #pragma unroll
    for (int mi = 0; mi < 3; mi++){
        int tmi = wm*3 + mi;
        int r = tmi/6, xb = (tmi%6)*16;
        int gp = (y0 + r)*Ww + xb + (lane>>2);
        #pragma unroll
        for (int j = 0; j < 2; j++){
            int oc = wn*16 + j*8 + (lane&3)*2;
            if (oc < 10){
                float bv0 = b_fl[oc], bv1 = b_fl[oc+1];
                float* f0 = g_flows + ((size_t)b*10 + oc)*HW;
                float* f1 = g_flows + ((size_t)b*10 + oc + 1)*HW;
                f0[gp]     = c[mi][j][0] + bv0;
                f1[gp]     = c[mi][j][1] + bv1;
                f0[gp + 8] = c[mi][j][2] + bv0;
                f1[gp + 8] = c[mi][j][3] + bv1;
            }
        }
    }
}

// ============================================================
// warp: bilinear-warp h -> fp16 hi [b][p][k], smem-staged
// coalesced writes. grid (B*L, H), block 96
// ============================================================
__global__ void k_warp(const float* __restrict__ h){
    __shared__ uint32_t sHi[96*49];
    int bl = blockIdx.x, y = blockIdx.y, tx = threadIdx.x;
    int b = bl / Lk, l = bl % Lk;
    const float* fl = g_flows + (size_t)b*10*HW + y*Ww + tx;
    float fx = fl[(size_t)(2*l)*HW];
    float fy = fl[(size_t)(2*l+1)*HW];
    float vx = (float)tx - fx;
    float vy = (float)y  - fy;
    const float sc = 96.0f/95.0f;
    float ix = vx*sc - 0.5f;
    float iy = vy*sc - 0.5f;
    float fx0 = floorf(ix), fy0 = floorf(iy);
    int ix0 = (int)fx0, iy0 = (int)fy0;
    int ix1 = ix0 + 1, iy1 = iy0 + 1;
    float wx1 = ix - fx0, wy1 = iy - fy0;
    float wx0 = 1.f - wx1, wy0 = 1.f - wy1;
    float mx0 = (ix0 >= 0 && ix0 < Ww) ? 1.f : 0.f;
    float mx1 = (ix1 >= 0 && ix1 < Ww) ? 1.f : 0.f;
    float my0 = (iy0 >= 0 && iy0 < Hh) ? 1.f : 0.f;
    float my1 = (iy1 >= 0 && iy1 < Hh) ? 1.f : 0.f;
    int cx0 = min(max(ix0, 0), Ww-1), cx1 = min(max(ix1, 0), Ww-1);
    int cy0 = min(max(iy0, 0), Hh-1), cy1 = min(max(iy1, 0), Hh-1);
    int o00 = cy0*Ww + cx0, o01 = cy0*Ww + cx1;
    int o10 = cy1*Ww + cx0, o11 = cy1*Ww + cx1;
    float w00 = wy0*wx0*my0*mx0, w01 = wy0*wx1*my0*mx1;
    float w10 = wy1*wx0*my1*mx0, w11 = wy1*wx1*my1*mx1;
    const float* hb = h + (size_t)b*Fch*HW;

    #pragma unroll 1
    for (int c0 = 0; c0 < Fch; c0 += 8){
        #pragma unroll
        for (int j = 0; j < 4; j++){
            const float* p0 = hb + (size_t)(c0 + 2*j)*HW;
            const float* p1 = p0 + HW;
            float v0 = w00*p0[o00] + w01*p0[o01] + w10*p0[o10] + w11*p0[o11];
            float v1 = w00*p1[o00] + w01*p1[o01] + w10*p1[o10] + w11*p1[o11];
            sHi[tx*49 + (c0>>1) + j] = pack2(v0, v1);
        }
    }
    __syncthreads();
    size_t rowbase = ((size_t)b*HW + y*Ww)*KPAD + (size_t)l*Fch;
    for (int e = tx; e < 96*12; e += 96){
        int pl = e/12, u = e%12;
        uint4 vh;
        vh.x = sHi[pl*49 + u*4 + 0]; vh.y = sHi[pl*49 + u*4 + 1];
        vh.z = sHi[pl*49 + u*4 + 2]; vh.w = sHi[pl*49 + u*4 + 3];
        *reinterpret_cast<uint4*>(g_whi + rowbase + (size_t)pl*KPAD + u*8) = vh;
    }
}

// ============================================================
// prep: split w_ret (288 x 480, stride KPAD) fp16 hi/lo
// ============================================================
__global__ void k_prepA(const float* __restrict__ w_ret){
    int idx = blockIdx.x*blockDim.x + threadIdx.x;
    if (idx >= FH3*KPAD) return;
    int m = idx / KPAD, k = idx % KPAD;
    float v = (k < K1) ? w_ret[m*K1 + k] : 0.f;
    __half hi = __float2half(v);
    g_Ahi[idx] = hi;
    g_Alo[idx] = __float2half(v - __half2float(hi));
}

// ============================================================
// FUSED h2h GEMM (2-term fp16: AhBh + AlBh) + GRU gates.
// One CTA = 288 m-rows x 128 pixels. B (hi only) staged once/chunk.
// grid (72, B), 256 thr, dyn smem 112.6 KB
// ============================================================
#define TS 40
#define H2_ABUF (288*TS)
#define H2_BBUF (128*TS)
#define H2_SMEM ((4*H2_ABUF + 2*H2_BBUF)*2)   // 112640 B

__global__ void __launch_bounds__(256, 1) k_h2hg(int t,
                                                 const float* __restrict__ bias,
                                                 const float* __restrict__ hprev,
                                                 float* __restrict__ hnext,
                                                 int pack){
    extern __shared__ __half sm[];
    __half* sAh = sm;                      // 2*H2_ABUF
    __half* sAl = sm + 2*H2_ABUF;          // 2*H2_ABUF
    __half* sBh = sm + 4*H2_ABUF;          // 2*H2_BBUF
    uint32_t aSh = smem_u32(sAh), aSl = smem_u32(sAl), aBh = smem_u32(sBh);

    int tid = threadIdx.x, lane = tid & 31, wid = tid >> 5;
    int wm = wid & 1, wn = wid >> 1;
    int n0 = blockIdx.x*128, b = blockIdx.y;

    const __half* Bh = g_whi + ((size_t)b*HW + n0)*KPAD;

    int arow = wm*48 + (lane & 15);
    int acol = (lane >> 4) * 8;
    int brow = wn*32 + (lane & 7) + ((lane >> 4) & 1)*8;
    int bcol = ((lane >> 3) & 1) * 8;

    float c[3][3][4][4];
    #pragma unroll
    for (int mt = 0; mt < 3; mt++)
        #pragma unroll
        for (int i = 0; i < 3; i++)
            #pragma unroll
            for (int j = 0; j < 4; j++)
                #pragma unroll
                for (int q = 0; q < 4; q++) c[mt][i][j][q] = 0.f;

    #define H2G_STAGE(chunk, buf) do { \
        uint32_t sbA = (uint32_t)(buf)*(H2_ABUF*2); \
        uint32_t sbB = (uint32_t)(buf)*(H2_BBUF*2); \
        for (int e = tid; e < 1152; e += 256){ \
            int r = e >> 2, u = e & 3; \
            size_t goff = (size_t)r*KPAD + (chunk)*32 + u*8; \
            uint32_t soff = sbA + (uint32_t)(r*TS + u*8)*2u; \
            CPA16(aSh + soff, g_Ahi + goff); \
            CPA16(aSl + soff, g_Alo + goff); \
        } \
        for (int e = tid; e < 512; e += 256){ \
            int r = e >> 2, u = e & 3; \
            size_t goff = (size_t)r*KPAD + (chunk)*32 + u*8; \
            uint32_t soff = sbB + (uint32_t)(r*TS + u*8)*2u; \
            CPA16(aBh + soff, Bh + goff); \
        } \
        CPA_COMMIT(); \
    } while(0)

    H2G_STAGE(0, 0);
    for (int chunk = 0; chunk < 15; chunk++){
        if (chunk + 1 < 15){
            H2G_STAGE(chunk + 1, (chunk + 1) & 1);
            asm volatile("cp.async.wait_group 1;" ::: "memory");
        } else {
            asm volatile("cp.async.wait_group 0;" ::: "memory");
        }
        __syncthreads();

        uint32_t sbA = (uint32_t)(chunk & 1)*(H2_ABUF*2);
        uint32_t sbB = (uint32_t)(chunk & 1)*(H2_BBUF*2);
        #pragma unroll
        for (int ks = 0; ks < 2; ks++){
            int kc = ks*16;
            uint32_t bh[2][4];
            #pragma unroll
            for (int jp = 0; jp < 2; jp++){
                uint32_t off = sbB + 2u*((brow + jp*16)*TS + kc + bcol);
                ldm_x4(bh[jp], aBh + off);
            }
            #pragma unroll
            for (int mt = 0; mt < 3; mt++){
                uint32_t ah[3][4], al[3][4];
                #pragma unroll
                for (int mi = 0; mi < 3; mi++){
                    uint32_t off = sbA + 2u*((mt*96 + arow + mi*16)*TS + kc + acol);
                    ldm_x4(ah[mi], aSh + off);
                    ldm_x4(al[mi], aSl + off);
                }
                #pragma unroll
                for (int mi = 0; mi < 3; mi++){
                    #pragma unroll
                    for (int j = 0; j < 4; j++){
                        uint32_t* fh = &bh[j >> 1][(j & 1)*2];
                        MMA_F16(c[mt][mi][j], ah[mi], fh);
                        MMA_F16(c[mt][mi][j], al[mi], fh);
                    }
                }
            }
        }
        __syncthreads();
    }

    // ---- fused GRU gate epilogue ----
    __syncthreads();
    float* sF = reinterpret_cast<float*>(sm);   // [128 px][stride 100]

    const float* i2hb = g_i2h + (size_t)(t*Bg + b)*FH3*HW;
    const float* hpb  = hprev + (size_t)b*Fch*HW;
    float* hnb        = hnext + (size_t)b*Fch*HW;

    #pragma unroll
    for (int mi = 0; mi < 3; mi++){
        int fc0 = wm*48 + mi*16 + (lane >> 2);
        #pragma unroll
        for (int j = 0; j < 4; j++){
            int pl = wn*32 + (lane & 3)*2 + j*8;
            int p = n0 + pl;
            #pragma unroll
            for (int half_ = 0; half_ < 2; half_++){
                int fc = fc0 + half_*8;
                int q0 = half_*2;
                float rb = bias[fc], ub = bias[96 + fc], mb = bias[192 + fc];
                float2 i2r = *reinterpret_cast<const float2*>(i2hb + (size_t)fc*HW + p);
                float2 i2u = *reinterpret_cast<const float2*>(i2hb + (size_t)(96+fc)*HW + p);
                float2 i2m = *reinterpret_cast<const float2*>(i2hb + (size_t)(192+fc)*HW + p);
                float2 hpv = *reinterpret_cast<const float2*>(hpb + (size_t)fc*HW + p);
                float nh[2];
                #pragma unroll
                for (int s = 0; s < 2; s++){
                    float hr = c[0][mi][j][q0+s] + rb;
                    float hu = c[1][mi][j][q0+s] + ub;
                    float hm = c[2][mi][j][q0+s] + mb;
                    float ir = s ? i2r.y : i2r.x;
                    float iu = s ? i2u.y : i2u.x;
                    float im = s ? i2m.y : i2m.x;
                    float hp = s ? hpv.y : hpv.x;
                    float reset  = sigm(ir + hr);
                    float update = sigm(iu + hu);
                    float newmem = leaky(im + reset*hm);
                    nh[s] = update*hp + (1.f - update)*newmem;
                }
                float2 wv; wv.x = nh[0]; wv.y = nh[1];
                *reinterpret_cast<float2*>(hnb + (size_t)fc*HW + p) = wv;
                sF[pl*100 + fc]     = nh[0];
                sF[(pl+1)*100 + fc] = nh[1];
            }
        }
    }
    __syncthreads();
    if (pack){
        size_t slotn = (size_t)((t+1)*Bg + b)*HW;
        for (int e = tid; e < 128*12; e += 256){
            int pl = e/12, u = e%12;
            const float* src = sF + pl*100 + u*8;
            uint32_t hw[4];
            #pragma unroll
            for (int q = 0; q < 4; q++)
                hw[q] = pack2(src[2*q], src[2*q+1]);
            size_t off = (slotn + n0 + pl)*CH + 8 + u*8;
            *reinterpret_cast<uint4*>(g_inhi + off) = *reinterpret_cast<uint4*>(hw);
        }
    }
}

// ============================================================
extern "C" void kernel_launch(void* const* d_in, const int* in_sizes, int n_in,
                              void* d_out, int out_size){
    const float* inputs = (const float*)d_in[0];
    const float* h0     = (const float*)d_in[1];
    const float* w_i2h  = (const float*)d_in[2];
    const float* b_i2h  = (const float*)d_in[3];
    const float* w_i2f  = (const float*)d_in[4];
    const float* b_i2f  = (const float*)d_in[5];
    const float* w_h2f  = (const float*)d_in[6];
    const float* b_h2f  = (const float*)d_in[7];
    const float* w_fl   = (const float*)d_in[8];
    const float* b_fl   = (const float*)d_in[9];
    const float* w_ret  = (const float*)d_in[10];
    const float* b_ret  = (const float*)d_in[11];
    float* out = (float*)d_out;

    cudaFuncSetAttribute(k_fconv,  cudaFuncAttributeMaxDynamicSharedMemorySize, FSM_BYTES);
    cudaFuncSetAttribute(k_flowsT, cudaFuncAttributeMaxDynamicSharedMemorySize, FSM_BYTES);
    cudaFuncSetAttribute(k_h2hg,   cudaFuncAttributeMaxDynamicSharedMemorySize, H2_SMEM);

    // once per launch
    k_prepX   <<<(Sg*Bg*HW + 255)/256, 256>>>(inputs, h0);
    k_prepWall<<<(89600 + 25600 + 20736 + 255)/256, 256>>>(w_i2f, w_h2f, w_fl, w_i2h);
    k_prepA   <<<(FH3*KPAD + 255)/256, 256>>>(w_ret);
    k_i2hT    <<<dim3(48, Sg*Bg, 3), 256>>>(b_i2h);

    for (int t = 0; t < Sg; t++){
        const float* h = (t == 0) ? h0 : out + (size_t)(t-1)*STEP_ELEMS;
        float* hn = out + (size_t)t*STEP_ELEMS;

        k_fconv <<<dim3(48, Bg), 256, FSM_BYTES>>>(t, b_i2f, b_h2f);
        k_flowsT<<<dim3(48, Bg), 256, FSM_BYTES>>>(b_fl);
        k_warp  <<<dim3(Bg*Lk, Hh), 96>>>(h);
        k_h2hg  <<<dim3(HW/128, Bg), 256, H2_SMEM>>>(t, b_ret, h, hn, (t < Sg-1) ? 1 : 0);
    }

    const size_t OUT_SEQ = (size_t)Sg*STEP_ELEMS;
    if ((size_t)out_size >= OUT_SEQ + STEP_ELEMS){
        cudaMemcpyAsync(out + OUT_SEQ, out + (size_t)(Sg-1)*STEP_ELEMS,
                        (size_t)STEP_ELEMS*sizeof(float),
                        cudaMemcpyDeviceToDevice);
    }
}

// round 11
// speedup vs baseline: 5.0371x; 1.0487x over previous
#include <cuda_runtime.h>
#include <cuda_fp16.h>
#include <cstdint>
#include <math.h>

#define Hh 96
#define Ww 96
#define HW 9216
#define Fch 96
#define CIN 8
#define Lk 5
#define Sg 10
#define Bg 4
#define FH3 288          // 3*F
#define K1 480           // L*F
#define KPAD 512         // row STRIDE of k-major operands (pad cols never read)
#define CH 112           // packed input channels: 8 x | 96 h | 8 zero
#define STEP_ELEMS (Bg*Fch*HW)   // 3,538,944

// ---- scratch (device globals) ----
__device__ __align__(16) __half g_i2h[(size_t)Sg*Bg*FH3*HW];  // 212 MB (once), fp16
__device__ float g_flows[Bg*10*HW];
__device__ __align__(16) __half g_whi[(size_t)Bg*HW*KPAD];    // warped^T hi [b][p][k]
__device__ __align__(16) __half g_Ahi[(size_t)FH3*KPAD];      // w_ret hi [m][k]
__device__ __align__(16) __half g_Alo[(size_t)FH3*KPAD];
// fconv inputs: per-step slots [Sg][Bg][p][112] (hi only)
__device__ __align__(16) __half g_inhi[(size_t)Sg*Bg*HW*CH];
__device__ __align__(16) __half g_wfhi[7*25*32*16];           // [chunk][tap][oc][16]
// f (1-term) [b][p][32]
__device__ __align__(16) __half g_fhi[(size_t)Bg*HW*32];
// flows weights [chunk2][tap25][oc32][16] (oc>=10 zero)
__device__ __align__(16) __half g_w2hi[2*25*32*16];
// i2h weights [ocg3][tap9][oc96][8] hi/lo
__device__ __align__(16) __half g_w3hi[3*9*96*8];
__device__ __align__(16) __half g_w3lo[3*9*96*8];

__device__ __forceinline__ float leaky(float v){ return v > 0.f ? v : 0.2f*v; }
__device__ __forceinline__ float sigm(float v){ return 1.f/(1.f + expf(-v)); }

__device__ __forceinline__ uint32_t smem_u32(const void* p){
    uint32_t a;
    asm("{ .reg .u64 t; cvta.to.shared.u64 t, %1; cvt.u32.u64 %0, t; }" : "=r"(a) : "l"(p));
    return a;
}
__device__ __forceinline__ void ldm_x4(uint32_t* r, uint32_t addr){
    asm volatile("ldmatrix.sync.aligned.m8n8.x4.shared.b16 {%0,%1,%2,%3}, [%4];"
        : "=r"(r[0]), "=r"(r[1]), "=r"(r[2]), "=r"(r[3]) : "r"(addr));
}
__device__ __forceinline__ void ldm_x2(uint32_t* r, uint32_t addr){
    asm volatile("ldmatrix.sync.aligned.m8n8.x2.shared.b16 {%0,%1}, [%2];"
        : "=r"(r[0]), "=r"(r[1]) : "r"(addr));
}
#define MMA_F16(c, a, b) \
    asm volatile("mma.sync.aligned.m16n8k16.row.col.f32.f16.f16.f32 " \
        "{%0,%1,%2,%3}, {%4,%5,%6,%7}, {%8,%9}, {%0,%1,%2,%3};" \
        : "+f"((c)[0]), "+f"((c)[1]), "+f"((c)[2]), "+f"((c)[3]) \
        : "r"((a)[0]), "r"((a)[1]), "r"((a)[2]), "r"((a)[3]), \
          "r"((b)[0]), "r"((b)[1]))
#define MMA_F16_K8(c, a, b) \
    asm volatile("mma.sync.aligned.m16n8k8.row.col.f32.f16.f16.f32 " \
        "{%0,%1,%2,%3}, {%4,%5}, {%6}, {%0,%1,%2,%3};" \
        : "+f"((c)[0]), "+f"((c)[1]), "+f"((c)[2]), "+f"((c)[3]) \
        : "r"((a)[0]), "r"((a)[1]), "r"(b))
#define CPA16(sm, gp) asm volatile("cp.async.ca.shared.global [%0], [%1], 16;" :: "r"(sm), "l"(gp))
#define CPA_COMMIT()  asm volatile("cp.async.commit_group;" ::: "memory")

__device__ __forceinline__ uint32_t pack2(float v0, float v1){
    __half2 hp = __halves2half2(__float2half(v0), __float2half(v1));
    return *reinterpret_cast<uint32_t*>(&hp);
}

// ============================================================
// k_prepX (once): pack x channels (hi) for ALL step slots, zero pad,
// slot-0 h channels from h0.
// ============================================================
__global__ void k_prepX(const float* __restrict__ inputs, const float* __restrict__ h0){
    int idx = blockIdx.x*blockDim.x + threadIdx.x;
    if (idx >= Sg*Bg*HW) return;
    int p = idx % HW, b = (idx/HW) % Bg, t = idx/(HW*Bg);
    size_t base = ((size_t)(t*Bg + b)*HW + p)*CH;
    const float* xp = inputs + ((size_t)(t*Bg + b)*CIN)*HW + p;
    uint32_t hw[4];
    #pragma unroll
    for (int q = 0; q < 4; q++)
        hw[q] = pack2(xp[(size_t)(2*q)*HW], xp[(size_t)(2*q+1)*HW]);
    *reinterpret_cast<uint4*>(g_inhi + base) = *reinterpret_cast<uint4*>(hw);
    uint4 z = make_uint4(0,0,0,0);
    *reinterpret_cast<uint4*>(g_inhi + base + 104) = z;
    if (t == 0){
        const float* hp = h0 + (size_t)b*Fch*HW + p;
        for (int g = 0; g < 12; g++){
            #pragma unroll
            for (int q = 0; q < 4; q++)
                hw[q] = pack2(hp[(size_t)(g*8 + 2*q)*HW], hp[(size_t)(g*8 + 2*q+1)*HW]);
            *reinterpret_cast<uint4*>(g_inhi + base + 8 + g*8) = *reinterpret_cast<uint4*>(hw);
        }
    }
}

// ============================================================
// k_prepWall (once): conv-weight repacks (fp16)
// ============================================================
__global__ void k_prepWall(const float* __restrict__ w_i2f, const float* __restrict__ w_h2f,
                           const float* __restrict__ w_fl,  const float* __restrict__ w_i2h){
    int idx = blockIdx.x*blockDim.x + threadIdx.x;
    if (idx < 89600){
        int o = idx;
        int kc = o & 15, oc = (o >> 4) & 31, tap = (o >> 9) % 25, chunk = o / 12800;
        int ch = chunk*16 + kc;
        float v = 0.f;
        if (ch < 8)        v = w_i2f[(oc*8 + ch)*25 + tap];
        else if (ch < 104) v = w_h2f[((size_t)oc*Fch + (ch-8))*25 + tap];
        g_wfhi[o] = __float2half(v);
    } else if (idx < 89600 + 25600){
        int o = idx - 89600;
        int kc = o & 15, oc = (o >> 4) & 31, tap = (o >> 9) % 25, chunk = o / 12800;
        int ch = chunk*16 + kc;
        float v = (oc < 10) ? w_fl[((size_t)oc*32 + ch)*25 + tap] : 0.f;
        g_w2hi[o] = __float2half(v);
    } else if (idx < 89600 + 25600 + 20736){
        int o = idx - 89600 - 25600;
        int ch = o & 7, oc = (o >> 3) % 96, tap = (o/(96*8)) % 9, ocg = o/(9*96*8);
        float v = w_i2h[((size_t)(ocg*96 + oc)*CIN + ch)*9 + tap];
        __half hi = __float2half(v);
        g_w3hi[o] = hi;
        g_w3lo[o] = __float2half(v - __half2float(hi));
    }
}

// ============================================================
// i2h implicit GEMM (m16n8k8, fp16 2-term: ah*bh + ah*bl), once.
// Output fp16 planar [img][oc][p].
// ============================================================
__global__ void __launch_bounds__(256, 2) k_i2hT(const float* __restrict__ bias){
    __shared__ __half sInH[400*8];
    __shared__ __half sWH[9*96*8], sWL[9*96*8];
    uint32_t aInH = smem_u32(sInH);
    uint32_t aWH  = smem_u32(sWH),  aWL  = smem_u32(sWL);

    int tid = threadIdx.x, lane = tid & 31, wid = tid >> 5;
    int wm = wid & 3, wn = wid >> 2;
    int y0 = blockIdx.x*2, img = blockIdx.y, ocg = blockIdx.z;

    for (int e = tid; e < 400; e += 256){
        int row = e/100, cc = e%100;
        int y = y0 + row - 1, x = cc - 1;
        uint4 vh = make_uint4(0,0,0,0);
        if ((unsigned)y < 96u && (unsigned)x < 96u)
            vh = *reinterpret_cast<const uint4*>(g_inhi + ((size_t)img*HW + y*Ww + x)*CH);
        *reinterpret_cast<uint4*>(sInH + e*8) = vh;
    }
    for (int e = tid; e < 864; e += 256){
        reinterpret_cast<uint4*>(sWH)[e] = reinterpret_cast<const uint4*>(g_w3hi + (size_t)ocg*9*96*8)[e];
        reinterpret_cast<uint4*>(sWL)[e] = reinterpret_cast<const uint4*>(g_w3lo + (size_t)ocg*9*96*8)[e];
    }
    __syncthreads();

    float c[3][6][4];
    #pragma unroll
    for (int i = 0; i < 3; i++)
        #pragma unroll
        for (int j = 0; j < 6; j++)
            #pragma unroll
            for (int q = 0; q < 4; q++) c[i][j][q] = 0.f;

    #pragma unroll 1
    for (int tap = 0; tap < 9; tap++){
        int dy = tap/3, dx = tap%3;
        uint32_t bh[6], bl[6];
        {
            ldm_x4(bh, aWH + 2u*(uint32_t)((tap*96 + wn*48 + lane)*8));
            ldm_x4(bl, aWL + 2u*(uint32_t)((tap*96 + wn*48 + lane)*8));
            uint32_t a2 = 2u*(uint32_t)((tap*96 + wn*48 + 32 + (lane & 15))*8);
            ldm_x2(bh + 4, aWH + a2);
            ldm_x2(bl + 4, aWL + a2);
        }
        uint32_t ah[3][2];
        #pragma unroll
        for (int mi = 0; mi < 3; mi++){
            int tmi = wm*3 + mi;
            int r = tmi/6, xb = (tmi%6)*16;
            uint32_t aoff = 2u*(uint32_t)(((r+dy)*100 + xb + (lane&15) + dx)*8);
            ldm_x2(ah[mi], aInH + aoff);
        }
        #pragma unroll
        for (int mi = 0; mi < 3; mi++){
            #pragma unroll
            for (int j = 0; j < 6; j++){
                MMA_F16_K8(c[mi][j], ah[mi], bh[j]);
                MMA_F16_K8(c[mi][j], ah[mi], bl[j]);
            }
        }
    }

    __half* Ob = g_i2h + (size_t)img*FH3*HW;
    #pragma unroll
    for (int mi = 0; mi < 3; mi++){
        int tmi = wm*3 + mi;
        int r = tmi/6, xb = (tmi%6)*16;
        int p = (y0 + r)*Ww + xb + (lane>>2);
        #pragma unroll
        for (int j = 0; j < 6; j++){
            int oc = ocg*96 + wn*48 + j*8 + (lane&3)*2;
            float bv0 = bias[oc], bv1 = bias[oc+1];
            Ob[(size_t)oc*HW + p]         = __float2half(c[mi][j][0] + bv0);
            Ob[(size_t)(oc+1)*HW + p]     = __float2half(c[mi][j][1] + bv1);
            Ob[(size_t)oc*HW + p + 8]     = __float2half(c[mi][j][2] + bv0);
            Ob[(size_t)(oc+1)*HW + p + 8] = __float2half(c[mi][j][3] + bv1);
        }
    }
}

// ============================================================
// fconv implicit GEMM — 1-term fp16. CTA = 2 rows x 96 px, N=32.
// ============================================================
#define FSM_BYTES ((14400 + 12800)*2)

__global__ void __launch_bounds__(256, 2) k_fconv(int t,
                                                  const float* __restrict__ b_i2f,
                                                  const float* __restrict__ b_h2f){
    extern __shared__ __half sm[];
    __half* sInH = sm;
    __half* sWH  = sm + 14400;
    uint32_t aInH = smem_u32(sInH), aWH = smem_u32(sWH);

    int tid = threadIdx.x, lane = tid & 31, wid = tid >> 5;
    int wm = wid & 3, wn = wid >> 2;
    int y0 = blockIdx.x*2, b = blockIdx.y;
    size_t slot = (size_t)(t*Bg + b)*HW;

    float c[3][2][4];
    #pragma unroll
    for (int i = 0; i < 3; i++)
        #pragma unroll
        for (int j = 0; j < 2; j++)
            #pragma unroll
            for (int q = 0; q < 4; q++) c[i][j][q] = 0.f;

    for (int chunk = 0; chunk < 7; chunk++){
        __syncthreads();
        for (int e = tid; e < 1200; e += 256){
            int ent = e >> 1, half_ = e & 1;
            int row = ent/100, cc = ent%100;
            int y = y0 + row - 2, x = cc - 2;
            uint4 vh = make_uint4(0,0,0,0);
            if ((unsigned)y < 96u && (unsigned)x < 96u){
                size_t off = (slot + y*Ww + x)*CH + chunk*16 + half_*8;
                vh = *reinterpret_cast<const uint4*>(g_inhi + off);
            }
            *reinterpret_cast<uint4*>(sInH + ent*24 + half_*8) = vh;
        }
        for (int e = tid; e < 1600; e += 256){
            reinterpret_cast<uint4*>(sWH)[e] = reinterpret_cast<const uint4*>(g_wfhi + chunk*12800)[e];
        }
        __syncthreads();

        #pragma unroll 1
        for (int tap = 0; tap < 25; tap++){
            int dy = tap/5, dx = tap%5;
            uint32_t bh[4];
            uint32_t boff = 2u*(uint32_t)((tap*32 + wn*16 + (lane&7) + ((lane>>4)&1)*8)*16
                                          + ((lane>>3)&1)*8);
            ldm_x4(bh, aWH + boff);
            uint32_t ah[3][4];
            #pragma unroll
            for (int mi = 0; mi < 3; mi++){
                int tmi = wm*3 + mi;
                int r = tmi/6, xb = (tmi%6)*16;
                uint32_t aoff = 2u*(uint32_t)(((r+dy)*100 + xb + (lane&15) + dx)*24
                                              + (lane>>4)*8);
                ldm_x4(ah[mi], aInH + aoff);
            }
            #pragma unroll
            for (int mi = 0; mi < 3; mi++){
                #pragma unroll
                for (int j = 0; j < 2; j++){
                    MMA_F16(c[mi][j], ah[mi], &bh[j*2]);
                }
            }
        }
    }

    #pragma unroll
    for (int mi = 0; mi < 3; mi++){
        int tmi = wm*3 + mi;
        int r = tmi/6, xb = (tmi%6)*16;
        int gp = (y0 + r)*Ww + xb + (lane>>2);
        #pragma unroll
        for (int j = 0; j < 2; j++){
            int oc = wn*16 + j*8 + (lane&3)*2;
            float bb0 = b_i2f[oc]   + b_h2f[oc];
            float bb1 = b_i2f[oc+1] + b_h2f[oc+1];
            *reinterpret_cast<uint32_t*>(g_fhi + ((size_t)b*HW + gp)*32 + oc)
                = pack2(leaky(c[mi][j][0] + bb0), leaky(c[mi][j][1] + bb1));
            *reinterpret_cast<uint32_t*>(g_fhi + ((size_t)b*HW + gp + 8)*32 + oc)
                = pack2(leaky(c[mi][j][2] + bb0), leaky(c[mi][j][3] + bb1));
        }
    }
}

// ============================================================
// flows implicit GEMM — 1-term fp16 (2 chunks, oc padded to 32)
// ============================================================
__global__ void __launch_bounds__(256, 2) k_flowsT(const float* __restrict__ b_fl){
    extern __shared__ __half sm[];
    __half* sInH = sm;
    __half* sWH  = sm + 14400;
    uint32_t aInH = smem_u32(sInH), aWH = smem_u32(sWH);

    int tid = threadIdx.x, lane = tid & 31, wid = tid >> 5;
    int wm = wid & 3, wn = wid >> 2;
    int y0 = blockIdx.x*2, b = blockIdx.y;

    float c[3][2][4];
    #pragma unroll
    for (int i = 0; i < 3; i++)
        #pragma unroll
        for (int j = 0; j < 2; j++)
            #pragma unroll
            for (int q = 0; q < 4; q++) c[i][j][q] = 0.f;

    for (int chunk = 0; chunk < 2; chunk++){
        __syncthreads();
        for (int e = tid; e < 1200; e += 256){
            int ent = e >> 1, half_ = e & 1;
            int row = ent/100, cc = ent%100;
            int y = y0 + row - 2, x = cc - 2;
            uint4 vh = make_uint4(0,0,0,0);
            if ((unsigned)y < 96u && (unsigned)x < 96u){
                size_t off = ((size_t)b*HW + y*Ww + x)*32 + chunk*16 + half_*8;
                vh = *reinterpret_cast<const uint4*>(g_fhi + off);
            }
            *reinterpret_cast<uint4*>(sInH + ent*24 + half_*8) = vh;
        }
        for (int e = tid; e < 1600; e += 256){
            reinterpret_cast<uint4*>(sWH)[e] = reinterpret_cast<const uint4*>(g_w2hi + chunk*12800)[e];
        }
        __syncthreads();

        #pragma unroll 1
        for (int tap = 0; tap < 25; tap++){
            int dy = tap/5, dx = tap%5;
            uint32_t bh[4];
            uint32_t boff = 2u*(uint32_t)((tap*32 + wn*16 + (lane&7) + ((lane>>4)&1)*8)*16
                                          + ((lane>>3)&1)*8);
            ldm_x4(bh, aWH + boff);
            uint32_t ah[3][4];
            #pragma unroll
            for (int mi = 0; mi < 3; mi++){
                int tmi = wm*3 + mi;
                int r = tmi/6, xb = (tmi%6)*16;
                uint32_t aoff = 2u*(uint32_t)(((r+dy)*100 + xb + (lane&15) + dx)*24
                                              + (lane>>4)*8);
                ldm_x4(ah[mi], aInH + aoff);
            }
            #pragma unroll
            for (int mi = 0; mi < 3; mi++){
                #pragma unroll
                for (int j = 0; j < 2; j++){
                    MMA_F16(c[mi][j], ah[mi], &bh[j*2]);
                }
            }
        }
    }

    #pragma unroll
    for (int mi = 0; mi < 3; mi++){
        int tmi = wm*3 + mi;
        int r = tmi/6, xb = (tmi%6)*16;
        int gp = (y0 + r)*Ww + xb + (lane>>2);
        #pragma unroll
        for (int j = 0; j < 2; j++){
            int oc = wn*16 + j*8 + (lane&3)*2;
            if (oc < 10){
                float bv0 = b_fl[oc], bv1 = b_fl[oc+1];
                float* f0 = g_flows + ((size_t)b*10 + oc)*HW;
                float* f1 = g_flows + ((size_t)b*10 + oc + 1)*HW;
                f0[gp]     = c[mi][j][0] + bv0;
                f1[gp]     = c[mi][j][1] + bv1;
                f0[gp + 8] = c[mi][j][2] + bv0;
                f1[gp + 8] = c[mi][j][3] + bv1;
            }
        }
    }
}

// ============================================================
// warp: bilinear-warp h_{t-1} read from g_inhi slot t ([p][ch] fp16,
// h at +8) with vectorized uint4 corner loads. Output fp16 [b][p][k].
// grid (B*L, H), block 96
// ============================================================
__global__ void k_warp(int t){
    __shared__ uint32_t sHi[96*49];
    int bl = blockIdx.x, y = blockIdx.y, tx = threadIdx.x;
    int b = bl / Lk, l = bl % Lk;
    const float* fl = g_flows + (size_t)b*10*HW + y*Ww + tx;
    float fx = fl[(size_t)(2*l)*HW];
    float fy = fl[(size_t)(2*l+1)*HW];
    float vx = (float)tx - fx;
    float vy = (float)y  - fy;
    const float sc = 96.0f/95.0f;
    float ix = vx*sc - 0.5f;
    float iy = vy*sc - 0.5f;
    float fx0 = floorf(ix), fy0 = floorf(iy);
    int ix0 = (int)fx0, iy0 = (int)fy0;
    int ix1 = ix0 + 1, iy1 = iy0 + 1;
    float wx1 = ix - fx0, wy1 = iy - fy0;
    float wx0 = 1.f - wx1, wy0 = 1.f - wy1;
    float mx0 = (ix0 >= 0 && ix0 < Ww) ? 1.f : 0.f;
    float mx1 = (ix1 >= 0 && ix1 < Ww) ? 1.f : 0.f;
    float my0 = (iy0 >= 0 && iy0 < Hh) ? 1.f : 0.f;
    float my1 = (iy1 >= 0 && iy1 < Hh) ? 1.f : 0.f;
    int cx0 = min(max(ix0, 0), Ww-1), cx1 = min(max(ix1, 0), Ww-1);
    int cy0 = min(max(iy0, 0), Hh-1), cy1 = min(max(iy1, 0), Hh-1);
    float w00 = wy0*wx0*my0*mx0, w01 = wy0*wx1*my0*mx1;
    float w10 = wy1*wx0*my1*mx0, w11 = wy1*wx1*my1*mx1;

    const __half* hb = g_inhi + (size_t)(t*Bg + b)*HW*CH + 8;   // h section
    const __half* p00 = hb + (size_t)(cy0*Ww + cx0)*CH;
    const __half* p01 = hb + (size_t)(cy0*Ww + cx1)*CH;
    const __half* p10 = hb + (size_t)(cy1*Ww + cx0)*CH;
    const __half* p11 = hb + (size_t)(cy1*Ww + cx1)*CH;

    #pragma unroll 1
    for (int cg = 0; cg < 12; cg++){
        uint4 v00 = *reinterpret_cast<const uint4*>(p00 + cg*8);
        uint4 v01 = *reinterpret_cast<const uint4*>(p01 + cg*8);
        uint4 v10 = *reinterpret_cast<const uint4*>(p10 + cg*8);
        uint4 v11 = *reinterpret_cast<const uint4*>(p11 + cg*8);
        const uint32_t* a00 = reinterpret_cast<const uint32_t*>(&v00);
        const uint32_t* a01 = reinterpret_cast<const uint32_t*>(&v01);
        const uint32_t* a10 = reinterpret_cast<const uint32_t*>(&v10);
        const uint32_t* a11 = reinterpret_cast<const uint32_t*>(&v11);
        #pragma unroll
        for (int q = 0; q < 4; q++){
            float2 f00 = __half22float2(*reinterpret_cast<const __half2*>(&a00[q]));
            float2 f01 = __half22float2(*reinterpret_cast<const __half2*>(&a01[q]));
            float2 f10 = __half22float2(*reinterpret_cast<const __half2*>(&a10[q]));
            float2 f11 = __half22float2(*reinterpret_cast<const __half2*>(&a11[q]));
            float r0 = w00*f00.x + w01*f01.x + w10*f10.x + w11*f11.x;
            float r1 = w00*f00.y + w01*f01.y + w10*f10.y + w11*f11.y;
            sHi[tx*49 + cg*4 + q] = pack2(r0, r1);
        }
    }
    __syncthreads();
    size_t rowbase = ((size_t)b*HW + y*Ww)*KPAD + (size_t)l*Fch;
    for (int e = tx; e < 96*12; e += 96){
        int pl = e/12, u = e%12;
        uint4 vh;
        vh.x = sHi[pl*49 + u*4 + 0]; vh.y = sHi[pl*49 + u*4 + 1];
        vh.z = sHi[pl*49 + u*4 + 2]; vh.w = sHi[pl*49 + u*4 + 3];
        *reinterpret_cast<uint4*>(g_whi + rowbase + (size_t)pl*KPAD + u*8) = vh;
    }
}

// ============================================================
// prep: split w_ret (288 x 480, stride KPAD) fp16 hi/lo
// ============================================================
__global__ void k_prepA(const float* __restrict__ w_ret){
    int idx = blockIdx.x*blockDim.x + threadIdx.x;
    if (idx >= FH3*KPAD) return;
    int m = idx / KPAD, k = idx % KPAD;
    float v = (k < K1) ? w_ret[m*K1 + k] : 0.f;
    __half hi = __float2half(v);
    g_Ahi[idx] = hi;
    g_Alo[idx] = __float2half(v - __half2float(hi));
}

// ============================================================
// FUSED h2h GEMM (2-term fp16: AhBh + AlBh) + GRU gates.
// grid (72, B), 256 thr, dyn smem 112.6 KB
// ============================================================
#define TS 40
#define H2_ABUF (288*TS)
#define H2_BBUF (128*TS)
#define H2_SMEM ((4*H2_ABUF + 2*H2_BBUF)*2)   // 112640 B

__global__ void __launch_bounds__(256, 1) k_h2hg(int t,
                                                 const float* __restrict__ bias,
                                                 const float* __restrict__ hprev,
                                                 float* __restrict__ hnext,
                                                 int pack){
    extern __shared__ __half sm[];
    __half* sAh = sm;
    __half* sAl = sm + 2*H2_ABUF;
    __half* sBh = sm + 4*H2_ABUF;
    uint32_t aSh = smem_u32(sAh), aSl = smem_u32(sAl), aBh = smem_u32(sBh);

    int tid = threadIdx.x, lane = tid & 31, wid = tid >> 5;
    int wm = wid & 1, wn = wid >> 1;
    int n0 = blockIdx.x*128, b = blockIdx.y;

    const __half* Bh = g_whi + ((size_t)b*HW + n0)*KPAD;

    int arow = wm*48 + (lane & 15);
    int acol = (lane >> 4) * 8;
    int brow = wn*32 + (lane & 7) + ((lane >> 4) & 1)*8;
    int bcol = ((lane >> 3) & 1) * 8;

    float c[3][3][4][4];
    #pragma unroll
    for (int mt = 0; mt < 3; mt++)
        #pragma unroll
        for (int i = 0; i < 3; i++)
            #pragma unroll
            for (int j = 0; j < 4; j++)
                #pragma unroll
                for (int q = 0; q < 4; q++) c[mt][i][j][q] = 0.f;

    #define H2G_STAGE(chunk, buf) do { \
        uint32_t sbA = (uint32_t)(buf)*(H2_ABUF*2); \
        uint32_t sbB = (uint32_t)(buf)*(H2_BBUF*2); \
        for (int e = tid; e < 1152; e += 256){ \
            int r = e >> 2, u = e & 3; \
            size_t goff = (size_t)r*KPAD + (chunk)*32 + u*8; \
            uint32_t soff = sbA + (uint32_t)(r*TS + u*8)*2u; \
            CPA16(aSh + soff, g_Ahi + goff); \
            CPA16(aSl + soff, g_Alo + goff); \
        } \
        for (int e = tid; e < 512; e += 256){ \
            int r = e >> 2, u = e & 3; \
            size_t goff = (size_t)r*KPAD + (chunk)*32 + u*8; \
            uint32_t soff = sbB + (uint32_t)(r*TS + u*8)*2u; \
            CPA16(aBh + soff, Bh + goff); \
        } \
        CPA_COMMIT(); \
    } while(0)

    H2G_STAGE(0, 0);
    for (int chunk = 0; chunk < 15; chunk++){
        if (chunk + 1 < 15){
            H2G_STAGE(chunk + 1, (chunk + 1) & 1);
            asm volatile("cp.async.wait_group 1;" ::: "memory");
        } else {
            asm volatile("cp.async.wait_group 0;" ::: "memory");
        }
        __syncthreads();

        uint32_t sbA = (uint32_t)(chunk & 1)*(H2_ABUF*2);
        uint32_t sbB = (uint32_t)(chunk & 1)*(H2_BBUF*2);
        #pragma unroll
        for (int ks = 0; ks < 2; ks++){
            int kc = ks*16;
            uint32_t bh[2][4];
            #pragma unroll
            for (int jp = 0; jp < 2; jp++){
                uint32_t off = sbB + 2u*((brow + jp*16)*TS + kc + bcol);
                ldm_x4(bh[jp], aBh + off);
            }
            #pragma unroll
            for (int mt = 0; mt < 3; mt++){
                uint32_t ah[3][4], al[3][4];
                #pragma unroll
                for (int mi = 0; mi < 3; mi++){
                    uint32_t off = sbA + 2u*((mt*96 + arow + mi*16)*TS + kc + acol);
                    ldm_x4(ah[mi], aSh + off);
                    ldm_x4(al[mi], aSl + off);
                }
                #pragma unroll
                for (int mi = 0; mi < 3; mi++){
                    #pragma unroll
                    for (int j = 0; j < 4; j++){
                        uint32_t* fh = &bh[j >> 1][(j & 1)*2];
                        MMA_F16(c[mt][mi][j], ah[mi], fh);
                        MMA_F16(c[mt][mi][j], al[mi], fh);
                    }
                }
            }
        }
        __syncthreads();
    }

    // ---- fused GRU gate epilogue ----
    __syncthreads();
    float* sF = reinterpret_cast<float*>(sm);   // [128 px][stride 100]

    const __half* i2hb = g_i2h + (size_t)(t*Bg + b)*FH3*HW;
    const float* hpb  = hprev + (size_t)b*Fch*HW;
    float* hnb        = hnext + (size_t)b*Fch*HW;

    #pragma unroll
    for (int mi = 0; mi < 3; mi++){
        int fc0 = wm*48 + mi*16 + (lane >> 2);
        #pragma unroll
        for (int j = 0; j < 4; j++){
            int pl = wn*32 + (lane & 3)*2 + j*8;
            int p = n0 + pl;
            #pragma unroll
            for (int half_ = 0; half_ < 2; half_++){
                int fc = fc0 + half_*8;
                int q0 = half_*2;
                float rb = bias[fc], ub = bias[96 + fc], mb = bias[192 + fc];
                float2 i2r = __half22float2(*reinterpret_cast<const __half2*>(i2hb + (size_t)fc*HW + p));
                float2 i2u = __half22float2(*reinterpret_cast<const __half2*>(i2hb + (size_t)(96+fc)*HW + p));
                float2 i2m = __half22float2(*reinterpret_cast<const __half2*>(i2hb + (size_t)(192+fc)*HW + p));
                float2 hpv = *reinterpret_cast<const float2*>(hpb + (size_t)fc*HW + p);
                float nh[2];
                #pragma unroll
                for (int s = 0; s < 2; s++){
                    float hr = c[0][mi][j][q0+s] + rb;
                    float hu = c[1][mi][j][q0+s] + ub;
                    float hm = c[2][mi][j][q0+s] + mb;
                    float ir = s ? i2r.y : i2r.x;
                    float iu = s ? i2u.y : i2u.x;
                    float im = s ? i2m.y : i2m.x;
                    float hp = s ? hpv.y : hpv.x;
                    float reset  = sigm(ir + hr);
                    float update = sigm(iu + hu);
                    float newmem = leaky(im + reset*hm);
                    nh[s] = update*hp + (1.f - update)*newmem;
                }
                float2 wv; wv.x = nh[0]; wv.y = nh[1];
                *reinterpret_cast<float2*>(hnb + (size_t)fc*HW + p) = wv;
                sF[pl*100 + fc]     = nh[0];
                sF[(pl+1)*100 + fc] = nh[1];
            }
        }
    }
    __syncthreads();
    if (pack){
        size_t slotn = (size_t)((t+1)*Bg + b)*HW;
        for (int e = tid; e < 128*12; e += 256){
            int pl = e/12, u = e%12;
            const float* src = sF + pl*100 + u*8;
            uint32_t hw[4];
            #pragma unroll
            for (int q = 0; q < 4; q++)
                hw[q] = pack2(src[2*q], src[2*q+1]);
            size_t off = (slotn + n0 + pl)*CH + 8 + u*8;
            *reinterpret_cast<uint4*>(g_inhi + off) = *reinterpret_cast<uint4*>(hw);
        }
    }
}

// ============================================================
extern "C" void kernel_launch(void* const* d_in, const int* in_sizes, int n_in,
                              void* d_out, int out_size){
    const float* inputs = (const float*)d_in[0];
    const float* h0     = (const float*)d_in[1];
    const float* w_i2h  = (const float*)d_in[2];
    const float* b_i2h  = (const float*)d_in[3];
    const float* w_i2f  = (const float*)d_in[4];
    const float* b_i2f  = (const float*)d_in[5];
    const float* w_h2f  = (const float*)d_in[6];
    const float* b_h2f  = (const float*)d_in[7];
    const float* w_fl   = (const float*)d_in[8];
    const float* b_fl   = (const float*)d_in[9];
    const float* w_ret  = (const float*)d_in[10];
    const float* b_ret  = (const float*)d_in[11];
    float* out = (float*)d_out;

    cudaFuncSetAttribute(k_fconv,  cudaFuncAttributeMaxDynamicSharedMemorySize, FSM_BYTES);
    cudaFuncSetAttribute(k_flowsT, cudaFuncAttributeMaxDynamicSharedMemorySize, FSM_BYTES);
    cudaFuncSetAttribute(k_h2hg,   cudaFuncAttributeMaxDynamicSharedMemorySize, H2_SMEM);

    // once per launch
    k_prepX   <<<(Sg*Bg*HW + 255)/256, 256>>>(inputs, h0);
    k_prepWall<<<(89600 + 25600 + 20736 + 255)/256, 256>>>(w_i2f, w_h2f, w_fl, w_i2h);
    k_prepA   <<<(FH3*KPAD + 255)/256, 256>>>(w_ret);
    k_i2hT    <<<dim3(48, Sg*Bg, 3), 256>>>(b_i2h);

    for (int t = 0; t < Sg; t++){
        const float* h = (t == 0) ? h0 : out + (size_t)(t-1)*STEP_ELEMS;
        float* hn = out + (size_t)t*STEP_ELEMS;

        k_fconv <<<dim3(48, Bg), 256, FSM_BYTES>>>(t, b_i2f, b_h2f);
        k_flowsT<<<dim3(48, Bg), 256, FSM_BYTES>>>(b_fl);
        k_warp  <<<dim3(Bg*Lk, Hh), 96>>>(t);
        k_h2hg  <<<dim3(HW/128, Bg), 256, H2_SMEM>>>(t, b_ret, h, hn, (t < Sg-1) ? 1 : 0);
    }

    const size_t OUT_SEQ = (size_t)Sg*STEP_ELEMS;
    if ((size_t)out_size >= OUT_SEQ + STEP_ELEMS){
        cudaMemcpyAsync(out + OUT_SEQ, out + (size_t)(Sg-1)*STEP_ELEMS,
                        (size_t)STEP_ELEMS*sizeof(float),
                        cudaMemcpyDeviceToDevice);
    }
}

// round 12
// speedup vs baseline: 5.5137x; 1.0946x over previous
#include <cuda_runtime.h>
#include <cuda_fp16.h>
#include <cstdint>
#include <math.h>

#define Hh 96
#define Ww 96
#define HW 9216
#define Fch 96
#define CIN 8
#define Lk 5
#define Sg 10
#define Bg 4
#define FH3 288          // 3*F
#define K1 480           // L*F
#define KPAD 512         // row STRIDE of k-major operands (pad cols never read)
#define CH 112           // packed input channels: 8 x | 96 h | 8 zero
#define STEP_ELEMS (Bg*Fch*HW)   // 3,538,944

// ---- scratch (device globals) ----
__device__ __align__(16) __half g_i2h[(size_t)Sg*Bg*FH3*HW];  // 212 MB (once), fp16
__device__ __align__(16) __half g_whi[(size_t)Bg*HW*KPAD];    // warped^T hi [b][p][k]
__device__ __align__(16) __half g_Ahi[(size_t)FH3*KPAD];      // w_ret hi [m][k]
__device__ __align__(16) __half g_Alo[(size_t)FH3*KPAD];
// fconv inputs: per-step slots [Sg][Bg][p][112] (hi only)
__device__ __align__(16) __half g_inhi[(size_t)Sg*Bg*HW*CH];
__device__ __align__(16) __half g_wfhi[7*25*32*16];           // [chunk][tap][oc][16]
// f (1-term) [b][p][32]
__device__ __align__(16) __half g_fhi[(size_t)Bg*HW*32];
// flows weights [chunk2][tap25][oc32][16] (oc>=10 zero)
__device__ __align__(16) __half g_w2hi[2*25*32*16];
// i2h weights [ocg3][tap9][oc96][8] hi/lo
__device__ __align__(16) __half g_w3hi[3*9*96*8];
__device__ __align__(16) __half g_w3lo[3*9*96*8];

__device__ __forceinline__ float leaky(float v){ return v > 0.f ? v : 0.2f*v; }
__device__ __forceinline__ float sigm(float v){ return 1.f/(1.f + expf(-v)); }

__device__ __forceinline__ uint32_t smem_u32(const void* p){
    uint32_t a;
    asm("{ .reg .u64 t; cvta.to.shared.u64 t, %1; cvt.u32.u64 %0, t; }" : "=r"(a) : "l"(p));
    return a;
}
__device__ __forceinline__ void ldm_x4(uint32_t* r, uint32_t addr){
    asm volatile("ldmatrix.sync.aligned.m8n8.x4.shared.b16 {%0,%1,%2,%3}, [%4];"
        : "=r"(r[0]), "=r"(r[1]), "=r"(r[2]), "=r"(r[3]) : "r"(addr));
}
__device__ __forceinline__ void ldm_x2(uint32_t* r, uint32_t addr){
    asm volatile("ldmatrix.sync.aligned.m8n8.x2.shared.b16 {%0,%1}, [%2];"
        : "=r"(r[0]), "=r"(r[1]) : "r"(addr));
}
#define MMA_F16(c, a, b) \
    asm volatile("mma.sync.aligned.m16n8k16.row.col.f32.f16.f16.f32 " \
        "{%0,%1,%2,%3}, {%4,%5,%6,%7}, {%8,%9}, {%0,%1,%2,%3};" \
        : "+f"((c)[0]), "+f"((c)[1]), "+f"((c)[2]), "+f"((c)[3]) \
        : "r"((a)[0]), "r"((a)[1]), "r"((a)[2]), "r"((a)[3]), \
          "r"((b)[0]), "r"((b)[1]))
#define MMA_F16_K8(c, a, b) \
    asm volatile("mma.sync.aligned.m16n8k8.row.col.f32.f16.f16.f32 " \
        "{%0,%1,%2,%3}, {%4,%5}, {%6}, {%0,%1,%2,%3};" \
        : "+f"((c)[0]), "+f"((c)[1]), "+f"((c)[2]), "+f"((c)[3]) \
        : "r"((a)[0]), "r"((a)[1]), "r"(b))
#define CPA16(sm, gp) asm volatile("cp.async.ca.shared.global [%0], [%1], 16;" :: "r"(sm), "l"(gp))
#define CPA_COMMIT()  asm volatile("cp.async.commit_group;" ::: "memory")

__device__ __forceinline__ uint32_t pack2(float v0, float v1){
    __half2 hp = __halves2half2(__float2half(v0), __float2half(v1));
    return *reinterpret_cast<uint32_t*>(&hp);
}

// ============================================================
// k_prepX (once): pack x channels (hi) for ALL step slots, zero pad,
// slot-0 h channels from h0.
// ============================================================
__global__ void k_prepX(const float* __restrict__ inputs, const float* __restrict__ h0){
    int idx = blockIdx.x*blockDim.x + threadIdx.x;
    if (idx >= Sg*Bg*HW) return;
    int p = idx % HW, b = (idx/HW) % Bg, t = idx/(HW*Bg);
    size_t base = ((size_t)(t*Bg + b)*HW + p)*CH;
    const float* xp = inputs + ((size_t)(t*Bg + b)*CIN)*HW + p;
    uint32_t hw[4];
    #pragma unroll
    for (int q = 0; q < 4; q++)
        hw[q] = pack2(xp[(size_t)(2*q)*HW], xp[(size_t)(2*q+1)*HW]);
    *reinterpret_cast<uint4*>(g_inhi + base) = *reinterpret_cast<uint4*>(hw);
    uint4 z = make_uint4(0,0,0,0);
    *reinterpret_cast<uint4*>(g_inhi + base + 104) = z;
    if (t == 0){
        const float* hp = h0 + (size_t)b*Fch*HW + p;
        for (int g = 0; g < 12; g++){
            #pragma unroll
            for (int q = 0; q < 4; q++)
                hw[q] = pack2(hp[(size_t)(g*8 + 2*q)*HW], hp[(size_t)(g*8 + 2*q+1)*HW]);
            *reinterpret_cast<uint4*>(g_inhi + base + 8 + g*8) = *reinterpret_cast<uint4*>(hw);
        }
    }
}

// ============================================================
// k_prepWall (once): conv-weight repacks (fp16)
// ============================================================
__global__ void k_prepWall(const float* __restrict__ w_i2f, const float* __restrict__ w_h2f,
                           const float* __restrict__ w_fl,  const float* __restrict__ w_i2h){
    int idx = blockIdx.x*blockDim.x + threadIdx.x;
    if (idx < 89600){
        int o = idx;
        int kc = o & 15, oc = (o >> 4) & 31, tap = (o >> 9) % 25, chunk = o / 12800;
        int ch = chunk*16 + kc;
        float v = 0.f;
        if (ch < 8)        v = w_i2f[(oc*8 + ch)*25 + tap];
        else if (ch < 104) v = w_h2f[((size_t)oc*Fch + (ch-8))*25 + tap];
        g_wfhi[o] = __float2half(v);
    } else if (idx < 89600 + 25600){
        int o = idx - 89600;
        int kc = o & 15, oc = (o >> 4) & 31, tap = (o >> 9) % 25, chunk = o / 12800;
        int ch = chunk*16 + kc;
        float v = (oc < 10) ? w_fl[((size_t)oc*32 + ch)*25 + tap] : 0.f;
        g_w2hi[o] = __float2half(v);
    } else if (idx < 89600 + 25600 + 20736){
        int o = idx - 89600 - 25600;
        int ch = o & 7, oc = (o >> 3) % 96, tap = (o/(96*8)) % 9, ocg = o/(9*96*8);
        float v = w_i2h[((size_t)(ocg*96 + oc)*CIN + ch)*9 + tap];
        __half hi = __float2half(v);
        g_w3hi[o] = hi;
        g_w3lo[o] = __float2half(v - __half2float(hi));
    }
}

// ============================================================
// i2h implicit GEMM (m16n8k8, fp16 2-term), once.
// Input halo staged ONCE, all 3 oc-groups computed in-CTA.
// grid (48, 40 img), 256 thr
// ============================================================
__global__ void __launch_bounds__(256, 2) k_i2hT(const float* __restrict__ bias){
    __shared__ __half sInH[400*8];
    __shared__ __half sWH[9*96*8], sWL[9*96*8];
    uint32_t aInH = smem_u32(sInH);
    uint32_t aWH  = smem_u32(sWH),  aWL  = smem_u32(sWL);

    int tid = threadIdx.x, lane = tid & 31, wid = tid >> 5;
    int wm = wid & 3, wn = wid >> 2;
    int y0 = blockIdx.x*2, img = blockIdx.y;

    for (int e = tid; e < 400; e += 256){
        int row = e/100, cc = e%100;
        int y = y0 + row - 1, x = cc - 1;
        uint4 vh = make_uint4(0,0,0,0);
        if ((unsigned)y < 96u && (unsigned)x < 96u)
            vh = *reinterpret_cast<const uint4*>(g_inhi + ((size_t)img*HW + y*Ww + x)*CH);
        *reinterpret_cast<uint4*>(sInH + e*8) = vh;
    }

    __half* Ob = g_i2h + (size_t)img*FH3*HW;

    #pragma unroll 1
    for (int ocg = 0; ocg < 3; ocg++){
        __syncthreads();   // input visible (iter0) / previous compute done
        for (int e = tid; e < 864; e += 256){
            reinterpret_cast<uint4*>(sWH)[e] = reinterpret_cast<const uint4*>(g_w3hi + (size_t)ocg*9*96*8)[e];
            reinterpret_cast<uint4*>(sWL)[e] = reinterpret_cast<const uint4*>(g_w3lo + (size_t)ocg*9*96*8)[e];
        }
        __syncthreads();

        float c[3][6][4];
        #pragma unroll
        for (int i = 0; i < 3; i++)
            #pragma unroll
            for (int j = 0; j < 6; j++)
                #pragma unroll
                for (int q = 0; q < 4; q++) c[i][j][q] = 0.f;

        #pragma unroll 1
        for (int tap = 0; tap < 9; tap++){
            int dy = tap/3, dx = tap%3;
            uint32_t bh[6], bl[6];
            {
                ldm_x4(bh, aWH + 2u*(uint32_t)((tap*96 + wn*48 + lane)*8));
                ldm_x4(bl, aWL + 2u*(uint32_t)((tap*96 + wn*48 + lane)*8));
                uint32_t a2 = 2u*(uint32_t)((tap*96 + wn*48 + 32 + (lane & 15))*8);
                ldm_x2(bh + 4, aWH + a2);
                ldm_x2(bl + 4, aWL + a2);
            }
            uint32_t ah[3][2];
            #pragma unroll
            for (int mi = 0; mi < 3; mi++){
                int tmi = wm*3 + mi;
                int r = tmi/6, xb = (tmi%6)*16;
                uint32_t aoff = 2u*(uint32_t)(((r+dy)*100 + xb + (lane&15) + dx)*8);
                ldm_x2(ah[mi], aInH + aoff);
            }
            #pragma unroll
            for (int mi = 0; mi < 3; mi++){
                #pragma unroll
                for (int j = 0; j < 6; j++){
                    MMA_F16_K8(c[mi][j], ah[mi], bh[j]);
                    MMA_F16_K8(c[mi][j], ah[mi], bl[j]);
                }
            }
        }

        #pragma unroll
        for (int mi = 0; mi < 3; mi++){
            int tmi = wm*3 + mi;
            int r = tmi/6, xb = (tmi%6)*16;
            int p = (y0 + r)*Ww + xb + (lane>>2);
            #pragma unroll
            for (int j = 0; j < 6; j++){
                int oc = ocg*96 + wn*48 + j*8 + (lane&3)*2;
                float bv0 = bias[oc], bv1 = bias[oc+1];
                Ob[(size_t)oc*HW + p]         = __float2half(c[mi][j][0] + bv0);
                Ob[(size_t)(oc+1)*HW + p]     = __float2half(c[mi][j][1] + bv1);
                Ob[(size_t)oc*HW + p + 8]     = __float2half(c[mi][j][2] + bv0);
                Ob[(size_t)(oc+1)*HW + p + 8] = __float2half(c[mi][j][3] + bv1);
            }
        }
    }
}

// ============================================================
// fconv implicit GEMM — 1-term fp16. CTA = 2 rows x 96 px, N=32.
// ============================================================
#define FSM_BYTES ((14400 + 12800)*2)

__global__ void __launch_bounds__(256, 2) k_fconv(int t,
                                                  const float* __restrict__ b_i2f,
                                                  const float* __restrict__ b_h2f){
    extern __shared__ __half sm[];
    __half* sInH = sm;
    __half* sWH  = sm + 14400;
    uint32_t aInH = smem_u32(sInH), aWH = smem_u32(sWH);

    int tid = threadIdx.x, lane = tid & 31, wid = tid >> 5;
    int wm = wid & 3, wn = wid >> 2;
    int y0 = blockIdx.x*2, b = blockIdx.y;
    size_t slot = (size_t)(t*Bg + b)*HW;

    float c[3][2][4];
    #pragma unroll
    for (int i = 0; i < 3; i++)
        #pragma unroll
        for (int j = 0; j < 2; j++)
            #pragma unroll
            for (int q = 0; q < 4; q++) c[i][j][q] = 0.f;

    for (int chunk = 0; chunk < 7; chunk++){
        __syncthreads();
        for (int e = tid; e < 1200; e += 256){
            int ent = e >> 1, half_ = e & 1;
            int row = ent/100, cc = ent%100;
            int y = y0 + row - 2, x = cc - 2;
            uint4 vh = make_uint4(0,0,0,0);
            if ((unsigned)y < 96u && (unsigned)x < 96u){
                size_t off = (slot + y*Ww + x)*CH + chunk*16 + half_*8;
                vh = *reinterpret_cast<const uint4*>(g_inhi + off);
            }
            *reinterpret_cast<uint4*>(sInH + ent*24 + half_*8) = vh;
        }
        for (int e = tid; e < 1600; e += 256){
            reinterpret_cast<uint4*>(sWH)[e] = reinterpret_cast<const uint4*>(g_wfhi + chunk*12800)[e];
        }
        __syncthreads();

        #pragma unroll 1
        for (int tap = 0; tap < 25; tap++){
            int dy = tap/5, dx = tap%5;
            uint32_t bh[4];
            uint32_t boff = 2u*(uint32_t)((tap*32 + wn*16 + (lane&7) + ((lane>>4)&1)*8)*16
                                          + ((lane>>3)&1)*8);
            ldm_x4(bh, aWH + boff);
            uint32_t ah[3][4];
            #pragma unroll
            for (int mi = 0; mi < 3; mi++){
                int tmi = wm*3 + mi;
                int r = tmi/6, xb = (tmi%6)*16;
                uint32_t aoff = 2u*(uint32_t)(((r+dy)*100 + xb + (lane&15) + dx)*24
                                              + (lane>>4)*8);
                ldm_x4(ah[mi], aInH + aoff);
            }
            #pragma unroll
            for (int mi = 0; mi < 3; mi++){
                #pragma unroll
                for (int j = 0; j < 2; j++){
                    MMA_F16(c[mi][j], ah[mi], &bh[j*2]);
                }
            }
        }
    }

    #pragma unroll
    for (int mi = 0; mi < 3; mi++){
        int tmi = wm*3 + mi;
        int r = tmi/6, xb = (tmi%6)*16;
        int gp = (y0 + r)*Ww + xb + (lane>>2);
        #pragma unroll
        for (int j = 0; j < 2; j++){
            int oc = wn*16 + j*8 + (lane&3)*2;
            float bb0 = b_i2f[oc]   + b_h2f[oc];
            float bb1 = b_i2f[oc+1] + b_h2f[oc+1];
            *reinterpret_cast<uint32_t*>(g_fhi + ((size_t)b*HW + gp)*32 + oc)
                = pack2(leaky(c[mi][j][0] + bb0), leaky(c[mi][j][1] + bb1));
            *reinterpret_cast<uint32_t*>(g_fhi + ((size_t)b*HW + gp + 8)*32 + oc)
                = pack2(leaky(c[mi][j][2] + bb0), leaky(c[mi][j][3] + bb1));
        }
    }
}

// ============================================================
// flowsT + FUSED warp: compute flows for 192-px tile (smem only),
// then bilinear-warp h_{t-1} (from g_inhi slot t) for those pixels
// x 5 links -> g_whi. grid (48, B), 256 thr
// ============================================================
__global__ void __launch_bounds__(256, 2) k_flowsW(int t, const float* __restrict__ b_fl){
    extern __shared__ __half sm[];
    __half* sInH = sm;
    __half* sWH  = sm + 14400;
    uint32_t aInH = smem_u32(sInH), aWH = smem_u32(sWH);

    int tid = threadIdx.x, lane = tid & 31, wid = tid >> 5;
    int wm = wid & 3, wn = wid >> 2;
    int y0 = blockIdx.x*2, b = blockIdx.y;

    float c[3][2][4];
    #pragma unroll
    for (int i = 0; i < 3; i++)
        #pragma unroll
        for (int j = 0; j < 2; j++)
            #pragma unroll
            for (int q = 0; q < 4; q++) c[i][j][q] = 0.f;

    for (int chunk = 0; chunk < 2; chunk++){
        __syncthreads();
        for (int e = tid; e < 1200; e += 256){
            int ent = e >> 1, half_ = e & 1;
            int row = ent/100, cc = ent%100;
            int y = y0 + row - 2, x = cc - 2;
            uint4 vh = make_uint4(0,0,0,0);
            if ((unsigned)y < 96u && (unsigned)x < 96u){
                size_t off = ((size_t)b*HW + y*Ww + x)*32 + chunk*16 + half_*8;
                vh = *reinterpret_cast<const uint4*>(g_fhi + off);
            }
            *reinterpret_cast<uint4*>(sInH + ent*24 + half_*8) = vh;
        }
        for (int e = tid; e < 1600; e += 256){
            reinterpret_cast<uint4*>(sWH)[e] = reinterpret_cast<const uint4*>(g_w2hi + chunk*12800)[e];
        }
        __syncthreads();

        #pragma unroll 1
        for (int tap = 0; tap < 25; tap++){
            int dy = tap/5, dx = tap%5;
            uint32_t bh[4];
            uint32_t boff = 2u*(uint32_t)((tap*32 + wn*16 + (lane&7) + ((lane>>4)&1)*8)*16
                                          + ((lane>>3)&1)*8);
            ldm_x4(bh, aWH + boff);
            uint32_t ah[3][4];
            #pragma unroll
            for (int mi = 0; mi < 3; mi++){
                int tmi = wm*3 + mi;
                int r = tmi/6, xb = (tmi%6)*16;
                uint32_t aoff = 2u*(uint32_t)(((r+dy)*100 + xb + (lane&15) + dx)*24
                                              + (lane>>4)*8);
                ldm_x4(ah[mi], aInH + aoff);
            }
            #pragma unroll
            for (int mi = 0; mi < 3; mi++){
                #pragma unroll
                for (int j = 0; j < 2; j++){
                    MMA_F16(c[mi][j], ah[mi], &bh[j*2]);
                }
            }
        }
    }

    // ---- stage flows into smem [192 px][10] (aliases sInH) ----
    __syncthreads();
    float* sFl = reinterpret_cast<float*>(sm);
    #pragma unroll
    for (int mi = 0; mi < 3; mi++){
        int tmi = wm*3 + mi;
        int r = tmi/6, xb = (tmi%6)*16;
        int pl = r*96 + xb + (lane>>2);
        #pragma unroll
        for (int j = 0; j < 2; j++){
            int oc = wn*16 + j*8 + (lane&3)*2;
            if (oc < 10){
                float bv0 = b_fl[oc], bv1 = b_fl[oc+1];
                sFl[pl*10 + oc]         = c[mi][j][0] + bv0;
                sFl[pl*10 + oc + 1]     = c[mi][j][1] + bv1;
                sFl[(pl+8)*10 + oc]     = c[mi][j][2] + bv0;
                sFl[(pl+8)*10 + oc + 1] = c[mi][j][3] + bv1;
            }
        }
    }
    __syncthreads();

    // ---- fused warp: 960 tasks = 192 px x 5 links ----
    const __half* hb = g_inhi + (size_t)(t*Bg + b)*HW*CH + 8;   // h section
    const float scg = 96.0f/95.0f;
    for (int task = tid; task < 960; task += 256){
        int px = task/5, l = task%5;
        int y = y0 + px/96, x = px%96;
        float fx = sFl[px*10 + 2*l];
        float fy = sFl[px*10 + 2*l + 1];
        float ix = ((float)x - fx)*scg - 0.5f;
        float iy = ((float)y - fy)*scg - 0.5f;
        float fx0 = floorf(ix), fy0 = floorf(iy);
        int ix0 = (int)fx0, iy0 = (int)fy0;
        int ix1 = ix0 + 1, iy1 = iy0 + 1;
        float wx1 = ix - fx0, wy1 = iy - fy0;
        float wx0 = 1.f - wx1, wy0 = 1.f - wy1;
        float mx0 = (ix0 >= 0 && ix0 < Ww) ? 1.f : 0.f;
        float mx1 = (ix1 >= 0 && ix1 < Ww) ? 1.f : 0.f;
        float my0 = (iy0 >= 0 && iy0 < Hh) ? 1.f : 0.f;
        float my1 = (iy1 >= 0 && iy1 < Hh) ? 1.f : 0.f;
        int cx0 = min(max(ix0, 0), Ww-1), cx1 = min(max(ix1, 0), Ww-1);
        int cy0 = min(max(iy0, 0), Hh-1), cy1 = min(max(iy1, 0), Hh-1);
        float w00 = wy0*wx0*my0*mx0, w01 = wy0*wx1*my0*mx1;
        float w10 = wy1*wx0*my1*mx0, w11 = wy1*wx1*my1*mx1;
        const __half* p00 = hb + (size_t)(cy0*Ww + cx0)*CH;
        const __half* p01 = hb + (size_t)(cy0*Ww + cx1)*CH;
        const __half* p10 = hb + (size_t)(cy1*Ww + cx0)*CH;
        const __half* p11 = hb + (size_t)(cy1*Ww + cx1)*CH;
        __half* op = g_whi + ((size_t)b*HW + y*Ww + x)*KPAD + (size_t)l*Fch;
        #pragma unroll 1
        for (int cg = 0; cg < 12; cg++){
            uint4 v00 = *reinterpret_cast<const uint4*>(p00 + cg*8);
            uint4 v01 = *reinterpret_cast<const uint4*>(p01 + cg*8);
            uint4 v10 = *reinterpret_cast<const uint4*>(p10 + cg*8);
            uint4 v11 = *reinterpret_cast<const uint4*>(p11 + cg*8);
            const uint32_t* a00 = reinterpret_cast<const uint32_t*>(&v00);
            const uint32_t* a01 = reinterpret_cast<const uint32_t*>(&v01);
            const uint32_t* a10 = reinterpret_cast<const uint32_t*>(&v10);
            const uint32_t* a11 = reinterpret_cast<const uint32_t*>(&v11);
            uint32_t outw[4];
            #pragma unroll
            for (int q = 0; q < 4; q++){
                float2 f00 = __half22float2(*reinterpret_cast<const __half2*>(&a00[q]));
                float2 f01 = __half22float2(*reinterpret_cast<const __half2*>(&a01[q]));
                float2 f10 = __half22float2(*reinterpret_cast<const __half2*>(&a10[q]));
                float2 f11 = __half22float2(*reinterpret_cast<const __half2*>(&a11[q]));
                float r0 = w00*f00.x + w01*f01.x + w10*f10.x + w11*f11.x;
                float r1 = w00*f00.y + w01*f01.y + w10*f10.y + w11*f11.y;
                outw[q] = pack2(r0, r1);
            }
            *reinterpret_cast<uint4*>(op + cg*8) = *reinterpret_cast<uint4*>(outw);
        }
    }
}

// ============================================================
// prep: split w_ret (288 x 480, stride KPAD) fp16 hi/lo
// ============================================================
__global__ void k_prepA(const float* __restrict__ w_ret){
    int idx = blockIdx.x*blockDim.x + threadIdx.x;
    if (idx >= FH3*KPAD) return;
    int m = idx / KPAD, k = idx % KPAD;
    float v = (k < K1) ? w_ret[m*K1 + k] : 0.f;
    __half hi = __float2half(v);
    g_Ahi[idx] = hi;
    g_Alo[idx] = __float2half(v - __half2float(hi));
}

// ============================================================
// FUSED h2h GEMM (2-term fp16: AhBh + AlBh) + GRU gates.
// grid (72, B), 256 thr, dyn smem 112.6 KB
// ============================================================
#define TS 40
#define H2_ABUF (288*TS)
#define H2_BBUF (128*TS)
#define H2_SMEM ((4*H2_ABUF + 2*H2_BBUF)*2)   // 112640 B

__global__ void __launch_bounds__(256, 1) k_h2hg(int t,
                                                 const float* __restrict__ bias,
                                                 const float* __restrict__ hprev,
                                                 float* __restrict__ hnext,
                                                 int pack){
    extern __shared__ __half sm[];
    __half* sAh = sm;
    __half* sAl = sm + 2*H2_ABUF;
    __half* sBh = sm + 4*H2_ABUF;
    uint32_t aSh = smem_u32(sAh), aSl = smem_u32(sAl), aBh = smem_u32(sBh);

    int tid = threadIdx.x, lane = tid & 31, wid = tid >> 5;
    int wm = wid & 1, wn = wid >> 1;
    int n0 = blockIdx.x*128, b = blockIdx.y;

    const __half* Bh = g_whi + ((size_t)b*HW + n0)*KPAD;

    int arow = wm*48 + (lane & 15);
    int acol = (lane >> 4) * 8;
    int brow = wn*32 + (lane & 7) + ((lane >> 4) & 1)*8;
    int bcol = ((lane >> 3) & 1) * 8;

    float c[3][3][4][4];
    #pragma unroll
    for (int mt = 0; mt < 3; mt++)
        #pragma unroll
        for (int i = 0; i < 3; i++)
            #pragma unroll
            for (int j = 0; j < 4; j++)
                #pragma unroll
                for (int q = 0; q < 4; q++) c[mt][i][j][q] = 0.f;

    #define H2G_STAGE(chunk, buf) do { \
        uint32_t sbA = (uint32_t)(buf)*(H2_ABUF*2); \
        uint32_t sbB = (uint32_t)(buf)*(H2_BBUF*2); \
        for (int e = tid; e < 1152; e += 256){ \
            int r = e >> 2, u = e & 3; \
            size_t goff = (size_t)r*KPAD + (chunk)*32 + u*8; \
            uint32_t soff = sbA + (uint32_t)(r*TS + u*8)*2u; \
            CPA16(aSh + soff, g_Ahi + goff); \
            CPA16(aSl + soff, g_Alo + goff); \
        } \
        for (int e = tid; e < 512; e += 256){ \
            int r = e >> 2, u = e & 3; \
            size_t goff = (size_t)r*KPAD + (chunk)*32 + u*8; \
            uint32_t soff = sbB + (uint32_t)(r*TS + u*8)*2u; \
            CPA16(aBh + soff, Bh + goff); \
        } \
        CPA_COMMIT(); \
    } while(0)

    H2G_STAGE(0, 0);
    for (int chunk = 0; chunk < 15; chunk++){
        if (chunk + 1 < 15){
            H2G_STAGE(chunk + 1, (chunk + 1) & 1);
            asm volatile("cp.async.wait_group 1;" ::: "memory");
        } else {
            asm volatile("cp.async.wait_group 0;" ::: "memory");
        }
        __syncthreads();

        uint32_t sbA = (uint32_t)(chunk & 1)*(H2_ABUF*2);
        uint32_t sbB = (uint32_t)(chunk & 1)*(H2_BBUF*2);
        #pragma unroll
        for (int ks = 0; ks < 2; ks++){
            int kc = ks*16;
            uint32_t bh[2][4];
            #pragma unroll
            for (int jp = 0; jp < 2; jp++){
                uint32_t off = sbB + 2u*((brow + jp*16)*TS + kc + bcol);
                ldm_x4(bh[jp], aBh + off);
            }
            #pragma unroll
            for (int mt = 0; mt < 3; mt++){
                uint32_t ah[3][4], al[3][4];
                #pragma unroll
                for (int mi = 0; mi < 3; mi++){
                    uint32_t off = sbA + 2u*((mt*96 + arow + mi*16)*TS + kc + acol);
                    ldm_x4(ah[mi], aSh + off);
                    ldm_x4(al[mi], aSl + off);
                }
                #pragma unroll
                for (int mi = 0; mi < 3; mi++){
                    #pragma unroll
                    for (int j = 0; j < 4; j++){
                        uint32_t* fh = &bh[j >> 1][(j & 1)*2];
                        MMA_F16(c[mt][mi][j], ah[mi], fh);
                        MMA_F16(c[mt][mi][j], al[mi], fh);
                    }
                }
            }
        }
        __syncthreads();
    }

    // ---- fused GRU gate epilogue ----
    __syncthreads();
    float* sF = reinterpret_cast<float*>(sm);   // [128 px][stride 100]

    const __half* i2hb = g_i2h + (size_t)(t*Bg + b)*FH3*HW;
    const float* hpb  = hprev + (size_t)b*Fch*HW;
    float* hnb        = hnext + (size_t)b*Fch*HW;

    #pragma unroll
    for (int mi = 0; mi < 3; mi++){
        int fc0 = wm*48 + mi*16 + (lane >> 2);
        #pragma unroll
        for (int j = 0; j < 4; j++){
            int pl = wn*32 + (lane & 3)*2 + j*8;
            int p = n0 + pl;
            #pragma unroll
            for (int half_ = 0; half_ < 2; half_++){
                int fc = fc0 + half_*8;
                int q0 = half_*2;
                float rb = bias[fc], ub = bias[96 + fc], mb = bias[192 + fc];
                float2 i2r = __half22float2(*reinterpret_cast<const __half2*>(i2hb + (size_t)fc*HW + p));
                float2 i2u = __half22float2(*reinterpret_cast<const __half2*>(i2hb + (size_t)(96+fc)*HW + p));
                float2 i2m = __half22float2(*reinterpret_cast<const __half2*>(i2hb + (size_t)(192+fc)*HW + p));
                float2 hpv = *reinterpret_cast<const float2*>(hpb + (size_t)fc*HW + p);
                float nh[2];
                #pragma unroll
                for (int s = 0; s < 2; s++){
                    float hr = c[0][mi][j][q0+s] + rb;
                    float hu = c[1][mi][j][q0+s] + ub;
                    float hm = c[2][mi][j][q0+s] + mb;
                    float ir = s ? i2r.y : i2r.x;
                    float iu = s ? i2u.y : i2u.x;
                    float im = s ? i2m.y : i2m.x;
                    float hp = s ? hpv.y : hpv.x;
                    float reset  = sigm(ir + hr);
                    float update = sigm(iu + hu);
                    float newmem = leaky(im + reset*hm);
                    nh[s] = update*hp + (1.f - update)*newmem;
                }
                float2 wv; wv.x = nh[0]; wv.y = nh[1];
                *reinterpret_cast<float2*>(hnb + (size_t)fc*HW + p) = wv;
                sF[pl*100 + fc]     = nh[0];
                sF[(pl+1)*100 + fc] = nh[1];
            }
        }
    }
    __syncthreads();
    if (pack){
        size_t slotn = (size_t)((t+1)*Bg + b)*HW;
        for (int e = tid; e < 128*12; e += 256){
            int pl = e/12, u = e%12;
            const float* src = sF + pl*100 + u*8;
            uint32_t hw[4];
            #pragma unroll
            for (int q = 0; q < 4; q++)
                hw[q] = pack2(src[2*q], src[2*q+1]);
            size_t off = (slotn + n0 + pl)*CH + 8 + u*8;
            *reinterpret_cast<uint4*>(g_inhi + off) = *reinterpret_cast<uint4*>(hw);
        }
    }
}

// ============================================================
extern "C" void kernel_launch(void* const* d_in, const int* in_sizes, int n_in,
                              void* d_out, int out_size){
    const float* inputs = (const float*)d_in[0];
    const float* h0     = (const float*)d_in[1];
    const float* w_i2h  = (const float*)d_in[2];
    const float* b_i2h  = (const float*)d_in[3];
    const float* w_i2f  = (const float*)d_in[4];
    const float* b_i2f  = (const float*)d_in[5];
    const float* w_h2f  = (const float*)d_in[6];
    const float* b_h2f  = (const float*)d_in[7];
    const float* w_fl   = (const float*)d_in[8];
    const float* b_fl   = (const float*)d_in[9];
    const float* w_ret  = (const float*)d_in[10];
    const float* b_ret  = (const float*)d_in[11];
    float* out = (float*)d_out;

    cudaFuncSetAttribute(k_fconv,  cudaFuncAttributeMaxDynamicSharedMemorySize, FSM_BYTES);
    cudaFuncSetAttribute(k_flowsW, cudaFuncAttributeMaxDynamicSharedMemorySize, FSM_BYTES);
    cudaFuncSetAttribute(k_h2hg,   cudaFuncAttributeMaxDynamicSharedMemorySize, H2_SMEM);

    // once per launch
    k_prepX   <<<(Sg*Bg*HW + 255)/256, 256>>>(inputs, h0);
    k_prepWall<<<(89600 + 25600 + 20736 + 255)/256, 256>>>(w_i2f, w_h2f, w_fl, w_i2h);
    k_prepA   <<<(FH3*KPAD + 255)/256, 256>>>(w_ret);
    k_i2hT    <<<dim3(48, Sg*Bg), 256>>>(b_i2h);

    for (int t = 0; t < Sg; t++){
        const float* h = (t == 0) ? h0 : out + (size_t)(t-1)*STEP_ELEMS;
        float* hn = out + (size_t)t*STEP_ELEMS;

        k_fconv <<<dim3(48, Bg), 256, FSM_BYTES>>>(t, b_i2f, b_h2f);
        k_flowsW<<<dim3(48, Bg), 256, FSM_BYTES>>>(t, b_fl);
        k_h2hg  <<<dim3(HW/128, Bg), 256, H2_SMEM>>>(t, b_ret, h, hn, (t < Sg-1) ? 1 : 0);
    }

    const size_t OUT_SEQ = (size_t)Sg*STEP_ELEMS;
    if ((size_t)out_size >= OUT_SEQ + STEP_ELEMS){
        cudaMemcpyAsync(out + OUT_SEQ, out + (size_t)(Sg-1)*STEP_ELEMS,
                        (size_t)STEP_ELEMS*sizeof(float),
                        cudaMemcpyDeviceToDevice);
    }
}

// round 13
// speedup vs baseline: 6.1714x; 1.1193x over previous
#include <cuda_runtime.h>
#include <cuda_fp16.h>
#include <cstdint>
#include <math.h>

#define Hh 96
#define Ww 96
#define HW 9216
#define Fch 96
#define CIN 8
#define Lk 5
#define Sg 10
#define Bg 4
#define FH3 288          // 3*F
#define K1 480           // L*F
#define KPAD 512         // row STRIDE of k-major operands (pad cols never read)
#define CH 112           // packed input channels: 8 x | 96 h | 8 zero
#define STEP_ELEMS (Bg*Fch*HW)   // 3,538,944

// ---- scratch (device globals) ----
__device__ __align__(16) __half g_i2h[(size_t)Sg*Bg*FH3*HW];  // 212 MB (once), fp16
__device__ __align__(16) __half g_whi[(size_t)Bg*HW*KPAD];    // warped^T hi [b][p][k]
__device__ __align__(16) __half g_Ahi[(size_t)FH3*KPAD];      // w_ret hi [m][k]
// fconv inputs: per-step slots [Sg][Bg][p][112] (hi only)
__device__ __align__(16) __half g_inhi[(size_t)Sg*Bg*HW*CH];
__device__ __align__(16) __half g_wfhi[7*25*32*16];           // [chunk][tap][oc][16]
// f (1-term) [b][p][32]
__device__ __align__(16) __half g_fhi[(size_t)Bg*HW*32];
// flows weights [chunk2][tap25][oc32][16] (oc>=10 zero)
__device__ __align__(16) __half g_w2hi[2*25*32*16];
// i2h weights [ocg3][tap9][oc96][8] hi/lo
__device__ __align__(16) __half g_w3hi[3*9*96*8];
__device__ __align__(16) __half g_w3lo[3*9*96*8];

__device__ __forceinline__ float leaky(float v){ return v > 0.f ? v : 0.2f*v; }
__device__ __forceinline__ float sigm(float v){ return 1.f/(1.f + expf(-v)); }

__device__ __forceinline__ uint32_t smem_u32(const void* p){
    uint32_t a;
    asm("{ .reg .u64 t; cvta.to.shared.u64 t, %1; cvt.u32.u64 %0, t; }" : "=r"(a) : "l"(p));
    return a;
}
__device__ __forceinline__ void ldm_x4(uint32_t* r, uint32_t addr){
    asm volatile("ldmatrix.sync.aligned.m8n8.x4.shared.b16 {%0,%1,%2,%3}, [%4];"
        : "=r"(r[0]), "=r"(r[1]), "=r"(r[2]), "=r"(r[3]) : "r"(addr));
}
__device__ __forceinline__ void ldm_x2(uint32_t* r, uint32_t addr){
    asm volatile("ldmatrix.sync.aligned.m8n8.x2.shared.b16 {%0,%1}, [%2];"
        : "=r"(r[0]), "=r"(r[1]) : "r"(addr));
}
#define MMA_F16(c, a, b) \
    asm volatile("mma.sync.aligned.m16n8k16.row.col.f32.f16.f16.f32 " \
        "{%0,%1,%2,%3}, {%4,%5,%6,%7}, {%8,%9}, {%0,%1,%2,%3};" \
        : "+f"((c)[0]), "+f"((c)[1]), "+f"((c)[2]), "+f"((c)[3]) \
        : "r"((a)[0]), "r"((a)[1]), "r"((a)[2]), "r"((a)[3]), \
          "r"((b)[0]), "r"((b)[1]))
#define MMA_F16_K8(c, a, b) \
    asm volatile("mma.sync.aligned.m16n8k8.row.col.f32.f16.f16.f32 " \
        "{%0,%1,%2,%3}, {%4,%5}, {%6}, {%0,%1,%2,%3};" \
        : "+f"((c)[0]), "+f"((c)[1]), "+f"((c)[2]), "+f"((c)[3]) \
        : "r"((a)[0]), "r"((a)[1]), "r"(b))
#define CPA16(sm, gp) asm volatile("cp.async.ca.shared.global [%0], [%1], 16;" :: "r"(sm), "l"(gp))
#define CPA_COMMIT()  asm volatile("cp.async.commit_group;" ::: "memory")

__device__ __forceinline__ uint32_t pack2(float v0, float v1){
    __half2 hp = __halves2half2(__float2half(v0), __float2half(v1));
    return *reinterpret_cast<uint32_t*>(&hp);
}

// ============================================================
// k_prepX (once): pack x channels (hi) for ALL step slots, zero pad,
// slot-0 h channels from h0.
// ============================================================
__global__ void k_prepX(const float* __restrict__ inputs, const float* __restrict__ h0){
    int idx = blockIdx.x*blockDim.x + threadIdx.x;
    if (idx >= Sg*Bg*HW) return;
    int p = idx % HW, b = (idx/HW) % Bg, t = idx/(HW*Bg);
    size_t base = ((size_t)(t*Bg + b)*HW + p)*CH;
    const float* xp = inputs + ((size_t)(t*Bg + b)*CIN)*HW + p;
    uint32_t hw[4];
    #pragma unroll
    for (int q = 0; q < 4; q++)
        hw[q] = pack2(xp[(size_t)(2*q)*HW], xp[(size_t)(2*q+1)*HW]);
    *reinterpret_cast<uint4*>(g_inhi + base) = *reinterpret_cast<uint4*>(hw);
    uint4 z = make_uint4(0,0,0,0);
    *reinterpret_cast<uint4*>(g_inhi + base + 104) = z;
    if (t == 0){
        const float* hp = h0 + (size_t)b*Fch*HW + p;
        for (int g = 0; g < 12; g++){
            #pragma unroll
            for (int q = 0; q < 4; q++)
                hw[q] = pack2(hp[(size_t)(g*8 + 2*q)*HW], hp[(size_t)(g*8 + 2*q+1)*HW]);
            *reinterpret_cast<uint4*>(g_inhi + base + 8 + g*8) = *reinterpret_cast<uint4*>(hw);
        }
    }
}

// ============================================================
// k_prepWall (once): conv-weight repacks (fp16)
// ============================================================
__global__ void k_prepWall(const float* __restrict__ w_i2f, const float* __restrict__ w_h2f,
                           const float* __restrict__ w_fl,  const float* __restrict__ w_i2h){
    int idx = blockIdx.x*blockDim.x + threadIdx.x;
    if (idx < 89600){
        int o = idx;
        int kc = o & 15, oc = (o >> 4) & 31, tap = (o >> 9) % 25, chunk = o / 12800;
        int ch = chunk*16 + kc;
        float v = 0.f;
        if (ch < 8)        v = w_i2f[(oc*8 + ch)*25 + tap];
        else if (ch < 104) v = w_h2f[((size_t)oc*Fch + (ch-8))*25 + tap];
        g_wfhi[o] = __float2half(v);
    } else if (idx < 89600 + 25600){
        int o = idx - 89600;
        int kc = o & 15, oc = (o >> 4) & 31, tap = (o >> 9) % 25, chunk = o / 12800;
        int ch = chunk*16 + kc;
        float v = (oc < 10) ? w_fl[((size_t)oc*32 + ch)*25 + tap] : 0.f;
        g_w2hi[o] = __float2half(v);
    } else if (idx < 89600 + 25600 + 20736){
        int o = idx - 89600 - 25600;
        int ch = o & 7, oc = (o >> 3) % 96, tap = (o/(96*8)) % 9, ocg = o/(9*96*8);
        float v = w_i2h[((size_t)(ocg*96 + oc)*CIN + ch)*9 + tap];
        __half hi = __float2half(v);
        g_w3hi[o] = hi;
        g_w3lo[o] = __float2half(v - __half2float(hi));
    }
}

// ============================================================
// i2h implicit GEMM (m16n8k8, fp16 2-term), once.
// 2 IMAGES per CTA: inputs staged once each, weights staged once
// per ocg and reused for both images. grid (48, 20), 256 thr
// ============================================================
__global__ void __launch_bounds__(256, 2) k_i2hT(const float* __restrict__ bias){
    __shared__ __half sInH[2][400*8];
    __shared__ __half sWH[9*96*8], sWL[9*96*8];
    uint32_t aIn0 = smem_u32(sInH[0]);
    uint32_t aWH  = smem_u32(sWH),  aWL  = smem_u32(sWL);

    int tid = threadIdx.x, lane = tid & 31, wid = tid >> 5;
    int wm = wid & 3, wn = wid >> 2;
    int y0 = blockIdx.x*2, img0 = blockIdx.y*2;

    for (int e = tid; e < 800; e += 256){
        int im = e/400, ent = e%400;
        int row = ent/100, cc = ent%100;
        int y = y0 + row - 1, x = cc - 1;
        uint4 vh = make_uint4(0,0,0,0);
        if ((unsigned)y < 96u && (unsigned)x < 96u)
            vh = *reinterpret_cast<const uint4*>(g_inhi + ((size_t)(img0+im)*HW + y*Ww + x)*CH);
        *reinterpret_cast<uint4*>(sInH[im] + ent*8) = vh;
    }

    #pragma unroll 1
    for (int ocg = 0; ocg < 3; ocg++){
        __syncthreads();   // inputs visible (iter0) / prev compute done
        for (int e = tid; e < 864; e += 256){
            reinterpret_cast<uint4*>(sWH)[e] = reinterpret_cast<const uint4*>(g_w3hi + (size_t)ocg*9*96*8)[e];
            reinterpret_cast<uint4*>(sWL)[e] = reinterpret_cast<const uint4*>(g_w3lo + (size_t)ocg*9*96*8)[e];
        }
        __syncthreads();

        #pragma unroll 1
        for (int im = 0; im < 2; im++){
            uint32_t aInH = aIn0 + (uint32_t)im*(400*8*2);
            float c[3][6][4];
            #pragma unroll
            for (int i = 0; i < 3; i++)
                #pragma unroll
                for (int j = 0; j < 6; j++)
                    #pragma unroll
                    for (int q = 0; q < 4; q++) c[i][j][q] = 0.f;

            #pragma unroll 1
            for (int tap = 0; tap < 9; tap++){
                int dy = tap/3, dx = tap%3;
                uint32_t bh[6], bl[6];
                {
                    ldm_x4(bh, aWH + 2u*(uint32_t)((tap*96 + wn*48 + lane)*8));
                    ldm_x4(bl, aWL + 2u*(uint32_t)((tap*96 + wn*48 + lane)*8));
                    uint32_t a2 = 2u*(uint32_t)((tap*96 + wn*48 + 32 + (lane & 15))*8);
                    ldm_x2(bh + 4, aWH + a2);
                    ldm_x2(bl + 4, aWL + a2);
                }
                uint32_t ah[3][2];
                #pragma unroll
                for (int mi = 0; mi < 3; mi++){
                    int tmi = wm*3 + mi;
                    int r = tmi/6, xb = (tmi%6)*16;
                    uint32_t aoff = 2u*(uint32_t)(((r+dy)*100 + xb + (lane&15) + dx)*8);
                    ldm_x2(ah[mi], aInH + aoff);
                }
                #pragma unroll
                for (int mi = 0; mi < 3; mi++){
                    #pragma unroll
                    for (int j = 0; j < 6; j++){
                        MMA_F16_K8(c[mi][j], ah[mi], bh[j]);
                        MMA_F16_K8(c[mi][j], ah[mi], bl[j]);
                    }
                }
            }

            __half* Ob = g_i2h + (size_t)(img0+im)*FH3*HW;
            #pragma unroll
            for (int mi = 0; mi < 3; mi++){
                int tmi = wm*3 + mi;
                int r = tmi/6, xb = (tmi%6)*16;
                int p = (y0 + r)*Ww + xb + (lane>>2);
                #pragma unroll
                for (int j = 0; j < 6; j++){
                    int oc = ocg*96 + wn*48 + j*8 + (lane&3)*2;
                    float bv0 = bias[oc], bv1 = bias[oc+1];
                    Ob[(size_t)oc*HW + p]         = __float2half(c[mi][j][0] + bv0);
                    Ob[(size_t)(oc+1)*HW + p]     = __float2half(c[mi][j][1] + bv1);
                    Ob[(size_t)oc*HW + p + 8]     = __float2half(c[mi][j][2] + bv0);
                    Ob[(size_t)(oc+1)*HW + p + 8] = __float2half(c[mi][j][3] + bv1);
                }
            }
        }
    }
}

// ============================================================
// fconv implicit GEMM — 1-term fp16. CTA = 2 rows x 96 px, N=32.
// ============================================================
#define FSM_BYTES ((14400 + 12800)*2)

__global__ void __launch_bounds__(256, 2) k_fconv(int t,
                                                  const float* __restrict__ b_i2f,
                                                  const float* __restrict__ b_h2f){
    extern __shared__ __half sm[];
    __half* sInH = sm;
    __half* sWH  = sm + 14400;
    uint32_t aInH = smem_u32(sInH), aWH = smem_u32(sWH);

    int tid = threadIdx.x, lane = tid & 31, wid = tid >> 5;
    int wm = wid & 3, wn = wid >> 2;
    int y0 = blockIdx.x*2, b = blockIdx.y;
    size_t slot = (size_t)(t*Bg + b)*HW;

    float c[3][2][4];
    #pragma unroll
    for (int i = 0; i < 3; i++)
        #pragma unroll
        for (int j = 0; j < 2; j++)
            #pragma unroll
            for (int q = 0; q < 4; q++) c[i][j][q] = 0.f;

    for (int chunk = 0; chunk < 7; chunk++){
        __syncthreads();
        for (int e = tid; e < 1200; e += 256){
            int ent = e >> 1, half_ = e & 1;
            int row = ent/100, cc = ent%100;
            int y = y0 + row - 2, x = cc - 2;
            uint4 vh = make_uint4(0,0,0,0);
            if ((unsigned)y < 96u && (unsigned)x < 96u){
                size_t off = (slot + y*Ww + x)*CH + chunk*16 + half_*8;
                vh = *reinterpret_cast<const uint4*>(g_inhi + off);
            }
            *reinterpret_cast<uint4*>(sInH + ent*24 + half_*8) = vh;
        }
        for (int e = tid; e < 1600; e += 256){
            reinterpret_cast<uint4*>(sWH)[e] = reinterpret_cast<const uint4*>(g_wfhi + chunk*12800)[e];
        }
        __syncthreads();

        #pragma unroll 1
        for (int tap = 0; tap < 25; tap++){
            int dy = tap/5, dx = tap%5;
            uint32_t bh[4];
            uint32_t boff = 2u*(uint32_t)((tap*32 + wn*16 + (lane&7) + ((lane>>4)&1)*8)*16
                                          + ((lane>>3)&1)*8);
            ldm_x4(bh, aWH + boff);
            uint32_t ah[3][4];
            #pragma unroll
            for (int mi = 0; mi < 3; mi++){
                int tmi = wm*3 + mi;
                int r = tmi/6, xb = (tmi%6)*16;
                uint32_t aoff = 2u*(uint32_t)(((r+dy)*100 + xb + (lane&15) + dx)*24
                                              + (lane>>4)*8);
                ldm_x4(ah[mi], aInH + aoff);
            }
            #pragma unroll
            for (int mi = 0; mi < 3; mi++){
                #pragma unroll
                for (int j = 0; j < 2; j++){
                    MMA_F16(c[mi][j], ah[mi], &bh[j*2]);
                }
            }
        }
    }

    #pragma unroll
    for (int mi = 0; mi < 3; mi++){
        int tmi = wm*3 + mi;
        int r = tmi/6, xb = (tmi%6)*16;
        int gp = (y0 + r)*Ww + xb + (lane>>2);
        #pragma unroll
        for (int j = 0; j < 2; j++){
            int oc = wn*16 + j*8 + (lane&3)*2;
            float bb0 = b_i2f[oc]   + b_h2f[oc];
            float bb1 = b_i2f[oc+1] + b_h2f[oc+1];
            *reinterpret_cast<uint32_t*>(g_fhi + ((size_t)b*HW + gp)*32 + oc)
                = pack2(leaky(c[mi][j][0] + bb0), leaky(c[mi][j][1] + bb1));
            *reinterpret_cast<uint32_t*>(g_fhi + ((size_t)b*HW + gp + 8)*32 + oc)
                = pack2(leaky(c[mi][j][2] + bb0), leaky(c[mi][j][3] + bb1));
        }
    }
}

// ============================================================
// flowsT + FUSED warp (as R12). grid (48, B), 256 thr
// ============================================================
__global__ void __launch_bounds__(256, 2) k_flowsW(int t, const float* __restrict__ b_fl){
    extern __shared__ __half sm[];
    __half* sInH = sm;
    __half* sWH  = sm + 14400;
    uint32_t aInH = smem_u32(sInH), aWH = smem_u32(sWH);

    int tid = threadIdx.x, lane = tid & 31, wid = tid >> 5;
    int wm = wid & 3, wn = wid >> 2;
    int y0 = blockIdx.x*2, b = blockIdx.y;

    float c[3][2][4];
    #pragma unroll
    for (int i = 0; i < 3; i++)
        #pragma unroll
        for (int j = 0; j < 2; j++)
            #pragma unroll
            for (int q = 0; q < 4; q++) c[i][j][q] = 0.f;

    for (int chunk = 0; chunk < 2; chunk++){
        __syncthreads();
        for (int e = tid; e < 1200; e += 256){
            int ent = e >> 1, half_ = e & 1;
            int row = ent/100, cc = ent%100;
            int y = y0 + row - 2, x = cc - 2;
            uint4 vh = make_uint4(0,0,0,0);
            if ((unsigned)y < 96u && (unsigned)x < 96u){
                size_t off = ((size_t)b*HW + y*Ww + x)*32 + chunk*16 + half_*8;
                vh = *reinterpret_cast<const uint4*>(g_fhi + off);
            }
            *reinterpret_cast<uint4*>(sInH + ent*24 + half_*8) = vh;
        }
        for (int e = tid; e < 1600; e += 256){
            reinterpret_cast<uint4*>(sWH)[e] = reinterpret_cast<const uint4*>(g_w2hi + chunk*12800)[e];
        }
        __syncthreads();

        #pragma unroll 1
        for (int tap = 0; tap < 25; tap++){
            int dy = tap/5, dx = tap%5;
            uint32_t bh[4];
            uint32_t boff = 2u*(uint32_t)((tap*32 + wn*16 + (lane&7) + ((lane>>4)&1)*8)*16
                                          + ((lane>>3)&1)*8);
            ldm_x4(bh, aWH + boff);
            uint32_t ah[3][4];
            #pragma unroll
            for (int mi = 0; mi < 3; mi++){
                int tmi = wm*3 + mi;
                int r = tmi/6, xb = (tmi%6)*16;
                uint32_t aoff = 2u*(uint32_t)(((r+dy)*100 + xb + (lane&15) + dx)*24
                                              + (lane>>4)*8);
                ldm_x4(ah[mi], aInH + aoff);
            }
            #pragma unroll
            for (int mi = 0; mi < 3; mi++){
                #pragma unroll
                for (int j = 0; j < 2; j++){
                    MMA_F16(c[mi][j], ah[mi], &bh[j*2]);
                }
            }
        }
    }

    // ---- stage flows into smem [192 px][10] (aliases sInH) ----
    __syncthreads();
    float* sFl = reinterpret_cast<float*>(sm);
    #pragma unroll
    for (int mi = 0; mi < 3; mi++){
        int tmi = wm*3 + mi;
        int r = tmi/6, xb = (tmi%6)*16;
        int pl = r*96 + xb + (lane>>2);
        #pragma unroll
        for (int j = 0; j < 2; j++){
            int oc = wn*16 + j*8 + (lane&3)*2;
            if (oc < 10){
                float bv0 = b_fl[oc], bv1 = b_fl[oc+1];
                sFl[pl*10 + oc]         = c[mi][j][0] + bv0;
                sFl[pl*10 + oc + 1]     = c[mi][j][1] + bv1;
                sFl[(pl+8)*10 + oc]     = c[mi][j][2] + bv0;
                sFl[(pl+8)*10 + oc + 1] = c[mi][j][3] + bv1;
            }
        }
    }
    __syncthreads();

    // ---- fused warp: 960 tasks = 192 px x 5 links ----
    const __half* hb = g_inhi + (size_t)(t*Bg + b)*HW*CH + 8;   // h section
    const float scg = 96.0f/95.0f;
    for (int task = tid; task < 960; task += 256){
        int px = task/5, l = task%5;
        int y = y0 + px/96, x = px%96;
        float fx = sFl[px*10 + 2*l];
        float fy = sFl[px*10 + 2*l + 1];
        float ix = ((float)x - fx)*scg - 0.5f;
        float iy = ((float)y - fy)*scg - 0.5f;
        float fx0 = floorf(ix), fy0 = floorf(iy);
        int ix0 = (int)fx0, iy0 = (int)fy0;
        int ix1 = ix0 + 1, iy1 = iy0 + 1;
        float wx1 = ix - fx0, wy1 = iy - fy0;
        float wx0 = 1.f - wx1, wy0 = 1.f - wy1;
        float mx0 = (ix0 >= 0 && ix0 < Ww) ? 1.f : 0.f;
        float mx1 = (ix1 >= 0 && ix1 < Ww) ? 1.f : 0.f;
        float my0 = (iy0 >= 0 && iy0 < Hh) ? 1.f : 0.f;
        float my1 = (iy1 >= 0 && iy1 < Hh) ? 1.f : 0.f;
        int cx0 = min(max(ix0, 0), Ww-1), cx1 = min(max(ix1, 0), Ww-1);
        int cy0 = min(max(iy0, 0), Hh-1), cy1 = min(max(iy1, 0), Hh-1);
        float w00 = wy0*wx0*my0*mx0, w01 = wy0*wx1*my0*mx1;
        float w10 = wy1*wx0*my1*mx0, w11 = wy1*wx1*my1*mx1;
        const __half* p00 = hb + (size_t)(cy0*Ww + cx0)*CH;
        const __half* p01 = hb + (size_t)(cy0*Ww + cx1)*CH;
        const __half* p10 = hb + (size_t)(cy1*Ww + cx0)*CH;
        const __half* p11 = hb + (size_t)(cy1*Ww + cx1)*CH;
        __half* op = g_whi + ((size_t)b*HW + y*Ww + x)*KPAD + (size_t)l*Fch;
        #pragma unroll 1
        for (int cg = 0; cg < 12; cg++){
            uint4 v00 = *reinterpret_cast<const uint4*>(p00 + cg*8);
            uint4 v01 = *reinterpret_cast<const uint4*>(p01 + cg*8);
            uint4 v10 = *reinterpret_cast<const uint4*>(p10 + cg*8);
            uint4 v11 = *reinterpret_cast<const uint4*>(p11 + cg*8);
            const uint32_t* a00 = reinterpret_cast<const uint32_t*>(&v00);
            const uint32_t* a01 = reinterpret_cast<const uint32_t*>(&v01);
            const uint32_t* a10 = reinterpret_cast<const uint32_t*>(&v10);
            const uint32_t* a11 = reinterpret_cast<const uint32_t*>(&v11);
            uint32_t outw[4];
            #pragma unroll
            for (int q = 0; q < 4; q++){
                float2 f00 = __half22float2(*reinterpret_cast<const __half2*>(&a00[q]));
                float2 f01 = __half22float2(*reinterpret_cast<const __half2*>(&a01[q]));
                float2 f10 = __half22float2(*reinterpret_cast<const __half2*>(&a10[q]));
                float2 f11 = __half22float2(*reinterpret_cast<const __half2*>(&a11[q]));
                float r0 = w00*f00.x + w01*f01.x + w10*f10.x + w11*f11.x;
                float r1 = w00*f00.y + w01*f01.y + w10*f10.y + w11*f11.y;
                outw[q] = pack2(r0, r1);
            }
            *reinterpret_cast<uint4*>(op + cg*8) = *reinterpret_cast<uint4*>(outw);
        }
    }
}

// ============================================================
// prep: w_ret hi (288 x 480, stride KPAD) fp16
// ============================================================
__global__ void k_prepA(const float* __restrict__ w_ret){
    int idx = blockIdx.x*blockDim.x + threadIdx.x;
    if (idx >= FH3*KPAD) return;
    int m = idx / KPAD, k = idx % KPAD;
    float v = (k < K1) ? w_ret[m*K1 + k] : 0.f;
    g_Ahi[idx] = __float2half(v);
}

// ============================================================
// FUSED h2h GEMM (1-term fp16) + GRU gates.
// grid (72, B), 256 thr, dyn smem 66.6 KB
// ============================================================
#define TS 40
#define H2_ABUF (288*TS)
#define H2_BBUF (128*TS)
#define H2_SMEM ((2*H2_ABUF + 2*H2_BBUF)*2)   // 66560 B

__global__ void __launch_bounds__(256, 1) k_h2hg(int t,
                                                 const float* __restrict__ bias,
                                                 const float* __restrict__ hprev,
                                                 float* __restrict__ hnext,
                                                 int pack){
    extern __shared__ __half sm[];
    __half* sAh = sm;                      // 2*H2_ABUF (double buffer)
    __half* sBh = sm + 2*H2_ABUF;          // 2*H2_BBUF
    uint32_t aSh = smem_u32(sAh), aBh = smem_u32(sBh);

    int tid = threadIdx.x, lane = tid & 31, wid = tid >> 5;
    int wm = wid & 1, wn = wid >> 1;
    int n0 = blockIdx.x*128, b = blockIdx.y;

    const __half* Bh = g_whi + ((size_t)b*HW + n0)*KPAD;

    int arow = wm*48 + (lane & 15);
    int acol = (lane >> 4) * 8;
    int brow = wn*32 + (lane & 7) + ((lane >> 4) & 1)*8;
    int bcol = ((lane >> 3) & 1) * 8;

    float c[3][3][4][4];
    #pragma unroll
    for (int mt = 0; mt < 3; mt++)
        #pragma unroll
        for (int i = 0; i < 3; i++)
            #pragma unroll
            for (int j = 0; j < 4; j++)
                #pragma unroll
                for (int q = 0; q < 4; q++) c[mt][i][j][q] = 0.f;

    #define H2G_STAGE(chunk, buf) do { \
        uint32_t sbA = (uint32_t)(buf)*(H2_ABUF*2); \
        uint32_t sbB = (uint32_t)(buf)*(H2_BBUF*2); \
        for (int e = tid; e < 1152; e += 256){ \
            int r = e >> 2, u = e & 3; \
            size_t goff = (size_t)r*KPAD + (chunk)*32 + u*8; \
            uint32_t soff = sbA + (uint32_t)(r*TS + u*8)*2u; \
            CPA16(aSh + soff, g_Ahi + goff); \
        } \
        for (int e = tid; e < 512; e += 256){ \
            int r = e >> 2, u = e & 3; \
            size_t goff = (size_t)r*KPAD + (chunk)*32 + u*8; \
            uint32_t soff = sbB + (uint32_t)(r*TS + u*8)*2u; \
            CPA16(aBh + soff, Bh + goff); \
        } \
        CPA_COMMIT(); \
    } while(0)

    H2G_STAGE(0, 0);
    for (int chunk = 0; chunk < 15; chunk++){
        if (chunk + 1 < 15){
            H2G_STAGE(chunk + 1, (chunk + 1) & 1);
            asm volatile("cp.async.wait_group 1;" ::: "memory");
        } else {
            asm volatile("cp.async.wait_group 0;" ::: "memory");
        }
        __syncthreads();

        uint32_t sbA = (uint32_t)(chunk & 1)*(H2_ABUF*2);
        uint32_t sbB = (uint32_t)(chunk & 1)*(H2_BBUF*2);
        #pragma unroll
        for (int ks = 0; ks < 2; ks++){
            int kc = ks*16;
            uint32_t bh[2][4];
            #pragma unroll
            for (int jp = 0; jp < 2; jp++){
                uint32_t off = sbB + 2u*((brow + jp*16)*TS + kc + bcol);
                ldm_x4(bh[jp], aBh + off);
            }
            #pragma unroll
            for (int mt = 0; mt < 3; mt++){
                uint32_t ah[3][4];
                #pragma unroll
                for (int mi = 0; mi < 3; mi++){
                    uint32_t off = sbA + 2u*((mt*96 + arow + mi*16)*TS + kc + acol);
                    ldm_x4(ah[mi], aSh + off);
                }
                #pragma unroll
                for (int mi = 0; mi < 3; mi++){
                    #pragma unroll
                    for (int j = 0; j < 4; j++){
                        uint32_t* fh = &bh[j >> 1][(j & 1)*2];
                        MMA_F16(c[mt][mi][j], ah[mi], fh);
                    }
                }
            }
        }
        __syncthreads();
    }

    // ---- fused GRU gate epilogue ----
    __syncthreads();
    float* sF = reinterpret_cast<float*>(sm);   // [128 px][stride 100]

    const __half* i2hb = g_i2h + (size_t)(t*Bg + b)*FH3*HW;
    const float* hpb  = hprev + (size_t)b*Fch*HW;
    float* hnb        = hnext + (size_t)b*Fch*HW;

    #pragma unroll
    for (int mi = 0; mi < 3; mi++){
        int fc0 = wm*48 + mi*16 + (lane >> 2);
        #pragma unroll
        for (int j = 0; j < 4; j++){
            int pl = wn*32 + (lane & 3)*2 + j*8;
            int p = n0 + pl;
            #pragma unroll
            for (int half_ = 0; half_ < 2; half_++){
                int fc = fc0 + half_*8;
                int q0 = half_*2;
                float rb = bias[fc], ub = bias[96 + fc], mb = bias[192 + fc];
                float2 i2r = __half22float2(*reinterpret_cast<const __half2*>(i2hb + (size_t)fc*HW + p));
                float2 i2u = __half22float2(*reinterpret_cast<const __half2*>(i2hb + (size_t)(96+fc)*HW + p));
                float2 i2m = __half22float2(*reinterpret_cast<const __half2*>(i2hb + (size_t)(192+fc)*HW + p));
                float2 hpv = *reinterpret_cast<const float2*>(hpb + (size_t)fc*HW + p);
                float nh[2];
                #pragma unroll
                for (int s = 0; s < 2; s++){
                    float hr = c[0][mi][j][q0+s] + rb;
                    float hu = c[1][mi][j][q0+s] + ub;
                    float hm = c[2][mi][j][q0+s] + mb;
                    float ir = s ? i2r.y : i2r.x;
                    float iu = s ? i2u.y : i2u.x;
                    float im = s ? i2m.y : i2m.x;
                    float hp = s ? hpv.y : hpv.x;
                    float reset  = sigm(ir + hr);
                    float update = sigm(iu + hu);
                    float newmem = leaky(im + reset*hm);
                    nh[s] = update*hp + (1.f - update)*newmem;
                }
                float2 wv; wv.x = nh[0]; wv.y = nh[1];
                *reinterpret_cast<float2*>(hnb + (size_t)fc*HW + p) = wv;
                sF[pl*100 + fc]     = nh[0];
                sF[(pl+1)*100 + fc] = nh[1];
            }
        }
    }
    __syncthreads();
    if (pack){
        size_t slotn = (size_t)((t+1)*Bg + b)*HW;
        for (int e = tid; e < 128*12; e += 256){
            int pl = e/12, u = e%12;
            const float* src = sF + pl*100 + u*8;
            uint32_t hw[4];
            #pragma unroll
            for (int q = 0; q < 4; q++)
                hw[q] = pack2(src[2*q], src[2*q+1]);
            size_t off = (slotn + n0 + pl)*CH + 8 + u*8;
            *reinterpret_cast<uint4*>(g_inhi + off) = *reinterpret_cast<uint4*>(hw);
        }
    }
}

// ============================================================
extern "C" void kernel_launch(void* const* d_in, const int* in_sizes, int n_in,
                              void* d_out, int out_size){
    const float* inputs = (const float*)d_in[0];
    const float* h0     = (const float*)d_in[1];
    const float* w_i2h  = (const float*)d_in[2];
    const float* b_i2h  = (const float*)d_in[3];
    const float* w_i2f  = (const float*)d_in[4];
    const float* b_i2f  = (const float*)d_in[5];
    const float* w_h2f  = (const float*)d_in[6];
    const float* b_h2f  = (const float*)d_in[7];
    const float* w_fl   = (const float*)d_in[8];
    const float* b_fl   = (const float*)d_in[9];
    const float* w_ret  = (const float*)d_in[10];
    const float* b_ret  = (const float*)d_in[11];
    float* out = (float*)d_out;

    cudaFuncSetAttribute(k_fconv,  cudaFuncAttributeMaxDynamicSharedMemorySize, FSM_BYTES);
    cudaFuncSetAttribute(k_flowsW, cudaFuncAttributeMaxDynamicSharedMemorySize, FSM_BYTES);
    cudaFuncSetAttribute(k_h2hg,   cudaFuncAttributeMaxDynamicSharedMemorySize, H2_SMEM);

    // once per launch
    k_prepX   <<<(Sg*Bg*HW + 255)/256, 256>>>(inputs, h0);
    k_prepWall<<<(89600 + 25600 + 20736 + 255)/256, 256>>>(w_i2f, w_h2f, w_fl, w_i2h);
    k_prepA   <<<(FH3*KPAD + 255)/256, 256>>>(w_ret);
    k_i2hT    <<<dim3(48, Sg*Bg/2), 256>>>(b_i2h);

    for (int t = 0; t < Sg; t++){
        const float* h = (t == 0) ? h0 : out + (size_t)(t-1)*STEP_ELEMS;
        float* hn = out + (size_t)t*STEP_ELEMS;

        k_fconv <<<dim3(48, Bg), 256, FSM_BYTES>>>(t, b_i2f, b_h2f);
        k_flowsW<<<dim3(48, Bg), 256, FSM_BYTES>>>(t, b_fl);
        k_h2hg  <<<dim3(HW/128, Bg), 256, H2_SMEM>>>(t, b_ret, h, hn, (t < Sg-1) ? 1 : 0);
    }

    const size_t OUT_SEQ = (size_t)Sg*STEP_ELEMS;
    if ((size_t)out_size >= OUT_SEQ + STEP_ELEMS){
        cudaMemcpyAsync(out + OUT_SEQ, out + (size_t)(Sg-1)*STEP_ELEMS,
                        (size_t)STEP_ELEMS*sizeof(float),
                        cudaMemcpyDeviceToDevice);
    }
}

// round 14
// speedup vs baseline: 6.2375x; 1.0107x over previous
#include <cuda_runtime.h>
#include <cuda_fp16.h>
#include <cstdint>
#include <math.h>

#define Hh 96
#define Ww 96
#define HW 9216
#define Fch 96
#define CIN 8
#define Lk 5
#define Sg 10
#define Bg 4
#define FH3 288          // 3*F
#define K1 480           // L*F
#define KPAD 512         // row STRIDE of k-major operands (pad cols never read)
#define CH 112           // packed input channels: 8 x | 96 h | 8 zero
#define STEP_ELEMS (Bg*Fch*HW)   // 3,538,944

// ---- scratch (device globals) ----
__device__ __align__(16) __half g_i2h[(size_t)Sg*Bg*FH3*HW];  // 212 MB (once), fp16
__device__ __align__(16) __half g_whi[(size_t)Bg*HW*KPAD];    // warped^T hi [b][p][k]
__device__ __align__(16) __half g_Ahi[(size_t)FH3*KPAD];      // w_ret hi [m][k]
// fconv inputs: per-step slots [Sg][Bg][p][112] (hi only)
__device__ __align__(16) __half g_inhi[(size_t)Sg*Bg*HW*CH];
__device__ __align__(16) __half g_wfhi[7*25*32*16];           // [chunk][tap][oc][16]
// f (1-term) [b][p][32]
__device__ __align__(16) __half g_fhi[(size_t)Bg*HW*32];
// flows weights [chunk2][tap25][oc32][16] (oc>=10 zero)
__device__ __align__(16) __half g_w2hi[2*25*32*16];
// i2h weights [ocg3][tap9][oc96][8] hi/lo
__device__ __align__(16) __half g_w3hi[3*9*96*8];
__device__ __align__(16) __half g_w3lo[3*9*96*8];

__device__ __forceinline__ float leaky(float v){ return v > 0.f ? v : 0.2f*v; }
__device__ __forceinline__ float sigm(float v){ return 1.f/(1.f + expf(-v)); }

__device__ __forceinline__ uint32_t smem_u32(const void* p){
    uint32_t a;
    asm("{ .reg .u64 t; cvta.to.shared.u64 t, %1; cvt.u32.u64 %0, t; }" : "=r"(a) : "l"(p));
    return a;
}
__device__ __forceinline__ void ldm_x4(uint32_t* r, uint32_t addr){
    asm volatile("ldmatrix.sync.aligned.m8n8.x4.shared.b16 {%0,%1,%2,%3}, [%4];"
        : "=r"(r[0]), "=r"(r[1]), "=r"(r[2]), "=r"(r[3]) : "r"(addr));
}
__device__ __forceinline__ void ldm_x2(uint32_t* r, uint32_t addr){
    asm volatile("ldmatrix.sync.aligned.m8n8.x2.shared.b16 {%0,%1}, [%2];"
        : "=r"(r[0]), "=r"(r[1]) : "r"(addr));
}
#define MMA_F16(c, a, b) \
    asm volatile("mma.sync.aligned.m16n8k16.row.col.f32.f16.f16.f32 " \
        "{%0,%1,%2,%3}, {%4,%5,%6,%7}, {%8,%9}, {%0,%1,%2,%3};" \
        : "+f"((c)[0]), "+f"((c)[1]), "+f"((c)[2]), "+f"((c)[3]) \
        : "r"((a)[0]), "r"((a)[1]), "r"((a)[2]), "r"((a)[3]), \
          "r"((b)[0]), "r"((b)[1]))
#define MMA_F16_K8(c, a, b) \
    asm volatile("mma.sync.aligned.m16n8k8.row.col.f32.f16.f16.f32 " \
        "{%0,%1,%2,%3}, {%4,%5}, {%6}, {%0,%1,%2,%3};" \
        : "+f"((c)[0]), "+f"((c)[1]), "+f"((c)[2]), "+f"((c)[3]) \
        : "r"((a)[0]), "r"((a)[1]), "r"(b))
#define CPA16(sm, gp) asm volatile("cp.async.ca.shared.global [%0], [%1], 16;" :: "r"(sm), "l"(gp))
#define CPA_COMMIT()  asm volatile("cp.async.commit_group;" ::: "memory")

__device__ __forceinline__ uint32_t pack2(float v0, float v1){
    __half2 hp = __halves2half2(__float2half(v0), __float2half(v1));
    return *reinterpret_cast<uint32_t*>(&hp);
}

// ============================================================
// k_prepX (once): pack x channels (hi) for ALL step slots, zero pad,
// slot-0 h channels from h0.
// ============================================================
__global__ void k_prepX(const float* __restrict__ inputs, const float* __restrict__ h0){
    int idx = blockIdx.x*blockDim.x + threadIdx.x;
    if (idx >= Sg*Bg*HW) return;
    int p = idx % HW, b = (idx/HW) % Bg, t = idx/(HW*Bg);
    size_t base = ((size_t)(t*Bg + b)*HW + p)*CH;
    const float* xp = inputs + ((size_t)(t*Bg + b)*CIN)*HW + p;
    uint32_t hw[4];
    #pragma unroll
    for (int q = 0; q < 4; q++)
        hw[q] = pack2(xp[(size_t)(2*q)*HW], xp[(size_t)(2*q+1)*HW]);
    *reinterpret_cast<uint4*>(g_inhi + base) = *reinterpret_cast<uint4*>(hw);
    uint4 z = make_uint4(0,0,0,0);
    *reinterpret_cast<uint4*>(g_inhi + base + 104) = z;
    if (t == 0){
        const float* hp = h0 + (size_t)b*Fch*HW + p;
        for (int g = 0; g < 12; g++){
            #pragma unroll
            for (int q = 0; q < 4; q++)
                hw[q] = pack2(hp[(size_t)(g*8 + 2*q)*HW], hp[(size_t)(g*8 + 2*q+1)*HW]);
            *reinterpret_cast<uint4*>(g_inhi + base + 8 + g*8) = *reinterpret_cast<uint4*>(hw);
        }
    }
}

// ============================================================
// k_prepWall (once): conv-weight repacks (fp16)
// ============================================================
__global__ void k_prepWall(const float* __restrict__ w_i2f, const float* __restrict__ w_h2f,
                           const float* __restrict__ w_fl,  const float* __restrict__ w_i2h){
    int idx = blockIdx.x*blockDim.x + threadIdx.x;
    if (idx < 89600){
        int o = idx;
        int kc = o & 15, oc = (o >> 4) & 31, tap = (o >> 9) % 25, chunk = o / 12800;
        int ch = chunk*16 + kc;
        float v = 0.f;
        if (ch < 8)        v = w_i2f[(oc*8 + ch)*25 + tap];
        else if (ch < 104) v = w_h2f[((size_t)oc*Fch + (ch-8))*25 + tap];
        g_wfhi[o] = __float2half(v);
    } else if (idx < 89600 + 25600){
        int o = idx - 89600;
        int kc = o & 15, oc = (o >> 4) & 31, tap = (o >> 9) % 25, chunk = o / 12800;
        int ch = chunk*16 + kc;
        float v = (oc < 10) ? w_fl[((size_t)oc*32 + ch)*25 + tap] : 0.f;
        g_w2hi[o] = __float2half(v);
    } else if (idx < 89600 + 25600 + 20736){
        int o = idx - 89600 - 25600;
        int ch = o & 7, oc = (o >> 3) % 96, tap = (o/(96*8)) % 9, ocg = o/(9*96*8);
        float v = w_i2h[((size_t)(ocg*96 + oc)*CIN + ch)*9 + tap];
        __half hi = __float2half(v);
        g_w3hi[o] = hi;
        g_w3lo[o] = __float2half(v - __half2float(hi));
    }
}

// ============================================================
// i2h implicit GEMM (m16n8k8, fp16 2-term).
// 2 IMAGES per CTA; launched PER TIMESTEP (4 images) on stream 2.
// grid (48, 2), 256 thr. img = img0 + blockIdx.y*2
// ============================================================
__global__ void __launch_bounds__(256, 2) k_i2hT(int img0, const float* __restrict__ bias){
    __shared__ __half sInH[2][400*8];
    __shared__ __half sWH[9*96*8], sWL[9*96*8];
    uint32_t aIn0 = smem_u32(sInH[0]);
    uint32_t aWH  = smem_u32(sWH),  aWL  = smem_u32(sWL);

    int tid = threadIdx.x, lane = tid & 31, wid = tid >> 5;
    int wm = wid & 3, wn = wid >> 2;
    int y0 = blockIdx.x*2;
    int imgb = img0 + blockIdx.y*2;

    for (int e = tid; e < 800; e += 256){
        int im = e/400, ent = e%400;
        int row = ent/100, cc = ent%100;
        int y = y0 + row - 1, x = cc - 1;
        uint4 vh = make_uint4(0,0,0,0);
        if ((unsigned)y < 96u && (unsigned)x < 96u)
            vh = *reinterpret_cast<const uint4*>(g_inhi + ((size_t)(imgb+im)*HW + y*Ww + x)*CH);
        *reinterpret_cast<uint4*>(sInH[im] + ent*8) = vh;
    }

    #pragma unroll 1
    for (int ocg = 0; ocg < 3; ocg++){
        __syncthreads();
        for (int e = tid; e < 864; e += 256){
            reinterpret_cast<uint4*>(sWH)[e] = reinterpret_cast<const uint4*>(g_w3hi + (size_t)ocg*9*96*8)[e];
            reinterpret_cast<uint4*>(sWL)[e] = reinterpret_cast<const uint4*>(g_w3lo + (size_t)ocg*9*96*8)[e];
        }
        __syncthreads();

        #pragma unroll 1
        for (int im = 0; im < 2; im++){
            uint32_t aInH = aIn0 + (uint32_t)im*(400*8*2);
            float c[3][6][4];
            #pragma unroll
            for (int i = 0; i < 3; i++)
                #pragma unroll
                for (int j = 0; j < 6; j++)
                    #pragma unroll
                    for (int q = 0; q < 4; q++) c[i][j][q] = 0.f;

            #pragma unroll 1
            for (int tap = 0; tap < 9; tap++){
                int dy = tap/3, dx = tap%3;
                uint32_t bh[6], bl[6];
                {
                    ldm_x4(bh, aWH + 2u*(uint32_t)((tap*96 + wn*48 + lane)*8));
                    ldm_x4(bl, aWL + 2u*(uint32_t)((tap*96 + wn*48 + lane)*8));
                    uint32_t a2 = 2u*(uint32_t)((tap*96 + wn*48 + 32 + (lane & 15))*8);
                    ldm_x2(bh + 4, aWH + a2);
                    ldm_x2(bl + 4, aWL + a2);
                }
                uint32_t ah[3][2];
                #pragma unroll
                for (int mi = 0; mi < 3; mi++){
                    int tmi = wm*3 + mi;
                    int r = tmi/6, xb = (tmi%6)*16;
                    uint32_t aoff = 2u*(uint32_t)(((r+dy)*100 + xb + (lane&15) + dx)*8);
                    ldm_x2(ah[mi], aInH + aoff);
                }
                #pragma unroll
                for (int mi = 0; mi < 3; mi++){
                    #pragma unroll
                    for (int j = 0; j < 6; j++){
                        MMA_F16_K8(c[mi][j], ah[mi], bh[j]);
                        MMA_F16_K8(c[mi][j], ah[mi], bl[j]);
                    }
                }
            }

            __half* Ob = g_i2h + (size_t)(imgb+im)*FH3*HW;
            #pragma unroll
            for (int mi = 0; mi < 3; mi++){
                int tmi = wm*3 + mi;
                int r = tmi/6, xb = (tmi%6)*16;
                int p = (y0 + r)*Ww + xb + (lane>>2);
                #pragma unroll
                for (int j = 0; j < 6; j++){
                    int oc = ocg*96 + wn*48 + j*8 + (lane&3)*2;
                    float bv0 = bias[oc], bv1 = bias[oc+1];
                    Ob[(size_t)oc*HW + p]         = __float2half(c[mi][j][0] + bv0);
                    Ob[(size_t)(oc+1)*HW + p]     = __float2half(c[mi][j][1] + bv1);
                    Ob[(size_t)oc*HW + p + 8]     = __float2half(c[mi][j][2] + bv0);
                    Ob[(size_t)(oc+1)*HW + p + 8] = __float2half(c[mi][j][3] + bv1);
                }
            }
        }
    }
}

// ============================================================
// fconv implicit GEMM — 1-term fp16. CTA = 2 rows x 96 px, N=32.
// ============================================================
#define FSM_BYTES ((14400 + 12800)*2)

__global__ void __launch_bounds__(256, 2) k_fconv(int t,
                                                  const float* __restrict__ b_i2f,
                                                  const float* __restrict__ b_h2f){
    extern __shared__ __half sm[];
    __half* sInH = sm;
    __half* sWH  = sm + 14400;
    uint32_t aInH = smem_u32(sInH), aWH = smem_u32(sWH);

    int tid = threadIdx.x, lane = tid & 31, wid = tid >> 5;
    int wm = wid & 3, wn = wid >> 2;
    int y0 = blockIdx.x*2, b = blockIdx.y;
    size_t slot = (size_t)(t*Bg + b)*HW;

    float c[3][2][4];
    #pragma unroll
    for (int i = 0; i < 3; i++)
        #pragma unroll
        for (int j = 0; j < 2; j++)
            #pragma unroll
            for (int q = 0; q < 4; q++) c[i][j][q] = 0.f;

    for (int chunk = 0; chunk < 7; chunk++){
        __syncthreads();
        for (int e = tid; e < 1200; e += 256){
            int ent = e >> 1, half_ = e & 1;
            int row = ent/100, cc = ent%100;
            int y = y0 + row - 2, x = cc - 2;
            uint4 vh = make_uint4(0,0,0,0);
            if ((unsigned)y < 96u && (unsigned)x < 96u){
                size_t off = (slot + y*Ww + x)*CH + chunk*16 + half_*8;
                vh = *reinterpret_cast<const uint4*>(g_inhi + off);
            }
            *reinterpret_cast<uint4*>(sInH + ent*24 + half_*8) = vh;
        }
        for (int e = tid; e < 1600; e += 256){
            reinterpret_cast<uint4*>(sWH)[e] = reinterpret_cast<const uint4*>(g_wfhi + chunk*12800)[e];
        }
        __syncthreads();

        #pragma unroll 1
        for (int tap = 0; tap < 25; tap++){
            int dy = tap/5, dx = tap%5;
            uint32_t bh[4];
            uint32_t boff = 2u*(uint32_t)((tap*32 + wn*16 + (lane&7) + ((lane>>4)&1)*8)*16
                                          + ((lane>>3)&1)*8);
            ldm_x4(bh, aWH + boff);
            uint32_t ah[3][4];
            #pragma unroll
            for (int mi = 0; mi < 3; mi++){
                int tmi = wm*3 + mi;
                int r = tmi/6, xb = (tmi%6)*16;
                uint32_t aoff = 2u*(uint32_t)(((r+dy)*100 + xb + (lane&15) + dx)*24
                                              + (lane>>4)*8);
                ldm_x4(ah[mi], aInH + aoff);
            }
            #pragma unroll
            for (int mi = 0; mi < 3; mi++){
                #pragma unroll
                for (int j = 0; j < 2; j++){
                    MMA_F16(c[mi][j], ah[mi], &bh[j*2]);
                }
            }
        }
    }

    #pragma unroll
    for (int mi = 0; mi < 3; mi++){
        int tmi = wm*3 + mi;
        int r = tmi/6, xb = (tmi%6)*16;
        int gp = (y0 + r)*Ww + xb + (lane>>2);
        #pragma unroll
        for (int j = 0; j < 2; j++){
            int oc = wn*16 + j*8 + (lane&3)*2;
            float bb0 = b_i2f[oc]   + b_h2f[oc];
            float bb1 = b_i2f[oc+1] + b_h2f[oc+1];
            *reinterpret_cast<uint32_t*>(g_fhi + ((size_t)b*HW + gp)*32 + oc)
                = pack2(leaky(c[mi][j][0] + bb0), leaky(c[mi][j][1] + bb1));
            *reinterpret_cast<uint32_t*>(g_fhi + ((size_t)b*HW + gp + 8)*32 + oc)
                = pack2(leaky(c[mi][j][2] + bb0), leaky(c[mi][j][3] + bb1));
        }
    }
}

// ============================================================
// flowsT + FUSED warp. grid (48, B), 256 thr
// ============================================================
__global__ void __launch_bounds__(256, 2) k_flowsW(int t, const float* __restrict__ b_fl){
    extern __shared__ __half sm[];
    __half* sInH = sm;
    __half* sWH  = sm + 14400;
    uint32_t aInH = smem_u32(sInH), aWH = smem_u32(sWH);

    int tid = threadIdx.x, lane = tid & 31, wid = tid >> 5;
    int wm = wid & 3, wn = wid >> 2;
    int y0 = blockIdx.x*2, b = blockIdx.y;

    float c[3][2][4];
    #pragma unroll
    for (int i = 0; i < 3; i++)
        #pragma unroll
        for (int j = 0; j < 2; j++)
            #pragma unroll
            for (int q = 0; q < 4; q++) c[i][j][q] = 0.f;

    for (int chunk = 0; chunk < 2; chunk++){
        __syncthreads();
        for (int e = tid; e < 1200; e += 256){
            int ent = e >> 1, half_ = e & 1;
            int row = ent/100, cc = ent%100;
            int y = y0 + row - 2, x = cc - 2;
            uint4 vh = make_uint4(0,0,0,0);
            if ((unsigned)y < 96u && (unsigned)x < 96u){
                size_t off = ((size_t)b*HW + y*Ww + x)*32 + chunk*16 + half_*8;
                vh = *reinterpret_cast<const uint4*>(g_fhi + off);
            }
            *reinterpret_cast<uint4*>(sInH + ent*24 + half_*8) = vh;
        }
        for (int e = tid; e < 1600; e += 256){
            reinterpret_cast<uint4*>(sWH)[e] = reinterpret_cast<const uint4*>(g_w2hi + chunk*12800)[e];
        }
        __syncthreads();

        #pragma unroll 1
        for (int tap = 0; tap < 25; tap++){
            int dy = tap/5, dx = tap%5;
            uint32_t bh[4];
            uint32_t boff = 2u*(uint32_t)((tap*32 + wn*16 + (lane&7) + ((lane>>4)&1)*8)*16
                                          + ((lane>>3)&1)*8);
            ldm_x4(bh, aWH + boff);
            uint32_t ah[3][4];
            #pragma unroll
            for (int mi = 0; mi < 3; mi++){
                int tmi = wm*3 + mi;
                int r = tmi/6, xb = (tmi%6)*16;
                uint32_t aoff = 2u*(uint32_t)(((r+dy)*100 + xb + (lane&15) + dx)*24
                                              + (lane>>4)*8);
                ldm_x4(ah[mi], aInH + aoff);
            }
            #pragma unroll
            for (int mi = 0; mi < 3; mi++){
                #pragma unroll
                for (int j = 0; j < 2; j++){
                    MMA_F16(c[mi][j], ah[mi], &bh[j*2]);
                }
            }
        }
    }

    // ---- stage flows into smem [192 px][10] (aliases sInH) ----
    __syncthreads();
    float* sFl = reinterpret_cast<float*>(sm);
    #pragma unroll
    for (int mi = 0; mi < 3; mi++){
        int tmi = wm*3 + mi;
        int r = tmi/6, xb = (tmi%6)*16;
        int pl = r*96 + xb + (lane>>2);
        #pragma unroll
        for (int j = 0; j < 2; j++){
            int oc = wn*16 + j*8 + (lane&3)*2;
            if (oc < 10){
                float bv0 = b_fl[oc], bv1 = b_fl[oc+1];
                sFl[pl*10 + oc]         = c[mi][j][0] + bv0;
                sFl[pl*10 + oc + 1]     = c[mi][j][1] + bv1;
                sFl[(pl+8)*10 + oc]     = c[mi][j][2] + bv0;
                sFl[(pl+8)*10 + oc + 1] = c[mi][j][3] + bv1;
            }
        }
    }
    __syncthreads();

    // ---- fused warp: 960 tasks = 192 px x 5 links ----
    const __half* hb = g_inhi + (size_t)(t*Bg + b)*HW*CH + 8;
    const float scg = 96.0f/95.0f;
    for (int task = tid; task < 960; task += 256){
        int px = task/5, l = task%5;
        int y = y0 + px/96, x = px%96;
        float fx = sFl[px*10 + 2*l];
        float fy = sFl[px*10 + 2*l + 1];
        float ix = ((float)x - fx)*scg - 0.5f;
        float iy = ((float)y - fy)*scg - 0.5f;
        float fx0 = floorf(ix), fy0 = floorf(iy);
        int ix0 = (int)fx0, iy0 = (int)fy0;
        int ix1 = ix0 + 1, iy1 = iy0 + 1;
        float wx1 = ix - fx0, wy1 = iy - fy0;
        float wx0 = 1.f - wx1, wy0 = 1.f - wy1;
        float mx0 = (ix0 >= 0 && ix0 < Ww) ? 1.f : 0.f;
        float mx1 = (ix1 >= 0 && ix1 < Ww) ? 1.f : 0.f;
        float my0 = (iy0 >= 0 && iy0 < Hh) ? 1.f : 0.f;
        float my1 = (iy1 >= 0 && iy1 < Hh) ? 1.f : 0.f;
        int cx0 = min(max(ix0, 0), Ww-1), cx1 = min(max(ix1, 0), Ww-1);
        int cy0 = min(max(iy0, 0), Hh-1), cy1 = min(max(iy1, 0), Hh-1);
        float w00 = wy0*wx0*my0*mx0, w01 = wy0*wx1*my0*mx1;
        float w10 = wy1*wx0*my1*mx0, w11 = wy1*wx1*my1*mx1;
        const __half* p00 = hb + (size_t)(cy0*Ww + cx0)*CH;
        const __half* p01 = hb + (size_t)(cy0*Ww + cx1)*CH;
        const __half* p10 = hb + (size_t)(cy1*Ww + cx0)*CH;
        const __half* p11 = hb + (size_t)(cy1*Ww + cx1)*CH;
        __half* op = g_whi + ((size_t)b*HW + y*Ww + x)*KPAD + (size_t)l*Fch;
        #pragma unroll 1
        for (int cg = 0; cg < 12; cg++){
            uint4 v00 = *reinterpret_cast<const uint4*>(p00 + cg*8);
            uint4 v01 = *reinterpret_cast<const uint4*>(p01 + cg*8);
            uint4 v10 = *reinterpret_cast<const uint4*>(p10 + cg*8);
            uint4 v11 = *reinterpret_cast<const uint4*>(p11 + cg*8);
            const uint32_t* a00 = reinterpret_cast<const uint32_t*>(&v00);
            const uint32_t* a01 = reinterpret_cast<const uint32_t*>(&v01);
            const uint32_t* a10 = reinterpret_cast<const uint32_t*>(&v10);
            const uint32_t* a11 = reinterpret_cast<const uint32_t*>(&v11);
            uint32_t outw[4];
            #pragma unroll
            for (int q = 0; q < 4; q++){
                float2 f00 = __half22float2(*reinterpret_cast<const __half2*>(&a00[q]));
                float2 f01 = __half22float2(*reinterpret_cast<const __half2*>(&a01[q]));
                float2 f10 = __half22float2(*reinterpret_cast<const __half2*>(&a10[q]));
                float2 f11 = __half22float2(*reinterpret_cast<const __half2*>(&a11[q]));
                float r0 = w00*f00.x + w01*f01.x + w10*f10.x + w11*f11.x;
                float r1 = w00*f00.y + w01*f01.y + w10*f10.y + w11*f11.y;
                outw[q] = pack2(r0, r1);
            }
            *reinterpret_cast<uint4*>(op + cg*8) = *reinterpret_cast<uint4*>(outw);
        }
    }
}

// ============================================================
// prep: w_ret hi (288 x 480, stride KPAD) fp16
// ============================================================
__global__ void k_prepA(const float* __restrict__ w_ret){
    int idx = blockIdx.x*blockDim.x + threadIdx.x;
    if (idx >= FH3*KPAD) return;
    int m = idx / KPAD, k = idx % KPAD;
    float v = (k < K1) ? w_ret[m*K1 + k] : 0.f;
    g_Ahi[idx] = __float2half(v);
}

// ============================================================
// FUSED h2h GEMM (1-term fp16) + GRU gates.
// grid (72, B), 256 thr, dyn smem 66.6 KB
// ============================================================
#define TS 40
#define H2_ABUF (288*TS)
#define H2_BBUF (128*TS)
#define H2_SMEM ((2*H2_ABUF + 2*H2_BBUF)*2)   // 66560 B

__global__ void __launch_bounds__(256, 1) k_h2hg(int t,
                                                 const float* __restrict__ bias,
                                                 const float* __restrict__ hprev,
                                                 float* __restrict__ hnext,
                                                 int pack){
    extern __shared__ __half sm[];
    __half* sAh = sm;
    __half* sBh = sm + 2*H2_ABUF;
    uint32_t aSh = smem_u32(sAh), aBh = smem_u32(sBh);

    int tid = threadIdx.x, lane = tid & 31, wid = tid >> 5;
    int wm = wid & 1, wn = wid >> 1;
    int n0 = blockIdx.x*128, b = blockIdx.y;

    const __half* Bh = g_whi + ((size_t)b*HW + n0)*KPAD;

    int arow = wm*48 + (lane & 15);
    int acol = (lane >> 4) * 8;
    int brow = wn*32 + (lane & 7) + ((lane >> 4) & 1)*8;
    int bcol = ((lane >> 3) & 1) * 8;

    float c[3][3][4][4];
    #pragma unroll
    for (int mt = 0; mt < 3; mt++)
        #pragma unroll
        for (int i = 0; i < 3; i++)
            #pragma unroll
            for (int j = 0; j < 4; j++)
                #pragma unroll
                for (int q = 0; q < 4; q++) c[mt][i][j][q] = 0.f;

    #define H2G_STAGE(chunk, buf) do { \
        uint32_t sbA = (uint32_t)(buf)*(H2_ABUF*2); \
        uint32_t sbB = (uint32_t)(buf)*(H2_BBUF*2); \
        for (int e = tid; e < 1152; e += 256){ \
            int r = e >> 2, u = e & 3; \
            size_t goff = (size_t)r*KPAD + (chunk)*32 + u*8; \
            uint32_t soff = sbA + (uint32_t)(r*TS + u*8)*2u; \
            CPA16(aSh + soff, g_Ahi + goff); \
        } \
        for (int e = tid; e < 512; e += 256){ \
            int r = e >> 2, u = e & 3; \
            size_t goff = (size_t)r*KPAD + (chunk)*32 + u*8; \
            uint32_t soff = sbB + (uint32_t)(r*TS + u*8)*2u; \
            CPA16(aBh + soff, Bh + goff); \
        } \
        CPA_COMMIT(); \
    } while(0)

    H2G_STAGE(0, 0);
    for (int chunk = 0; chunk < 15; chunk++){
        if (chunk + 1 < 15){
            H2G_STAGE(chunk + 1, (chunk + 1) & 1);
            asm volatile("cp.async.wait_group 1;" ::: "memory");
        } else {
            asm volatile("cp.async.wait_group 0;" ::: "memory");
        }
        __syncthreads();

        uint32_t sbA = (uint32_t)(chunk & 1)*(H2_ABUF*2);
        uint32_t sbB = (uint32_t)(chunk & 1)*(H2_BBUF*2);
        #pragma unroll
        for (int ks = 0; ks < 2; ks++){
            int kc = ks*16;
            uint32_t bh[2][4];
            #pragma unroll
            for (int jp = 0; jp < 2; jp++){
                uint32_t off = sbB + 2u*((brow + jp*16)*TS + kc + bcol);
                ldm_x4(bh[jp], aBh + off);
            }
            #pragma unroll
            for (int mt = 0; mt < 3; mt++){
                uint32_t ah[3][4];
                #pragma unroll
                for (int mi = 0; mi < 3; mi++){
                    uint32_t off = sbA + 2u*((mt*96 + arow + mi*16)*TS + kc + acol);
                    ldm_x4(ah[mi], aSh + off);
                }
                #pragma unroll
                for (int mi = 0; mi < 3; mi++){
                    #pragma unroll
                    for (int j = 0; j < 4; j++){
                        uint32_t* fh = &bh[j >> 1][(j & 1)*2];
                        MMA_F16(c[mt][mi][j], ah[mi], fh);
                    }
                }
            }
        }
        __syncthreads();
    }

    // ---- fused GRU gate epilogue ----
    __syncthreads();
    float* sF = reinterpret_cast<float*>(sm);   // [128 px][stride 100]

    const __half* i2hb = g_i2h + (size_t)(t*Bg + b)*FH3*HW;
    const float* hpb  = hprev + (size_t)b*Fch*HW;
    float* hnb        = hnext + (size_t)b*Fch*HW;

    #pragma unroll
    for (int mi = 0; mi < 3; mi++){
        int fc0 = wm*48 + mi*16 + (lane >> 2);
        #pragma unroll
        for (int j = 0; j < 4; j++){
            int pl = wn*32 + (lane & 3)*2 + j*8;
            int p = n0 + pl;
            #pragma unroll
            for (int half_ = 0; half_ < 2; half_++){
                int fc = fc0 + half_*8;
                int q0 = half_*2;
                float rb = bias[fc], ub = bias[96 + fc], mb = bias[192 + fc];
                float2 i2r = __half22float2(*reinterpret_cast<const __half2*>(i2hb + (size_t)fc*HW + p));
                float2 i2u = __half22float2(*reinterpret_cast<const __half2*>(i2hb + (size_t)(96+fc)*HW + p));
                float2 i2m = __half22float2(*reinterpret_cast<const __half2*>(i2hb + (size_t)(192+fc)*HW + p));
                float2 hpv = *reinterpret_cast<const float2*>(hpb + (size_t)fc*HW + p);
                float nh[2];
                #pragma unroll
                for (int s = 0; s < 2; s++){
                    float hr = c[0][mi][j][q0+s] + rb;
                    float hu = c[1][mi][j][q0+s] + ub;
                    float hm = c[2][mi][j][q0+s] + mb;
                    float ir = s ? i2r.y : i2r.x;
                    float iu = s ? i2u.y : i2u.x;
                    float im = s ? i2m.y : i2m.x;
                    float hp = s ? hpv.y : hpv.x;
                    float reset  = sigm(ir + hr);
                    float update = sigm(iu + hu);
                    float newmem = leaky(im + reset*hm);
                    nh[s] = update*hp + (1.f - update)*newmem;
                }
                float2 wv; wv.x = nh[0]; wv.y = nh[1];
                *reinterpret_cast<float2*>(hnb + (size_t)fc*HW + p) = wv;
                sF[pl*100 + fc]     = nh[0];
                sF[(pl+1)*100 + fc] = nh[1];
            }
        }
    }
    __syncthreads();
    if (pack){
        size_t slotn = (size_t)((t+1)*Bg + b)*HW;
        for (int e = tid; e < 128*12; e += 256){
            int pl = e/12, u = e%12;
            const float* src = sF + pl*100 + u*8;
            uint32_t hw[4];
            #pragma unroll
            for (int q = 0; q < 4; q++)
                hw[q] = pack2(src[2*q], src[2*q+1]);
            size_t off = (slotn + n0 + pl)*CH + 8 + u*8;
            *reinterpret_cast<uint4*>(g_inhi + off) = *reinterpret_cast<uint4*>(hw);
        }
    }
}

// ============================================================
extern "C" void kernel_launch(void* const* d_in, const int* in_sizes, int n_in,
                              void* d_out, int out_size){
    const float* inputs = (const float*)d_in[0];
    const float* h0     = (const float*)d_in[1];
    const float* w_i2h  = (const float*)d_in[2];
    const float* b_i2h  = (const float*)d_in[3];
    const float* w_i2f  = (const float*)d_in[4];
    const float* b_i2f  = (const float*)d_in[5];
    const float* w_h2f  = (const float*)d_in[6];
    const float* b_h2f  = (const float*)d_in[7];
    const float* w_fl   = (const float*)d_in[8];
    const float* b_fl   = (const float*)d_in[9];
    const float* w_ret  = (const float*)d_in[10];
    const float* b_ret  = (const float*)d_in[11];
    float* out = (float*)d_out;

    // lazy one-time setup (first call is the un-captured correctness run;
    // creating streams/events during capture is illegal, so guard)
    static cudaStream_t s2 = nullptr;
    static cudaEvent_t evRoot = nullptr;
    static cudaEvent_t evI[Sg];
    if (!s2){
        cudaStreamCreateWithFlags(&s2, cudaStreamNonBlocking);
        cudaEventCreateWithFlags(&evRoot, cudaEventDisableTiming);
        for (int t = 0; t < Sg; t++)
            cudaEventCreateWithFlags(&evI[t], cudaEventDisableTiming);
        cudaFuncSetAttribute(k_fconv,  cudaFuncAttributeMaxDynamicSharedMemorySize, FSM_BYTES);
        cudaFuncSetAttribute(k_flowsW, cudaFuncAttributeMaxDynamicSharedMemorySize, FSM_BYTES);
        cudaFuncSetAttribute(k_h2hg,   cudaFuncAttributeMaxDynamicSharedMemorySize, H2_SMEM);
    }

    // prep on default stream (i2hT depends on prepX + prepWall)
    k_prepX   <<<(Sg*Bg*HW + 255)/256, 256>>>(inputs, h0);
    k_prepWall<<<(89600 + 25600 + 20736 + 255)/256, 256>>>(w_i2f, w_h2f, w_fl, w_i2h);
    k_prepA   <<<(FH3*KPAD + 255)/256, 256>>>(w_ret);

    // fork: i2h chunks per timestep on s2, overlapping the step loop
    cudaEventRecord(evRoot, 0);
    cudaStreamWaitEvent(s2, evRoot, 0);
    for (int t = 0; t < Sg; t++){
        k_i2hT<<<dim3(48, 2), 256, 0, s2>>>(t*Bg, b_i2h);
        cudaEventRecord(evI[t], s2);
    }

    for (int t = 0; t < Sg; t++){
        const float* h = (t == 0) ? h0 : out + (size_t)(t-1)*STEP_ELEMS;
        float* hn = out + (size_t)t*STEP_ELEMS;

        k_fconv <<<dim3(48, Bg), 256, FSM_BYTES>>>(t, b_i2f, b_h2f);
        k_flowsW<<<dim3(48, Bg), 256, FSM_BYTES>>>(t, b_fl);
        cudaStreamWaitEvent(0, evI[t], 0);   // join: i2h[t] ready
        k_h2hg  <<<dim3(HW/128, Bg), 256, H2_SMEM>>>(t, b_ret, h, hn, (t < Sg-1) ? 1 : 0);
    }

    const size_t OUT_SEQ = (size_t)Sg*STEP_ELEMS;
    if ((size_t)out_size >= OUT_SEQ + STEP_ELEMS){
        cudaMemcpyAsync(out + OUT_SEQ, out + (size_t)(Sg-1)*STEP_ELEMS,
                        (size_t)STEP_ELEMS*sizeof(float),
                        cudaMemcpyDeviceToDevice);
    }
}